// round 11
// baseline (speedup 1.0000x reference)
#include <cuda_runtime.h>
#include <cuda_bf16.h>
#include <cstdint>

// ---------------------------------------------------------------------------
// Problem constants: b=4, n=4096, D=512, H=8, dh=64, M=256, l=16, 6 iters,
// conv k=33, eps=1e-5
// ---------------------------------------------------------------------------
#define NB   (4*4096*512)
#define MM   (32*256*256)
#define MD   (32*256*64)

__device__ float g_xn[NB];
__device__ float g_q[NB];
__device__ float g_k[NB];
__device__ float g_v[NB];
__device__ float g_ql[MD];
__device__ float g_kl[MD];
__device__ float g_a2[MM];
__device__ float g_z0[MM];
__device__ float g_t1[MM];   // Y ping / flash1 split-K O partials
__device__ float g_t2[MM];   // W2 scratch / flash1 split-K m/l partials
__device__ float g_t3[MM];   // Y pong
__device__ float g_w40[MM];
__device__ float g_w41[MM];
__device__ float g_w42[MM];
__device__ float g_w43[MM];
__device__ float g_w44[MM];
__device__ float g_w[MD];
__device__ float g_w2[MD];
__device__ float g_u[MD];
__device__ float g_r3[MD];
__device__ float g_u5[MD];
__device__ float g_attn[NB];
__device__ float g_attn2[NB];
__device__ float g_red[2];

__device__ __forceinline__ float f2tf(float x) {
    uint32_t u;
    asm("cvt.rna.tf32.f32 %0, %1;" : "=r"(u) : "f"(x));
    return __uint_as_float(u);
}

// ---------------------------------------------------------------------------
// LayerNorm (standalone — fusing it into QKV staging regressed in R10)
// ---------------------------------------------------------------------------
__global__ void ln_kernel(const float* __restrict__ x, const float* __restrict__ w,
                          const float* __restrict__ bb, float* __restrict__ out) {
    int row = blockIdx.x;
    const float* xr = x + (size_t)row * 512;
    float* orow = out + (size_t)row * 512;
    int t = threadIdx.x;
    float v[4];
    float s = 0.f;
#pragma unroll
    for (int i = 0; i < 4; i++) { v[i] = xr[t + 128*i]; s += v[i]; }
#pragma unroll
    for (int o = 16; o; o >>= 1) s += __shfl_xor_sync(0xffffffffu, s, o);
    __shared__ float red[4];
    if ((t & 31) == 0) red[t >> 5] = s;
    __syncthreads();
    float mean = (red[0]+red[1]+red[2]+red[3]) * (1.f/512.f);
    float vs = 0.f;
#pragma unroll
    for (int i = 0; i < 4; i++) { float d = v[i]-mean; vs += d*d; }
#pragma unroll
    for (int o = 16; o; o >>= 1) vs += __shfl_xor_sync(0xffffffffu, vs, o);
    __syncthreads();
    if ((t & 31) == 0) red[t >> 5] = vs;
    __syncthreads();
    float var = (red[0]+red[1]+red[2]+red[3]) * (1.f/512.f);
    float rstd = rsqrtf(var + 1e-5f);
#pragma unroll
    for (int i = 0; i < 4; i++) {
        int c = t + 128*i;
        orow[c] = (v[i]-mean)*rstd*w[c] + bb[c];
    }
}

// ---------------------------------------------------------------------------
// TF32 GEMM (proven): block 128x128, BK=16, 8 warps 64x32, occ 2.
// EPI 0: QKV scatter. EPI 1: bias + residual.
// ---------------------------------------------------------------------------
template<int EPI, int LDA, int LDB, int KD>
__global__ __launch_bounds__(256, 2) void mma_gemm(
        const float* __restrict__ A, const float* __restrict__ B,
        float* __restrict__ C0, float* __restrict__ C1, float* __restrict__ C2,
        const float* __restrict__ e0, const float* __restrict__ e1) {
    __shared__ float Asm[2][128*20];
    __shared__ float Bsm[2][16*136];
    int tid = threadIdx.x;
    int lane = tid & 31, wid = tid >> 5;
    int wm = wid & 1, wn = wid >> 1;
    int g = lane >> 2, t4 = lane & 3;
    int row0 = blockIdx.y * 128, col0 = blockIdx.x * 128;
    int arow = tid >> 1, akq = (tid & 1) * 8;
    int bkr = tid >> 4, bnc = (tid & 15) * 8;

    {
        const float* ap = A + (size_t)(row0 + arow) * LDA + akq;
        float4 a0 = *(const float4*)ap;
        float4 a1 = *(const float4*)(ap + 4);
        float* as = &Asm[0][arow*20 + akq];
        as[0]=f2tf(a0.x); as[1]=f2tf(a0.y); as[2]=f2tf(a0.z); as[3]=f2tf(a0.w);
        as[4]=f2tf(a1.x); as[5]=f2tf(a1.y); as[6]=f2tf(a1.z); as[7]=f2tf(a1.w);
        const float* bp = B + (size_t)bkr * LDB + col0 + bnc;
        float4 b0 = *(const float4*)bp;
        float4 b1 = *(const float4*)(bp + 4);
        float* bs = &Bsm[0][bkr*136 + bnc];
        bs[0]=f2tf(b0.x); bs[1]=f2tf(b0.y); bs[2]=f2tf(b0.z); bs[3]=f2tf(b0.w);
        bs[4]=f2tf(b1.x); bs[5]=f2tf(b1.y); bs[6]=f2tf(b1.z); bs[7]=f2tf(b1.w);
    }
    __syncthreads();

    float c[4][4][4];
#pragma unroll
    for (int i=0;i<4;i++)
#pragma unroll
        for (int j=0;j<4;j++)
#pragma unroll
            for (int h=0;h<4;h++) c[i][j][h]=0.f;

    const int NIT = KD / 16;
    for (int it = 0; it < NIT; it++) {
        int buf = it & 1;
        float4 pa0, pa1, pb0, pb1;
        if (it + 1 < NIT) {
            int k0 = (it + 1) * 16;
            const float* ap = A + (size_t)(row0 + arow) * LDA + k0 + akq;
            pa0 = *(const float4*)ap;
            pa1 = *(const float4*)(ap + 4);
            const float* bp = B + (size_t)(k0 + bkr) * LDB + col0 + bnc;
            pb0 = *(const float4*)bp;
            pb1 = *(const float4*)(bp + 4);
        }
#pragma unroll
        for (int ks = 0; ks < 16; ks += 8) {
            uint32_t af[4][4], bf[4][2];
#pragma unroll
            for (int i = 0; i < 4; i++) {
                int r0i = (wm*64 + i*16 + g) * 20 + ks + t4;
                int r1i = r0i + 8*20;
                af[i][0] = __float_as_uint(Asm[buf][r0i]);
                af[i][1] = __float_as_uint(Asm[buf][r1i]);
                af[i][2] = __float_as_uint(Asm[buf][r0i + 4]);
                af[i][3] = __float_as_uint(Asm[buf][r1i + 4]);
            }
#pragma unroll
            for (int j = 0; j < 4; j++) {
                int nc2 = wn*32 + j*8 + g;
                bf[j][0] = __float_as_uint(Bsm[buf][(ks + t4)*136 + nc2]);
                bf[j][1] = __float_as_uint(Bsm[buf][(ks + t4 + 4)*136 + nc2]);
            }
#pragma unroll
            for (int i = 0; i < 4; i++)
#pragma unroll
                for (int j = 0; j < 4; j++) {
                    asm volatile(
                        "mma.sync.aligned.m16n8k8.row.col.f32.tf32.tf32.f32 "
                        "{%0,%1,%2,%3}, {%4,%5,%6,%7}, {%8,%9}, {%0,%1,%2,%3};\n"
                        : "+f"(c[i][j][0]), "+f"(c[i][j][1]),
                          "+f"(c[i][j][2]), "+f"(c[i][j][3])
                        : "r"(af[i][0]), "r"(af[i][1]), "r"(af[i][2]), "r"(af[i][3]),
                          "r"(bf[j][0]), "r"(bf[j][1]));
                }
        }
        if (it + 1 < NIT) {
            int nb = buf ^ 1;
            float* as = &Asm[nb][arow*20 + akq];
            as[0]=f2tf(pa0.x); as[1]=f2tf(pa0.y); as[2]=f2tf(pa0.z); as[3]=f2tf(pa0.w);
            as[4]=f2tf(pa1.x); as[5]=f2tf(pa1.y); as[6]=f2tf(pa1.z); as[7]=f2tf(pa1.w);
            float* bs = &Bsm[nb][bkr*136 + bnc];
            bs[0]=f2tf(pb0.x); bs[1]=f2tf(pb0.y); bs[2]=f2tf(pb0.z); bs[3]=f2tf(pb0.w);
            bs[4]=f2tf(pb1.x); bs[5]=f2tf(pb1.y); bs[6]=f2tf(pb1.z); bs[7]=f2tf(pb1.w);
        }
        __syncthreads();
    }

#pragma unroll
    for (int i = 0; i < 4; i++) {
#pragma unroll
        for (int j = 0; j < 4; j++) {
#pragma unroll
            for (int h = 0; h < 2; h++) {
                int r = row0 + wm*64 + i*16 + g + h*8;
                int cc = col0 + wn*32 + j*8 + 2*t4;
                float v0 = c[i][j][h*2+0], v1 = c[i][j][h*2+1];
                if (EPI == 0) {
                    int b4 = r >> 12, nn = r & 4095;
                    int which = cc >> 9, cs = cc & 511;
                    int hh = cs >> 6, dh = cs & 63;
                    size_t di = ((size_t)(b4*8+hh)*4096 + nn)*64 + dh;
                    if (which == 0) {
                        *(float2*)&C0[di] = make_float2(v0*0.125f, v1*0.125f);
                    } else if (which == 1) {
                        *(float2*)&C1[di] = make_float2(v0, v1);
                    } else {
                        *(float2*)&C2[di] = make_float2(v0, v1);
                    }
                } else {
                    size_t di = (size_t)r*512 + cc;
                    float2 bias = *(const float2*)&e0[cc];
                    float2 xr = *(const float2*)&e1[di];
                    *(float2*)&C0[di] = make_float2(v0+bias.x+xr.x, v1+bias.y+xr.y);
                }
            }
        }
    }
}

// ---------------------------------------------------------------------------
// TF32 pinv GEMM, 128x64 tile -> grid (4,2,32)=256 CTAs, occ 2 (was 128 CTAs,
// occ 1 at 128x128 — no second CTA to hide staging latency).
// C = cA*A + cAB*(A@B), all [32][256][256].
// 8 warps: wm=wid&3 (32 rows each), wn=wid>>2 (32 cols each).
// ---------------------------------------------------------------------------
__global__ __launch_bounds__(256, 2) void mma_pinv64(
        const float* __restrict__ A, const float* __restrict__ B,
        float* __restrict__ C, float cA, float cAB) {
    __shared__ float Asm[2][128*20];
    __shared__ float Bsm[2][16*72];
    int tid = threadIdx.x;
    int lane = tid & 31, wid = tid >> 5;
    int wm = wid & 3, wn = wid >> 2;
    int g = lane >> 2, t4 = lane & 3;
    int row0 = blockIdx.y * 128, col0 = blockIdx.x * 64;
    const float* Ag = A + (size_t)blockIdx.z * 65536;
    const float* Bg = B + (size_t)blockIdx.z * 65536;
    float* Cg = C + (size_t)blockIdx.z * 65536;
    int arow = tid >> 1, akq = (tid & 1) * 8;
    int bkr = tid >> 4, bnc = (tid & 15) * 4;

    {
        const float* ap = Ag + (size_t)(row0 + arow) * 256 + akq;
        float4 a0 = *(const float4*)ap;
        float4 a1 = *(const float4*)(ap + 4);
        float* as = &Asm[0][arow*20 + akq];
        as[0]=f2tf(a0.x); as[1]=f2tf(a0.y); as[2]=f2tf(a0.z); as[3]=f2tf(a0.w);
        as[4]=f2tf(a1.x); as[5]=f2tf(a1.y); as[6]=f2tf(a1.z); as[7]=f2tf(a1.w);
        float4 bv = *(const float4*)(Bg + (size_t)bkr * 256 + col0 + bnc);
        float* bs = &Bsm[0][bkr*72 + bnc];
        bs[0]=f2tf(bv.x); bs[1]=f2tf(bv.y); bs[2]=f2tf(bv.z); bs[3]=f2tf(bv.w);
    }
    __syncthreads();

    float c[2][4][4];
#pragma unroll
    for (int i=0;i<2;i++)
#pragma unroll
        for (int j=0;j<4;j++)
#pragma unroll
            for (int h=0;h<4;h++) c[i][j][h]=0.f;

    const int NIT = 16;
    for (int it = 0; it < NIT; it++) {
        int buf = it & 1;
        float4 pa0, pa1, pb;
        if (it + 1 < NIT) {
            int k0 = (it + 1) * 16;
            const float* ap = Ag + (size_t)(row0 + arow) * 256 + k0 + akq;
            pa0 = *(const float4*)ap;
            pa1 = *(const float4*)(ap + 4);
            pb = *(const float4*)(Bg + (size_t)(k0 + bkr) * 256 + col0 + bnc);
        }
#pragma unroll
        for (int ks = 0; ks < 16; ks += 8) {
            uint32_t af[2][4], bf[4][2];
#pragma unroll
            for (int i = 0; i < 2; i++) {
                int r0i = (wm*32 + i*16 + g) * 20 + ks + t4;
                int r1i = r0i + 8*20;
                af[i][0] = __float_as_uint(Asm[buf][r0i]);
                af[i][1] = __float_as_uint(Asm[buf][r1i]);
                af[i][2] = __float_as_uint(Asm[buf][r0i + 4]);
                af[i][3] = __float_as_uint(Asm[buf][r1i + 4]);
            }
#pragma unroll
            for (int j = 0; j < 4; j++) {
                int nc2 = wn*32 + j*8 + g;
                bf[j][0] = __float_as_uint(Bsm[buf][(ks + t4)*72 + nc2]);
                bf[j][1] = __float_as_uint(Bsm[buf][(ks + t4 + 4)*72 + nc2]);
            }
#pragma unroll
            for (int i = 0; i < 2; i++)
#pragma unroll
                for (int j = 0; j < 4; j++) {
                    asm volatile(
                        "mma.sync.aligned.m16n8k8.row.col.f32.tf32.tf32.f32 "
                        "{%0,%1,%2,%3}, {%4,%5,%6,%7}, {%8,%9}, {%0,%1,%2,%3};\n"
                        : "+f"(c[i][j][0]), "+f"(c[i][j][1]),
                          "+f"(c[i][j][2]), "+f"(c[i][j][3])
                        : "r"(af[i][0]), "r"(af[i][1]), "r"(af[i][2]), "r"(af[i][3]),
                          "r"(bf[j][0]), "r"(bf[j][1]));
                }
        }
        if (it + 1 < NIT) {
            int nb = buf ^ 1;
            float* as = &Asm[nb][arow*20 + akq];
            as[0]=f2tf(pa0.x); as[1]=f2tf(pa0.y); as[2]=f2tf(pa0.z); as[3]=f2tf(pa0.w);
            as[4]=f2tf(pa1.x); as[5]=f2tf(pa1.y); as[6]=f2tf(pa1.z); as[7]=f2tf(pa1.w);
            float* bs = &Bsm[nb][bkr*72 + bnc];
            bs[0]=f2tf(pb.x); bs[1]=f2tf(pb.y); bs[2]=f2tf(pb.z); bs[3]=f2tf(pb.w);
        }
        __syncthreads();
    }

#pragma unroll
    for (int i = 0; i < 2; i++)
#pragma unroll
        for (int j = 0; j < 4; j++)
#pragma unroll
            for (int h = 0; h < 2; h++) {
                int r = row0 + wm*32 + i*16 + g + h*8;
                int cc = col0 + wn*32 + j*8 + 2*t4;
                float v0 = cAB * c[i][j][h*2+0];
                float v1 = cAB * c[i][j][h*2+1];
                if (cA != 0.f) {
                    float2 ae = *(const float2*)&Ag[(size_t)r*256 + cc];
                    v0 += cA * ae.x; v1 += cA * ae.y;
                }
                *(float2*)&Cg[(size_t)r*256 + cc] = make_float2(v0, v1);
            }
}

// ---------------------------------------------------------------------------
// TF32 MMA narrow GEMM: C = cB*B + cAB*(A@B), A [32][256][256], B,C [32][256][64].
// ---------------------------------------------------------------------------
__global__ __launch_bounds__(256, 2) void mma_nar_kernel(
        const float* __restrict__ A, const float* __restrict__ B,
        float* __restrict__ C, float cB, float cAB) {
    __shared__ float Asm[2][128*20];
    __shared__ float Bsm[2][16*72];
    int tid = threadIdx.x;
    int lane = tid & 31, wid = tid >> 5;
    int wm = wid & 3, wn = wid >> 2;
    int g = lane >> 2, t4 = lane & 3;
    int row0 = blockIdx.y * 128;
    const float* Ag = A + (size_t)blockIdx.z * 65536;
    const float* Bg = B + (size_t)blockIdx.z * 16384;
    float* Cg = C + (size_t)blockIdx.z * 16384;
    int arow = tid >> 1, akq = (tid & 1) * 8;
    int bkr = tid >> 4, bnc = (tid & 15) * 4;

    {
        const float* ap = Ag + (size_t)(row0 + arow) * 256 + akq;
        float4 a0 = *(const float4*)ap;
        float4 a1 = *(const float4*)(ap + 4);
        float* as = &Asm[0][arow*20 + akq];
        as[0]=f2tf(a0.x); as[1]=f2tf(a0.y); as[2]=f2tf(a0.z); as[3]=f2tf(a0.w);
        as[4]=f2tf(a1.x); as[5]=f2tf(a1.y); as[6]=f2tf(a1.z); as[7]=f2tf(a1.w);
        float4 bv = *(const float4*)(Bg + (size_t)bkr * 64 + bnc);
        float* bs = &Bsm[0][bkr*72 + bnc];
        bs[0]=f2tf(bv.x); bs[1]=f2tf(bv.y); bs[2]=f2tf(bv.z); bs[3]=f2tf(bv.w);
    }
    __syncthreads();

    float c[2][4][4];
#pragma unroll
    for (int i=0;i<2;i++)
#pragma unroll
        for (int j=0;j<4;j++)
#pragma unroll
            for (int h=0;h<4;h++) c[i][j][h]=0.f;

    const int NIT = 16;
    for (int it = 0; it < NIT; it++) {
        int buf = it & 1;
        float4 pa0, pa1, pb;
        if (it + 1 < NIT) {
            int k0 = (it + 1) * 16;
            const float* ap = Ag + (size_t)(row0 + arow) * 256 + k0 + akq;
            pa0 = *(const float4*)ap;
            pa1 = *(const float4*)(ap + 4);
            pb = *(const float4*)(Bg + (size_t)(k0 + bkr) * 64 + bnc);
        }
#pragma unroll
        for (int ks = 0; ks < 16; ks += 8) {
            uint32_t af[2][4], bf[4][2];
#pragma unroll
            for (int i = 0; i < 2; i++) {
                int r0i = (wm*32 + i*16 + g) * 20 + ks + t4;
                int r1i = r0i + 8*20;
                af[i][0] = __float_as_uint(Asm[buf][r0i]);
                af[i][1] = __float_as_uint(Asm[buf][r1i]);
                af[i][2] = __float_as_uint(Asm[buf][r0i + 4]);
                af[i][3] = __float_as_uint(Asm[buf][r1i + 4]);
            }
#pragma unroll
            for (int j = 0; j < 4; j++) {
                int nc2 = wn*32 + j*8 + g;
                bf[j][0] = __float_as_uint(Bsm[buf][(ks + t4)*72 + nc2]);
                bf[j][1] = __float_as_uint(Bsm[buf][(ks + t4 + 4)*72 + nc2]);
            }
#pragma unroll
            for (int i = 0; i < 2; i++)
#pragma unroll
                for (int j = 0; j < 4; j++) {
                    asm volatile(
                        "mma.sync.aligned.m16n8k8.row.col.f32.tf32.tf32.f32 "
                        "{%0,%1,%2,%3}, {%4,%5,%6,%7}, {%8,%9}, {%0,%1,%2,%3};\n"
                        : "+f"(c[i][j][0]), "+f"(c[i][j][1]),
                          "+f"(c[i][j][2]), "+f"(c[i][j][3])
                        : "r"(af[i][0]), "r"(af[i][1]), "r"(af[i][2]), "r"(af[i][3]),
                          "r"(bf[j][0]), "r"(bf[j][1]));
                }
        }
        if (it + 1 < NIT) {
            int nb = buf ^ 1;
            float* as = &Asm[nb][arow*20 + akq];
            as[0]=f2tf(pa0.x); as[1]=f2tf(pa0.y); as[2]=f2tf(pa0.z); as[3]=f2tf(pa0.w);
            as[4]=f2tf(pa1.x); as[5]=f2tf(pa1.y); as[6]=f2tf(pa1.z); as[7]=f2tf(pa1.w);
            float* bs = &Bsm[nb][bkr*72 + bnc];
            bs[0]=f2tf(pb.x); bs[1]=f2tf(pb.y); bs[2]=f2tf(pb.z); bs[3]=f2tf(pb.w);
        }
        __syncthreads();
    }

#pragma unroll
    for (int i = 0; i < 2; i++)
#pragma unroll
        for (int j = 0; j < 4; j++)
#pragma unroll
            for (int h = 0; h < 2; h++) {
                int r = row0 + wm*32 + i*16 + g + h*8;
                int cc = wn*32 + j*8 + 2*t4;
                float v0 = cAB * c[i][j][h*2+0];
                float v1 = cAB * c[i][j][h*2+1];
                if (cB != 0.f) {
                    float2 be = *(const float2*)&Bg[(size_t)r*64 + cc];
                    v0 += cB * be.x; v1 += cB * be.y;
                }
                *(float2*)&Cg[(size_t)r*64 + cc] = make_float2(v0, v1);
            }
}

// ---------------------------------------------------------------------------
// u5 = 13*w - 15*r1 + 7*r2 - r3  (elementwise, MD elems)
// ---------------------------------------------------------------------------
__global__ void comb4_kernel(const float* __restrict__ w, const float* __restrict__ r1,
                             const float* __restrict__ r2, const float* __restrict__ r3,
                             float* __restrict__ u5) {
    int i = blockIdx.x * 256 + threadIdx.x;
    u5[i] = 13.f*w[i] - 15.f*r1[i] + 7.f*r2[i] - r3[i];
}

// ---------------------------------------------------------------------------
// TF32 MMA a2 = softmax(q_l @ k_l^T)
// ---------------------------------------------------------------------------
#define A2_KS   8704
#define A2_RM   26112
#define A2_RS   26624
#define SMEM_A2 (27136*4)
__global__ __launch_bounds__(256, 1) void a2_tc_kernel(
        const float* __restrict__ ql, const float* __restrict__ kl,
        float* __restrict__ a2) {
    extern __shared__ float sm2[];
    float* Qs = sm2;
    float* Ks = sm2 + A2_KS;
    float (*redm)[4] = (float(*)[4])(sm2 + A2_RM);
    float (*reds)[4] = (float(*)[4])(sm2 + A2_RS);

    int tid = threadIdx.x;
    int lane = tid & 31, wid = tid >> 5;
    int wm = wid & 1, wn = wid >> 1;
    int g = lane >> 2, t4 = lane & 3;
    int bh = blockIdx.y;
    int row0 = blockIdx.x * 128;
    const float* qb = ql + ((size_t)bh*256 + row0) * 64;
    const float* kb = kl + (size_t)bh*256*64;

    for (int i = tid*4; i < 8192; i += 1024) {
        float4 qv = *(const float4*)&qb[i];
        int r = i >> 6, cc = i & 63;
        float* qs = &Qs[r*68 + cc];
        qs[0]=f2tf(qv.x); qs[1]=f2tf(qv.y); qs[2]=f2tf(qv.z); qs[3]=f2tf(qv.w);
    }
    for (int i = tid*4; i < 16384; i += 1024) {
        float4 kv = *(const float4*)&kb[i];
        int r = i >> 6, cc = i & 63;
        float* ks = &Ks[r*68 + cc];
        ks[0]=f2tf(kv.x); ks[1]=f2tf(kv.y); ks[2]=f2tf(kv.z); ks[3]=f2tf(kv.w);
    }
    __syncthreads();

    float c[4][8][4];
#pragma unroll
    for (int i=0;i<4;i++)
#pragma unroll
        for (int j=0;j<8;j++)
#pragma unroll
            for (int h=0;h<4;h++) c[i][j][h]=0.f;

#pragma unroll
    for (int ks = 0; ks < 64; ks += 8) {
        uint32_t af[4][4], bf[8][2];
#pragma unroll
        for (int i = 0; i < 4; i++) {
            int r0i = (wm*64 + i*16 + g)*68 + ks + t4;
            int r1i = r0i + 8*68;
            af[i][0] = __float_as_uint(Qs[r0i]);
            af[i][1] = __float_as_uint(Qs[r1i]);
            af[i][2] = __float_as_uint(Qs[r0i + 4]);
            af[i][3] = __float_as_uint(Qs[r1i + 4]);
        }
#pragma unroll
        for (int j = 0; j < 8; j++) {
            int cr = (wn*64 + j*8 + g)*68 + ks + t4;
            bf[j][0] = __float_as_uint(Ks[cr]);
            bf[j][1] = __float_as_uint(Ks[cr + 4]);
        }
#pragma unroll
        for (int i = 0; i < 4; i++)
#pragma unroll
            for (int j = 0; j < 8; j++) {
                asm volatile(
                    "mma.sync.aligned.m16n8k8.row.col.f32.tf32.tf32.f32 "
                    "{%0,%1,%2,%3}, {%4,%5,%6,%7}, {%8,%9}, {%0,%1,%2,%3};\n"
                    : "+f"(c[i][j][0]), "+f"(c[i][j][1]),
                      "+f"(c[i][j][2]), "+f"(c[i][j][3])
                    : "r"(af[i][0]), "r"(af[i][1]), "r"(af[i][2]), "r"(af[i][3]),
                      "r"(bf[j][0]), "r"(bf[j][1]));
            }
    }

    float pm[4][2];
#pragma unroll
    for (int i=0;i<4;i++)
#pragma unroll
        for (int h=0;h<2;h++) {
            float m = c[i][0][2*h];
#pragma unroll
            for (int j=0;j<8;j++) {
                m = fmaxf(m, c[i][j][2*h]);
                m = fmaxf(m, c[i][j][2*h+1]);
            }
#pragma unroll
            for (int off = 1; off <= 2; off <<= 1)
                m = fmaxf(m, __shfl_xor_sync(0xffffffffu, m, off));
            pm[i][h] = m;
        }
    if (t4 == 0) {
#pragma unroll
        for (int i=0;i<4;i++)
#pragma unroll
            for (int h=0;h<2;h++)
                redm[wm*64 + i*16 + g + h*8][wn] = pm[i][h];
    }
    __syncthreads();

    float psum[4][2];
#pragma unroll
    for (int i=0;i<4;i++)
#pragma unroll
        for (int h=0;h<2;h++) {
            int r = wm*64 + i*16 + g + h*8;
            float m = fmaxf(fmaxf(redm[r][0], redm[r][1]),
                            fmaxf(redm[r][2], redm[r][3]));
            float s = 0.f;
#pragma unroll
            for (int j=0;j<8;j++) {
                float p0 = __expf(c[i][j][2*h]   - m);
                float p1 = __expf(c[i][j][2*h+1] - m);
                c[i][j][2*h] = p0; c[i][j][2*h+1] = p1;
                s += p0 + p1;
            }
#pragma unroll
            for (int off = 1; off <= 2; off <<= 1)
                s += __shfl_xor_sync(0xffffffffu, s, off);
            psum[i][h] = s;
        }
    if (t4 == 0) {
#pragma unroll
        for (int i=0;i<4;i++)
#pragma unroll
            for (int h=0;h<2;h++)
                reds[wm*64 + i*16 + g + h*8][wn] = psum[i][h];
    }
    __syncthreads();

#pragma unroll
    for (int i=0;i<4;i++)
#pragma unroll
        for (int h=0;h<2;h++) {
            int r = wm*64 + i*16 + g + h*8;
            float inv = 1.f / (reds[r][0]+reds[r][1]+reds[r][2]+reds[r][3]);
            float* orow = a2 + ((size_t)bh*256 + row0 + r) * 256;
#pragma unroll
            for (int j=0;j<8;j++) {
                int cc = wn*64 + j*8 + 2*t4;
                *(float2*)&orow[cc] = make_float2(c[i][j][2*h]*inv, c[i][j][2*h+1]*inv);
            }
        }
}

// ---------------------------------------------------------------------------
// Landmarks (merged q+k)
// ---------------------------------------------------------------------------
__global__ void landmark2_kernel(const float* __restrict__ q, const float* __restrict__ k,
                                 float* __restrict__ ql, float* __restrict__ kl) {
    int gidx = blockIdx.x * 256 + threadIdx.x;
    const float* src = (gidx < 524288) ? q : k;
    float* dst = (gidx < 524288) ? ql : kl;
    int idx = gidx & 524287;
    int dh = idx & 63;
    int mi = (idx >> 6) & 255;
    int bh = idx >> 14;
    const float* p = src + ((size_t)bh*4096 + mi*16)*64 + dh;
    float s = 0.f;
#pragma unroll
    for (int j = 0; j < 16; j++) s += p[j*64];
    dst[idx] = s * 0.0625f;
}

// ---------------------------------------------------------------------------
// pinv scalars: row-sum max == 1 exactly (softmax rows); need col-sum max.
// ---------------------------------------------------------------------------
__global__ void red_init_kernel(float* g) { if (threadIdx.x < 2) g[threadIdx.x] = 0.f; }

__global__ void colsum_kernel(const float* __restrict__ a2, float* __restrict__ gred) {
    int bh = blockIdx.x; int j = threadIdx.x;
    const float* base = a2 + (size_t)bh*65536;
    float s = 0.f;
    for (int i=0;i<256;i++) s += fabsf(base[(size_t)i*256 + j]);
#pragma unroll
    for (int o=16;o;o>>=1) s = fmaxf(s, __shfl_xor_sync(0xffffffffu,s,o));
    __shared__ float red[8];
    if ((j&31)==0) red[j>>5]=s;
    __syncthreads();
    if (j==0) {
        float m = red[0];
#pragma unroll
        for (int u=1;u<8;u++) m = fmaxf(m, red[u]);
        atomicMax((int*)&gred[1], __float_as_int(m));
    }
}

__global__ void zinit_kernel(const float* __restrict__ a2, const float* __restrict__ gred,
                             float* __restrict__ z) {
    int idx = blockIdx.x*256 + threadIdx.x;
    int j = idx & 255, i = (idx>>8) & 255, bh = idx >> 16;
    float inv = 1.f/gred[1];
    z[idx] = a2[((size_t)bh*256 + j)*256 + i] * inv;
}

// ---------------------------------------------------------------------------
// TF32 flash attention with optional split-K
// ---------------------------------------------------------------------------
#define QP 68
#define VP 72
#define OFF_KS   4352
#define OFF_PS   8704
#define OFF_VS   13056
#define OFF_ROWM 17664
#define OFF_ROWL 17728
#define OFF_REDM 17792
#define OFF_REDS 18048
#define SMEM_FLASH_TC ((18304)*4)

__global__ __launch_bounds__(256) void flash_tc_kernel(
        const float* __restrict__ Q, const float* __restrict__ K,
        const float* __restrict__ V, float* __restrict__ O, int nq, int nk,
        int chunk, float* __restrict__ mpart, float* __restrict__ lpart) {
    extern __shared__ float sm[];
    float (*Qs)[QP] = (float(*)[QP])sm;
    float (*Ks)[QP] = (float(*)[QP])(sm + OFF_KS);
    float (*Ps)[QP] = (float(*)[QP])(sm + OFF_PS);
    float (*Vs)[VP] = (float(*)[VP])(sm + OFF_VS);
    float* rowm = sm + OFF_ROWM;
    float* rowl = sm + OFF_ROWL;
    float (*redm)[4] = (float(*)[4])(sm + OFF_REDM);
    float (*reds)[4] = (float(*)[4])(sm + OFF_REDS);

    int tid = threadIdx.x;
    int lane = tid & 31, wid = tid >> 5;
    int wm = wid & 1, wn = wid >> 1;
    int g = lane >> 2, t4 = lane & 3;
    int bh = blockIdx.y;
    int q0 = blockIdx.x * 64;
    size_t koff = (size_t)blockIdx.z * chunk * 64;
    const float* Qb = Q + ((size_t)bh*nq + q0) * 64;
    const float* Kb = K + (size_t)bh*nk*64 + koff;
    const float* Vb = V + (size_t)bh*nk*64 + koff;

    {
        int r = tid >> 2, kc = (tid & 3) * 16;
#pragma unroll
        for (int ii = 0; ii < 4; ii++) {
            float4 qv = *(const float4*)&Qb[(size_t)r*64 + kc + ii*4];
            Qs[r][kc+ii*4+0]=f2tf(qv.x); Qs[r][kc+ii*4+1]=f2tf(qv.y);
            Qs[r][kc+ii*4+2]=f2tf(qv.z); Qs[r][kc+ii*4+3]=f2tf(qv.w);
        }
    }
    if (tid < 64) { rowm[tid] = -1e30f; rowl[tid] = 0.f; }
    float o[2][2][4];
#pragma unroll
    for (int i=0;i<2;i++)
#pragma unroll
        for (int j=0;j<2;j++)
#pragma unroll
            for (int h=0;h<4;h++) o[i][j][h]=0.f;
    __syncthreads();

    for (int c0 = 0; c0 < chunk; c0 += 64) {
        {
            int r = tid >> 2, kc = (tid & 3) * 16;
#pragma unroll
            for (int ii = 0; ii < 4; ii++) {
                float4 kv = *(const float4*)&Kb[(size_t)(c0+r)*64 + kc + ii*4];
                Ks[r][kc+ii*4+0]=f2tf(kv.x); Ks[r][kc+ii*4+1]=f2tf(kv.y);
                Ks[r][kc+ii*4+2]=f2tf(kv.z); Ks[r][kc+ii*4+3]=f2tf(kv.w);
                float4 vv = *(const float4*)&Vb[(size_t)(c0+r)*64 + kc + ii*4];
                Vs[r][kc+ii*4+0]=f2tf(vv.x); Vs[r][kc+ii*4+1]=f2tf(vv.y);
                Vs[r][kc+ii*4+2]=f2tf(vv.z); Vs[r][kc+ii*4+3]=f2tf(vv.w);
            }
        }
        __syncthreads();

        float s[2][2][4];
#pragma unroll
        for (int i=0;i<2;i++)
#pragma unroll
            for (int j=0;j<2;j++)
#pragma unroll
                for (int h=0;h<4;h++) s[i][j][h]=0.f;
#pragma unroll
        for (int ks = 0; ks < 64; ks += 8) {
            uint32_t af[2][4], bf[2][2];
#pragma unroll
            for (int i = 0; i < 2; i++) {
                int r = wm*32 + i*16 + g;
                af[i][0] = __float_as_uint(Qs[r][ks+t4]);
                af[i][1] = __float_as_uint(Qs[r+8][ks+t4]);
                af[i][2] = __float_as_uint(Qs[r][ks+t4+4]);
                af[i][3] = __float_as_uint(Qs[r+8][ks+t4+4]);
            }
#pragma unroll
            for (int j = 0; j < 2; j++) {
                int cc = wn*16 + j*8 + g;
                bf[j][0] = __float_as_uint(Ks[cc][ks+t4]);
                bf[j][1] = __float_as_uint(Ks[cc][ks+t4+4]);
            }
#pragma unroll
            for (int i = 0; i < 2; i++)
#pragma unroll
                for (int j = 0; j < 2; j++) {
                    asm volatile(
                        "mma.sync.aligned.m16n8k8.row.col.f32.tf32.tf32.f32 "
                        "{%0,%1,%2,%3}, {%4,%5,%6,%7}, {%8,%9}, {%0,%1,%2,%3};\n"
                        : "+f"(s[i][j][0]), "+f"(s[i][j][1]),
                          "+f"(s[i][j][2]), "+f"(s[i][j][3])
                        : "r"(af[i][0]), "r"(af[i][1]), "r"(af[i][2]), "r"(af[i][3]),
                          "r"(bf[j][0]), "r"(bf[j][1]));
                }
        }

        float pm[2][2];
#pragma unroll
        for (int i=0;i<2;i++)
#pragma unroll
            for (int h=0;h<2;h++)
                pm[i][h] = fmaxf(fmaxf(s[i][0][2*h], s[i][0][2*h+1]),
                                 fmaxf(s[i][1][2*h], s[i][1][2*h+1]));
#pragma unroll
        for (int off = 1; off <= 2; off <<= 1) {
#pragma unroll
            for (int i=0;i<2;i++)
#pragma unroll
                for (int h=0;h<2;h++)
                    pm[i][h] = fmaxf(pm[i][h], __shfl_xor_sync(0xffffffffu, pm[i][h], off));
        }
        if (t4 == 0) {
#pragma unroll
            for (int i=0;i<2;i++)
#pragma unroll
                for (int h=0;h<2;h++)
                    redm[wm*32 + i*16 + g + h*8][wn] = pm[i][h];
        }
        __syncthreads();

        float mnew[2][2], scale[2][2];
#pragma unroll
        for (int i=0;i<2;i++)
#pragma unroll
            for (int h=0;h<2;h++) {
                int r = wm*32 + i*16 + g + h*8;
                float m = fmaxf(fmaxf(redm[r][0], redm[r][1]),
                                fmaxf(redm[r][2], redm[r][3]));
                float mo = rowm[r];
                mnew[i][h] = fmaxf(mo, m);
                scale[i][h] = __expf(mo - mnew[i][h]);
            }

        float psum[2][2] = {{0.f,0.f},{0.f,0.f}};
#pragma unroll
        for (int i=0;i<2;i++)
#pragma unroll
            for (int j=0;j<2;j++)
#pragma unroll
                for (int h=0;h<2;h++) {
                    int r = wm*32 + i*16 + g + h*8;
                    float p0 = __expf(s[i][j][2*h]   - mnew[i][h]);
                    float p1 = __expf(s[i][j][2*h+1] - mnew[i][h]);
                    *(float2*)&Ps[r][wn*16 + j*8 + 2*t4] = make_float2(f2tf(p0), f2tf(p1));
                    psum[i][h] += p0 + p1;
                    o[i][j][2*h]   *= scale[i][h];
                    o[i][j][2*h+1] *= scale[i][h];
                }
#pragma unroll
        for (int off = 1; off <= 2; off <<= 1) {
#pragma unroll
            for (int i=0;i<2;i++)
#pragma unroll
                for (int h=0;h<2;h++)
                    psum[i][h] += __shfl_xor_sync(0xffffffffu, psum[i][h], off);
        }
        if (t4 == 0) {
#pragma unroll
            for (int i=0;i<2;i++)
#pragma unroll
                for (int h=0;h<2;h++)
                    reds[wm*32 + i*16 + g + h*8][wn] = psum[i][h];
        }
        __syncthreads();

        if (wn == 0 && t4 == 0) {
#pragma unroll
            for (int i=0;i<2;i++)
#pragma unroll
                for (int h=0;h<2;h++) {
                    int r = wm*32 + i*16 + g + h*8;
                    float ps = reds[r][0] + reds[r][1] + reds[r][2] + reds[r][3];
                    rowl[r] = rowl[r]*scale[i][h] + ps;
                    rowm[r] = mnew[i][h];
                }
        }

#pragma unroll
        for (int ks = 0; ks < 64; ks += 8) {
            uint32_t af[2][4], bf[2][2];
#pragma unroll
            for (int i = 0; i < 2; i++) {
                int r = wm*32 + i*16 + g;
                af[i][0] = __float_as_uint(Ps[r][ks+t4]);
                af[i][1] = __float_as_uint(Ps[r+8][ks+t4]);
                af[i][2] = __float_as_uint(Ps[r][ks+t4+4]);
                af[i][3] = __float_as_uint(Ps[r+8][ks+t4+4]);
            }
#pragma unroll
            for (int j = 0; j < 2; j++) {
                int cc = wn*16 + j*8 + g;
                bf[j][0] = __float_as_uint(Vs[ks+t4][cc]);
                bf[j][1] = __float_as_uint(Vs[ks+t4+4][cc]);
            }
#pragma unroll
            for (int i = 0; i < 2; i++)
#pragma unroll
                for (int j = 0; j < 2; j++) {
                    asm volatile(
                        "mma.sync.aligned.m16n8k8.row.col.f32.tf32.tf32.f32 "
                        "{%0,%1,%2,%3}, {%4,%5,%6,%7}, {%8,%9}, {%0,%1,%2,%3};\n"
                        : "+f"(o[i][j][0]), "+f"(o[i][j][1]),
                          "+f"(o[i][j][2]), "+f"(o[i][j][3])
                        : "r"(af[i][0]), "r"(af[i][1]), "r"(af[i][2]), "r"(af[i][3]),
                          "r"(bf[j][0]), "r"(bf[j][1]));
                }
        }
        __syncthreads();
    }

    if (lpart != nullptr) {
        float* Ob = O + ((size_t)(blockIdx.z*32 + bh)*nq + q0) * 64;
#pragma unroll
        for (int i=0;i<2;i++)
#pragma unroll
            for (int j=0;j<2;j++)
#pragma unroll
                for (int h=0;h<2;h++) {
                    int r = wm*32 + i*16 + g + h*8;
                    int cc = wn*16 + j*8 + 2*t4;
                    *(float2*)&Ob[(size_t)r*64 + cc] =
                        make_float2(o[i][j][2*h], o[i][j][2*h+1]);
                }
        if (tid < 64) {
            size_t ri = (size_t)(blockIdx.z*32 + bh)*nq + q0 + tid;
            mpart[ri] = rowm[tid];
            lpart[ri] = rowl[tid];
        }
    } else {
        float* Ob = O + ((size_t)bh*nq + q0) * 64;
#pragma unroll
        for (int i=0;i<2;i++)
#pragma unroll
            for (int j=0;j<2;j++)
#pragma unroll
                for (int h=0;h<2;h++) {
                    int r = wm*32 + i*16 + g + h*8;
                    int cc = wn*16 + j*8 + 2*t4;
                    float inv = 1.f / rowl[r];
                    *(float2*)&Ob[(size_t)r*64 + cc] =
                        make_float2(o[i][j][2*h]*inv, o[i][j][2*h+1]*inv);
                }
    }
}

// ---------------------------------------------------------------------------
// Split-K combine
// ---------------------------------------------------------------------------
__global__ void combine_kernel(const float* __restrict__ Op,
                               const float* __restrict__ mp,
                               const float* __restrict__ lp,
                               float* __restrict__ w) {
    int row = blockIdx.x;
    int c = threadIdx.x;
    int bh = row >> 8, qr = row & 255;
    float m0 = mp[(0*32+bh)*256+qr], m1 = mp[(1*32+bh)*256+qr];
    float m2 = mp[(2*32+bh)*256+qr], m3 = mp[(3*32+bh)*256+qr];
    float ms = fmaxf(fmaxf(m0,m1), fmaxf(m2,m3));
    float w0 = __expf(m0-ms), w1 = __expf(m1-ms), w2 = __expf(m2-ms), w3 = __expf(m3-ms);
    float l = w0*lp[(0*32+bh)*256+qr] + w1*lp[(1*32+bh)*256+qr]
            + w2*lp[(2*32+bh)*256+qr] + w3*lp[(3*32+bh)*256+qr];
    float acc = w0*Op[((size_t)(0*32+bh)*256+qr)*64 + c]
              + w1*Op[((size_t)(1*32+bh)*256+qr)*64 + c]
              + w2*Op[((size_t)(2*32+bh)*256+qr)*64 + c]
              + w3*Op[((size_t)(3*32+bh)*256+qr)*64 + c];
    w[((size_t)bh*256+qr)*64 + c] = acc / l;
}

// ---------------------------------------------------------------------------
// Depthwise seq-conv residual + layout transform
// ---------------------------------------------------------------------------
__global__ __launch_bounds__(256) void conv_kernel(
        const float* __restrict__ attn, const float* __restrict__ v,
        const float* __restrict__ cw, float* __restrict__ attn2) {
    __shared__ float vt[96][64];
    __shared__ float wk[33];
    int bh = blockIdx.y; int h = bh & 7; int b4 = bh >> 3;
    int row0 = blockIdx.x * 64;
    int t = threadIdx.x;
    if (t < 33) wk[t] = cw[h*33 + t];
    const float* vb = v + (size_t)bh*4096*64;
#pragma unroll
    for (int i=0;i<6;i++){
        int f = t + i*256;
        int r = f >> 4;
        int c4 = (f & 15) * 4;
        int gr = row0 - 16 + r;
        float4 val = make_float4(0.f,0.f,0.f,0.f);
        if (gr >= 0 && gr < 4096) val = *(const float4*)&vb[(size_t)gr*64 + c4];
        *(float4*)&vt[r][c4] = val;
    }
    __syncthreads();
    int dh = t & 63;
    int rr = t >> 6;
#pragma unroll
    for (int q=0;q<16;q++){
        int lr = rr + q*4;
        float acc = attn[((size_t)bh*4096 + row0 + lr)*64 + dh];
#pragma unroll
        for (int s=0;s<33;s++) acc += wk[s]*vt[lr+s][dh];
        attn2[((size_t)b4*4096 + row0 + lr)*512 + h*64 + dh] = acc;
    }
}

// ---------------------------------------------------------------------------
// Host orchestration
// ---------------------------------------------------------------------------
extern "C" void kernel_launch(void* const* d_in, const int* in_sizes, int n_in,
                              void* d_out, int out_size) {
    const float* x      = (const float*)d_in[0];
    const float* norm_w = (const float*)d_in[1];
    const float* norm_b = (const float*)d_in[2];
    const float* Wqkv   = (const float*)d_in[3];
    const float* Wout   = (const float*)d_in[4];
    const float* bout   = (const float*)d_in[5];
    const float* conv_w = (const float*)d_in[6];
    float* out = (float*)d_out;

    float *xn,*q,*k,*v,*ql,*kl,*a2,*z0,*t1,*t2,*t3,*w,*w2,*uu,*r3,*u5,*attn,*attn2,*red;
    float *w4s[5];
    cudaGetSymbolAddress((void**)&xn,   g_xn);
    cudaGetSymbolAddress((void**)&q,    g_q);
    cudaGetSymbolAddress((void**)&k,    g_k);
    cudaGetSymbolAddress((void**)&v,    g_v);
    cudaGetSymbolAddress((void**)&ql,   g_ql);
    cudaGetSymbolAddress((void**)&kl,   g_kl);
    cudaGetSymbolAddress((void**)&a2,   g_a2);
    cudaGetSymbolAddress((void**)&z0,   g_z0);
    cudaGetSymbolAddress((void**)&t1,   g_t1);
    cudaGetSymbolAddress((void**)&t2,   g_t2);
    cudaGetSymbolAddress((void**)&t3,   g_t3);
    cudaGetSymbolAddress((void**)&w4s[0], g_w40);
    cudaGetSymbolAddress((void**)&w4s[1], g_w41);
    cudaGetSymbolAddress((void**)&w4s[2], g_w42);
    cudaGetSymbolAddress((void**)&w4s[3], g_w43);
    cudaGetSymbolAddress((void**)&w4s[4], g_w44);
    cudaGetSymbolAddress((void**)&w,    g_w);
    cudaGetSymbolAddress((void**)&w2,   g_w2);
    cudaGetSymbolAddress((void**)&uu,   g_u);
    cudaGetSymbolAddress((void**)&r3,   g_r3);
    cudaGetSymbolAddress((void**)&u5,   g_u5);
    cudaGetSymbolAddress((void**)&attn, g_attn);
    cudaGetSymbolAddress((void**)&attn2,g_attn2);
    cudaGetSymbolAddress((void**)&red,  g_red);

    cudaFuncSetAttribute(flash_tc_kernel, cudaFuncAttributeMaxDynamicSharedMemorySize, SMEM_FLASH_TC);
    cudaFuncSetAttribute(a2_tc_kernel, cudaFuncAttributeMaxDynamicSharedMemorySize, SMEM_A2);

    // 1. LayerNorm
    ln_kernel<<<16384, 128>>>(x, norm_w, norm_b, xn);
    // 2. QKV projection (tf32 MMA, fused scatter + q scale)
    mma_gemm<0,512,1536,512><<<dim3(12,128), 256>>>(
        xn, Wqkv, q, k, v, nullptr, nullptr);
    // 3. landmarks (merged)
    landmark2_kernel<<<4096, 256>>>(q, k, ql, kl);
    // 4. a2 = softmax(q_l k_l^T) (tf32 MMA)
    a2_tc_kernel<<<dim3(2,32), 256, SMEM_A2>>>(ql, kl, a2);
    // 5. pinv init scalar + z0 = s*a2^T
    red_init_kernel<<<1, 32>>>(red);
    colsum_kernel<<<32, 256>>>(a2, red);
    zinit_kernel<<<8192, 256>>>(a2, red, z0);
    // 6. w = softmax(q_l k^T) @ v — split-K x4 flash + combine
    flash_tc_kernel<<<dim3(4,32,4), 256, SMEM_FLASH_TC>>>(
        ql, k, v, t1, 256, 4096, 1024, t2, t2 + 32768);
    combine_kernel<<<8192, 64>>>(t1, t2, t2 + 32768, w);
    // 7. Newton-Schulz pinv, Y-only recurrence, 128x64 tiles (256 CTAs, occ 2):
    //    W2 = Y(7I-Y); W4_i = Y(15I-W2); Y' = 0.25*Y(13I-W4_i)   [it=0..4]
    mma_pinv64<<<dim3(4,2,32), 256>>>(a2, z0, t1, 0.f, 1.f);   // Y0 = a2 @ z0
    float* Y = t1; float* Yn = t3;
    for (int it = 0; it < 5; it++) {
        mma_pinv64<<<dim3(4,2,32), 256>>>(Y, Y, t2, 7.f, -1.f);        // W2
        mma_pinv64<<<dim3(4,2,32), 256>>>(Y, t2, w4s[it], 15.f, -1.f); // W4_i
        mma_pinv64<<<dim3(4,2,32), 256>>>(Y, w4s[it], Yn, 3.25f, -0.25f);
        float* tmp = Y; Y = Yn; Yn = tmp;
    }
    // Y == Y5. Narrow last iteration: r1=Y5 w, r2=Y5 r1, r3=Y5 r2,
    // u5 = 13w - 15 r1 + 7 r2 - r3
    mma_nar_kernel<<<dim3(1,2,32), 256>>>(Y, w,  uu, 0.f, 1.f);   // r1
    mma_nar_kernel<<<dim3(1,2,32), 256>>>(Y, uu, w2, 0.f, 1.f);   // r2
    mma_nar_kernel<<<dim3(1,2,32), 256>>>(Y, w2, r3, 0.f, 1.f);   // r3
    comb4_kernel<<<2048, 256>>>(w, uu, w2, r3, u5);
    // 8. narrow chain down: u_i = 13*u_{i+1} - W4_i @ u_{i+1}
    mma_nar_kernel<<<dim3(1,2,32), 256>>>(w4s[4], u5, uu, 13.f, -1.f);
    mma_nar_kernel<<<dim3(1,2,32), 256>>>(w4s[3], uu, w2, 13.f, -1.f);
    mma_nar_kernel<<<dim3(1,2,32), 256>>>(w4s[2], w2, uu, 13.f, -1.f);
    mma_nar_kernel<<<dim3(1,2,32), 256>>>(w4s[1], uu, w2, 13.f, -1.f);
    mma_nar_kernel<<<dim3(1,2,32), 256>>>(w4s[0], w2, uu, 13.f, -1.f);
    mma_nar_kernel<<<dim3(1,2,32), 256>>>(z0, uu, w2, 0.f, 1.f/4096.f);
    // 9. attn = softmax(q k_l^T) @ w2 (tf32 flash, no split)
    flash_tc_kernel<<<dim3(64,32,1), 256, SMEM_FLASH_TC>>>(
        q, kl, w2, attn, 4096, 256, 256, nullptr, nullptr);
    // 10. conv residual + layout
    conv_kernel<<<dim3(64,32), 256>>>(attn, v, conv_w, attn2);
    // 11. output projection + bias + input residual (tf32 MMA)
    mma_gemm<1,512,512,512><<<dim3(4,128), 256>>>(
        attn2, Wout, out, nullptr, nullptr, bout, x);
}

// round 12
// speedup vs baseline: 1.0406x; 1.0406x over previous
#include <cuda_runtime.h>
#include <cuda_bf16.h>
#include <cstdint>

// ---------------------------------------------------------------------------
// Problem constants: b=4, n=4096, D=512, H=8, dh=64, M=256, l=16, 6 iters,
// conv k=33, eps=1e-5
// ---------------------------------------------------------------------------
#define NB   (4*4096*512)
#define MM   (32*256*256)
#define MD   (32*256*64)

__device__ float g_xn[NB];
__device__ float g_q[NB];
__device__ float g_k[NB];
__device__ float g_v[NB];
__device__ float g_ql[MD];
__device__ float g_kl[MD];
__device__ float g_a2[MM];
__device__ float g_z0[MM];
__device__ float g_t1[MM];   // Y ping / flash1 split-K O partials
__device__ float g_t2[MM];   // W2 scratch / flash1 split-K m/l partials
__device__ float g_t3[MM];   // Y pong
__device__ float g_w40[MM];
__device__ float g_w41[MM];
__device__ float g_w42[MM];
__device__ float g_w43[MM];
__device__ float g_w44[MM];
__device__ float g_w[MD];
__device__ float g_w2[MD];
__device__ float g_u[MD];
__device__ float g_r3[MD];
__device__ float g_u5[MD];
__device__ float g_attn[NB];
__device__ float g_attn2[NB];
__device__ float g_red[2];

__device__ __forceinline__ float f2tf(float x) {
    uint32_t u;
    asm("cvt.rna.tf32.f32 %0, %1;" : "=r"(u) : "f"(x));
    return __uint_as_float(u);
}

// ---------------------------------------------------------------------------
// LayerNorm (standalone — fusion into QKV staging regressed, R10)
// ---------------------------------------------------------------------------
__global__ void ln_kernel(const float* __restrict__ x, const float* __restrict__ w,
                          const float* __restrict__ bb, float* __restrict__ out) {
    int row = blockIdx.x;
    const float* xr = x + (size_t)row * 512;
    float* orow = out + (size_t)row * 512;
    int t = threadIdx.x;
    float v[4];
    float s = 0.f;
#pragma unroll
    for (int i = 0; i < 4; i++) { v[i] = xr[t + 128*i]; s += v[i]; }
#pragma unroll
    for (int o = 16; o; o >>= 1) s += __shfl_xor_sync(0xffffffffu, s, o);
    __shared__ float red[4];
    if ((t & 31) == 0) red[t >> 5] = s;
    __syncthreads();
    float mean = (red[0]+red[1]+red[2]+red[3]) * (1.f/512.f);
    float vs = 0.f;
#pragma unroll
    for (int i = 0; i < 4; i++) { float d = v[i]-mean; vs += d*d; }
#pragma unroll
    for (int o = 16; o; o >>= 1) vs += __shfl_xor_sync(0xffffffffu, vs, o);
    __syncthreads();
    if ((t & 31) == 0) red[t >> 5] = vs;
    __syncthreads();
    float var = (red[0]+red[1]+red[2]+red[3]) * (1.f/512.f);
    float rstd = rsqrtf(var + 1e-5f);
#pragma unroll
    for (int i = 0; i < 4; i++) {
        int c = t + 128*i;
        orow[c] = (v[i]-mean)*rstd*w[c] + bb[c];
    }
}

// ---------------------------------------------------------------------------
// TF32 GEMM (proven): block 128x128, BK=16, 8 warps 64x32, occ 2.
// EPI 0: QKV scatter. EPI 1: bias + residual.
// ---------------------------------------------------------------------------
template<int EPI, int LDA, int LDB, int KD>
__global__ __launch_bounds__(256, 2) void mma_gemm(
        const float* __restrict__ A, const float* __restrict__ B,
        float* __restrict__ C0, float* __restrict__ C1, float* __restrict__ C2,
        const float* __restrict__ e0, const float* __restrict__ e1) {
    __shared__ float Asm[2][128*20];
    __shared__ float Bsm[2][16*136];
    int tid = threadIdx.x;
    int lane = tid & 31, wid = tid >> 5;
    int wm = wid & 1, wn = wid >> 1;
    int g = lane >> 2, t4 = lane & 3;
    int row0 = blockIdx.y * 128, col0 = blockIdx.x * 128;
    int arow = tid >> 1, akq = (tid & 1) * 8;
    int bkr = tid >> 4, bnc = (tid & 15) * 8;

    {
        const float* ap = A + (size_t)(row0 + arow) * LDA + akq;
        float4 a0 = *(const float4*)ap;
        float4 a1 = *(const float4*)(ap + 4);
        float* as = &Asm[0][arow*20 + akq];
        as[0]=f2tf(a0.x); as[1]=f2tf(a0.y); as[2]=f2tf(a0.z); as[3]=f2tf(a0.w);
        as[4]=f2tf(a1.x); as[5]=f2tf(a1.y); as[6]=f2tf(a1.z); as[7]=f2tf(a1.w);
        const float* bp = B + (size_t)bkr * LDB + col0 + bnc;
        float4 b0 = *(const float4*)bp;
        float4 b1 = *(const float4*)(bp + 4);
        float* bs = &Bsm[0][bkr*136 + bnc];
        bs[0]=f2tf(b0.x); bs[1]=f2tf(b0.y); bs[2]=f2tf(b0.z); bs[3]=f2tf(b0.w);
        bs[4]=f2tf(b1.x); bs[5]=f2tf(b1.y); bs[6]=f2tf(b1.z); bs[7]=f2tf(b1.w);
    }
    __syncthreads();

    float c[4][4][4];
#pragma unroll
    for (int i=0;i<4;i++)
#pragma unroll
        for (int j=0;j<4;j++)
#pragma unroll
            for (int h=0;h<4;h++) c[i][j][h]=0.f;

    const int NIT = KD / 16;
    for (int it = 0; it < NIT; it++) {
        int buf = it & 1;
        float4 pa0, pa1, pb0, pb1;
        if (it + 1 < NIT) {
            int k0 = (it + 1) * 16;
            const float* ap = A + (size_t)(row0 + arow) * LDA + k0 + akq;
            pa0 = *(const float4*)ap;
            pa1 = *(const float4*)(ap + 4);
            const float* bp = B + (size_t)(k0 + bkr) * LDB + col0 + bnc;
            pb0 = *(const float4*)bp;
            pb1 = *(const float4*)(bp + 4);
        }
#pragma unroll
        for (int ks = 0; ks < 16; ks += 8) {
            uint32_t af[4][4], bf[4][2];
#pragma unroll
            for (int i = 0; i < 4; i++) {
                int r0i = (wm*64 + i*16 + g) * 20 + ks + t4;
                int r1i = r0i + 8*20;
                af[i][0] = __float_as_uint(Asm[buf][r0i]);
                af[i][1] = __float_as_uint(Asm[buf][r1i]);
                af[i][2] = __float_as_uint(Asm[buf][r0i + 4]);
                af[i][3] = __float_as_uint(Asm[buf][r1i + 4]);
            }
#pragma unroll
            for (int j = 0; j < 4; j++) {
                int nc2 = wn*32 + j*8 + g;
                bf[j][0] = __float_as_uint(Bsm[buf][(ks + t4)*136 + nc2]);
                bf[j][1] = __float_as_uint(Bsm[buf][(ks + t4 + 4)*136 + nc2]);
            }
#pragma unroll
            for (int i = 0; i < 4; i++)
#pragma unroll
                for (int j = 0; j < 4; j++) {
                    asm volatile(
                        "mma.sync.aligned.m16n8k8.row.col.f32.tf32.tf32.f32 "
                        "{%0,%1,%2,%3}, {%4,%5,%6,%7}, {%8,%9}, {%0,%1,%2,%3};\n"
                        : "+f"(c[i][j][0]), "+f"(c[i][j][1]),
                          "+f"(c[i][j][2]), "+f"(c[i][j][3])
                        : "r"(af[i][0]), "r"(af[i][1]), "r"(af[i][2]), "r"(af[i][3]),
                          "r"(bf[j][0]), "r"(bf[j][1]));
                }
        }
        if (it + 1 < NIT) {
            int nb = buf ^ 1;
            float* as = &Asm[nb][arow*20 + akq];
            as[0]=f2tf(pa0.x); as[1]=f2tf(pa0.y); as[2]=f2tf(pa0.z); as[3]=f2tf(pa0.w);
            as[4]=f2tf(pa1.x); as[5]=f2tf(pa1.y); as[6]=f2tf(pa1.z); as[7]=f2tf(pa1.w);
            float* bs = &Bsm[nb][bkr*136 + bnc];
            bs[0]=f2tf(pb0.x); bs[1]=f2tf(pb0.y); bs[2]=f2tf(pb0.z); bs[3]=f2tf(pb0.w);
            bs[4]=f2tf(pb1.x); bs[5]=f2tf(pb1.y); bs[6]=f2tf(pb1.z); bs[7]=f2tf(pb1.w);
        }
        __syncthreads();
    }

#pragma unroll
    for (int i = 0; i < 4; i++) {
#pragma unroll
        for (int j = 0; j < 4; j++) {
#pragma unroll
            for (int h = 0; h < 2; h++) {
                int r = row0 + wm*64 + i*16 + g + h*8;
                int cc = col0 + wn*32 + j*8 + 2*t4;
                float v0 = c[i][j][h*2+0], v1 = c[i][j][h*2+1];
                if (EPI == 0) {
                    int b4 = r >> 12, nn = r & 4095;
                    int which = cc >> 9, cs = cc & 511;
                    int hh = cs >> 6, dh = cs & 63;
                    size_t di = ((size_t)(b4*8+hh)*4096 + nn)*64 + dh;
                    if (which == 0) {
                        *(float2*)&C0[di] = make_float2(v0*0.125f, v1*0.125f);
                    } else if (which == 1) {
                        *(float2*)&C1[di] = make_float2(v0, v1);
                    } else {
                        *(float2*)&C2[di] = make_float2(v0, v1);
                    }
                } else {
                    size_t di = (size_t)r*512 + cc;
                    float2 bias = *(const float2*)&e0[cc];
                    float2 xr = *(const float2*)&e1[di];
                    *(float2*)&C0[di] = make_float2(v0+bias.x+xr.x, v1+bias.y+xr.y);
                }
            }
        }
    }
}

// ---------------------------------------------------------------------------
// TF32 GEMM, pinv variant (proven 128x128): batched over z (stride 65536):
// C0 = cA*A + cAB*(A@B)
// ---------------------------------------------------------------------------
__global__ __launch_bounds__(256, 2) void mma_gemm_pinv(
        const float* __restrict__ A, const float* __restrict__ B,
        float* __restrict__ C0, float cA, float cAB) {
    __shared__ float Asm[2][128*20];
    __shared__ float Bsm[2][16*136];
    int tid = threadIdx.x;
    int lane = tid & 31, wid = tid >> 5;
    int wm = wid & 1, wn = wid >> 1;
    int g = lane >> 2, t4 = lane & 3;
    int row0 = blockIdx.y * 128, col0 = blockIdx.x * 128;
    const float* Ag = A + (size_t)blockIdx.z * 65536;
    const float* Bg = B + (size_t)blockIdx.z * 65536;
    int arow = tid >> 1, akq = (tid & 1) * 8;
    int bkr = tid >> 4, bnc = (tid & 15) * 8;

    {
        const float* ap = Ag + (size_t)(row0 + arow) * 256 + akq;
        float4 a0 = *(const float4*)ap;
        float4 a1 = *(const float4*)(ap + 4);
        float* as = &Asm[0][arow*20 + akq];
        as[0]=f2tf(a0.x); as[1]=f2tf(a0.y); as[2]=f2tf(a0.z); as[3]=f2tf(a0.w);
        as[4]=f2tf(a1.x); as[5]=f2tf(a1.y); as[6]=f2tf(a1.z); as[7]=f2tf(a1.w);
        const float* bp = Bg + (size_t)bkr * 256 + col0 + bnc;
        float4 b0 = *(const float4*)bp;
        float4 b1 = *(const float4*)(bp + 4);
        float* bs = &Bsm[0][bkr*136 + bnc];
        bs[0]=f2tf(b0.x); bs[1]=f2tf(b0.y); bs[2]=f2tf(b0.z); bs[3]=f2tf(b0.w);
        bs[4]=f2tf(b1.x); bs[5]=f2tf(b1.y); bs[6]=f2tf(b1.z); bs[7]=f2tf(b1.w);
    }
    __syncthreads();

    float c[4][4][4];
#pragma unroll
    for (int i=0;i<4;i++)
#pragma unroll
        for (int j=0;j<4;j++)
#pragma unroll
            for (int h=0;h<4;h++) c[i][j][h]=0.f;

    const int NIT = 16;
    for (int it = 0; it < NIT; it++) {
        int buf = it & 1;
        float4 pa0, pa1, pb0, pb1;
        if (it + 1 < NIT) {
            int k0 = (it + 1) * 16;
            const float* ap = Ag + (size_t)(row0 + arow) * 256 + k0 + akq;
            pa0 = *(const float4*)ap;
            pa1 = *(const float4*)(ap + 4);
            const float* bp = Bg + (size_t)(k0 + bkr) * 256 + col0 + bnc;
            pb0 = *(const float4*)bp;
            pb1 = *(const float4*)(bp + 4);
        }
#pragma unroll
        for (int ks = 0; ks < 16; ks += 8) {
            uint32_t af[4][4], bf[4][2];
#pragma unroll
            for (int i = 0; i < 4; i++) {
                int r0i = (wm*64 + i*16 + g) * 20 + ks + t4;
                int r1i = r0i + 8*20;
                af[i][0] = __float_as_uint(Asm[buf][r0i]);
                af[i][1] = __float_as_uint(Asm[buf][r1i]);
                af[i][2] = __float_as_uint(Asm[buf][r0i + 4]);
                af[i][3] = __float_as_uint(Asm[buf][r1i + 4]);
            }
#pragma unroll
            for (int j = 0; j < 4; j++) {
                int nc2 = wn*32 + j*8 + g;
                bf[j][0] = __float_as_uint(Bsm[buf][(ks + t4)*136 + nc2]);
                bf[j][1] = __float_as_uint(Bsm[buf][(ks + t4 + 4)*136 + nc2]);
            }
#pragma unroll
            for (int i = 0; i < 4; i++)
#pragma unroll
                for (int j = 0; j < 4; j++) {
                    asm volatile(
                        "mma.sync.aligned.m16n8k8.row.col.f32.tf32.tf32.f32 "
                        "{%0,%1,%2,%3}, {%4,%5,%6,%7}, {%8,%9}, {%0,%1,%2,%3};\n"
                        : "+f"(c[i][j][0]), "+f"(c[i][j][1]),
                          "+f"(c[i][j][2]), "+f"(c[i][j][3])
                        : "r"(af[i][0]), "r"(af[i][1]), "r"(af[i][2]), "r"(af[i][3]),
                          "r"(bf[j][0]), "r"(bf[j][1]));
                }
        }
        if (it + 1 < NIT) {
            int nb = buf ^ 1;
            float* as = &Asm[nb][arow*20 + akq];
            as[0]=f2tf(pa0.x); as[1]=f2tf(pa0.y); as[2]=f2tf(pa0.z); as[3]=f2tf(pa0.w);
            as[4]=f2tf(pa1.x); as[5]=f2tf(pa1.y); as[6]=f2tf(pa1.z); as[7]=f2tf(pa1.w);
            float* bs = &Bsm[nb][bkr*136 + bnc];
            bs[0]=f2tf(pb0.x); bs[1]=f2tf(pb0.y); bs[2]=f2tf(pb0.z); bs[3]=f2tf(pb0.w);
            bs[4]=f2tf(pb1.x); bs[5]=f2tf(pb1.y); bs[6]=f2tf(pb1.z); bs[7]=f2tf(pb1.w);
        }
        __syncthreads();
    }

#pragma unroll
    for (int i = 0; i < 4; i++) {
#pragma unroll
        for (int j = 0; j < 4; j++) {
#pragma unroll
            for (int h = 0; h < 2; h++) {
                int r = row0 + wm*64 + i*16 + g + h*8;
                int cc = col0 + wn*32 + j*8 + 2*t4;
                float v0 = c[i][j][h*2+0], v1 = c[i][j][h*2+1];
                float2 ae = *(const float2*)&Ag[(size_t)r*256 + cc];
                size_t di = (size_t)blockIdx.z*65536 + (size_t)r*256 + cc;
                *(float2*)&C0[di] = make_float2(cA*ae.x + cAB*v0,
                                                cA*ae.y + cAB*v1);
            }
        }
    }
}

// ---------------------------------------------------------------------------
// TF32 MMA narrow GEMM: C = cB*B + cAB*(A@B), A [32][256][256], B,C [32][256][64].
// ---------------------------------------------------------------------------
__global__ __launch_bounds__(256, 2) void mma_nar_kernel(
        const float* __restrict__ A, const float* __restrict__ B,
        float* __restrict__ C, float cB, float cAB) {
    __shared__ float Asm[2][128*20];
    __shared__ float Bsm[2][16*72];
    int tid = threadIdx.x;
    int lane = tid & 31, wid = tid >> 5;
    int wm = wid & 3, wn = wid >> 2;
    int g = lane >> 2, t4 = lane & 3;
    int row0 = blockIdx.y * 128;
    const float* Ag = A + (size_t)blockIdx.z * 65536;
    const float* Bg = B + (size_t)blockIdx.z * 16384;
    float* Cg = C + (size_t)blockIdx.z * 16384;
    int arow = tid >> 1, akq = (tid & 1) * 8;
    int bkr = tid >> 4, bnc = (tid & 15) * 4;

    {
        const float* ap = Ag + (size_t)(row0 + arow) * 256 + akq;
        float4 a0 = *(const float4*)ap;
        float4 a1 = *(const float4*)(ap + 4);
        float* as = &Asm[0][arow*20 + akq];
        as[0]=f2tf(a0.x); as[1]=f2tf(a0.y); as[2]=f2tf(a0.z); as[3]=f2tf(a0.w);
        as[4]=f2tf(a1.x); as[5]=f2tf(a1.y); as[6]=f2tf(a1.z); as[7]=f2tf(a1.w);
        float4 bv = *(const float4*)(Bg + (size_t)bkr * 64 + bnc);
        float* bs = &Bsm[0][bkr*72 + bnc];
        bs[0]=f2tf(bv.x); bs[1]=f2tf(bv.y); bs[2]=f2tf(bv.z); bs[3]=f2tf(bv.w);
    }
    __syncthreads();

    float c[2][4][4];
#pragma unroll
    for (int i=0;i<2;i++)
#pragma unroll
        for (int j=0;j<4;j++)
#pragma unroll
            for (int h=0;h<4;h++) c[i][j][h]=0.f;

    const int NIT = 16;
    for (int it = 0; it < NIT; it++) {
        int buf = it & 1;
        float4 pa0, pa1, pb;
        if (it + 1 < NIT) {
            int k0 = (it + 1) * 16;
            const float* ap = Ag + (size_t)(row0 + arow) * 256 + k0 + akq;
            pa0 = *(const float4*)ap;
            pa1 = *(const float4*)(ap + 4);
            pb = *(const float4*)(Bg + (size_t)(k0 + bkr) * 64 + bnc);
        }
#pragma unroll
        for (int ks = 0; ks < 16; ks += 8) {
            uint32_t af[2][4], bf[4][2];
#pragma unroll
            for (int i = 0; i < 2; i++) {
                int r0i = (wm*32 + i*16 + g) * 20 + ks + t4;
                int r1i = r0i + 8*20;
                af[i][0] = __float_as_uint(Asm[buf][r0i]);
                af[i][1] = __float_as_uint(Asm[buf][r1i]);
                af[i][2] = __float_as_uint(Asm[buf][r0i + 4]);
                af[i][3] = __float_as_uint(Asm[buf][r1i + 4]);
            }
#pragma unroll
            for (int j = 0; j < 4; j++) {
                int nc2 = wn*32 + j*8 + g;
                bf[j][0] = __float_as_uint(Bsm[buf][(ks + t4)*72 + nc2]);
                bf[j][1] = __float_as_uint(Bsm[buf][(ks + t4 + 4)*72 + nc2]);
            }
#pragma unroll
            for (int i = 0; i < 2; i++)
#pragma unroll
                for (int j = 0; j < 4; j++) {
                    asm volatile(
                        "mma.sync.aligned.m16n8k8.row.col.f32.tf32.tf32.f32 "
                        "{%0,%1,%2,%3}, {%4,%5,%6,%7}, {%8,%9}, {%0,%1,%2,%3};\n"
                        : "+f"(c[i][j][0]), "+f"(c[i][j][1]),
                          "+f"(c[i][j][2]), "+f"(c[i][j][3])
                        : "r"(af[i][0]), "r"(af[i][1]), "r"(af[i][2]), "r"(af[i][3]),
                          "r"(bf[j][0]), "r"(bf[j][1]));
                }
        }
        if (it + 1 < NIT) {
            int nb = buf ^ 1;
            float* as = &Asm[nb][arow*20 + akq];
            as[0]=f2tf(pa0.x); as[1]=f2tf(pa0.y); as[2]=f2tf(pa0.z); as[3]=f2tf(pa0.w);
            as[4]=f2tf(pa1.x); as[5]=f2tf(pa1.y); as[6]=f2tf(pa1.z); as[7]=f2tf(pa1.w);
            float* bs = &Bsm[nb][bkr*72 + bnc];
            bs[0]=f2tf(pb.x); bs[1]=f2tf(pb.y); bs[2]=f2tf(pb.z); bs[3]=f2tf(pb.w);
        }
        __syncthreads();
    }

#pragma unroll
    for (int i = 0; i < 2; i++)
#pragma unroll
        for (int j = 0; j < 4; j++)
#pragma unroll
            for (int h = 0; h < 2; h++) {
                int r = row0 + wm*32 + i*16 + g + h*8;
                int cc = wn*32 + j*8 + 2*t4;
                float v0 = cAB * c[i][j][h*2+0];
                float v1 = cAB * c[i][j][h*2+1];
                if (cB != 0.f) {
                    float2 be = *(const float2*)&Bg[(size_t)r*64 + cc];
                    v0 += cB * be.x; v1 += cB * be.y;
                }
                *(float2*)&Cg[(size_t)r*64 + cc] = make_float2(v0, v1);
            }
}

// ---------------------------------------------------------------------------
// u5 = 13*w - 15*r1 + 7*r2 - r3  (elementwise, MD elems)
// ---------------------------------------------------------------------------
__global__ void comb4_kernel(const float* __restrict__ w, const float* __restrict__ r1,
                             const float* __restrict__ r2, const float* __restrict__ r3,
                             float* __restrict__ u5) {
    int i = blockIdx.x * 256 + threadIdx.x;
    u5[i] = 13.f*w[i] - 15.f*r1[i] + 7.f*r2[i] - r3[i];
}

// ---------------------------------------------------------------------------
// TF32 MMA a2 = softmax(q_l @ k_l^T)
// ---------------------------------------------------------------------------
#define A2_KS   8704
#define A2_RM   26112
#define A2_RS   26624
#define SMEM_A2 (27136*4)
__global__ __launch_bounds__(256, 1) void a2_tc_kernel(
        const float* __restrict__ ql, const float* __restrict__ kl,
        float* __restrict__ a2) {
    extern __shared__ float sm2[];
    float* Qs = sm2;
    float* Ks = sm2 + A2_KS;
    float (*redm)[4] = (float(*)[4])(sm2 + A2_RM);
    float (*reds)[4] = (float(*)[4])(sm2 + A2_RS);

    int tid = threadIdx.x;
    int lane = tid & 31, wid = tid >> 5;
    int wm = wid & 1, wn = wid >> 1;
    int g = lane >> 2, t4 = lane & 3;
    int bh = blockIdx.y;
    int row0 = blockIdx.x * 128;
    const float* qb = ql + ((size_t)bh*256 + row0) * 64;
    const float* kb = kl + (size_t)bh*256*64;

    for (int i = tid*4; i < 8192; i += 1024) {
        float4 qv = *(const float4*)&qb[i];
        int r = i >> 6, cc = i & 63;
        float* qs = &Qs[r*68 + cc];
        qs[0]=f2tf(qv.x); qs[1]=f2tf(qv.y); qs[2]=f2tf(qv.z); qs[3]=f2tf(qv.w);
    }
    for (int i = tid*4; i < 16384; i += 1024) {
        float4 kv = *(const float4*)&kb[i];
        int r = i >> 6, cc = i & 63;
        float* ks = &Ks[r*68 + cc];
        ks[0]=f2tf(kv.x); ks[1]=f2tf(kv.y); ks[2]=f2tf(kv.z); ks[3]=f2tf(kv.w);
    }
    __syncthreads();

    float c[4][8][4];
#pragma unroll
    for (int i=0;i<4;i++)
#pragma unroll
        for (int j=0;j<8;j++)
#pragma unroll
            for (int h=0;h<4;h++) c[i][j][h]=0.f;

#pragma unroll
    for (int ks = 0; ks < 64; ks += 8) {
        uint32_t af[4][4], bf[8][2];
#pragma unroll
        for (int i = 0; i < 4; i++) {
            int r0i = (wm*64 + i*16 + g)*68 + ks + t4;
            int r1i = r0i + 8*68;
            af[i][0] = __float_as_uint(Qs[r0i]);
            af[i][1] = __float_as_uint(Qs[r1i]);
            af[i][2] = __float_as_uint(Qs[r0i + 4]);
            af[i][3] = __float_as_uint(Qs[r1i + 4]);
        }
#pragma unroll
        for (int j = 0; j < 8; j++) {
            int cr = (wn*64 + j*8 + g)*68 + ks + t4;
            bf[j][0] = __float_as_uint(Ks[cr]);
            bf[j][1] = __float_as_uint(Ks[cr + 4]);
        }
#pragma unroll
        for (int i = 0; i < 4; i++)
#pragma unroll
            for (int j = 0; j < 8; j++) {
                asm volatile(
                    "mma.sync.aligned.m16n8k8.row.col.f32.tf32.tf32.f32 "
                    "{%0,%1,%2,%3}, {%4,%5,%6,%7}, {%8,%9}, {%0,%1,%2,%3};\n"
                    : "+f"(c[i][j][0]), "+f"(c[i][j][1]),
                      "+f"(c[i][j][2]), "+f"(c[i][j][3])
                    : "r"(af[i][0]), "r"(af[i][1]), "r"(af[i][2]), "r"(af[i][3]),
                      "r"(bf[j][0]), "r"(bf[j][1]));
            }
    }

    float pm[4][2];
#pragma unroll
    for (int i=0;i<4;i++)
#pragma unroll
        for (int h=0;h<2;h++) {
            float m = c[i][0][2*h];
#pragma unroll
            for (int j=0;j<8;j++) {
                m = fmaxf(m, c[i][j][2*h]);
                m = fmaxf(m, c[i][j][2*h+1]);
            }
#pragma unroll
            for (int off = 1; off <= 2; off <<= 1)
                m = fmaxf(m, __shfl_xor_sync(0xffffffffu, m, off));
            pm[i][h] = m;
        }
    if (t4 == 0) {
#pragma unroll
        for (int i=0;i<4;i++)
#pragma unroll
            for (int h=0;h<2;h++)
                redm[wm*64 + i*16 + g + h*8][wn] = pm[i][h];
    }
    __syncthreads();

    float psum[4][2];
#pragma unroll
    for (int i=0;i<4;i++)
#pragma unroll
        for (int h=0;h<2;h++) {
            int r = wm*64 + i*16 + g + h*8;
            float m = fmaxf(fmaxf(redm[r][0], redm[r][1]),
                            fmaxf(redm[r][2], redm[r][3]));
            float s = 0.f;
#pragma unroll
            for (int j=0;j<8;j++) {
                float p0 = __expf(c[i][j][2*h]   - m);
                float p1 = __expf(c[i][j][2*h+1] - m);
                c[i][j][2*h] = p0; c[i][j][2*h+1] = p1;
                s += p0 + p1;
            }
#pragma unroll
            for (int off = 1; off <= 2; off <<= 1)
                s += __shfl_xor_sync(0xffffffffu, s, off);
            psum[i][h] = s;
        }
    if (t4 == 0) {
#pragma unroll
        for (int i=0;i<4;i++)
#pragma unroll
            for (int h=0;h<2;h++)
                reds[wm*64 + i*16 + g + h*8][wn] = psum[i][h];
    }
    __syncthreads();

#pragma unroll
    for (int i=0;i<4;i++)
#pragma unroll
        for (int h=0;h<2;h++) {
            int r = wm*64 + i*16 + g + h*8;
            float inv = 1.f / (reds[r][0]+reds[r][1]+reds[r][2]+reds[r][3]);
            float* orow = a2 + ((size_t)bh*256 + row0 + r) * 256;
#pragma unroll
            for (int j=0;j<8;j++) {
                int cc = wn*64 + j*8 + 2*t4;
                *(float2*)&orow[cc] = make_float2(c[i][j][2*h]*inv, c[i][j][2*h+1]*inv);
            }
        }
}

// ---------------------------------------------------------------------------
// Landmarks (merged q+k)
// ---------------------------------------------------------------------------
__global__ void landmark2_kernel(const float* __restrict__ q, const float* __restrict__ k,
                                 float* __restrict__ ql, float* __restrict__ kl) {
    int gidx = blockIdx.x * 256 + threadIdx.x;
    const float* src = (gidx < 524288) ? q : k;
    float* dst = (gidx < 524288) ? ql : kl;
    int idx = gidx & 524287;
    int dh = idx & 63;
    int mi = (idx >> 6) & 255;
    int bh = idx >> 14;
    const float* p = src + ((size_t)bh*4096 + mi*16)*64 + dh;
    float s = 0.f;
#pragma unroll
    for (int j = 0; j < 16; j++) s += p[j*64];
    dst[idx] = s * 0.0625f;
}

// ---------------------------------------------------------------------------
// pinv scalars: row-sum max == 1 exactly (softmax rows); need col-sum max.
// ---------------------------------------------------------------------------
__global__ void red_init_kernel(float* g) { if (threadIdx.x < 2) g[threadIdx.x] = 0.f; }

__global__ void colsum_kernel(const float* __restrict__ a2, float* __restrict__ gred) {
    int bh = blockIdx.x; int j = threadIdx.x;
    const float* base = a2 + (size_t)bh*65536;
    float s = 0.f;
    for (int i=0;i<256;i++) s += fabsf(base[(size_t)i*256 + j]);
#pragma unroll
    for (int o=16;o;o>>=1) s = fmaxf(s, __shfl_xor_sync(0xffffffffu,s,o));
    __shared__ float red[8];
    if ((j&31)==0) red[j>>5]=s;
    __syncthreads();
    if (j==0) {
        float m = red[0];
#pragma unroll
        for (int u=1;u<8;u++) m = fmaxf(m, red[u]);
        atomicMax((int*)&gred[1], __float_as_int(m));
    }
}

__global__ void zinit_kernel(const float* __restrict__ a2, const float* __restrict__ gred,
                             float* __restrict__ z) {
    int idx = blockIdx.x*256 + threadIdx.x;
    int j = idx & 255, i = (idx>>8) & 255, bh = idx >> 16;
    float inv = 1.f/gred[1];
    z[idx] = a2[((size_t)bh*256 + j)*256 + i] * inv;
}

// ---------------------------------------------------------------------------
// TF32 flash attention with optional split-K
// ---------------------------------------------------------------------------
#define QP 68
#define VP 72
#define OFF_KS   4352
#define OFF_PS   8704
#define OFF_VS   13056
#define OFF_ROWM 17664
#define OFF_ROWL 17728
#define OFF_REDM 17792
#define OFF_REDS 18048
#define SMEM_FLASH_TC ((18304)*4)

__global__ __launch_bounds__(256) void flash_tc_kernel(
        const float* __restrict__ Q, const float* __restrict__ K,
        const float* __restrict__ V, float* __restrict__ O, int nq, int nk,
        int chunk, float* __restrict__ mpart, float* __restrict__ lpart) {
    extern __shared__ float sm[];
    float (*Qs)[QP] = (float(*)[QP])sm;
    float (*Ks)[QP] = (float(*)[QP])(sm + OFF_KS);
    float (*Ps)[QP] = (float(*)[QP])(sm + OFF_PS);
    float (*Vs)[VP] = (float(*)[VP])(sm + OFF_VS);
    float* rowm = sm + OFF_ROWM;
    float* rowl = sm + OFF_ROWL;
    float (*redm)[4] = (float(*)[4])(sm + OFF_REDM);
    float (*reds)[4] = (float(*)[4])(sm + OFF_REDS);

    int tid = threadIdx.x;
    int lane = tid & 31, wid = tid >> 5;
    int wm = wid & 1, wn = wid >> 1;
    int g = lane >> 2, t4 = lane & 3;
    int bh = blockIdx.y;
    int q0 = blockIdx.x * 64;
    size_t koff = (size_t)blockIdx.z * chunk * 64;
    const float* Qb = Q + ((size_t)bh*nq + q0) * 64;
    const float* Kb = K + (size_t)bh*nk*64 + koff;
    const float* Vb = V + (size_t)bh*nk*64 + koff;

    {
        int r = tid >> 2, kc = (tid & 3) * 16;
#pragma unroll
        for (int ii = 0; ii < 4; ii++) {
            float4 qv = *(const float4*)&Qb[(size_t)r*64 + kc + ii*4];
            Qs[r][kc+ii*4+0]=f2tf(qv.x); Qs[r][kc+ii*4+1]=f2tf(qv.y);
            Qs[r][kc+ii*4+2]=f2tf(qv.z); Qs[r][kc+ii*4+3]=f2tf(qv.w);
        }
    }
    if (tid < 64) { rowm[tid] = -1e30f; rowl[tid] = 0.f; }
    float o[2][2][4];
#pragma unroll
    for (int i=0;i<2;i++)
#pragma unroll
        for (int j=0;j<2;j++)
#pragma unroll
            for (int h=0;h<4;h++) o[i][j][h]=0.f;
    __syncthreads();

    for (int c0 = 0; c0 < chunk; c0 += 64) {
        {
            int r = tid >> 2, kc = (tid & 3) * 16;
#pragma unroll
            for (int ii = 0; ii < 4; ii++) {
                float4 kv = *(const float4*)&Kb[(size_t)(c0+r)*64 + kc + ii*4];
                Ks[r][kc+ii*4+0]=f2tf(kv.x); Ks[r][kc+ii*4+1]=f2tf(kv.y);
                Ks[r][kc+ii*4+2]=f2tf(kv.z); Ks[r][kc+ii*4+3]=f2tf(kv.w);
                float4 vv = *(const float4*)&Vb[(size_t)(c0+r)*64 + kc + ii*4];
                Vs[r][kc+ii*4+0]=f2tf(vv.x); Vs[r][kc+ii*4+1]=f2tf(vv.y);
                Vs[r][kc+ii*4+2]=f2tf(vv.z); Vs[r][kc+ii*4+3]=f2tf(vv.w);
            }
        }
        __syncthreads();

        float s[2][2][4];
#pragma unroll
        for (int i=0;i<2;i++)
#pragma unroll
            for (int j=0;j<2;j++)
#pragma unroll
                for (int h=0;h<4;h++) s[i][j][h]=0.f;
#pragma unroll
        for (int ks = 0; ks < 64; ks += 8) {
            uint32_t af[2][4], bf[2][2];
#pragma unroll
            for (int i = 0; i < 2; i++) {
                int r = wm*32 + i*16 + g;
                af[i][0] = __float_as_uint(Qs[r][ks+t4]);
                af[i][1] = __float_as_uint(Qs[r+8][ks+t4]);
                af[i][2] = __float_as_uint(Qs[r][ks+t4+4]);
                af[i][3] = __float_as_uint(Qs[r+8][ks+t4+4]);
            }
#pragma unroll
            for (int j = 0; j < 2; j++) {
                int cc = wn*16 + j*8 + g;
                bf[j][0] = __float_as_uint(Ks[cc][ks+t4]);
                bf[j][1] = __float_as_uint(Ks[cc][ks+t4+4]);
            }
#pragma unroll
            for (int i = 0; i < 2; i++)
#pragma unroll
                for (int j = 0; j < 2; j++) {
                    asm volatile(
                        "mma.sync.aligned.m16n8k8.row.col.f32.tf32.tf32.f32 "
                        "{%0,%1,%2,%3}, {%4,%5,%6,%7}, {%8,%9}, {%0,%1,%2,%3};\n"
                        : "+f"(s[i][j][0]), "+f"(s[i][j][1]),
                          "+f"(s[i][j][2]), "+f"(s[i][j][3])
                        : "r"(af[i][0]), "r"(af[i][1]), "r"(af[i][2]), "r"(af[i][3]),
                          "r"(bf[j][0]), "r"(bf[j][1]));
                }
        }

        float pm[2][2];
#pragma unroll
        for (int i=0;i<2;i++)
#pragma unroll
            for (int h=0;h<2;h++)
                pm[i][h] = fmaxf(fmaxf(s[i][0][2*h], s[i][0][2*h+1]),
                                 fmaxf(s[i][1][2*h], s[i][1][2*h+1]));
#pragma unroll
        for (int off = 1; off <= 2; off <<= 1) {
#pragma unroll
            for (int i=0;i<2;i++)
#pragma unroll
                for (int h=0;h<2;h++)
                    pm[i][h] = fmaxf(pm[i][h], __shfl_xor_sync(0xffffffffu, pm[i][h], off));
        }
        if (t4 == 0) {
#pragma unroll
            for (int i=0;i<2;i++)
#pragma unroll
                for (int h=0;h<2;h++)
                    redm[wm*32 + i*16 + g + h*8][wn] = pm[i][h];
        }
        __syncthreads();

        float mnew[2][2], scale[2][2];
#pragma unroll
        for (int i=0;i<2;i++)
#pragma unroll
            for (int h=0;h<2;h++) {
                int r = wm*32 + i*16 + g + h*8;
                float m = fmaxf(fmaxf(redm[r][0], redm[r][1]),
                                fmaxf(redm[r][2], redm[r][3]));
                float mo = rowm[r];
                mnew[i][h] = fmaxf(mo, m);
                scale[i][h] = __expf(mo - mnew[i][h]);
            }

        float psum[2][2] = {{0.f,0.f},{0.f,0.f}};
#pragma unroll
        for (int i=0;i<2;i++)
#pragma unroll
            for (int j=0;j<2;j++)
#pragma unroll
                for (int h=0;h<2;h++) {
                    int r = wm*32 + i*16 + g + h*8;
                    float p0 = __expf(s[i][j][2*h]   - mnew[i][h]);
                    float p1 = __expf(s[i][j][2*h+1] - mnew[i][h]);
                    *(float2*)&Ps[r][wn*16 + j*8 + 2*t4] = make_float2(f2tf(p0), f2tf(p1));
                    psum[i][h] += p0 + p1;
                    o[i][j][2*h]   *= scale[i][h];
                    o[i][j][2*h+1] *= scale[i][h];
                }
#pragma unroll
        for (int off = 1; off <= 2; off <<= 1) {
#pragma unroll
            for (int i=0;i<2;i++)
#pragma unroll
                for (int h=0;h<2;h++)
                    psum[i][h] += __shfl_xor_sync(0xffffffffu, psum[i][h], off);
        }
        if (t4 == 0) {
#pragma unroll
            for (int i=0;i<2;i++)
#pragma unroll
                for (int h=0;h<2;h++)
                    reds[wm*32 + i*16 + g + h*8][wn] = psum[i][h];
        }
        __syncthreads();

        if (wn == 0 && t4 == 0) {
#pragma unroll
            for (int i=0;i<2;i++)
#pragma unroll
                for (int h=0;h<2;h++) {
                    int r = wm*32 + i*16 + g + h*8;
                    float ps = reds[r][0] + reds[r][1] + reds[r][2] + reds[r][3];
                    rowl[r] = rowl[r]*scale[i][h] + ps;
                    rowm[r] = mnew[i][h];
                }
        }

#pragma unroll
        for (int ks = 0; ks < 64; ks += 8) {
            uint32_t af[2][4], bf[2][2];
#pragma unroll
            for (int i = 0; i < 2; i++) {
                int r = wm*32 + i*16 + g;
                af[i][0] = __float_as_uint(Ps[r][ks+t4]);
                af[i][1] = __float_as_uint(Ps[r+8][ks+t4]);
                af[i][2] = __float_as_uint(Ps[r][ks+t4+4]);
                af[i][3] = __float_as_uint(Ps[r+8][ks+t4+4]);
            }
#pragma unroll
            for (int j = 0; j < 2; j++) {
                int cc = wn*16 + j*8 + g;
                bf[j][0] = __float_as_uint(Vs[ks+t4][cc]);
                bf[j][1] = __float_as_uint(Vs[ks+t4+4][cc]);
            }
#pragma unroll
            for (int i = 0; i < 2; i++)
#pragma unroll
                for (int j = 0; j < 2; j++) {
                    asm volatile(
                        "mma.sync.aligned.m16n8k8.row.col.f32.tf32.tf32.f32 "
                        "{%0,%1,%2,%3}, {%4,%5,%6,%7}, {%8,%9}, {%0,%1,%2,%3};\n"
                        : "+f"(o[i][j][0]), "+f"(o[i][j][1]),
                          "+f"(o[i][j][2]), "+f"(o[i][j][3])
                        : "r"(af[i][0]), "r"(af[i][1]), "r"(af[i][2]), "r"(af[i][3]),
                          "r"(bf[j][0]), "r"(bf[j][1]));
                }
        }
        __syncthreads();
    }

    if (lpart != nullptr) {
        float* Ob = O + ((size_t)(blockIdx.z*32 + bh)*nq + q0) * 64;
#pragma unroll
        for (int i=0;i<2;i++)
#pragma unroll
            for (int j=0;j<2;j++)
#pragma unroll
                for (int h=0;h<2;h++) {
                    int r = wm*32 + i*16 + g + h*8;
                    int cc = wn*16 + j*8 + 2*t4;
                    *(float2*)&Ob[(size_t)r*64 + cc] =
                        make_float2(o[i][j][2*h], o[i][j][2*h+1]);
                }
        if (tid < 64) {
            size_t ri = (size_t)(blockIdx.z*32 + bh)*nq + q0 + tid;
            mpart[ri] = rowm[tid];
            lpart[ri] = rowl[tid];
        }
    } else {
        float* Ob = O + ((size_t)bh*nq + q0) * 64;
#pragma unroll
        for (int i=0;i<2;i++)
#pragma unroll
            for (int j=0;j<2;j++)
#pragma unroll
                for (int h=0;h<2;h++) {
                    int r = wm*32 + i*16 + g + h*8;
                    int cc = wn*16 + j*8 + 2*t4;
                    float inv = 1.f / rowl[r];
                    *(float2*)&Ob[(size_t)r*64 + cc] =
                        make_float2(o[i][j][2*h]*inv, o[i][j][2*h+1]*inv);
                }
    }
}

// ---------------------------------------------------------------------------
// Split-K combine
// ---------------------------------------------------------------------------
__global__ void combine_kernel(const float* __restrict__ Op,
                               const float* __restrict__ mp,
                               const float* __restrict__ lp,
                               float* __restrict__ w) {
    int row = blockIdx.x;
    int c = threadIdx.x;
    int bh = row >> 8, qr = row & 255;
    float m0 = mp[(0*32+bh)*256+qr], m1 = mp[(1*32+bh)*256+qr];
    float m2 = mp[(2*32+bh)*256+qr], m3 = mp[(3*32+bh)*256+qr];
    float ms = fmaxf(fmaxf(m0,m1), fmaxf(m2,m3));
    float w0 = __expf(m0-ms), w1 = __expf(m1-ms), w2 = __expf(m2-ms), w3 = __expf(m3-ms);
    float l = w0*lp[(0*32+bh)*256+qr] + w1*lp[(1*32+bh)*256+qr]
            + w2*lp[(2*32+bh)*256+qr] + w3*lp[(3*32+bh)*256+qr];
    float acc = w0*Op[((size_t)(0*32+bh)*256+qr)*64 + c]
              + w1*Op[((size_t)(1*32+bh)*256+qr)*64 + c]
              + w2*Op[((size_t)(2*32+bh)*256+qr)*64 + c]
              + w3*Op[((size_t)(3*32+bh)*256+qr)*64 + c];
    w[((size_t)bh*256+qr)*64 + c] = acc / l;
}

// ---------------------------------------------------------------------------
// Depthwise seq-conv residual + layout transform
// ---------------------------------------------------------------------------
__global__ __launch_bounds__(256) void conv_kernel(
        const float* __restrict__ attn, const float* __restrict__ v,
        const float* __restrict__ cw, float* __restrict__ attn2) {
    __shared__ float vt[96][64];
    __shared__ float wk[33];
    int bh = blockIdx.y; int h = bh & 7; int b4 = bh >> 3;
    int row0 = blockIdx.x * 64;
    int t = threadIdx.x;
    if (t < 33) wk[t] = cw[h*33 + t];
    const float* vb = v + (size_t)bh*4096*64;
#pragma unroll
    for (int i=0;i<6;i++){
        int f = t + i*256;
        int r = f >> 4;
        int c4 = (f & 15) * 4;
        int gr = row0 - 16 + r;
        float4 val = make_float4(0.f,0.f,0.f,0.f);
        if (gr >= 0 && gr < 4096) val = *(const float4*)&vb[(size_t)gr*64 + c4];
        *(float4*)&vt[r][c4] = val;
    }
    __syncthreads();
    int dh = t & 63;
    int rr = t >> 6;
#pragma unroll
    for (int q=0;q<16;q++){
        int lr = rr + q*4;
        float acc = attn[((size_t)bh*4096 + row0 + lr)*64 + dh];
#pragma unroll
        for (int s=0;s<33;s++) acc += wk[s]*vt[lr+s][dh];
        attn2[((size_t)b4*4096 + row0 + lr)*512 + h*64 + dh] = acc;
    }
}

// ---------------------------------------------------------------------------
// Host orchestration
// ---------------------------------------------------------------------------
extern "C" void kernel_launch(void* const* d_in, const int* in_sizes, int n_in,
                              void* d_out, int out_size) {
    const float* x      = (const float*)d_in[0];
    const float* norm_w = (const float*)d_in[1];
    const float* norm_b = (const float*)d_in[2];
    const float* Wqkv   = (const float*)d_in[3];
    const float* Wout   = (const float*)d_in[4];
    const float* bout   = (const float*)d_in[5];
    const float* conv_w = (const float*)d_in[6];
    float* out = (float*)d_out;

    float *xn,*q,*k,*v,*ql,*kl,*a2,*z0,*t1,*t2,*t3,*w,*w2,*uu,*r3,*u5,*attn,*attn2,*red;
    float *w4s[5];
    cudaGetSymbolAddress((void**)&xn,   g_xn);
    cudaGetSymbolAddress((void**)&q,    g_q);
    cudaGetSymbolAddress((void**)&k,    g_k);
    cudaGetSymbolAddress((void**)&v,    g_v);
    cudaGetSymbolAddress((void**)&ql,   g_ql);
    cudaGetSymbolAddress((void**)&kl,   g_kl);
    cudaGetSymbolAddress((void**)&a2,   g_a2);
    cudaGetSymbolAddress((void**)&z0,   g_z0);
    cudaGetSymbolAddress((void**)&t1,   g_t1);
    cudaGetSymbolAddress((void**)&t2,   g_t2);
    cudaGetSymbolAddress((void**)&t3,   g_t3);
    cudaGetSymbolAddress((void**)&w4s[0], g_w40);
    cudaGetSymbolAddress((void**)&w4s[1], g_w41);
    cudaGetSymbolAddress((void**)&w4s[2], g_w42);
    cudaGetSymbolAddress((void**)&w4s[3], g_w43);
    cudaGetSymbolAddress((void**)&w4s[4], g_w44);
    cudaGetSymbolAddress((void**)&w,    g_w);
    cudaGetSymbolAddress((void**)&w2,   g_w2);
    cudaGetSymbolAddress((void**)&uu,   g_u);
    cudaGetSymbolAddress((void**)&r3,   g_r3);
    cudaGetSymbolAddress((void**)&u5,   g_u5);
    cudaGetSymbolAddress((void**)&attn, g_attn);
    cudaGetSymbolAddress((void**)&attn2,g_attn2);
    cudaGetSymbolAddress((void**)&red,  g_red);

    cudaFuncSetAttribute(flash_tc_kernel, cudaFuncAttributeMaxDynamicSharedMemorySize, SMEM_FLASH_TC);
    cudaFuncSetAttribute(a2_tc_kernel, cudaFuncAttributeMaxDynamicSharedMemorySize, SMEM_A2);

    // 1. LayerNorm
    ln_kernel<<<16384, 128>>>(x, norm_w, norm_b, xn);
    // 2. QKV projection (tf32 MMA, fused scatter + q scale)
    mma_gemm<0,512,1536,512><<<dim3(12,128), 256>>>(
        xn, Wqkv, q, k, v, nullptr, nullptr);
    // 3. landmarks (merged)
    landmark2_kernel<<<4096, 256>>>(q, k, ql, kl);
    // 4. a2 = softmax(q_l k_l^T) (tf32 MMA)
    a2_tc_kernel<<<dim3(2,32), 256, SMEM_A2>>>(ql, kl, a2);
    // 5. pinv init scalar + z0 = s*a2^T
    red_init_kernel<<<1, 32>>>(red);
    colsum_kernel<<<32, 256>>>(a2, red);
    zinit_kernel<<<8192, 256>>>(a2, red, z0);
    // 6. w = softmax(q_l k^T) @ v — split-K x4 flash + combine
    flash_tc_kernel<<<dim3(4,32,4), 256, SMEM_FLASH_TC>>>(
        ql, k, v, t1, 256, 4096, 1024, t2, t2 + 32768);
    combine_kernel<<<8192, 64>>>(t1, t2, t2 + 32768, w);
    // 7. Newton-Schulz pinv, Y-only recurrence, 128x128 tiles (R9 proven):
    //    W2 = Y(7I-Y); W4_i = Y(15I-W2); Y' = 0.25*Y(13I-W4_i)   [it=0..4]
    //    it=5's W4_5 is never formed: applied to narrow u6 via Y5-powers.
    mma_gemm_pinv<<<dim3(2,2,32), 256>>>(a2, z0, t1, 0.f, 1.f);   // Y0 = a2 @ z0
    float* Y = t1; float* Yn = t3;
    for (int it = 0; it < 5; it++) {
        mma_gemm_pinv<<<dim3(2,2,32), 256>>>(Y, Y, t2, 7.f, -1.f);        // W2
        mma_gemm_pinv<<<dim3(2,2,32), 256>>>(Y, t2, w4s[it], 15.f, -1.f); // W4_i
        mma_gemm_pinv<<<dim3(2,2,32), 256>>>(Y, w4s[it], Yn, 3.25f, -0.25f);
        float* tmp = Y; Y = Yn; Yn = tmp;
    }
    // Y == Y5. Narrow last iteration: r1=Y5 w, r2=Y5 r1, r3=Y5 r2,
    // u5 = 13w - 15 r1 + 7 r2 - r3  (same polynomial as 13I - W4_5 applied to w)
    mma_nar_kernel<<<dim3(1,2,32), 256>>>(Y, w,  uu, 0.f, 1.f);   // r1
    mma_nar_kernel<<<dim3(1,2,32), 256>>>(Y, uu, w2, 0.f, 1.f);   // r2
    mma_nar_kernel<<<dim3(1,2,32), 256>>>(Y, w2, r3, 0.f, 1.f);   // r3
    comb4_kernel<<<2048, 256>>>(w, uu, w2, r3, u5);
    // 8. narrow chain down: u_i = 13*u_{i+1} - W4_i @ u_{i+1}
    mma_nar_kernel<<<dim3(1,2,32), 256>>>(w4s[4], u5, uu, 13.f, -1.f);
    mma_nar_kernel<<<dim3(1,2,32), 256>>>(w4s[3], uu, w2, 13.f, -1.f);
    mma_nar_kernel<<<dim3(1,2,32), 256>>>(w4s[2], w2, uu, 13.f, -1.f);
    mma_nar_kernel<<<dim3(1,2,32), 256>>>(w4s[1], uu, w2, 13.f, -1.f);
    mma_nar_kernel<<<dim3(1,2,32), 256>>>(w4s[0], w2, uu, 13.f, -1.f);
    mma_nar_kernel<<<dim3(1,2,32), 256>>>(z0, uu, w2, 0.f, 1.f/4096.f);
    // 9. attn = softmax(q k_l^T) @ w2 (tf32 flash, no split)
    flash_tc_kernel<<<dim3(64,32,1), 256, SMEM_FLASH_TC>>>(
        q, kl, w2, attn, 4096, 256, 256, nullptr, nullptr);
    // 10. conv residual + layout
    conv_kernel<<<dim3(64,32), 256>>>(attn, v, conv_w, attn2);
    // 11. output projection + bias + input residual (tf32 MMA)
    mma_gemm<1,512,512,512><<<dim3(4,128), 256>>>(
        attn2, Wout, out, nullptr, nullptr, bout, x);
}

// round 13
// speedup vs baseline: 1.0496x; 1.0086x over previous
#include <cuda_runtime.h>
#include <cuda_bf16.h>
#include <cstdint>

// ---------------------------------------------------------------------------
// Problem constants: b=4, n=4096, D=512, H=8, dh=64, M=256, l=16, 6 iters,
// conv k=33, eps=1e-5
// ---------------------------------------------------------------------------
#define NB   (4*4096*512)
#define MM   (32*256*256)
#define MD   (32*256*64)

__device__ float g_xn[NB];
__device__ float g_q[NB];
__device__ float g_k[NB];
__device__ float g_v[NB];
__device__ float g_ql[MD];
__device__ float g_kl[MD];
__device__ float g_a2[MM];
__device__ float g_z0[MM];
__device__ float g_t1[MM];   // Y ping / flash1 split-K O partials
__device__ float g_t2[MM];   // W2 scratch / flash1 split-K m/l partials
__device__ float g_t3[MM];   // Y pong
__device__ float g_w40[MM];
__device__ float g_w41[MM];
__device__ float g_w42[MM];
__device__ float g_w43[MM];
__device__ float g_w44[MM];
__device__ float g_w[MD];
__device__ float g_w2[MD];
__device__ float g_u[MD];
__device__ float g_r3[MD];
__device__ float g_u5[MD];
__device__ float g_attn[NB];
__device__ float g_attn2[NB];
__device__ float g_red[2];

__device__ __forceinline__ float f2tf(float x) {
    uint32_t u;
    asm("cvt.rna.tf32.f32 %0, %1;" : "=r"(u) : "f"(x));
    return __uint_as_float(u);
}

// ---------------------------------------------------------------------------
// LayerNorm
// ---------------------------------------------------------------------------
__global__ void ln_kernel(const float* __restrict__ x, const float* __restrict__ w,
                          const float* __restrict__ bb, float* __restrict__ out) {
    int row = blockIdx.x;
    const float* xr = x + (size_t)row * 512;
    float* orow = out + (size_t)row * 512;
    int t = threadIdx.x;
    float v[4];
    float s = 0.f;
#pragma unroll
    for (int i = 0; i < 4; i++) { v[i] = xr[t + 128*i]; s += v[i]; }
#pragma unroll
    for (int o = 16; o; o >>= 1) s += __shfl_xor_sync(0xffffffffu, s, o);
    __shared__ float red[4];
    if ((t & 31) == 0) red[t >> 5] = s;
    __syncthreads();
    float mean = (red[0]+red[1]+red[2]+red[3]) * (1.f/512.f);
    float vs = 0.f;
#pragma unroll
    for (int i = 0; i < 4; i++) { float d = v[i]-mean; vs += d*d; }
#pragma unroll
    for (int o = 16; o; o >>= 1) vs += __shfl_xor_sync(0xffffffffu, vs, o);
    __syncthreads();
    if ((t & 31) == 0) red[t >> 5] = vs;
    __syncthreads();
    float var = (red[0]+red[1]+red[2]+red[3]) * (1.f/512.f);
    float rstd = rsqrtf(var + 1e-5f);
#pragma unroll
    for (int i = 0; i < 4; i++) {
        int c = t + 128*i;
        orow[c] = (v[i]-mean)*rstd*w[c] + bb[c];
    }
}

// ---------------------------------------------------------------------------
// TF32 GEMM (proven): block 128x128, BK=16, 8 warps 64x32, occ 2.
// EPI 0: QKV scatter. EPI 1: bias + residual.
// ---------------------------------------------------------------------------
template<int EPI, int LDA, int LDB, int KD>
__global__ __launch_bounds__(256, 2) void mma_gemm(
        const float* __restrict__ A, const float* __restrict__ B,
        float* __restrict__ C0, float* __restrict__ C1, float* __restrict__ C2,
        const float* __restrict__ e0, const float* __restrict__ e1) {
    __shared__ float Asm[2][128*20];
    __shared__ float Bsm[2][16*136];
    int tid = threadIdx.x;
    int lane = tid & 31, wid = tid >> 5;
    int wm = wid & 1, wn = wid >> 1;
    int g = lane >> 2, t4 = lane & 3;
    int row0 = blockIdx.y * 128, col0 = blockIdx.x * 128;
    int arow = tid >> 1, akq = (tid & 1) * 8;
    int bkr = tid >> 4, bnc = (tid & 15) * 8;

    {
        const float* ap = A + (size_t)(row0 + arow) * LDA + akq;
        float4 a0 = *(const float4*)ap;
        float4 a1 = *(const float4*)(ap + 4);
        float* as = &Asm[0][arow*20 + akq];
        as[0]=f2tf(a0.x); as[1]=f2tf(a0.y); as[2]=f2tf(a0.z); as[3]=f2tf(a0.w);
        as[4]=f2tf(a1.x); as[5]=f2tf(a1.y); as[6]=f2tf(a1.z); as[7]=f2tf(a1.w);
        const float* bp = B + (size_t)bkr * LDB + col0 + bnc;
        float4 b0 = *(const float4*)bp;
        float4 b1 = *(const float4*)(bp + 4);
        float* bs = &Bsm[0][bkr*136 + bnc];
        bs[0]=f2tf(b0.x); bs[1]=f2tf(b0.y); bs[2]=f2tf(b0.z); bs[3]=f2tf(b0.w);
        bs[4]=f2tf(b1.x); bs[5]=f2tf(b1.y); bs[6]=f2tf(b1.z); bs[7]=f2tf(b1.w);
    }
    __syncthreads();

    float c[4][4][4];
#pragma unroll
    for (int i=0;i<4;i++)
#pragma unroll
        for (int j=0;j<4;j++)
#pragma unroll
            for (int h=0;h<4;h++) c[i][j][h]=0.f;

    const int NIT = KD / 16;
    for (int it = 0; it < NIT; it++) {
        int buf = it & 1;
        float4 pa0, pa1, pb0, pb1;
        if (it + 1 < NIT) {
            int k0 = (it + 1) * 16;
            const float* ap = A + (size_t)(row0 + arow) * LDA + k0 + akq;
            pa0 = *(const float4*)ap;
            pa1 = *(const float4*)(ap + 4);
            const float* bp = B + (size_t)(k0 + bkr) * LDB + col0 + bnc;
            pb0 = *(const float4*)bp;
            pb1 = *(const float4*)(bp + 4);
        }
#pragma unroll
        for (int ks = 0; ks < 16; ks += 8) {
            uint32_t af[4][4], bf[4][2];
#pragma unroll
            for (int i = 0; i < 4; i++) {
                int r0i = (wm*64 + i*16 + g) * 20 + ks + t4;
                int r1i = r0i + 8*20;
                af[i][0] = __float_as_uint(Asm[buf][r0i]);
                af[i][1] = __float_as_uint(Asm[buf][r1i]);
                af[i][2] = __float_as_uint(Asm[buf][r0i + 4]);
                af[i][3] = __float_as_uint(Asm[buf][r1i + 4]);
            }
#pragma unroll
            for (int j = 0; j < 4; j++) {
                int nc2 = wn*32 + j*8 + g;
                bf[j][0] = __float_as_uint(Bsm[buf][(ks + t4)*136 + nc2]);
                bf[j][1] = __float_as_uint(Bsm[buf][(ks + t4 + 4)*136 + nc2]);
            }
#pragma unroll
            for (int i = 0; i < 4; i++)
#pragma unroll
                for (int j = 0; j < 4; j++) {
                    asm volatile(
                        "mma.sync.aligned.m16n8k8.row.col.f32.tf32.tf32.f32 "
                        "{%0,%1,%2,%3}, {%4,%5,%6,%7}, {%8,%9}, {%0,%1,%2,%3};\n"
                        : "+f"(c[i][j][0]), "+f"(c[i][j][1]),
                          "+f"(c[i][j][2]), "+f"(c[i][j][3])
                        : "r"(af[i][0]), "r"(af[i][1]), "r"(af[i][2]), "r"(af[i][3]),
                          "r"(bf[j][0]), "r"(bf[j][1]));
                }
        }
        if (it + 1 < NIT) {
            int nb = buf ^ 1;
            float* as = &Asm[nb][arow*20 + akq];
            as[0]=f2tf(pa0.x); as[1]=f2tf(pa0.y); as[2]=f2tf(pa0.z); as[3]=f2tf(pa0.w);
            as[4]=f2tf(pa1.x); as[5]=f2tf(pa1.y); as[6]=f2tf(pa1.z); as[7]=f2tf(pa1.w);
            float* bs = &Bsm[nb][bkr*136 + bnc];
            bs[0]=f2tf(pb0.x); bs[1]=f2tf(pb0.y); bs[2]=f2tf(pb0.z); bs[3]=f2tf(pb0.w);
            bs[4]=f2tf(pb1.x); bs[5]=f2tf(pb1.y); bs[6]=f2tf(pb1.z); bs[7]=f2tf(pb1.w);
        }
        __syncthreads();
    }

#pragma unroll
    for (int i = 0; i < 4; i++) {
#pragma unroll
        for (int j = 0; j < 4; j++) {
#pragma unroll
            for (int h = 0; h < 2; h++) {
                int r = row0 + wm*64 + i*16 + g + h*8;
                int cc = col0 + wn*32 + j*8 + 2*t4;
                float v0 = c[i][j][h*2+0], v1 = c[i][j][h*2+1];
                if (EPI == 0) {
                    int b4 = r >> 12, nn = r & 4095;
                    int which = cc >> 9, cs = cc & 511;
                    int hh = cs >> 6, dh = cs & 63;
                    size_t di = ((size_t)(b4*8+hh)*4096 + nn)*64 + dh;
                    if (which == 0) {
                        *(float2*)&C0[di] = make_float2(v0*0.125f, v1*0.125f);
                    } else if (which == 1) {
                        *(float2*)&C1[di] = make_float2(v0, v1);
                    } else {
                        *(float2*)&C2[di] = make_float2(v0, v1);
                    }
                } else {
                    size_t di = (size_t)r*512 + cc;
                    float2 bias = *(const float2*)&e0[cc];
                    float2 xr = *(const float2*)&e1[di];
                    *(float2*)&C0[di] = make_float2(v0+bias.x+xr.x, v1+bias.y+xr.y);
                }
            }
        }
    }
}

// ---------------------------------------------------------------------------
// TF32 GEMM, pinv variant (proven 128x128): batched over z (stride 65536):
// C0 = cA*A + cAB*(A@B)
// ---------------------------------------------------------------------------
__global__ __launch_bounds__(256, 2) void mma_gemm_pinv(
        const float* __restrict__ A, const float* __restrict__ B,
        float* __restrict__ C0, float cA, float cAB) {
    __shared__ float Asm[2][128*20];
    __shared__ float Bsm[2][16*136];
    int tid = threadIdx.x;
    int lane = tid & 31, wid = tid >> 5;
    int wm = wid & 1, wn = wid >> 1;
    int g = lane >> 2, t4 = lane & 3;
    int row0 = blockIdx.y * 128, col0 = blockIdx.x * 128;
    const float* Ag = A + (size_t)blockIdx.z * 65536;
    const float* Bg = B + (size_t)blockIdx.z * 65536;
    int arow = tid >> 1, akq = (tid & 1) * 8;
    int bkr = tid >> 4, bnc = (tid & 15) * 8;

    {
        const float* ap = Ag + (size_t)(row0 + arow) * 256 + akq;
        float4 a0 = *(const float4*)ap;
        float4 a1 = *(const float4*)(ap + 4);
        float* as = &Asm[0][arow*20 + akq];
        as[0]=f2tf(a0.x); as[1]=f2tf(a0.y); as[2]=f2tf(a0.z); as[3]=f2tf(a0.w);
        as[4]=f2tf(a1.x); as[5]=f2tf(a1.y); as[6]=f2tf(a1.z); as[7]=f2tf(a1.w);
        const float* bp = Bg + (size_t)bkr * 256 + col0 + bnc;
        float4 b0 = *(const float4*)bp;
        float4 b1 = *(const float4*)(bp + 4);
        float* bs = &Bsm[0][bkr*136 + bnc];
        bs[0]=f2tf(b0.x); bs[1]=f2tf(b0.y); bs[2]=f2tf(b0.z); bs[3]=f2tf(b0.w);
        bs[4]=f2tf(b1.x); bs[5]=f2tf(b1.y); bs[6]=f2tf(b1.z); bs[7]=f2tf(b1.w);
    }
    __syncthreads();

    float c[4][4][4];
#pragma unroll
    for (int i=0;i<4;i++)
#pragma unroll
        for (int j=0;j<4;j++)
#pragma unroll
            for (int h=0;h<4;h++) c[i][j][h]=0.f;

    const int NIT = 16;
    for (int it = 0; it < NIT; it++) {
        int buf = it & 1;
        float4 pa0, pa1, pb0, pb1;
        if (it + 1 < NIT) {
            int k0 = (it + 1) * 16;
            const float* ap = Ag + (size_t)(row0 + arow) * 256 + k0 + akq;
            pa0 = *(const float4*)ap;
            pa1 = *(const float4*)(ap + 4);
            const float* bp = Bg + (size_t)(k0 + bkr) * 256 + col0 + bnc;
            pb0 = *(const float4*)bp;
            pb1 = *(const float4*)(bp + 4);
        }
#pragma unroll
        for (int ks = 0; ks < 16; ks += 8) {
            uint32_t af[4][4], bf[4][2];
#pragma unroll
            for (int i = 0; i < 4; i++) {
                int r0i = (wm*64 + i*16 + g) * 20 + ks + t4;
                int r1i = r0i + 8*20;
                af[i][0] = __float_as_uint(Asm[buf][r0i]);
                af[i][1] = __float_as_uint(Asm[buf][r1i]);
                af[i][2] = __float_as_uint(Asm[buf][r0i + 4]);
                af[i][3] = __float_as_uint(Asm[buf][r1i + 4]);
            }
#pragma unroll
            for (int j = 0; j < 4; j++) {
                int nc2 = wn*32 + j*8 + g;
                bf[j][0] = __float_as_uint(Bsm[buf][(ks + t4)*136 + nc2]);
                bf[j][1] = __float_as_uint(Bsm[buf][(ks + t4 + 4)*136 + nc2]);
            }
#pragma unroll
            for (int i = 0; i < 4; i++)
#pragma unroll
                for (int j = 0; j < 4; j++) {
                    asm volatile(
                        "mma.sync.aligned.m16n8k8.row.col.f32.tf32.tf32.f32 "
                        "{%0,%1,%2,%3}, {%4,%5,%6,%7}, {%8,%9}, {%0,%1,%2,%3};\n"
                        : "+f"(c[i][j][0]), "+f"(c[i][j][1]),
                          "+f"(c[i][j][2]), "+f"(c[i][j][3])
                        : "r"(af[i][0]), "r"(af[i][1]), "r"(af[i][2]), "r"(af[i][3]),
                          "r"(bf[j][0]), "r"(bf[j][1]));
                }
        }
        if (it + 1 < NIT) {
            int nb = buf ^ 1;
            float* as = &Asm[nb][arow*20 + akq];
            as[0]=f2tf(pa0.x); as[1]=f2tf(pa0.y); as[2]=f2tf(pa0.z); as[3]=f2tf(pa0.w);
            as[4]=f2tf(pa1.x); as[5]=f2tf(pa1.y); as[6]=f2tf(pa1.z); as[7]=f2tf(pa1.w);
            float* bs = &Bsm[nb][bkr*136 + bnc];
            bs[0]=f2tf(pb0.x); bs[1]=f2tf(pb0.y); bs[2]=f2tf(pb0.z); bs[3]=f2tf(pb0.w);
            bs[4]=f2tf(pb1.x); bs[5]=f2tf(pb1.y); bs[6]=f2tf(pb1.z); bs[7]=f2tf(pb1.w);
        }
        __syncthreads();
    }

#pragma unroll
    for (int i = 0; i < 4; i++) {
#pragma unroll
        for (int j = 0; j < 4; j++) {
#pragma unroll
            for (int h = 0; h < 2; h++) {
                int r = row0 + wm*64 + i*16 + g + h*8;
                int cc = col0 + wn*32 + j*8 + 2*t4;
                float v0 = c[i][j][h*2+0], v1 = c[i][j][h*2+1];
                float2 ae = *(const float2*)&Ag[(size_t)r*256 + cc];
                size_t di = (size_t)blockIdx.z*65536 + (size_t)r*256 + cc;
                *(float2*)&C0[di] = make_float2(cA*ae.x + cAB*v0,
                                                cA*ae.y + cAB*v1);
            }
        }
    }
}

// ---------------------------------------------------------------------------
// TF32 MMA narrow GEMM: C = cB*B + cAB*(A@B), A [32][256][256], B,C [32][256][64].
// ---------------------------------------------------------------------------
__global__ __launch_bounds__(256, 2) void mma_nar_kernel(
        const float* __restrict__ A, const float* __restrict__ B,
        float* __restrict__ C, float cB, float cAB) {
    __shared__ float Asm[2][128*20];
    __shared__ float Bsm[2][16*72];
    int tid = threadIdx.x;
    int lane = tid & 31, wid = tid >> 5;
    int wm = wid & 3, wn = wid >> 2;
    int g = lane >> 2, t4 = lane & 3;
    int row0 = blockIdx.y * 128;
    const float* Ag = A + (size_t)blockIdx.z * 65536;
    const float* Bg = B + (size_t)blockIdx.z * 16384;
    float* Cg = C + (size_t)blockIdx.z * 16384;
    int arow = tid >> 1, akq = (tid & 1) * 8;
    int bkr = tid >> 4, bnc = (tid & 15) * 4;

    {
        const float* ap = Ag + (size_t)(row0 + arow) * 256 + akq;
        float4 a0 = *(const float4*)ap;
        float4 a1 = *(const float4*)(ap + 4);
        float* as = &Asm[0][arow*20 + akq];
        as[0]=f2tf(a0.x); as[1]=f2tf(a0.y); as[2]=f2tf(a0.z); as[3]=f2tf(a0.w);
        as[4]=f2tf(a1.x); as[5]=f2tf(a1.y); as[6]=f2tf(a1.z); as[7]=f2tf(a1.w);
        float4 bv = *(const float4*)(Bg + (size_t)bkr * 64 + bnc);
        float* bs = &Bsm[0][bkr*72 + bnc];
        bs[0]=f2tf(bv.x); bs[1]=f2tf(bv.y); bs[2]=f2tf(bv.z); bs[3]=f2tf(bv.w);
    }
    __syncthreads();

    float c[2][4][4];
#pragma unroll
    for (int i=0;i<2;i++)
#pragma unroll
        for (int j=0;j<4;j++)
#pragma unroll
            for (int h=0;h<4;h++) c[i][j][h]=0.f;

    const int NIT = 16;
    for (int it = 0; it < NIT; it++) {
        int buf = it & 1;
        float4 pa0, pa1, pb;
        if (it + 1 < NIT) {
            int k0 = (it + 1) * 16;
            const float* ap = Ag + (size_t)(row0 + arow) * 256 + k0 + akq;
            pa0 = *(const float4*)ap;
            pa1 = *(const float4*)(ap + 4);
            pb = *(const float4*)(Bg + (size_t)(k0 + bkr) * 64 + bnc);
        }
#pragma unroll
        for (int ks = 0; ks < 16; ks += 8) {
            uint32_t af[2][4], bf[4][2];
#pragma unroll
            for (int i = 0; i < 2; i++) {
                int r0i = (wm*32 + i*16 + g) * 20 + ks + t4;
                int r1i = r0i + 8*20;
                af[i][0] = __float_as_uint(Asm[buf][r0i]);
                af[i][1] = __float_as_uint(Asm[buf][r1i]);
                af[i][2] = __float_as_uint(Asm[buf][r0i + 4]);
                af[i][3] = __float_as_uint(Asm[buf][r1i + 4]);
            }
#pragma unroll
            for (int j = 0; j < 4; j++) {
                int nc2 = wn*32 + j*8 + g;
                bf[j][0] = __float_as_uint(Bsm[buf][(ks + t4)*72 + nc2]);
                bf[j][1] = __float_as_uint(Bsm[buf][(ks + t4 + 4)*72 + nc2]);
            }
#pragma unroll
            for (int i = 0; i < 2; i++)
#pragma unroll
                for (int j = 0; j < 4; j++) {
                    asm volatile(
                        "mma.sync.aligned.m16n8k8.row.col.f32.tf32.tf32.f32 "
                        "{%0,%1,%2,%3}, {%4,%5,%6,%7}, {%8,%9}, {%0,%1,%2,%3};\n"
                        : "+f"(c[i][j][0]), "+f"(c[i][j][1]),
                          "+f"(c[i][j][2]), "+f"(c[i][j][3])
                        : "r"(af[i][0]), "r"(af[i][1]), "r"(af[i][2]), "r"(af[i][3]),
                          "r"(bf[j][0]), "r"(bf[j][1]));
                }
        }
        if (it + 1 < NIT) {
            int nb = buf ^ 1;
            float* as = &Asm[nb][arow*20 + akq];
            as[0]=f2tf(pa0.x); as[1]=f2tf(pa0.y); as[2]=f2tf(pa0.z); as[3]=f2tf(pa0.w);
            as[4]=f2tf(pa1.x); as[5]=f2tf(pa1.y); as[6]=f2tf(pa1.z); as[7]=f2tf(pa1.w);
            float* bs = &Bsm[nb][bkr*72 + bnc];
            bs[0]=f2tf(pb.x); bs[1]=f2tf(pb.y); bs[2]=f2tf(pb.z); bs[3]=f2tf(pb.w);
        }
        __syncthreads();
    }

#pragma unroll
    for (int i = 0; i < 2; i++)
#pragma unroll
        for (int j = 0; j < 4; j++)
#pragma unroll
            for (int h = 0; h < 2; h++) {
                int r = row0 + wm*32 + i*16 + g + h*8;
                int cc = wn*32 + j*8 + 2*t4;
                float v0 = cAB * c[i][j][h*2+0];
                float v1 = cAB * c[i][j][h*2+1];
                if (cB != 0.f) {
                    float2 be = *(const float2*)&Bg[(size_t)r*64 + cc];
                    v0 += cB * be.x; v1 += cB * be.y;
                }
                *(float2*)&Cg[(size_t)r*64 + cc] = make_float2(v0, v1);
            }
}

// ---------------------------------------------------------------------------
// u5 = 13*w - 15*r1 + 7*r2 - r3  (elementwise, MD elems)
// ---------------------------------------------------------------------------
__global__ void comb4_kernel(const float* __restrict__ w, const float* __restrict__ r1,
                             const float* __restrict__ r2, const float* __restrict__ r3,
                             float* __restrict__ u5) {
    int i = blockIdx.x * 256 + threadIdx.x;
    u5[i] = 13.f*w[i] - 15.f*r1[i] + 7.f*r2[i] - r3[i];
}

// ---------------------------------------------------------------------------
// TF32 MMA a2 = softmax(q_l @ k_l^T)
// ---------------------------------------------------------------------------
#define A2_KS   8704
#define A2_RM   26112
#define A2_RS   26624
#define SMEM_A2 (27136*4)
__global__ __launch_bounds__(256, 1) void a2_tc_kernel(
        const float* __restrict__ ql, const float* __restrict__ kl,
        float* __restrict__ a2) {
    extern __shared__ float sm2[];
    float* Qs = sm2;
    float* Ks = sm2 + A2_KS;
    float (*redm)[4] = (float(*)[4])(sm2 + A2_RM);
    float (*reds)[4] = (float(*)[4])(sm2 + A2_RS);

    int tid = threadIdx.x;
    int lane = tid & 31, wid = tid >> 5;
    int wm = wid & 1, wn = wid >> 1;
    int g = lane >> 2, t4 = lane & 3;
    int bh = blockIdx.y;
    int row0 = blockIdx.x * 128;
    const float* qb = ql + ((size_t)bh*256 + row0) * 64;
    const float* kb = kl + (size_t)bh*256*64;

    for (int i = tid*4; i < 8192; i += 1024) {
        float4 qv = *(const float4*)&qb[i];
        int r = i >> 6, cc = i & 63;
        float* qs = &Qs[r*68 + cc];
        qs[0]=f2tf(qv.x); qs[1]=f2tf(qv.y); qs[2]=f2tf(qv.z); qs[3]=f2tf(qv.w);
    }
    for (int i = tid*4; i < 16384; i += 1024) {
        float4 kv = *(const float4*)&kb[i];
        int r = i >> 6, cc = i & 63;
        float* ks = &Ks[r*68 + cc];
        ks[0]=f2tf(kv.x); ks[1]=f2tf(kv.y); ks[2]=f2tf(kv.z); ks[3]=f2tf(kv.w);
    }
    __syncthreads();

    float c[4][8][4];
#pragma unroll
    for (int i=0;i<4;i++)
#pragma unroll
        for (int j=0;j<8;j++)
#pragma unroll
            for (int h=0;h<4;h++) c[i][j][h]=0.f;

#pragma unroll
    for (int ks = 0; ks < 64; ks += 8) {
        uint32_t af[4][4], bf[8][2];
#pragma unroll
        for (int i = 0; i < 4; i++) {
            int r0i = (wm*64 + i*16 + g)*68 + ks + t4;
            int r1i = r0i + 8*68;
            af[i][0] = __float_as_uint(Qs[r0i]);
            af[i][1] = __float_as_uint(Qs[r1i]);
            af[i][2] = __float_as_uint(Qs[r0i + 4]);
            af[i][3] = __float_as_uint(Qs[r1i + 4]);
        }
#pragma unroll
        for (int j = 0; j < 8; j++) {
            int cr = (wn*64 + j*8 + g)*68 + ks + t4;
            bf[j][0] = __float_as_uint(Ks[cr]);
            bf[j][1] = __float_as_uint(Ks[cr + 4]);
        }
#pragma unroll
        for (int i = 0; i < 4; i++)
#pragma unroll
            for (int j = 0; j < 8; j++) {
                asm volatile(
                    "mma.sync.aligned.m16n8k8.row.col.f32.tf32.tf32.f32 "
                    "{%0,%1,%2,%3}, {%4,%5,%6,%7}, {%8,%9}, {%0,%1,%2,%3};\n"
                    : "+f"(c[i][j][0]), "+f"(c[i][j][1]),
                      "+f"(c[i][j][2]), "+f"(c[i][j][3])
                    : "r"(af[i][0]), "r"(af[i][1]), "r"(af[i][2]), "r"(af[i][3]),
                      "r"(bf[j][0]), "r"(bf[j][1]));
            }
    }

    float pm[4][2];
#pragma unroll
    for (int i=0;i<4;i++)
#pragma unroll
        for (int h=0;h<2;h++) {
            float m = c[i][0][2*h];
#pragma unroll
            for (int j=0;j<8;j++) {
                m = fmaxf(m, c[i][j][2*h]);
                m = fmaxf(m, c[i][j][2*h+1]);
            }
#pragma unroll
            for (int off = 1; off <= 2; off <<= 1)
                m = fmaxf(m, __shfl_xor_sync(0xffffffffu, m, off));
            pm[i][h] = m;
        }
    if (t4 == 0) {
#pragma unroll
        for (int i=0;i<4;i++)
#pragma unroll
            for (int h=0;h<2;h++)
                redm[wm*64 + i*16 + g + h*8][wn] = pm[i][h];
    }
    __syncthreads();

    float psum[4][2];
#pragma unroll
    for (int i=0;i<4;i++)
#pragma unroll
        for (int h=0;h<2;h++) {
            int r = wm*64 + i*16 + g + h*8;
            float m = fmaxf(fmaxf(redm[r][0], redm[r][1]),
                            fmaxf(redm[r][2], redm[r][3]));
            float s = 0.f;
#pragma unroll
            for (int j=0;j<8;j++) {
                float p0 = __expf(c[i][j][2*h]   - m);
                float p1 = __expf(c[i][j][2*h+1] - m);
                c[i][j][2*h] = p0; c[i][j][2*h+1] = p1;
                s += p0 + p1;
            }
#pragma unroll
            for (int off = 1; off <= 2; off <<= 1)
                s += __shfl_xor_sync(0xffffffffu, s, off);
            psum[i][h] = s;
        }
    if (t4 == 0) {
#pragma unroll
        for (int i=0;i<4;i++)
#pragma unroll
            for (int h=0;h<2;h++)
                reds[wm*64 + i*16 + g + h*8][wn] = psum[i][h];
    }
    __syncthreads();

#pragma unroll
    for (int i=0;i<4;i++)
#pragma unroll
        for (int h=0;h<2;h++) {
            int r = wm*64 + i*16 + g + h*8;
            float inv = 1.f / (reds[r][0]+reds[r][1]+reds[r][2]+reds[r][3]);
            float* orow = a2 + ((size_t)bh*256 + row0 + r) * 256;
#pragma unroll
            for (int j=0;j<8;j++) {
                int cc = wn*64 + j*8 + 2*t4;
                *(float2*)&orow[cc] = make_float2(c[i][j][2*h]*inv, c[i][j][2*h+1]*inv);
            }
        }
}

// ---------------------------------------------------------------------------
// Landmarks (merged q+k)
// ---------------------------------------------------------------------------
__global__ void landmark2_kernel(const float* __restrict__ q, const float* __restrict__ k,
                                 float* __restrict__ ql, float* __restrict__ kl) {
    int gidx = blockIdx.x * 256 + threadIdx.x;
    const float* src = (gidx < 524288) ? q : k;
    float* dst = (gidx < 524288) ? ql : kl;
    int idx = gidx & 524287;
    int dh = idx & 63;
    int mi = (idx >> 6) & 255;
    int bh = idx >> 14;
    const float* p = src + ((size_t)bh*4096 + mi*16)*64 + dh;
    float s = 0.f;
#pragma unroll
    for (int j = 0; j < 16; j++) s += p[j*64];
    dst[idx] = s * 0.0625f;
}

// ---------------------------------------------------------------------------
// pinv scalars: row-sum max == 1 exactly (softmax rows); need col-sum max.
// ---------------------------------------------------------------------------
__global__ void red_init_kernel(float* g) { if (threadIdx.x < 2) g[threadIdx.x] = 0.f; }

__global__ void colsum_kernel(const float* __restrict__ a2, float* __restrict__ gred) {
    int bh = blockIdx.x; int j = threadIdx.x;
    const float* base = a2 + (size_t)bh*65536;
    float s = 0.f;
    for (int i=0;i<256;i++) s += fabsf(base[(size_t)i*256 + j]);
#pragma unroll
    for (int o=16;o;o>>=1) s = fmaxf(s, __shfl_xor_sync(0xffffffffu,s,o));
    __shared__ float red[8];
    if ((j&31)==0) red[j>>5]=s;
    __syncthreads();
    if (j==0) {
        float m = red[0];
#pragma unroll
        for (int u=1;u<8;u++) m = fmaxf(m, red[u]);
        atomicMax((int*)&gred[1], __float_as_int(m));
    }
}

__global__ void zinit_kernel(const float* __restrict__ a2, const float* __restrict__ gred,
                             float* __restrict__ z) {
    int idx = blockIdx.x*256 + threadIdx.x;
    int j = idx & 255, i = (idx>>8) & 255, bh = idx >> 16;
    float inv = 1.f/gred[1];
    z[idx] = a2[((size_t)bh*256 + j)*256 + i] * inv;
}

// ---------------------------------------------------------------------------
// TF32 flash attention with optional split-K (used for flash-1, nk=4096)
// ---------------------------------------------------------------------------
#define QP 68
#define VP 72
#define OFF_KS   4352
#define OFF_PS   8704
#define OFF_VS   13056
#define OFF_ROWM 17664
#define OFF_ROWL 17728
#define OFF_REDM 17792
#define OFF_REDS 18048
#define SMEM_FLASH_TC ((18304)*4)

__global__ __launch_bounds__(256) void flash_tc_kernel(
        const float* __restrict__ Q, const float* __restrict__ K,
        const float* __restrict__ V, float* __restrict__ O, int nq, int nk,
        int chunk, float* __restrict__ mpart, float* __restrict__ lpart) {
    extern __shared__ float sm[];
    float (*Qs)[QP] = (float(*)[QP])sm;
    float (*Ks)[QP] = (float(*)[QP])(sm + OFF_KS);
    float (*Ps)[QP] = (float(*)[QP])(sm + OFF_PS);
    float (*Vs)[VP] = (float(*)[VP])(sm + OFF_VS);
    float* rowm = sm + OFF_ROWM;
    float* rowl = sm + OFF_ROWL;
    float (*redm)[4] = (float(*)[4])(sm + OFF_REDM);
    float (*reds)[4] = (float(*)[4])(sm + OFF_REDS);

    int tid = threadIdx.x;
    int lane = tid & 31, wid = tid >> 5;
    int wm = wid & 1, wn = wid >> 1;
    int g = lane >> 2, t4 = lane & 3;
    int bh = blockIdx.y;
    int q0 = blockIdx.x * 64;
    size_t koff = (size_t)blockIdx.z * chunk * 64;
    const float* Qb = Q + ((size_t)bh*nq + q0) * 64;
    const float* Kb = K + (size_t)bh*nk*64 + koff;
    const float* Vb = V + (size_t)bh*nk*64 + koff;

    {
        int r = tid >> 2, kc = (tid & 3) * 16;
#pragma unroll
        for (int ii = 0; ii < 4; ii++) {
            float4 qv = *(const float4*)&Qb[(size_t)r*64 + kc + ii*4];
            Qs[r][kc+ii*4+0]=f2tf(qv.x); Qs[r][kc+ii*4+1]=f2tf(qv.y);
            Qs[r][kc+ii*4+2]=f2tf(qv.z); Qs[r][kc+ii*4+3]=f2tf(qv.w);
        }
    }
    if (tid < 64) { rowm[tid] = -1e30f; rowl[tid] = 0.f; }
    float o[2][2][4];
#pragma unroll
    for (int i=0;i<2;i++)
#pragma unroll
        for (int j=0;j<2;j++)
#pragma unroll
            for (int h=0;h<4;h++) o[i][j][h]=0.f;
    __syncthreads();

    for (int c0 = 0; c0 < chunk; c0 += 64) {
        {
            int r = tid >> 2, kc = (tid & 3) * 16;
#pragma unroll
            for (int ii = 0; ii < 4; ii++) {
                float4 kv = *(const float4*)&Kb[(size_t)(c0+r)*64 + kc + ii*4];
                Ks[r][kc+ii*4+0]=f2tf(kv.x); Ks[r][kc+ii*4+1]=f2tf(kv.y);
                Ks[r][kc+ii*4+2]=f2tf(kv.z); Ks[r][kc+ii*4+3]=f2tf(kv.w);
                float4 vv = *(const float4*)&Vb[(size_t)(c0+r)*64 + kc + ii*4];
                Vs[r][kc+ii*4+0]=f2tf(vv.x); Vs[r][kc+ii*4+1]=f2tf(vv.y);
                Vs[r][kc+ii*4+2]=f2tf(vv.z); Vs[r][kc+ii*4+3]=f2tf(vv.w);
            }
        }
        __syncthreads();

        float s[2][2][4];
#pragma unroll
        for (int i=0;i<2;i++)
#pragma unroll
            for (int j=0;j<2;j++)
#pragma unroll
                for (int h=0;h<4;h++) s[i][j][h]=0.f;
#pragma unroll
        for (int ks = 0; ks < 64; ks += 8) {
            uint32_t af[2][4], bf[2][2];
#pragma unroll
            for (int i = 0; i < 2; i++) {
                int r = wm*32 + i*16 + g;
                af[i][0] = __float_as_uint(Qs[r][ks+t4]);
                af[i][1] = __float_as_uint(Qs[r+8][ks+t4]);
                af[i][2] = __float_as_uint(Qs[r][ks+t4+4]);
                af[i][3] = __float_as_uint(Qs[r+8][ks+t4+4]);
            }
#pragma unroll
            for (int j = 0; j < 2; j++) {
                int cc = wn*16 + j*8 + g;
                bf[j][0] = __float_as_uint(Ks[cc][ks+t4]);
                bf[j][1] = __float_as_uint(Ks[cc][ks+t4+4]);
            }
#pragma unroll
            for (int i = 0; i < 2; i++)
#pragma unroll
                for (int j = 0; j < 2; j++) {
                    asm volatile(
                        "mma.sync.aligned.m16n8k8.row.col.f32.tf32.tf32.f32 "
                        "{%0,%1,%2,%3}, {%4,%5,%6,%7}, {%8,%9}, {%0,%1,%2,%3};\n"
                        : "+f"(s[i][j][0]), "+f"(s[i][j][1]),
                          "+f"(s[i][j][2]), "+f"(s[i][j][3])
                        : "r"(af[i][0]), "r"(af[i][1]), "r"(af[i][2]), "r"(af[i][3]),
                          "r"(bf[j][0]), "r"(bf[j][1]));
                }
        }

        float pm[2][2];
#pragma unroll
        for (int i=0;i<2;i++)
#pragma unroll
            for (int h=0;h<2;h++)
                pm[i][h] = fmaxf(fmaxf(s[i][0][2*h], s[i][0][2*h+1]),
                                 fmaxf(s[i][1][2*h], s[i][1][2*h+1]));
#pragma unroll
        for (int off = 1; off <= 2; off <<= 1) {
#pragma unroll
            for (int i=0;i<2;i++)
#pragma unroll
                for (int h=0;h<2;h++)
                    pm[i][h] = fmaxf(pm[i][h], __shfl_xor_sync(0xffffffffu, pm[i][h], off));
        }
        if (t4 == 0) {
#pragma unroll
            for (int i=0;i<2;i++)
#pragma unroll
                for (int h=0;h<2;h++)
                    redm[wm*32 + i*16 + g + h*8][wn] = pm[i][h];
        }
        __syncthreads();

        float mnew[2][2], scale[2][2];
#pragma unroll
        for (int i=0;i<2;i++)
#pragma unroll
            for (int h=0;h<2;h++) {
                int r = wm*32 + i*16 + g + h*8;
                float m = fmaxf(fmaxf(redm[r][0], redm[r][1]),
                                fmaxf(redm[r][2], redm[r][3]));
                float mo = rowm[r];
                mnew[i][h] = fmaxf(mo, m);
                scale[i][h] = __expf(mo - mnew[i][h]);
            }

        float psum[2][2] = {{0.f,0.f},{0.f,0.f}};
#pragma unroll
        for (int i=0;i<2;i++)
#pragma unroll
            for (int j=0;j<2;j++)
#pragma unroll
                for (int h=0;h<2;h++) {
                    int r = wm*32 + i*16 + g + h*8;
                    float p0 = __expf(s[i][j][2*h]   - mnew[i][h]);
                    float p1 = __expf(s[i][j][2*h+1] - mnew[i][h]);
                    *(float2*)&Ps[r][wn*16 + j*8 + 2*t4] = make_float2(f2tf(p0), f2tf(p1));
                    psum[i][h] += p0 + p1;
                    o[i][j][2*h]   *= scale[i][h];
                    o[i][j][2*h+1] *= scale[i][h];
                }
#pragma unroll
        for (int off = 1; off <= 2; off <<= 1) {
#pragma unroll
            for (int i=0;i<2;i++)
#pragma unroll
                for (int h=0;h<2;h++)
                    psum[i][h] += __shfl_xor_sync(0xffffffffu, psum[i][h], off);
        }
        if (t4 == 0) {
#pragma unroll
            for (int i=0;i<2;i++)
#pragma unroll
                for (int h=0;h<2;h++)
                    reds[wm*32 + i*16 + g + h*8][wn] = psum[i][h];
        }
        __syncthreads();

        if (wn == 0 && t4 == 0) {
#pragma unroll
            for (int i=0;i<2;i++)
#pragma unroll
                for (int h=0;h<2;h++) {
                    int r = wm*32 + i*16 + g + h*8;
                    float ps = reds[r][0] + reds[r][1] + reds[r][2] + reds[r][3];
                    rowl[r] = rowl[r]*scale[i][h] + ps;
                    rowm[r] = mnew[i][h];
                }
        }

#pragma unroll
        for (int ks = 0; ks < 64; ks += 8) {
            uint32_t af[2][4], bf[2][2];
#pragma unroll
            for (int i = 0; i < 2; i++) {
                int r = wm*32 + i*16 + g;
                af[i][0] = __float_as_uint(Ps[r][ks+t4]);
                af[i][1] = __float_as_uint(Ps[r+8][ks+t4]);
                af[i][2] = __float_as_uint(Ps[r][ks+t4+4]);
                af[i][3] = __float_as_uint(Ps[r+8][ks+t4+4]);
            }
#pragma unroll
            for (int j = 0; j < 2; j++) {
                int cc = wn*16 + j*8 + g;
                bf[j][0] = __float_as_uint(Vs[ks+t4][cc]);
                bf[j][1] = __float_as_uint(Vs[ks+t4+4][cc]);
            }
#pragma unroll
            for (int i = 0; i < 2; i++)
#pragma unroll
                for (int j = 0; j < 2; j++) {
                    asm volatile(
                        "mma.sync.aligned.m16n8k8.row.col.f32.tf32.tf32.f32 "
                        "{%0,%1,%2,%3}, {%4,%5,%6,%7}, {%8,%9}, {%0,%1,%2,%3};\n"
                        : "+f"(o[i][j][0]), "+f"(o[i][j][1]),
                          "+f"(o[i][j][2]), "+f"(o[i][j][3])
                        : "r"(af[i][0]), "r"(af[i][1]), "r"(af[i][2]), "r"(af[i][3]),
                          "r"(bf[j][0]), "r"(bf[j][1]));
                }
        }
        __syncthreads();
    }

    if (lpart != nullptr) {
        float* Ob = O + ((size_t)(blockIdx.z*32 + bh)*nq + q0) * 64;
#pragma unroll
        for (int i=0;i<2;i++)
#pragma unroll
            for (int j=0;j<2;j++)
#pragma unroll
                for (int h=0;h<2;h++) {
                    int r = wm*32 + i*16 + g + h*8;
                    int cc = wn*16 + j*8 + 2*t4;
                    *(float2*)&Ob[(size_t)r*64 + cc] =
                        make_float2(o[i][j][2*h], o[i][j][2*h+1]);
                }
        if (tid < 64) {
            size_t ri = (size_t)(blockIdx.z*32 + bh)*nq + q0 + tid;
            mpart[ri] = rowm[tid];
            lpart[ri] = rowl[tid];
        }
    } else {
        float* Ob = O + ((size_t)bh*nq + q0) * 64;
#pragma unroll
        for (int i=0;i<2;i++)
#pragma unroll
            for (int j=0;j<2;j++)
#pragma unroll
                for (int h=0;h<2;h++) {
                    int r = wm*32 + i*16 + g + h*8;
                    int cc = wn*16 + j*8 + 2*t4;
                    float inv = 1.f / rowl[r];
                    *(float2*)&Ob[(size_t)r*64 + cc] =
                        make_float2(o[i][j][2*h]*inv, o[i][j][2*h+1]*inv);
                }
    }
}

// ---------------------------------------------------------------------------
// Single-pass flash for flash-2 (nk == 256): all 4 S-tiles held in registers,
// ONE softmax (global row max, no O rescaling), then 4 P@V tiles.
// Removes 3 of 4 reduction round-trips and all rescale work.
// ---------------------------------------------------------------------------
__global__ __launch_bounds__(256) void flash2_sp_kernel(
        const float* __restrict__ Q, const float* __restrict__ K,
        const float* __restrict__ V, float* __restrict__ O) {
    extern __shared__ float sm[];
    float (*Qs)[QP] = (float(*)[QP])sm;
    float (*Ks)[QP] = (float(*)[QP])(sm + OFF_KS);
    float (*Ps)[QP] = (float(*)[QP])(sm + OFF_PS);
    float (*Vs)[VP] = (float(*)[VP])(sm + OFF_VS);
    float (*redm)[4] = (float(*)[4])(sm + OFF_REDM);
    float (*reds)[4] = (float(*)[4])(sm + OFF_REDS);

    int tid = threadIdx.x;
    int lane = tid & 31, wid = tid >> 5;
    int wm = wid & 1, wn = wid >> 1;
    int g = lane >> 2, t4 = lane & 3;
    int bh = blockIdx.y;
    int q0 = blockIdx.x * 64;
    const float* Qb = Q + ((size_t)bh*4096 + q0) * 64;
    const float* Kb = K + (size_t)bh*256*64;
    const float* Vb = V + (size_t)bh*256*64;
    float* Ob = O + ((size_t)bh*4096 + q0) * 64;

    int lr = tid >> 2, lk = (tid & 3) * 16;
    {
#pragma unroll
        for (int ii = 0; ii < 4; ii++) {
            float4 qv = *(const float4*)&Qb[(size_t)lr*64 + lk + ii*4];
            Qs[lr][lk+ii*4+0]=f2tf(qv.x); Qs[lr][lk+ii*4+1]=f2tf(qv.y);
            Qs[lr][lk+ii*4+2]=f2tf(qv.z); Qs[lr][lk+ii*4+3]=f2tf(qv.w);
        }
    }

    float s[4][2][2][4];
    float o[2][2][4];
#pragma unroll
    for (int i=0;i<2;i++)
#pragma unroll
        for (int j=0;j<2;j++)
#pragma unroll
            for (int h=0;h<4;h++) o[i][j][h]=0.f;

    // phase 1: all 4 S tiles into registers
#pragma unroll
    for (int t = 0; t < 4; t++) {
        {
#pragma unroll
            for (int ii = 0; ii < 4; ii++) {
                float4 kv = *(const float4*)&Kb[(size_t)(t*64+lr)*64 + lk + ii*4];
                Ks[lr][lk+ii*4+0]=f2tf(kv.x); Ks[lr][lk+ii*4+1]=f2tf(kv.y);
                Ks[lr][lk+ii*4+2]=f2tf(kv.z); Ks[lr][lk+ii*4+3]=f2tf(kv.w);
            }
        }
        __syncthreads();
#pragma unroll
        for (int i=0;i<2;i++)
#pragma unroll
            for (int j=0;j<2;j++)
#pragma unroll
                for (int h=0;h<4;h++) s[t][i][j][h]=0.f;
#pragma unroll
        for (int ks = 0; ks < 64; ks += 8) {
            uint32_t af[2][4], bf[2][2];
#pragma unroll
            for (int i = 0; i < 2; i++) {
                int r = wm*32 + i*16 + g;
                af[i][0] = __float_as_uint(Qs[r][ks+t4]);
                af[i][1] = __float_as_uint(Qs[r+8][ks+t4]);
                af[i][2] = __float_as_uint(Qs[r][ks+t4+4]);
                af[i][3] = __float_as_uint(Qs[r+8][ks+t4+4]);
            }
#pragma unroll
            for (int j = 0; j < 2; j++) {
                int cc = wn*16 + j*8 + g;
                bf[j][0] = __float_as_uint(Ks[cc][ks+t4]);
                bf[j][1] = __float_as_uint(Ks[cc][ks+t4+4]);
            }
#pragma unroll
            for (int i = 0; i < 2; i++)
#pragma unroll
                for (int j = 0; j < 2; j++) {
                    asm volatile(
                        "mma.sync.aligned.m16n8k8.row.col.f32.tf32.tf32.f32 "
                        "{%0,%1,%2,%3}, {%4,%5,%6,%7}, {%8,%9}, {%0,%1,%2,%3};\n"
                        : "+f"(s[t][i][j][0]), "+f"(s[t][i][j][1]),
                          "+f"(s[t][i][j][2]), "+f"(s[t][i][j][3])
                        : "r"(af[i][0]), "r"(af[i][1]), "r"(af[i][2]), "r"(af[i][3]),
                          "r"(bf[j][0]), "r"(bf[j][1]));
                }
        }
        __syncthreads();
    }

    // single softmax over all 256 cols
    float pm[2][2];
#pragma unroll
    for (int i=0;i<2;i++)
#pragma unroll
        for (int h=0;h<2;h++) {
            float m = s[0][i][0][2*h];
#pragma unroll
            for (int t=0;t<4;t++)
#pragma unroll
                for (int j=0;j<2;j++) {
                    m = fmaxf(m, s[t][i][j][2*h]);
                    m = fmaxf(m, s[t][i][j][2*h+1]);
                }
#pragma unroll
            for (int off = 1; off <= 2; off <<= 1)
                m = fmaxf(m, __shfl_xor_sync(0xffffffffu, m, off));
            pm[i][h] = m;
        }
    if (t4 == 0) {
#pragma unroll
        for (int i=0;i<2;i++)
#pragma unroll
            for (int h=0;h<2;h++)
                redm[wm*32 + i*16 + g + h*8][wn] = pm[i][h];
    }
    __syncthreads();

    float linv[2][2];
    {
        float psum[2][2];
#pragma unroll
        for (int i=0;i<2;i++)
#pragma unroll
            for (int h=0;h<2;h++) {
                int r = wm*32 + i*16 + g + h*8;
                float m = fmaxf(fmaxf(redm[r][0], redm[r][1]),
                                fmaxf(redm[r][2], redm[r][3]));
                float ps = 0.f;
#pragma unroll
                for (int t=0;t<4;t++)
#pragma unroll
                    for (int j=0;j<2;j++) {
                        float p0 = __expf(s[t][i][j][2*h]   - m);
                        float p1 = __expf(s[t][i][j][2*h+1] - m);
                        s[t][i][j][2*h] = p0; s[t][i][j][2*h+1] = p1;
                        ps += p0 + p1;
                    }
#pragma unroll
                for (int off = 1; off <= 2; off <<= 1)
                    ps += __shfl_xor_sync(0xffffffffu, ps, off);
                psum[i][h] = ps;
            }
        if (t4 == 0) {
#pragma unroll
            for (int i=0;i<2;i++)
#pragma unroll
                for (int h=0;h<2;h++)
                    reds[wm*32 + i*16 + g + h*8][wn] = psum[i][h];
        }
        __syncthreads();
#pragma unroll
        for (int i=0;i<2;i++)
#pragma unroll
            for (int h=0;h<2;h++) {
                int r = wm*32 + i*16 + g + h*8;
                linv[i][h] = 1.f / (reds[r][0]+reds[r][1]+reds[r][2]+reds[r][3]);
            }
    }

    // phase 2: P@V per tile (no rescaling, O accumulates final p)
#pragma unroll
    for (int t = 0; t < 4; t++) {
#pragma unroll
        for (int i=0;i<2;i++)
#pragma unroll
            for (int j=0;j<2;j++)
#pragma unroll
                for (int h=0;h<2;h++) {
                    int r = wm*32 + i*16 + g + h*8;
                    *(float2*)&Ps[r][wn*16 + j*8 + 2*t4] =
                        make_float2(f2tf(s[t][i][j][2*h]), f2tf(s[t][i][j][2*h+1]));
                }
        {
#pragma unroll
            for (int ii = 0; ii < 4; ii++) {
                float4 vv = *(const float4*)&Vb[(size_t)(t*64+lr)*64 + lk + ii*4];
                Vs[lr][lk+ii*4+0]=f2tf(vv.x); Vs[lr][lk+ii*4+1]=f2tf(vv.y);
                Vs[lr][lk+ii*4+2]=f2tf(vv.z); Vs[lr][lk+ii*4+3]=f2tf(vv.w);
            }
        }
        __syncthreads();
#pragma unroll
        for (int ks = 0; ks < 64; ks += 8) {
            uint32_t af[2][4], bf[2][2];
#pragma unroll
            for (int i = 0; i < 2; i++) {
                int r = wm*32 + i*16 + g;
                af[i][0] = __float_as_uint(Ps[r][ks+t4]);
                af[i][1] = __float_as_uint(Ps[r+8][ks+t4]);
                af[i][2] = __float_as_uint(Ps[r][ks+t4+4]);
                af[i][3] = __float_as_uint(Ps[r+8][ks+t4+4]);
            }
#pragma unroll
            for (int j = 0; j < 2; j++) {
                int cc = wn*16 + j*8 + g;
                bf[j][0] = __float_as_uint(Vs[ks+t4][cc]);
                bf[j][1] = __float_as_uint(Vs[ks+t4+4][cc]);
            }
#pragma unroll
            for (int i = 0; i < 2; i++)
#pragma unroll
                for (int j = 0; j < 2; j++) {
                    asm volatile(
                        "mma.sync.aligned.m16n8k8.row.col.f32.tf32.tf32.f32 "
                        "{%0,%1,%2,%3}, {%4,%5,%6,%7}, {%8,%9}, {%0,%1,%2,%3};\n"
                        : "+f"(o[i][j][0]), "+f"(o[i][j][1]),
                          "+f"(o[i][j][2]), "+f"(o[i][j][3])
                        : "r"(af[i][0]), "r"(af[i][1]), "r"(af[i][2]), "r"(af[i][3]),
                          "r"(bf[j][0]), "r"(bf[j][1]));
                }
        }
        __syncthreads();
    }

#pragma unroll
    for (int i=0;i<2;i++)
#pragma unroll
        for (int j=0;j<2;j++)
#pragma unroll
            for (int h=0;h<2;h++) {
                int r = wm*32 + i*16 + g + h*8;
                int cc = wn*16 + j*8 + 2*t4;
                *(float2*)&Ob[(size_t)r*64 + cc] =
                    make_float2(o[i][j][2*h]*linv[i][h], o[i][j][2*h+1]*linv[i][h]);
            }
}

// ---------------------------------------------------------------------------
// Split-K combine
// ---------------------------------------------------------------------------
__global__ void combine_kernel(const float* __restrict__ Op,
                               const float* __restrict__ mp,
                               const float* __restrict__ lp,
                               float* __restrict__ w) {
    int row = blockIdx.x;
    int c = threadIdx.x;
    int bh = row >> 8, qr = row & 255;
    float m0 = mp[(0*32+bh)*256+qr], m1 = mp[(1*32+bh)*256+qr];
    float m2 = mp[(2*32+bh)*256+qr], m3 = mp[(3*32+bh)*256+qr];
    float ms = fmaxf(fmaxf(m0,m1), fmaxf(m2,m3));
    float w0 = __expf(m0-ms), w1 = __expf(m1-ms), w2 = __expf(m2-ms), w3 = __expf(m3-ms);
    float l = w0*lp[(0*32+bh)*256+qr] + w1*lp[(1*32+bh)*256+qr]
            + w2*lp[(2*32+bh)*256+qr] + w3*lp[(3*32+bh)*256+qr];
    float acc = w0*Op[((size_t)(0*32+bh)*256+qr)*64 + c]
              + w1*Op[((size_t)(1*32+bh)*256+qr)*64 + c]
              + w2*Op[((size_t)(2*32+bh)*256+qr)*64 + c]
              + w3*Op[((size_t)(3*32+bh)*256+qr)*64 + c];
    w[((size_t)bh*256+qr)*64 + c] = acc / l;
}

// ---------------------------------------------------------------------------
// Depthwise seq-conv residual + layout transform
// ---------------------------------------------------------------------------
__global__ __launch_bounds__(256) void conv_kernel(
        const float* __restrict__ attn, const float* __restrict__ v,
        const float* __restrict__ cw, float* __restrict__ attn2) {
    __shared__ float vt[96][64];
    __shared__ float wk[33];
    int bh = blockIdx.y; int h = bh & 7; int b4 = bh >> 3;
    int row0 = blockIdx.x * 64;
    int t = threadIdx.x;
    if (t < 33) wk[t] = cw[h*33 + t];
    const float* vb = v + (size_t)bh*4096*64;
#pragma unroll
    for (int i=0;i<6;i++){
        int f = t + i*256;
        int r = f >> 4;
        int c4 = (f & 15) * 4;
        int gr = row0 - 16 + r;
        float4 val = make_float4(0.f,0.f,0.f,0.f);
        if (gr >= 0 && gr < 4096) val = *(const float4*)&vb[(size_t)gr*64 + c4];
        *(float4*)&vt[r][c4] = val;
    }
    __syncthreads();
    int dh = t & 63;
    int rr = t >> 6;
#pragma unroll
    for (int q=0;q<16;q++){
        int lr = rr + q*4;
        float acc = attn[((size_t)bh*4096 + row0 + lr)*64 + dh];
#pragma unroll
        for (int s=0;s<33;s++) acc += wk[s]*vt[lr+s][dh];
        attn2[((size_t)b4*4096 + row0 + lr)*512 + h*64 + dh] = acc;
    }
}

// ---------------------------------------------------------------------------
// Host orchestration
// ---------------------------------------------------------------------------
extern "C" void kernel_launch(void* const* d_in, const int* in_sizes, int n_in,
                              void* d_out, int out_size) {
    const float* x      = (const float*)d_in[0];
    const float* norm_w = (const float*)d_in[1];
    const float* norm_b = (const float*)d_in[2];
    const float* Wqkv   = (const float*)d_in[3];
    const float* Wout   = (const float*)d_in[4];
    const float* bout   = (const float*)d_in[5];
    const float* conv_w = (const float*)d_in[6];
    float* out = (float*)d_out;

    float *xn,*q,*k,*v,*ql,*kl,*a2,*z0,*t1,*t2,*t3,*w,*w2,*uu,*r3,*u5,*attn,*attn2,*red;
    float *w4s[5];
    cudaGetSymbolAddress((void**)&xn,   g_xn);
    cudaGetSymbolAddress((void**)&q,    g_q);
    cudaGetSymbolAddress((void**)&k,    g_k);
    cudaGetSymbolAddress((void**)&v,    g_v);
    cudaGetSymbolAddress((void**)&ql,   g_ql);
    cudaGetSymbolAddress((void**)&kl,   g_kl);
    cudaGetSymbolAddress((void**)&a2,   g_a2);
    cudaGetSymbolAddress((void**)&z0,   g_z0);
    cudaGetSymbolAddress((void**)&t1,   g_t1);
    cudaGetSymbolAddress((void**)&t2,   g_t2);
    cudaGetSymbolAddress((void**)&t3,   g_t3);
    cudaGetSymbolAddress((void**)&w4s[0], g_w40);
    cudaGetSymbolAddress((void**)&w4s[1], g_w41);
    cudaGetSymbolAddress((void**)&w4s[2], g_w42);
    cudaGetSymbolAddress((void**)&w4s[3], g_w43);
    cudaGetSymbolAddress((void**)&w4s[4], g_w44);
    cudaGetSymbolAddress((void**)&w,    g_w);
    cudaGetSymbolAddress((void**)&w2,   g_w2);
    cudaGetSymbolAddress((void**)&uu,   g_u);
    cudaGetSymbolAddress((void**)&r3,   g_r3);
    cudaGetSymbolAddress((void**)&u5,   g_u5);
    cudaGetSymbolAddress((void**)&attn, g_attn);
    cudaGetSymbolAddress((void**)&attn2,g_attn2);
    cudaGetSymbolAddress((void**)&red,  g_red);

    cudaFuncSetAttribute(flash_tc_kernel, cudaFuncAttributeMaxDynamicSharedMemorySize, SMEM_FLASH_TC);
    cudaFuncSetAttribute(flash2_sp_kernel, cudaFuncAttributeMaxDynamicSharedMemorySize, SMEM_FLASH_TC);
    cudaFuncSetAttribute(a2_tc_kernel, cudaFuncAttributeMaxDynamicSharedMemorySize, SMEM_A2);

    // 1. LayerNorm
    ln_kernel<<<16384, 128>>>(x, norm_w, norm_b, xn);
    // 2. QKV projection (tf32 MMA, fused scatter + q scale)
    mma_gemm<0,512,1536,512><<<dim3(12,128), 256>>>(
        xn, Wqkv, q, k, v, nullptr, nullptr);
    // 3. landmarks (merged)
    landmark2_kernel<<<4096, 256>>>(q, k, ql, kl);
    // 4. a2 = softmax(q_l k_l^T) (tf32 MMA)
    a2_tc_kernel<<<dim3(2,32), 256, SMEM_A2>>>(ql, kl, a2);
    // 5. pinv init scalar + z0 = s*a2^T
    red_init_kernel<<<1, 32>>>(red);
    colsum_kernel<<<32, 256>>>(a2, red);
    zinit_kernel<<<8192, 256>>>(a2, red, z0);
    // 6. w = softmax(q_l k^T) @ v — split-K x4 flash + combine
    flash_tc_kernel<<<dim3(4,32,4), 256, SMEM_FLASH_TC>>>(
        ql, k, v, t1, 256, 4096, 1024, t2, t2 + 32768);
    combine_kernel<<<8192, 64>>>(t1, t2, t2 + 32768, w);
    // 7. Newton-Schulz pinv, Y-only recurrence, 128x128 tiles (proven):
    //    W2 = Y(7I-Y); W4_i = Y(15I-W2); Y' = 0.25*Y(13I-W4_i)   [it=0..4]
    mma_gemm_pinv<<<dim3(2,2,32), 256>>>(a2, z0, t1, 0.f, 1.f);   // Y0 = a2 @ z0
    float* Y = t1; float* Yn = t3;
    for (int it = 0; it < 5; it++) {
        mma_gemm_pinv<<<dim3(2,2,32), 256>>>(Y, Y, t2, 7.f, -1.f);        // W2
        mma_gemm_pinv<<<dim3(2,2,32), 256>>>(Y, t2, w4s[it], 15.f, -1.f); // W4_i
        mma_gemm_pinv<<<dim3(2,2,32), 256>>>(Y, w4s[it], Yn, 3.25f, -0.25f);
        float* tmp = Y; Y = Yn; Yn = tmp;
    }
    // Y == Y5. Narrow last iteration: u5 = 13w - 15 Y5w + 7 Y5^2w - Y5^3w
    mma_nar_kernel<<<dim3(1,2,32), 256>>>(Y, w,  uu, 0.f, 1.f);   // r1
    mma_nar_kernel<<<dim3(1,2,32), 256>>>(Y, uu, w2, 0.f, 1.f);   // r2
    mma_nar_kernel<<<dim3(1,2,32), 256>>>(Y, w2, r3, 0.f, 1.f);   // r3
    comb4_kernel<<<2048, 256>>>(w, uu, w2, r3, u5);
    // 8. narrow chain down: u_i = 13*u_{i+1} - W4_i @ u_{i+1}
    mma_nar_kernel<<<dim3(1,2,32), 256>>>(w4s[4], u5, uu, 13.f, -1.f);
    mma_nar_kernel<<<dim3(1,2,32), 256>>>(w4s[3], uu, w2, 13.f, -1.f);
    mma_nar_kernel<<<dim3(1,2,32), 256>>>(w4s[2], w2, uu, 13.f, -1.f);
    mma_nar_kernel<<<dim3(1,2,32), 256>>>(w4s[1], uu, w2, 13.f, -1.f);
    mma_nar_kernel<<<dim3(1,2,32), 256>>>(w4s[0], w2, uu, 13.f, -1.f);
    mma_nar_kernel<<<dim3(1,2,32), 256>>>(z0, uu, w2, 0.f, 1.f/4096.f);
    // 9. attn = softmax(q k_l^T) @ w2 — single-pass flash (nk=256)
    flash2_sp_kernel<<<dim3(64,32), 256, SMEM_FLASH_TC>>>(q, kl, w2, attn);
    // 10. conv residual + layout
    conv_kernel<<<dim3(64,32), 256>>>(attn, v, conv_w, attn2);
    // 11. output projection + bias + input residual (tf32 MMA)
    mma_gemm<1,512,512,512><<<dim3(4,128), 256>>>(
        attn2, Wout, out, nullptr, nullptr, bout, x);
}

// round 14
// speedup vs baseline: 1.0547x; 1.0049x over previous
#include <cuda_runtime.h>
#include <cuda_bf16.h>
#include <cstdint>

// ---------------------------------------------------------------------------
// Problem constants: b=4, n=4096, D=512, H=8, dh=64, M=256, l=16, 6 iters,
// conv k=33, eps=1e-5
// ---------------------------------------------------------------------------
#define NB   (4*4096*512)
#define MM   (32*256*256)
#define MD   (32*256*64)

__device__ float g_xn[NB];
__device__ float g_q[NB];
__device__ float g_k[NB];
__device__ float g_v[NB];
__device__ float g_ql[MD];
__device__ float g_kl[MD];
__device__ float g_a2[MM];
__device__ float g_z0[MM];
__device__ float g_t1[MM];   // Y ping / flash1 split-K O partials
__device__ float g_t2[MM];   // W2 scratch / flash1 split-K m/l partials
__device__ float g_t3[MM];   // Y pong
__device__ float g_w40[MM];
__device__ float g_w41[MM];
__device__ float g_w42[MM];
__device__ float g_w43[MM];
__device__ float g_w44[MM];
__device__ float g_w[MD];
__device__ float g_w2[MD];
__device__ float g_u[MD];
__device__ float g_r3[MD];
__device__ float g_u5[MD];
__device__ float g_attn[NB];
__device__ float g_attn2[NB];
__device__ float g_red[2];

__device__ __forceinline__ float f2tf(float x) {
    uint32_t u;
    asm("cvt.rna.tf32.f32 %0, %1;" : "=r"(u) : "f"(x));
    return __uint_as_float(u);
}

// ---------------------------------------------------------------------------
// LayerNorm
// ---------------------------------------------------------------------------
__global__ void ln_kernel(const float* __restrict__ x, const float* __restrict__ w,
                          const float* __restrict__ bb, float* __restrict__ out) {
    int row = blockIdx.x;
    const float* xr = x + (size_t)row * 512;
    float* orow = out + (size_t)row * 512;
    int t = threadIdx.x;
    float v[4];
    float s = 0.f;
#pragma unroll
    for (int i = 0; i < 4; i++) { v[i] = xr[t + 128*i]; s += v[i]; }
#pragma unroll
    for (int o = 16; o; o >>= 1) s += __shfl_xor_sync(0xffffffffu, s, o);
    __shared__ float red[4];
    if ((t & 31) == 0) red[t >> 5] = s;
    __syncthreads();
    float mean = (red[0]+red[1]+red[2]+red[3]) * (1.f/512.f);
    float vs = 0.f;
#pragma unroll
    for (int i = 0; i < 4; i++) { float d = v[i]-mean; vs += d*d; }
#pragma unroll
    for (int o = 16; o; o >>= 1) vs += __shfl_xor_sync(0xffffffffu, vs, o);
    __syncthreads();
    if ((t & 31) == 0) red[t >> 5] = vs;
    __syncthreads();
    float var = (red[0]+red[1]+red[2]+red[3]) * (1.f/512.f);
    float rstd = rsqrtf(var + 1e-5f);
#pragma unroll
    for (int i = 0; i < 4; i++) {
        int c = t + 128*i;
        orow[c] = (v[i]-mean)*rstd*w[c] + bb[c];
    }
}

// ---------------------------------------------------------------------------
// TF32 GEMM (proven): block 128x128, BK=16, 8 warps 64x32, occ 2.
// EPI 0: QKV scatter. EPI 1: bias + residual.
// ---------------------------------------------------------------------------
template<int EPI, int LDA, int LDB, int KD>
__global__ __launch_bounds__(256, 2) void mma_gemm(
        const float* __restrict__ A, const float* __restrict__ B,
        float* __restrict__ C0, float* __restrict__ C1, float* __restrict__ C2,
        const float* __restrict__ e0, const float* __restrict__ e1) {
    __shared__ float Asm[2][128*20];
    __shared__ float Bsm[2][16*136];
    int tid = threadIdx.x;
    int lane = tid & 31, wid = tid >> 5;
    int wm = wid & 1, wn = wid >> 1;
    int g = lane >> 2, t4 = lane & 3;
    int row0 = blockIdx.y * 128, col0 = blockIdx.x * 128;
    int arow = tid >> 1, akq = (tid & 1) * 8;
    int bkr = tid >> 4, bnc = (tid & 15) * 8;

    {
        const float* ap = A + (size_t)(row0 + arow) * LDA + akq;
        float4 a0 = *(const float4*)ap;
        float4 a1 = *(const float4*)(ap + 4);
        float* as = &Asm[0][arow*20 + akq];
        as[0]=f2tf(a0.x); as[1]=f2tf(a0.y); as[2]=f2tf(a0.z); as[3]=f2tf(a0.w);
        as[4]=f2tf(a1.x); as[5]=f2tf(a1.y); as[6]=f2tf(a1.z); as[7]=f2tf(a1.w);
        const float* bp = B + (size_t)bkr * LDB + col0 + bnc;
        float4 b0 = *(const float4*)bp;
        float4 b1 = *(const float4*)(bp + 4);
        float* bs = &Bsm[0][bkr*136 + bnc];
        bs[0]=f2tf(b0.x); bs[1]=f2tf(b0.y); bs[2]=f2tf(b0.z); bs[3]=f2tf(b0.w);
        bs[4]=f2tf(b1.x); bs[5]=f2tf(b1.y); bs[6]=f2tf(b1.z); bs[7]=f2tf(b1.w);
    }
    __syncthreads();

    float c[4][4][4];
#pragma unroll
    for (int i=0;i<4;i++)
#pragma unroll
        for (int j=0;j<4;j++)
#pragma unroll
            for (int h=0;h<4;h++) c[i][j][h]=0.f;

    const int NIT = KD / 16;
    for (int it = 0; it < NIT; it++) {
        int buf = it & 1;
        float4 pa0, pa1, pb0, pb1;
        if (it + 1 < NIT) {
            int k0 = (it + 1) * 16;
            const float* ap = A + (size_t)(row0 + arow) * LDA + k0 + akq;
            pa0 = *(const float4*)ap;
            pa1 = *(const float4*)(ap + 4);
            const float* bp = B + (size_t)(k0 + bkr) * LDB + col0 + bnc;
            pb0 = *(const float4*)bp;
            pb1 = *(const float4*)(bp + 4);
        }
#pragma unroll
        for (int ks = 0; ks < 16; ks += 8) {
            uint32_t af[4][4], bf[4][2];
#pragma unroll
            for (int i = 0; i < 4; i++) {
                int r0i = (wm*64 + i*16 + g) * 20 + ks + t4;
                int r1i = r0i + 8*20;
                af[i][0] = __float_as_uint(Asm[buf][r0i]);
                af[i][1] = __float_as_uint(Asm[buf][r1i]);
                af[i][2] = __float_as_uint(Asm[buf][r0i + 4]);
                af[i][3] = __float_as_uint(Asm[buf][r1i + 4]);
            }
#pragma unroll
            for (int j = 0; j < 4; j++) {
                int nc2 = wn*32 + j*8 + g;
                bf[j][0] = __float_as_uint(Bsm[buf][(ks + t4)*136 + nc2]);
                bf[j][1] = __float_as_uint(Bsm[buf][(ks + t4 + 4)*136 + nc2]);
            }
#pragma unroll
            for (int i = 0; i < 4; i++)
#pragma unroll
                for (int j = 0; j < 4; j++) {
                    asm volatile(
                        "mma.sync.aligned.m16n8k8.row.col.f32.tf32.tf32.f32 "
                        "{%0,%1,%2,%3}, {%4,%5,%6,%7}, {%8,%9}, {%0,%1,%2,%3};\n"
                        : "+f"(c[i][j][0]), "+f"(c[i][j][1]),
                          "+f"(c[i][j][2]), "+f"(c[i][j][3])
                        : "r"(af[i][0]), "r"(af[i][1]), "r"(af[i][2]), "r"(af[i][3]),
                          "r"(bf[j][0]), "r"(bf[j][1]));
                }
        }
        if (it + 1 < NIT) {
            int nb = buf ^ 1;
            float* as = &Asm[nb][arow*20 + akq];
            as[0]=f2tf(pa0.x); as[1]=f2tf(pa0.y); as[2]=f2tf(pa0.z); as[3]=f2tf(pa0.w);
            as[4]=f2tf(pa1.x); as[5]=f2tf(pa1.y); as[6]=f2tf(pa1.z); as[7]=f2tf(pa1.w);
            float* bs = &Bsm[nb][bkr*136 + bnc];
            bs[0]=f2tf(pb0.x); bs[1]=f2tf(pb0.y); bs[2]=f2tf(pb0.z); bs[3]=f2tf(pb0.w);
            bs[4]=f2tf(pb1.x); bs[5]=f2tf(pb1.y); bs[6]=f2tf(pb1.z); bs[7]=f2tf(pb1.w);
        }
        __syncthreads();
    }

#pragma unroll
    for (int i = 0; i < 4; i++) {
#pragma unroll
        for (int j = 0; j < 4; j++) {
#pragma unroll
            for (int h = 0; h < 2; h++) {
                int r = row0 + wm*64 + i*16 + g + h*8;
                int cc = col0 + wn*32 + j*8 + 2*t4;
                float v0 = c[i][j][h*2+0], v1 = c[i][j][h*2+1];
                if (EPI == 0) {
                    int b4 = r >> 12, nn = r & 4095;
                    int which = cc >> 9, cs = cc & 511;
                    int hh = cs >> 6, dh = cs & 63;
                    size_t di = ((size_t)(b4*8+hh)*4096 + nn)*64 + dh;
                    if (which == 0) {
                        *(float2*)&C0[di] = make_float2(v0*0.125f, v1*0.125f);
                    } else if (which == 1) {
                        *(float2*)&C1[di] = make_float2(v0, v1);
                    } else {
                        *(float2*)&C2[di] = make_float2(v0, v1);
                    }
                } else {
                    size_t di = (size_t)r*512 + cc;
                    float2 bias = *(const float2*)&e0[cc];
                    float2 xr = *(const float2*)&e1[di];
                    *(float2*)&C0[di] = make_float2(v0+bias.x+xr.x, v1+bias.y+xr.y);
                }
            }
        }
    }
}

// ---------------------------------------------------------------------------
// TF32 GEMM, pinv variant (proven 128x128): batched over z (stride 65536):
// C0 = cA*A + cAB*(A@B)
// ---------------------------------------------------------------------------
__global__ __launch_bounds__(256, 2) void mma_gemm_pinv(
        const float* __restrict__ A, const float* __restrict__ B,
        float* __restrict__ C0, float cA, float cAB) {
    __shared__ float Asm[2][128*20];
    __shared__ float Bsm[2][16*136];
    int tid = threadIdx.x;
    int lane = tid & 31, wid = tid >> 5;
    int wm = wid & 1, wn = wid >> 1;
    int g = lane >> 2, t4 = lane & 3;
    int row0 = blockIdx.y * 128, col0 = blockIdx.x * 128;
    const float* Ag = A + (size_t)blockIdx.z * 65536;
    const float* Bg = B + (size_t)blockIdx.z * 65536;
    int arow = tid >> 1, akq = (tid & 1) * 8;
    int bkr = tid >> 4, bnc = (tid & 15) * 8;

    {
        const float* ap = Ag + (size_t)(row0 + arow) * 256 + akq;
        float4 a0 = *(const float4*)ap;
        float4 a1 = *(const float4*)(ap + 4);
        float* as = &Asm[0][arow*20 + akq];
        as[0]=f2tf(a0.x); as[1]=f2tf(a0.y); as[2]=f2tf(a0.z); as[3]=f2tf(a0.w);
        as[4]=f2tf(a1.x); as[5]=f2tf(a1.y); as[6]=f2tf(a1.z); as[7]=f2tf(a1.w);
        const float* bp = Bg + (size_t)bkr * 256 + col0 + bnc;
        float4 b0 = *(const float4*)bp;
        float4 b1 = *(const float4*)(bp + 4);
        float* bs = &Bsm[0][bkr*136 + bnc];
        bs[0]=f2tf(b0.x); bs[1]=f2tf(b0.y); bs[2]=f2tf(b0.z); bs[3]=f2tf(b0.w);
        bs[4]=f2tf(b1.x); bs[5]=f2tf(b1.y); bs[6]=f2tf(b1.z); bs[7]=f2tf(b1.w);
    }
    __syncthreads();

    float c[4][4][4];
#pragma unroll
    for (int i=0;i<4;i++)
#pragma unroll
        for (int j=0;j<4;j++)
#pragma unroll
            for (int h=0;h<4;h++) c[i][j][h]=0.f;

    const int NIT = 16;
    for (int it = 0; it < NIT; it++) {
        int buf = it & 1;
        float4 pa0, pa1, pb0, pb1;
        if (it + 1 < NIT) {
            int k0 = (it + 1) * 16;
            const float* ap = Ag + (size_t)(row0 + arow) * 256 + k0 + akq;
            pa0 = *(const float4*)ap;
            pa1 = *(const float4*)(ap + 4);
            const float* bp = Bg + (size_t)(k0 + bkr) * 256 + col0 + bnc;
            pb0 = *(const float4*)bp;
            pb1 = *(const float4*)(bp + 4);
        }
#pragma unroll
        for (int ks = 0; ks < 16; ks += 8) {
            uint32_t af[4][4], bf[4][2];
#pragma unroll
            for (int i = 0; i < 4; i++) {
                int r0i = (wm*64 + i*16 + g) * 20 + ks + t4;
                int r1i = r0i + 8*20;
                af[i][0] = __float_as_uint(Asm[buf][r0i]);
                af[i][1] = __float_as_uint(Asm[buf][r1i]);
                af[i][2] = __float_as_uint(Asm[buf][r0i + 4]);
                af[i][3] = __float_as_uint(Asm[buf][r1i + 4]);
            }
#pragma unroll
            for (int j = 0; j < 4; j++) {
                int nc2 = wn*32 + j*8 + g;
                bf[j][0] = __float_as_uint(Bsm[buf][(ks + t4)*136 + nc2]);
                bf[j][1] = __float_as_uint(Bsm[buf][(ks + t4 + 4)*136 + nc2]);
            }
#pragma unroll
            for (int i = 0; i < 4; i++)
#pragma unroll
                for (int j = 0; j < 4; j++) {
                    asm volatile(
                        "mma.sync.aligned.m16n8k8.row.col.f32.tf32.tf32.f32 "
                        "{%0,%1,%2,%3}, {%4,%5,%6,%7}, {%8,%9}, {%0,%1,%2,%3};\n"
                        : "+f"(c[i][j][0]), "+f"(c[i][j][1]),
                          "+f"(c[i][j][2]), "+f"(c[i][j][3])
                        : "r"(af[i][0]), "r"(af[i][1]), "r"(af[i][2]), "r"(af[i][3]),
                          "r"(bf[j][0]), "r"(bf[j][1]));
                }
        }
        if (it + 1 < NIT) {
            int nb = buf ^ 1;
            float* as = &Asm[nb][arow*20 + akq];
            as[0]=f2tf(pa0.x); as[1]=f2tf(pa0.y); as[2]=f2tf(pa0.z); as[3]=f2tf(pa0.w);
            as[4]=f2tf(pa1.x); as[5]=f2tf(pa1.y); as[6]=f2tf(pa1.z); as[7]=f2tf(pa1.w);
            float* bs = &Bsm[nb][bkr*136 + bnc];
            bs[0]=f2tf(pb0.x); bs[1]=f2tf(pb0.y); bs[2]=f2tf(pb0.z); bs[3]=f2tf(pb0.w);
            bs[4]=f2tf(pb1.x); bs[5]=f2tf(pb1.y); bs[6]=f2tf(pb1.z); bs[7]=f2tf(pb1.w);
        }
        __syncthreads();
    }

#pragma unroll
    for (int i = 0; i < 4; i++) {
#pragma unroll
        for (int j = 0; j < 4; j++) {
#pragma unroll
            for (int h = 0; h < 2; h++) {
                int r = row0 + wm*64 + i*16 + g + h*8;
                int cc = col0 + wn*32 + j*8 + 2*t4;
                float v0 = c[i][j][h*2+0], v1 = c[i][j][h*2+1];
                float2 ae = *(const float2*)&Ag[(size_t)r*256 + cc];
                size_t di = (size_t)blockIdx.z*65536 + (size_t)r*256 + cc;
                *(float2*)&C0[di] = make_float2(cA*ae.x + cAB*v0,
                                                cA*ae.y + cAB*v1);
            }
        }
    }
}

// ---------------------------------------------------------------------------
// TF32 MMA narrow GEMM: C = cB*B + cAB*(A@B), A [32][256][256], B,C [32][256][64].
// ---------------------------------------------------------------------------
__global__ __launch_bounds__(256, 2) void mma_nar_kernel(
        const float* __restrict__ A, const float* __restrict__ B,
        float* __restrict__ C, float cB, float cAB) {
    __shared__ float Asm[2][128*20];
    __shared__ float Bsm[2][16*72];
    int tid = threadIdx.x;
    int lane = tid & 31, wid = tid >> 5;
    int wm = wid & 3, wn = wid >> 2;
    int g = lane >> 2, t4 = lane & 3;
    int row0 = blockIdx.y * 128;
    const float* Ag = A + (size_t)blockIdx.z * 65536;
    const float* Bg = B + (size_t)blockIdx.z * 16384;
    float* Cg = C + (size_t)blockIdx.z * 16384;
    int arow = tid >> 1, akq = (tid & 1) * 8;
    int bkr = tid >> 4, bnc = (tid & 15) * 4;

    {
        const float* ap = Ag + (size_t)(row0 + arow) * 256 + akq;
        float4 a0 = *(const float4*)ap;
        float4 a1 = *(const float4*)(ap + 4);
        float* as = &Asm[0][arow*20 + akq];
        as[0]=f2tf(a0.x); as[1]=f2tf(a0.y); as[2]=f2tf(a0.z); as[3]=f2tf(a0.w);
        as[4]=f2tf(a1.x); as[5]=f2tf(a1.y); as[6]=f2tf(a1.z); as[7]=f2tf(a1.w);
        float4 bv = *(const float4*)(Bg + (size_t)bkr * 64 + bnc);
        float* bs = &Bsm[0][bkr*72 + bnc];
        bs[0]=f2tf(bv.x); bs[1]=f2tf(bv.y); bs[2]=f2tf(bv.z); bs[3]=f2tf(bv.w);
    }
    __syncthreads();

    float c[2][4][4];
#pragma unroll
    for (int i=0;i<2;i++)
#pragma unroll
        for (int j=0;j<4;j++)
#pragma unroll
            for (int h=0;h<4;h++) c[i][j][h]=0.f;

    const int NIT = 16;
    for (int it = 0; it < NIT; it++) {
        int buf = it & 1;
        float4 pa0, pa1, pb;
        if (it + 1 < NIT) {
            int k0 = (it + 1) * 16;
            const float* ap = Ag + (size_t)(row0 + arow) * 256 + k0 + akq;
            pa0 = *(const float4*)ap;
            pa1 = *(const float4*)(ap + 4);
            pb = *(const float4*)(Bg + (size_t)(k0 + bkr) * 64 + bnc);
        }
#pragma unroll
        for (int ks = 0; ks < 16; ks += 8) {
            uint32_t af[2][4], bf[4][2];
#pragma unroll
            for (int i = 0; i < 2; i++) {
                int r0i = (wm*32 + i*16 + g) * 20 + ks + t4;
                int r1i = r0i + 8*20;
                af[i][0] = __float_as_uint(Asm[buf][r0i]);
                af[i][1] = __float_as_uint(Asm[buf][r1i]);
                af[i][2] = __float_as_uint(Asm[buf][r0i + 4]);
                af[i][3] = __float_as_uint(Asm[buf][r1i + 4]);
            }
#pragma unroll
            for (int j = 0; j < 4; j++) {
                int nc2 = wn*32 + j*8 + g;
                bf[j][0] = __float_as_uint(Bsm[buf][(ks + t4)*72 + nc2]);
                bf[j][1] = __float_as_uint(Bsm[buf][(ks + t4 + 4)*72 + nc2]);
            }
#pragma unroll
            for (int i = 0; i < 2; i++)
#pragma unroll
                for (int j = 0; j < 4; j++) {
                    asm volatile(
                        "mma.sync.aligned.m16n8k8.row.col.f32.tf32.tf32.f32 "
                        "{%0,%1,%2,%3}, {%4,%5,%6,%7}, {%8,%9}, {%0,%1,%2,%3};\n"
                        : "+f"(c[i][j][0]), "+f"(c[i][j][1]),
                          "+f"(c[i][j][2]), "+f"(c[i][j][3])
                        : "r"(af[i][0]), "r"(af[i][1]), "r"(af[i][2]), "r"(af[i][3]),
                          "r"(bf[j][0]), "r"(bf[j][1]));
                }
        }
        if (it + 1 < NIT) {
            int nb = buf ^ 1;
            float* as = &Asm[nb][arow*20 + akq];
            as[0]=f2tf(pa0.x); as[1]=f2tf(pa0.y); as[2]=f2tf(pa0.z); as[3]=f2tf(pa0.w);
            as[4]=f2tf(pa1.x); as[5]=f2tf(pa1.y); as[6]=f2tf(pa1.z); as[7]=f2tf(pa1.w);
            float* bs = &Bsm[nb][bkr*72 + bnc];
            bs[0]=f2tf(pb.x); bs[1]=f2tf(pb.y); bs[2]=f2tf(pb.z); bs[3]=f2tf(pb.w);
        }
        __syncthreads();
    }

#pragma unroll
    for (int i = 0; i < 2; i++)
#pragma unroll
        for (int j = 0; j < 4; j++)
#pragma unroll
            for (int h = 0; h < 2; h++) {
                int r = row0 + wm*32 + i*16 + g + h*8;
                int cc = wn*32 + j*8 + 2*t4;
                float v0 = cAB * c[i][j][h*2+0];
                float v1 = cAB * c[i][j][h*2+1];
                if (cB != 0.f) {
                    float2 be = *(const float2*)&Bg[(size_t)r*64 + cc];
                    v0 += cB * be.x; v1 += cB * be.y;
                }
                *(float2*)&Cg[(size_t)r*64 + cc] = make_float2(v0, v1);
            }
}

// ---------------------------------------------------------------------------
// u5 = 13*w - 15*r1 + 7*r2 - r3  (elementwise, MD elems)
// ---------------------------------------------------------------------------
__global__ void comb4_kernel(const float* __restrict__ w, const float* __restrict__ r1,
                             const float* __restrict__ r2, const float* __restrict__ r3,
                             float* __restrict__ u5) {
    int i = blockIdx.x * 256 + threadIdx.x;
    u5[i] = 13.f*w[i] - 15.f*r1[i] + 7.f*r2[i] - r3[i];
}

// ---------------------------------------------------------------------------
// TF32 MMA a2 = softmax(q_l @ k_l^T), 64-row tiles -> grid (4,32) = 128 CTAs
// (was 128-row, grid 64: only 43% of SMs occupied).
// 8 warps: each owns all 64 rows x a 32-col slice (wn = wid).
// Dyn smem: Qs 64*68 + Ks 256*68 + redm 64*8 + reds 64*8 = 22784 floats.
// ---------------------------------------------------------------------------
#define A2_KS   4352
#define A2_RM   21760
#define A2_RS   22272
#define SMEM_A2 (22784*4)
__global__ __launch_bounds__(256, 1) void a2_tc_kernel(
        const float* __restrict__ ql, const float* __restrict__ kl,
        float* __restrict__ a2) {
    extern __shared__ float sm2[];
    float* Qs = sm2;                       // [64][68]
    float* Ks = sm2 + A2_KS;               // [256][68]
    float (*redm)[8] = (float(*)[8])(sm2 + A2_RM);
    float (*reds)[8] = (float(*)[8])(sm2 + A2_RS);

    int tid = threadIdx.x;
    int lane = tid & 31, wn = tid >> 5;    // warp owns cols wn*32..wn*32+31
    int g = lane >> 2, t4 = lane & 3;
    int bh = blockIdx.y;
    int row0 = blockIdx.x * 64;
    const float* qb = ql + ((size_t)bh*256 + row0) * 64;
    const float* kb = kl + (size_t)bh*256*64;

    for (int i = tid*4; i < 4096; i += 1024) {
        float4 qv = *(const float4*)&qb[i];
        int r = i >> 6, cc = i & 63;
        float* qs = &Qs[r*68 + cc];
        qs[0]=f2tf(qv.x); qs[1]=f2tf(qv.y); qs[2]=f2tf(qv.z); qs[3]=f2tf(qv.w);
    }
    for (int i = tid*4; i < 16384; i += 1024) {
        float4 kv = *(const float4*)&kb[i];
        int r = i >> 6, cc = i & 63;
        float* ks = &Ks[r*68 + cc];
        ks[0]=f2tf(kv.x); ks[1]=f2tf(kv.y); ks[2]=f2tf(kv.z); ks[3]=f2tf(kv.w);
    }
    __syncthreads();

    float c[4][4][4];
#pragma unroll
    for (int i=0;i<4;i++)
#pragma unroll
        for (int j=0;j<4;j++)
#pragma unroll
            for (int h=0;h<4;h++) c[i][j][h]=0.f;

#pragma unroll
    for (int ks = 0; ks < 64; ks += 8) {
        uint32_t af[4][4], bf[4][2];
#pragma unroll
        for (int i = 0; i < 4; i++) {
            int r0i = (i*16 + g)*68 + ks + t4;
            int r1i = r0i + 8*68;
            af[i][0] = __float_as_uint(Qs[r0i]);
            af[i][1] = __float_as_uint(Qs[r1i]);
            af[i][2] = __float_as_uint(Qs[r0i + 4]);
            af[i][3] = __float_as_uint(Qs[r1i + 4]);
        }
#pragma unroll
        for (int j = 0; j < 4; j++) {
            int cr = (wn*32 + j*8 + g)*68 + ks + t4;
            bf[j][0] = __float_as_uint(Ks[cr]);
            bf[j][1] = __float_as_uint(Ks[cr + 4]);
        }
#pragma unroll
        for (int i = 0; i < 4; i++)
#pragma unroll
            for (int j = 0; j < 4; j++) {
                asm volatile(
                    "mma.sync.aligned.m16n8k8.row.col.f32.tf32.tf32.f32 "
                    "{%0,%1,%2,%3}, {%4,%5,%6,%7}, {%8,%9}, {%0,%1,%2,%3};\n"
                    : "+f"(c[i][j][0]), "+f"(c[i][j][1]),
                      "+f"(c[i][j][2]), "+f"(c[i][j][3])
                    : "r"(af[i][0]), "r"(af[i][1]), "r"(af[i][2]), "r"(af[i][3]),
                      "r"(bf[j][0]), "r"(bf[j][1]));
            }
    }

    // per-warp row max over its 32 cols, quad-reduce, cross-warp via smem (8 warps)
    float pm[4][2];
#pragma unroll
    for (int i=0;i<4;i++)
#pragma unroll
        for (int h=0;h<2;h++) {
            float m = c[i][0][2*h];
#pragma unroll
            for (int j=0;j<4;j++) {
                m = fmaxf(m, c[i][j][2*h]);
                m = fmaxf(m, c[i][j][2*h+1]);
            }
#pragma unroll
            for (int off = 1; off <= 2; off <<= 1)
                m = fmaxf(m, __shfl_xor_sync(0xffffffffu, m, off));
            pm[i][h] = m;
        }
    if (t4 == 0) {
#pragma unroll
        for (int i=0;i<4;i++)
#pragma unroll
            for (int h=0;h<2;h++)
                redm[i*16 + g + h*8][wn] = pm[i][h];
    }
    __syncthreads();

    float psum[4][2];
#pragma unroll
    for (int i=0;i<4;i++)
#pragma unroll
        for (int h=0;h<2;h++) {
            int r = i*16 + g + h*8;
            float m = redm[r][0];
#pragma unroll
            for (int u=1;u<8;u++) m = fmaxf(m, redm[r][u]);
            float s = 0.f;
#pragma unroll
            for (int j=0;j<4;j++) {
                float p0 = __expf(c[i][j][2*h]   - m);
                float p1 = __expf(c[i][j][2*h+1] - m);
                c[i][j][2*h] = p0; c[i][j][2*h+1] = p1;
                s += p0 + p1;
            }
#pragma unroll
            for (int off = 1; off <= 2; off <<= 1)
                s += __shfl_xor_sync(0xffffffffu, s, off);
            psum[i][h] = s;
        }
    if (t4 == 0) {
#pragma unroll
        for (int i=0;i<4;i++)
#pragma unroll
            for (int h=0;h<2;h++)
                reds[i*16 + g + h*8][wn] = psum[i][h];
    }
    __syncthreads();

#pragma unroll
    for (int i=0;i<4;i++)
#pragma unroll
        for (int h=0;h<2;h++) {
            int r = i*16 + g + h*8;
            float ss = reds[r][0];
#pragma unroll
            for (int u=1;u<8;u++) ss += reds[r][u];
            float inv = 1.f / ss;
            float* orow = a2 + ((size_t)bh*256 + row0 + r) * 256;
#pragma unroll
            for (int j=0;j<4;j++) {
                int cc = wn*32 + j*8 + 2*t4;
                *(float2*)&orow[cc] = make_float2(c[i][j][2*h]*inv, c[i][j][2*h+1]*inv);
            }
        }
}

// ---------------------------------------------------------------------------
// Landmarks (merged q+k)
// ---------------------------------------------------------------------------
__global__ void landmark2_kernel(const float* __restrict__ q, const float* __restrict__ k,
                                 float* __restrict__ ql, float* __restrict__ kl) {
    int gidx = blockIdx.x * 256 + threadIdx.x;
    const float* src = (gidx < 524288) ? q : k;
    float* dst = (gidx < 524288) ? ql : kl;
    int idx = gidx & 524287;
    int dh = idx & 63;
    int mi = (idx >> 6) & 255;
    int bh = idx >> 14;
    const float* p = src + ((size_t)bh*4096 + mi*16)*64 + dh;
    float s = 0.f;
#pragma unroll
    for (int j = 0; j < 16; j++) s += p[j*64];
    dst[idx] = s * 0.0625f;
}

// ---------------------------------------------------------------------------
// pinv scalars: row-sum max == 1 exactly (softmax rows); need col-sum max.
// ---------------------------------------------------------------------------
__global__ void red_init_kernel(float* g) { if (threadIdx.x < 2) g[threadIdx.x] = 0.f; }

__global__ void colsum_kernel(const float* __restrict__ a2, float* __restrict__ gred) {
    int bh = blockIdx.x; int j = threadIdx.x;
    const float* base = a2 + (size_t)bh*65536;
    float s = 0.f;
    for (int i=0;i<256;i++) s += fabsf(base[(size_t)i*256 + j]);
#pragma unroll
    for (int o=16;o;o>>=1) s = fmaxf(s, __shfl_xor_sync(0xffffffffu,s,o));
    __shared__ float red[8];
    if ((j&31)==0) red[j>>5]=s;
    __syncthreads();
    if (j==0) {
        float m = red[0];
#pragma unroll
        for (int u=1;u<8;u++) m = fmaxf(m, red[u]);
        atomicMax((int*)&gred[1], __float_as_int(m));
    }
}

__global__ void zinit_kernel(const float* __restrict__ a2, const float* __restrict__ gred,
                             float* __restrict__ z) {
    int idx = blockIdx.x*256 + threadIdx.x;
    int j = idx & 255, i = (idx>>8) & 255, bh = idx >> 16;
    float inv = 1.f/gred[1];
    z[idx] = a2[((size_t)bh*256 + j)*256 + i] * inv;
}

// ---------------------------------------------------------------------------
// TF32 flash attention with optional split-K (used for flash-1, nk=4096)
// ---------------------------------------------------------------------------
#define QP 68
#define VP 72
#define OFF_KS   4352
#define OFF_PS   8704
#define OFF_VS   13056
#define OFF_ROWM 17664
#define OFF_ROWL 17728
#define OFF_REDM 17792
#define OFF_REDS 18048
#define SMEM_FLASH_TC ((18304)*4)

__global__ __launch_bounds__(256) void flash_tc_kernel(
        const float* __restrict__ Q, const float* __restrict__ K,
        const float* __restrict__ V, float* __restrict__ O, int nq, int nk,
        int chunk, float* __restrict__ mpart, float* __restrict__ lpart) {
    extern __shared__ float sm[];
    float (*Qs)[QP] = (float(*)[QP])sm;
    float (*Ks)[QP] = (float(*)[QP])(sm + OFF_KS);
    float (*Ps)[QP] = (float(*)[QP])(sm + OFF_PS);
    float (*Vs)[VP] = (float(*)[VP])(sm + OFF_VS);
    float* rowm = sm + OFF_ROWM;
    float* rowl = sm + OFF_ROWL;
    float (*redm)[4] = (float(*)[4])(sm + OFF_REDM);
    float (*reds)[4] = (float(*)[4])(sm + OFF_REDS);

    int tid = threadIdx.x;
    int lane = tid & 31, wid = tid >> 5;
    int wm = wid & 1, wn = wid >> 1;
    int g = lane >> 2, t4 = lane & 3;
    int bh = blockIdx.y;
    int q0 = blockIdx.x * 64;
    size_t koff = (size_t)blockIdx.z * chunk * 64;
    const float* Qb = Q + ((size_t)bh*nq + q0) * 64;
    const float* Kb = K + (size_t)bh*nk*64 + koff;
    const float* Vb = V + (size_t)bh*nk*64 + koff;

    {
        int r = tid >> 2, kc = (tid & 3) * 16;
#pragma unroll
        for (int ii = 0; ii < 4; ii++) {
            float4 qv = *(const float4*)&Qb[(size_t)r*64 + kc + ii*4];
            Qs[r][kc+ii*4+0]=f2tf(qv.x); Qs[r][kc+ii*4+1]=f2tf(qv.y);
            Qs[r][kc+ii*4+2]=f2tf(qv.z); Qs[r][kc+ii*4+3]=f2tf(qv.w);
        }
    }
    if (tid < 64) { rowm[tid] = -1e30f; rowl[tid] = 0.f; }
    float o[2][2][4];
#pragma unroll
    for (int i=0;i<2;i++)
#pragma unroll
        for (int j=0;j<2;j++)
#pragma unroll
            for (int h=0;h<4;h++) o[i][j][h]=0.f;
    __syncthreads();

    for (int c0 = 0; c0 < chunk; c0 += 64) {
        {
            int r = tid >> 2, kc = (tid & 3) * 16;
#pragma unroll
            for (int ii = 0; ii < 4; ii++) {
                float4 kv = *(const float4*)&Kb[(size_t)(c0+r)*64 + kc + ii*4];
                Ks[r][kc+ii*4+0]=f2tf(kv.x); Ks[r][kc+ii*4+1]=f2tf(kv.y);
                Ks[r][kc+ii*4+2]=f2tf(kv.z); Ks[r][kc+ii*4+3]=f2tf(kv.w);
                float4 vv = *(const float4*)&Vb[(size_t)(c0+r)*64 + kc + ii*4];
                Vs[r][kc+ii*4+0]=f2tf(vv.x); Vs[r][kc+ii*4+1]=f2tf(vv.y);
                Vs[r][kc+ii*4+2]=f2tf(vv.z); Vs[r][kc+ii*4+3]=f2tf(vv.w);
            }
        }
        __syncthreads();

        float s[2][2][4];
#pragma unroll
        for (int i=0;i<2;i++)
#pragma unroll
            for (int j=0;j<2;j++)
#pragma unroll
                for (int h=0;h<4;h++) s[i][j][h]=0.f;
#pragma unroll
        for (int ks = 0; ks < 64; ks += 8) {
            uint32_t af[2][4], bf[2][2];
#pragma unroll
            for (int i = 0; i < 2; i++) {
                int r = wm*32 + i*16 + g;
                af[i][0] = __float_as_uint(Qs[r][ks+t4]);
                af[i][1] = __float_as_uint(Qs[r+8][ks+t4]);
                af[i][2] = __float_as_uint(Qs[r][ks+t4+4]);
                af[i][3] = __float_as_uint(Qs[r+8][ks+t4+4]);
            }
#pragma unroll
            for (int j = 0; j < 2; j++) {
                int cc = wn*16 + j*8 + g;
                bf[j][0] = __float_as_uint(Ks[cc][ks+t4]);
                bf[j][1] = __float_as_uint(Ks[cc][ks+t4+4]);
            }
#pragma unroll
            for (int i = 0; i < 2; i++)
#pragma unroll
                for (int j = 0; j < 2; j++) {
                    asm volatile(
                        "mma.sync.aligned.m16n8k8.row.col.f32.tf32.tf32.f32 "
                        "{%0,%1,%2,%3}, {%4,%5,%6,%7}, {%8,%9}, {%0,%1,%2,%3};\n"
                        : "+f"(s[i][j][0]), "+f"(s[i][j][1]),
                          "+f"(s[i][j][2]), "+f"(s[i][j][3])
                        : "r"(af[i][0]), "r"(af[i][1]), "r"(af[i][2]), "r"(af[i][3]),
                          "r"(bf[j][0]), "r"(bf[j][1]));
                }
        }

        float pm[2][2];
#pragma unroll
        for (int i=0;i<2;i++)
#pragma unroll
            for (int h=0;h<2;h++)
                pm[i][h] = fmaxf(fmaxf(s[i][0][2*h], s[i][0][2*h+1]),
                                 fmaxf(s[i][1][2*h], s[i][1][2*h+1]));
#pragma unroll
        for (int off = 1; off <= 2; off <<= 1) {
#pragma unroll
            for (int i=0;i<2;i++)
#pragma unroll
                for (int h=0;h<2;h++)
                    pm[i][h] = fmaxf(pm[i][h], __shfl_xor_sync(0xffffffffu, pm[i][h], off));
        }
        if (t4 == 0) {
#pragma unroll
            for (int i=0;i<2;i++)
#pragma unroll
                for (int h=0;h<2;h++)
                    redm[wm*32 + i*16 + g + h*8][wn] = pm[i][h];
        }
        __syncthreads();

        float mnew[2][2], scale[2][2];
#pragma unroll
        for (int i=0;i<2;i++)
#pragma unroll
            for (int h=0;h<2;h++) {
                int r = wm*32 + i*16 + g + h*8;
                float m = fmaxf(fmaxf(redm[r][0], redm[r][1]),
                                fmaxf(redm[r][2], redm[r][3]));
                float mo = rowm[r];
                mnew[i][h] = fmaxf(mo, m);
                scale[i][h] = __expf(mo - mnew[i][h]);
            }

        float psum[2][2] = {{0.f,0.f},{0.f,0.f}};
#pragma unroll
        for (int i=0;i<2;i++)
#pragma unroll
            for (int j=0;j<2;j++)
#pragma unroll
                for (int h=0;h<2;h++) {
                    int r = wm*32 + i*16 + g + h*8;
                    float p0 = __expf(s[i][j][2*h]   - mnew[i][h]);
                    float p1 = __expf(s[i][j][2*h+1] - mnew[i][h]);
                    *(float2*)&Ps[r][wn*16 + j*8 + 2*t4] = make_float2(f2tf(p0), f2tf(p1));
                    psum[i][h] += p0 + p1;
                    o[i][j][2*h]   *= scale[i][h];
                    o[i][j][2*h+1] *= scale[i][h];
                }
#pragma unroll
        for (int off = 1; off <= 2; off <<= 1) {
#pragma unroll
            for (int i=0;i<2;i++)
#pragma unroll
                for (int h=0;h<2;h++)
                    psum[i][h] += __shfl_xor_sync(0xffffffffu, psum[i][h], off);
        }
        if (t4 == 0) {
#pragma unroll
            for (int i=0;i<2;i++)
#pragma unroll
                for (int h=0;h<2;h++)
                    reds[wm*32 + i*16 + g + h*8][wn] = psum[i][h];
        }
        __syncthreads();

        if (wn == 0 && t4 == 0) {
#pragma unroll
            for (int i=0;i<2;i++)
#pragma unroll
                for (int h=0;h<2;h++) {
                    int r = wm*32 + i*16 + g + h*8;
                    float ps = reds[r][0] + reds[r][1] + reds[r][2] + reds[r][3];
                    rowl[r] = rowl[r]*scale[i][h] + ps;
                    rowm[r] = mnew[i][h];
                }
        }

#pragma unroll
        for (int ks = 0; ks < 64; ks += 8) {
            uint32_t af[2][4], bf[2][2];
#pragma unroll
            for (int i = 0; i < 2; i++) {
                int r = wm*32 + i*16 + g;
                af[i][0] = __float_as_uint(Ps[r][ks+t4]);
                af[i][1] = __float_as_uint(Ps[r+8][ks+t4]);
                af[i][2] = __float_as_uint(Ps[r][ks+t4+4]);
                af[i][3] = __float_as_uint(Ps[r+8][ks+t4+4]);
            }
#pragma unroll
            for (int j = 0; j < 2; j++) {
                int cc = wn*16 + j*8 + g;
                bf[j][0] = __float_as_uint(Vs[ks+t4][cc]);
                bf[j][1] = __float_as_uint(Vs[ks+t4+4][cc]);
            }
#pragma unroll
            for (int i = 0; i < 2; i++)
#pragma unroll
                for (int j = 0; j < 2; j++) {
                    asm volatile(
                        "mma.sync.aligned.m16n8k8.row.col.f32.tf32.tf32.f32 "
                        "{%0,%1,%2,%3}, {%4,%5,%6,%7}, {%8,%9}, {%0,%1,%2,%3};\n"
                        : "+f"(o[i][j][0]), "+f"(o[i][j][1]),
                          "+f"(o[i][j][2]), "+f"(o[i][j][3])
                        : "r"(af[i][0]), "r"(af[i][1]), "r"(af[i][2]), "r"(af[i][3]),
                          "r"(bf[j][0]), "r"(bf[j][1]));
                }
        }
        __syncthreads();
    }

    if (lpart != nullptr) {
        float* Ob = O + ((size_t)(blockIdx.z*32 + bh)*nq + q0) * 64;
#pragma unroll
        for (int i=0;i<2;i++)
#pragma unroll
            for (int j=0;j<2;j++)
#pragma unroll
                for (int h=0;h<2;h++) {
                    int r = wm*32 + i*16 + g + h*8;
                    int cc = wn*16 + j*8 + 2*t4;
                    *(float2*)&Ob[(size_t)r*64 + cc] =
                        make_float2(o[i][j][2*h], o[i][j][2*h+1]);
                }
        if (tid < 64) {
            size_t ri = (size_t)(blockIdx.z*32 + bh)*nq + q0 + tid;
            mpart[ri] = rowm[tid];
            lpart[ri] = rowl[tid];
        }
    } else {
        float* Ob = O + ((size_t)bh*nq + q0) * 64;
#pragma unroll
        for (int i=0;i<2;i++)
#pragma unroll
            for (int j=0;j<2;j++)
#pragma unroll
                for (int h=0;h<2;h++) {
                    int r = wm*32 + i*16 + g + h*8;
                    int cc = wn*16 + j*8 + 2*t4;
                    float inv = 1.f / rowl[r];
                    *(float2*)&Ob[(size_t)r*64 + cc] =
                        make_float2(o[i][j][2*h]*inv, o[i][j][2*h+1]*inv);
                }
    }
}

// ---------------------------------------------------------------------------
// Single-pass flash for flash-2 (nk == 256): all 4 S-tiles in registers,
// ONE softmax (global row max, no O rescaling), then 4 P@V tiles.
// ---------------------------------------------------------------------------
__global__ __launch_bounds__(256) void flash2_sp_kernel(
        const float* __restrict__ Q, const float* __restrict__ K,
        const float* __restrict__ V, float* __restrict__ O) {
    extern __shared__ float sm[];
    float (*Qs)[QP] = (float(*)[QP])sm;
    float (*Ks)[QP] = (float(*)[QP])(sm + OFF_KS);
    float (*Ps)[QP] = (float(*)[QP])(sm + OFF_PS);
    float (*Vs)[VP] = (float(*)[VP])(sm + OFF_VS);
    float (*redm)[4] = (float(*)[4])(sm + OFF_REDM);
    float (*reds)[4] = (float(*)[4])(sm + OFF_REDS);

    int tid = threadIdx.x;
    int lane = tid & 31, wid = tid >> 5;
    int wm = wid & 1, wn = wid >> 1;
    int g = lane >> 2, t4 = lane & 3;
    int bh = blockIdx.y;
    int q0 = blockIdx.x * 64;
    const float* Qb = Q + ((size_t)bh*4096 + q0) * 64;
    const float* Kb = K + (size_t)bh*256*64;
    const float* Vb = V + (size_t)bh*256*64;
    float* Ob = O + ((size_t)bh*4096 + q0) * 64;

    int lr = tid >> 2, lk = (tid & 3) * 16;
    {
#pragma unroll
        for (int ii = 0; ii < 4; ii++) {
            float4 qv = *(const float4*)&Qb[(size_t)lr*64 + lk + ii*4];
            Qs[lr][lk+ii*4+0]=f2tf(qv.x); Qs[lr][lk+ii*4+1]=f2tf(qv.y);
            Qs[lr][lk+ii*4+2]=f2tf(qv.z); Qs[lr][lk+ii*4+3]=f2tf(qv.w);
        }
    }

    float s[4][2][2][4];
    float o[2][2][4];
#pragma unroll
    for (int i=0;i<2;i++)
#pragma unroll
        for (int j=0;j<2;j++)
#pragma unroll
            for (int h=0;h<4;h++) o[i][j][h]=0.f;

#pragma unroll
    for (int t = 0; t < 4; t++) {
        {
#pragma unroll
            for (int ii = 0; ii < 4; ii++) {
                float4 kv = *(const float4*)&Kb[(size_t)(t*64+lr)*64 + lk + ii*4];
                Ks[lr][lk+ii*4+0]=f2tf(kv.x); Ks[lr][lk+ii*4+1]=f2tf(kv.y);
                Ks[lr][lk+ii*4+2]=f2tf(kv.z); Ks[lr][lk+ii*4+3]=f2tf(kv.w);
            }
        }
        __syncthreads();
#pragma unroll
        for (int i=0;i<2;i++)
#pragma unroll
            for (int j=0;j<2;j++)
#pragma unroll
                for (int h=0;h<4;h++) s[t][i][j][h]=0.f;
#pragma unroll
        for (int ks = 0; ks < 64; ks += 8) {
            uint32_t af[2][4], bf[2][2];
#pragma unroll
            for (int i = 0; i < 2; i++) {
                int r = wm*32 + i*16 + g;
                af[i][0] = __float_as_uint(Qs[r][ks+t4]);
                af[i][1] = __float_as_uint(Qs[r+8][ks+t4]);
                af[i][2] = __float_as_uint(Qs[r][ks+t4+4]);
                af[i][3] = __float_as_uint(Qs[r+8][ks+t4+4]);
            }
#pragma unroll
            for (int j = 0; j < 2; j++) {
                int cc = wn*16 + j*8 + g;
                bf[j][0] = __float_as_uint(Ks[cc][ks+t4]);
                bf[j][1] = __float_as_uint(Ks[cc][ks+t4+4]);
            }
#pragma unroll
            for (int i = 0; i < 2; i++)
#pragma unroll
                for (int j = 0; j < 2; j++) {
                    asm volatile(
                        "mma.sync.aligned.m16n8k8.row.col.f32.tf32.tf32.f32 "
                        "{%0,%1,%2,%3}, {%4,%5,%6,%7}, {%8,%9}, {%0,%1,%2,%3};\n"
                        : "+f"(s[t][i][j][0]), "+f"(s[t][i][j][1]),
                          "+f"(s[t][i][j][2]), "+f"(s[t][i][j][3])
                        : "r"(af[i][0]), "r"(af[i][1]), "r"(af[i][2]), "r"(af[i][3]),
                          "r"(bf[j][0]), "r"(bf[j][1]));
                }
        }
        __syncthreads();
    }

    float pm[2][2];
#pragma unroll
    for (int i=0;i<2;i++)
#pragma unroll
        for (int h=0;h<2;h++) {
            float m = s[0][i][0][2*h];
#pragma unroll
            for (int t=0;t<4;t++)
#pragma unroll
                for (int j=0;j<2;j++) {
                    m = fmaxf(m, s[t][i][j][2*h]);
                    m = fmaxf(m, s[t][i][j][2*h+1]);
                }
#pragma unroll
            for (int off = 1; off <= 2; off <<= 1)
                m = fmaxf(m, __shfl_xor_sync(0xffffffffu, m, off));
            pm[i][h] = m;
        }
    if (t4 == 0) {
#pragma unroll
        for (int i=0;i<2;i++)
#pragma unroll
            for (int h=0;h<2;h++)
                redm[wm*32 + i*16 + g + h*8][wn] = pm[i][h];
    }
    __syncthreads();

    float linv[2][2];
    {
        float psum[2][2];
#pragma unroll
        for (int i=0;i<2;i++)
#pragma unroll
            for (int h=0;h<2;h++) {
                int r = wm*32 + i*16 + g + h*8;
                float m = fmaxf(fmaxf(redm[r][0], redm[r][1]),
                                fmaxf(redm[r][2], redm[r][3]));
                float ps = 0.f;
#pragma unroll
                for (int t=0;t<4;t++)
#pragma unroll
                    for (int j=0;j<2;j++) {
                        float p0 = __expf(s[t][i][j][2*h]   - m);
                        float p1 = __expf(s[t][i][j][2*h+1] - m);
                        s[t][i][j][2*h] = p0; s[t][i][j][2*h+1] = p1;
                        ps += p0 + p1;
                    }
#pragma unroll
                for (int off = 1; off <= 2; off <<= 1)
                    ps += __shfl_xor_sync(0xffffffffu, ps, off);
                psum[i][h] = ps;
            }
        if (t4 == 0) {
#pragma unroll
            for (int i=0;i<2;i++)
#pragma unroll
                for (int h=0;h<2;h++)
                    reds[wm*32 + i*16 + g + h*8][wn] = psum[i][h];
        }
        __syncthreads();
#pragma unroll
        for (int i=0;i<2;i++)
#pragma unroll
            for (int h=0;h<2;h++) {
                int r = wm*32 + i*16 + g + h*8;
                linv[i][h] = 1.f / (reds[r][0]+reds[r][1]+reds[r][2]+reds[r][3]);
            }
    }

#pragma unroll
    for (int t = 0; t < 4; t++) {
#pragma unroll
        for (int i=0;i<2;i++)
#pragma unroll
            for (int j=0;j<2;j++)
#pragma unroll
                for (int h=0;h<2;h++) {
                    int r = wm*32 + i*16 + g + h*8;
                    *(float2*)&Ps[r][wn*16 + j*8 + 2*t4] =
                        make_float2(f2tf(s[t][i][j][2*h]), f2tf(s[t][i][j][2*h+1]));
                }
        {
#pragma unroll
            for (int ii = 0; ii < 4; ii++) {
                float4 vv = *(const float4*)&Vb[(size_t)(t*64+lr)*64 + lk + ii*4];
                Vs[lr][lk+ii*4+0]=f2tf(vv.x); Vs[lr][lk+ii*4+1]=f2tf(vv.y);
                Vs[lr][lk+ii*4+2]=f2tf(vv.z); Vs[lr][lk+ii*4+3]=f2tf(vv.w);
            }
        }
        __syncthreads();
#pragma unroll
        for (int ks = 0; ks < 64; ks += 8) {
            uint32_t af[2][4], bf[2][2];
#pragma unroll
            for (int i = 0; i < 2; i++) {
                int r = wm*32 + i*16 + g;
                af[i][0] = __float_as_uint(Ps[r][ks+t4]);
                af[i][1] = __float_as_uint(Ps[r+8][ks+t4]);
                af[i][2] = __float_as_uint(Ps[r][ks+t4+4]);
                af[i][3] = __float_as_uint(Ps[r+8][ks+t4+4]);
            }
#pragma unroll
            for (int j = 0; j < 2; j++) {
                int cc = wn*16 + j*8 + g;
                bf[j][0] = __float_as_uint(Vs[ks+t4][cc]);
                bf[j][1] = __float_as_uint(Vs[ks+t4+4][cc]);
            }
#pragma unroll
            for (int i = 0; i < 2; i++)
#pragma unroll
                for (int j = 0; j < 2; j++) {
                    asm volatile(
                        "mma.sync.aligned.m16n8k8.row.col.f32.tf32.tf32.f32 "
                        "{%0,%1,%2,%3}, {%4,%5,%6,%7}, {%8,%9}, {%0,%1,%2,%3};\n"
                        : "+f"(o[i][j][0]), "+f"(o[i][j][1]),
                          "+f"(o[i][j][2]), "+f"(o[i][j][3])
                        : "r"(af[i][0]), "r"(af[i][1]), "r"(af[i][2]), "r"(af[i][3]),
                          "r"(bf[j][0]), "r"(bf[j][1]));
                }
        }
        __syncthreads();
    }

#pragma unroll
    for (int i=0;i<2;i++)
#pragma unroll
        for (int j=0;j<2;j++)
#pragma unroll
            for (int h=0;h<2;h++) {
                int r = wm*32 + i*16 + g + h*8;
                int cc = wn*16 + j*8 + 2*t4;
                *(float2*)&Ob[(size_t)r*64 + cc] =
                    make_float2(o[i][j][2*h]*linv[i][h], o[i][j][2*h+1]*linv[i][h]);
            }
}

// ---------------------------------------------------------------------------
// Split-K combine
// ---------------------------------------------------------------------------
__global__ void combine_kernel(const float* __restrict__ Op,
                               const float* __restrict__ mp,
                               const float* __restrict__ lp,
                               float* __restrict__ w) {
    int row = blockIdx.x;
    int c = threadIdx.x;
    int bh = row >> 8, qr = row & 255;
    float m0 = mp[(0*32+bh)*256+qr], m1 = mp[(1*32+bh)*256+qr];
    float m2 = mp[(2*32+bh)*256+qr], m3 = mp[(3*32+bh)*256+qr];
    float ms = fmaxf(fmaxf(m0,m1), fmaxf(m2,m3));
    float w0 = __expf(m0-ms), w1 = __expf(m1-ms), w2 = __expf(m2-ms), w3 = __expf(m3-ms);
    float l = w0*lp[(0*32+bh)*256+qr] + w1*lp[(1*32+bh)*256+qr]
            + w2*lp[(2*32+bh)*256+qr] + w3*lp[(3*32+bh)*256+qr];
    float acc = w0*Op[((size_t)(0*32+bh)*256+qr)*64 + c]
              + w1*Op[((size_t)(1*32+bh)*256+qr)*64 + c]
              + w2*Op[((size_t)(2*32+bh)*256+qr)*64 + c]
              + w3*Op[((size_t)(3*32+bh)*256+qr)*64 + c];
    w[((size_t)bh*256+qr)*64 + c] = acc / l;
}

// ---------------------------------------------------------------------------
// Depthwise seq-conv residual + layout transform
// ---------------------------------------------------------------------------
__global__ __launch_bounds__(256) void conv_kernel(
        const float* __restrict__ attn, const float* __restrict__ v,
        const float* __restrict__ cw, float* __restrict__ attn2) {
    __shared__ float vt[96][64];
    __shared__ float wk[33];
    int bh = blockIdx.y; int h = bh & 7; int b4 = bh >> 3;
    int row0 = blockIdx.x * 64;
    int t = threadIdx.x;
    if (t < 33) wk[t] = cw[h*33 + t];
    const float* vb = v + (size_t)bh*4096*64;
#pragma unroll
    for (int i=0;i<6;i++){
        int f = t + i*256;
        int r = f >> 4;
        int c4 = (f & 15) * 4;
        int gr = row0 - 16 + r;
        float4 val = make_float4(0.f,0.f,0.f,0.f);
        if (gr >= 0 && gr < 4096) val = *(const float4*)&vb[(size_t)gr*64 + c4];
        *(float4*)&vt[r][c4] = val;
    }
    __syncthreads();
    int dh = t & 63;
    int rr = t >> 6;
#pragma unroll
    for (int q=0;q<16;q++){
        int lr = rr + q*4;
        float acc = attn[((size_t)bh*4096 + row0 + lr)*64 + dh];
#pragma unroll
        for (int s=0;s<33;s++) acc += wk[s]*vt[lr+s][dh];
        attn2[((size_t)b4*4096 + row0 + lr)*512 + h*64 + dh] = acc;
    }
}

// ---------------------------------------------------------------------------
// Host orchestration
// ---------------------------------------------------------------------------
extern "C" void kernel_launch(void* const* d_in, const int* in_sizes, int n_in,
                              void* d_out, int out_size) {
    const float* x      = (const float*)d_in[0];
    const float* norm_w = (const float*)d_in[1];
    const float* norm_b = (const float*)d_in[2];
    const float* Wqkv   = (const float*)d_in[3];
    const float* Wout   = (const float*)d_in[4];
    const float* bout   = (const float*)d_in[5];
    const float* conv_w = (const float*)d_in[6];
    float* out = (float*)d_out;

    float *xn,*q,*k,*v,*ql,*kl,*a2,*z0,*t1,*t2,*t3,*w,*w2,*uu,*r3,*u5,*attn,*attn2,*red;
    float *w4s[5];
    cudaGetSymbolAddress((void**)&xn,   g_xn);
    cudaGetSymbolAddress((void**)&q,    g_q);
    cudaGetSymbolAddress((void**)&k,    g_k);
    cudaGetSymbolAddress((void**)&v,    g_v);
    cudaGetSymbolAddress((void**)&ql,   g_ql);
    cudaGetSymbolAddress((void**)&kl,   g_kl);
    cudaGetSymbolAddress((void**)&a2,   g_a2);
    cudaGetSymbolAddress((void**)&z0,   g_z0);
    cudaGetSymbolAddress((void**)&t1,   g_t1);
    cudaGetSymbolAddress((void**)&t2,   g_t2);
    cudaGetSymbolAddress((void**)&t3,   g_t3);
    cudaGetSymbolAddress((void**)&w4s[0], g_w40);
    cudaGetSymbolAddress((void**)&w4s[1], g_w41);
    cudaGetSymbolAddress((void**)&w4s[2], g_w42);
    cudaGetSymbolAddress((void**)&w4s[3], g_w43);
    cudaGetSymbolAddress((void**)&w4s[4], g_w44);
    cudaGetSymbolAddress((void**)&w,    g_w);
    cudaGetSymbolAddress((void**)&w2,   g_w2);
    cudaGetSymbolAddress((void**)&uu,   g_u);
    cudaGetSymbolAddress((void**)&r3,   g_r3);
    cudaGetSymbolAddress((void**)&u5,   g_u5);
    cudaGetSymbolAddress((void**)&attn, g_attn);
    cudaGetSymbolAddress((void**)&attn2,g_attn2);
    cudaGetSymbolAddress((void**)&red,  g_red);

    cudaFuncSetAttribute(flash_tc_kernel, cudaFuncAttributeMaxDynamicSharedMemorySize, SMEM_FLASH_TC);
    cudaFuncSetAttribute(flash2_sp_kernel, cudaFuncAttributeMaxDynamicSharedMemorySize, SMEM_FLASH_TC);
    cudaFuncSetAttribute(a2_tc_kernel, cudaFuncAttributeMaxDynamicSharedMemorySize, SMEM_A2);

    // 1. LayerNorm
    ln_kernel<<<16384, 128>>>(x, norm_w, norm_b, xn);
    // 2. QKV projection (tf32 MMA, fused scatter + q scale)
    mma_gemm<0,512,1536,512><<<dim3(12,128), 256>>>(
        xn, Wqkv, q, k, v, nullptr, nullptr);
    // 3. landmarks (merged)
    landmark2_kernel<<<4096, 256>>>(q, k, ql, kl);
    // 4. a2 = softmax(q_l k_l^T) (tf32 MMA, 64-row tiles -> 128 CTAs)
    a2_tc_kernel<<<dim3(4,32), 256, SMEM_A2>>>(ql, kl, a2);
    // 5. pinv init scalar + z0 = s*a2^T
    red_init_kernel<<<1, 32>>>(red);
    colsum_kernel<<<32, 256>>>(a2, red);
    zinit_kernel<<<8192, 256>>>(a2, red, z0);
    // 6. w = softmax(q_l k^T) @ v — split-K x4 flash + combine
    flash_tc_kernel<<<dim3(4,32,4), 256, SMEM_FLASH_TC>>>(
        ql, k, v, t1, 256, 4096, 1024, t2, t2 + 32768);
    combine_kernel<<<8192, 64>>>(t1, t2, t2 + 32768, w);
    // 7. Newton-Schulz pinv, Y-only recurrence, 128x128 tiles (proven):
    //    W2 = Y(7I-Y); W4_i = Y(15I-W2); Y' = 0.25*Y(13I-W4_i)   [it=0..4]
    mma_gemm_pinv<<<dim3(2,2,32), 256>>>(a2, z0, t1, 0.f, 1.f);   // Y0 = a2 @ z0
    float* Y = t1; float* Yn = t3;
    for (int it = 0; it < 5; it++) {
        mma_gemm_pinv<<<dim3(2,2,32), 256>>>(Y, Y, t2, 7.f, -1.f);        // W2
        mma_gemm_pinv<<<dim3(2,2,32), 256>>>(Y, t2, w4s[it], 15.f, -1.f); // W4_i
        mma_gemm_pinv<<<dim3(2,2,32), 256>>>(Y, w4s[it], Yn, 3.25f, -0.25f);
        float* tmp = Y; Y = Yn; Yn = tmp;
    }
    // Y == Y5. Narrow last iteration: u5 = 13w - 15 Y5w + 7 Y5^2w - Y5^3w
    mma_nar_kernel<<<dim3(1,2,32), 256>>>(Y, w,  uu, 0.f, 1.f);   // r1
    mma_nar_kernel<<<dim3(1,2,32), 256>>>(Y, uu, w2, 0.f, 1.f);   // r2
    mma_nar_kernel<<<dim3(1,2,32), 256>>>(Y, w2, r3, 0.f, 1.f);   // r3
    comb4_kernel<<<2048, 256>>>(w, uu, w2, r3, u5);
    // 8. narrow chain down: u_i = 13*u_{i+1} - W4_i @ u_{i+1}
    mma_nar_kernel<<<dim3(1,2,32), 256>>>(w4s[4], u5, uu, 13.f, -1.f);
    mma_nar_kernel<<<dim3(1,2,32), 256>>>(w4s[3], uu, w2, 13.f, -1.f);
    mma_nar_kernel<<<dim3(1,2,32), 256>>>(w4s[2], w2, uu, 13.f, -1.f);
    mma_nar_kernel<<<dim3(1,2,32), 256>>>(w4s[1], uu, w2, 13.f, -1.f);
    mma_nar_kernel<<<dim3(1,2,32), 256>>>(w4s[0], w2, uu, 13.f, -1.f);
    mma_nar_kernel<<<dim3(1,2,32), 256>>>(z0, uu, w2, 0.f, 1.f/4096.f);
    // 9. attn = softmax(q k_l^T) @ w2 — single-pass flash (nk=256)
    flash2_sp_kernel<<<dim3(64,32), 256, SMEM_FLASH_TC>>>(q, kl, w2, attn);
    // 10. conv residual + layout
    conv_kernel<<<dim3(64,32), 256>>>(attn, v, conv_w, attn2);
    // 11. output projection + bias + input residual (tf32 MMA)
    mma_gemm<1,512,512,512><<<dim3(4,128), 256>>>(
        attn2, Wout, out, nullptr, nullptr, bout, x);
}

// round 15
// speedup vs baseline: 1.0590x; 1.0040x over previous
#include <cuda_runtime.h>
#include <cuda_bf16.h>
#include <cstdint>

// ---------------------------------------------------------------------------
// Problem constants: b=4, n=4096, D=512, H=8, dh=64, M=256, l=16, 6 iters,
// conv k=33, eps=1e-5
// ---------------------------------------------------------------------------
#define NB   (4*4096*512)
#define MM   (32*256*256)
#define MD   (32*256*64)

__device__ float g_xn[NB];
__device__ float g_q[NB];
__device__ float g_k[NB];
__device__ float g_v[NB];
__device__ float g_ql[MD];
__device__ float g_kl[MD];
__device__ float g_a2[MM];
__device__ float g_z0[MM];
__device__ float g_t1[MM];   // Y ping / flash1 split-K O partials
__device__ float g_t2[MM];   // W2 scratch / flash1 split-K m/l partials
__device__ float g_t3[MM];   // Y pong
__device__ float g_w40[MM];
__device__ float g_w41[MM];
__device__ float g_w42[MM];
__device__ float g_w43[MM];
__device__ float g_w44[MM];
__device__ float g_w[MD];
__device__ float g_w2[MD];
__device__ float g_u[MD];
__device__ float g_r3[MD];
__device__ float g_u5[MD];
__device__ float g_attn[NB];
__device__ float g_attn2[NB];
__device__ float g_red[2];

__device__ __forceinline__ float f2tf(float x) {
    uint32_t u;
    asm("cvt.rna.tf32.f32 %0, %1;" : "=r"(u) : "f"(x));
    return __uint_as_float(u);
}

// ---------------------------------------------------------------------------
// LayerNorm
// ---------------------------------------------------------------------------
__global__ void ln_kernel(const float* __restrict__ x, const float* __restrict__ w,
                          const float* __restrict__ bb, float* __restrict__ out) {
    int row = blockIdx.x;
    const float* xr = x + (size_t)row * 512;
    float* orow = out + (size_t)row * 512;
    int t = threadIdx.x;
    float v[4];
    float s = 0.f;
#pragma unroll
    for (int i = 0; i < 4; i++) { v[i] = xr[t + 128*i]; s += v[i]; }
#pragma unroll
    for (int o = 16; o; o >>= 1) s += __shfl_xor_sync(0xffffffffu, s, o);
    __shared__ float red[4];
    if ((t & 31) == 0) red[t >> 5] = s;
    __syncthreads();
    float mean = (red[0]+red[1]+red[2]+red[3]) * (1.f/512.f);
    float vs = 0.f;
#pragma unroll
    for (int i = 0; i < 4; i++) { float d = v[i]-mean; vs += d*d; }
#pragma unroll
    for (int o = 16; o; o >>= 1) vs += __shfl_xor_sync(0xffffffffu, vs, o);
    __syncthreads();
    if ((t & 31) == 0) red[t >> 5] = vs;
    __syncthreads();
    float var = (red[0]+red[1]+red[2]+red[3]) * (1.f/512.f);
    float rstd = rsqrtf(var + 1e-5f);
#pragma unroll
    for (int i = 0; i < 4; i++) {
        int c = t + 128*i;
        orow[c] = (v[i]-mean)*rstd*w[c] + bb[c];
    }
}

// ---------------------------------------------------------------------------
// TF32 GEMM (proven): block 128x128, BK=16, 8 warps 64x32, occ 2.
// EPI 0: QKV scatter. EPI 1: bias + residual.
// ---------------------------------------------------------------------------
template<int EPI, int LDA, int LDB, int KD>
__global__ __launch_bounds__(256, 2) void mma_gemm(
        const float* __restrict__ A, const float* __restrict__ B,
        float* __restrict__ C0, float* __restrict__ C1, float* __restrict__ C2,
        const float* __restrict__ e0, const float* __restrict__ e1) {
    __shared__ float Asm[2][128*20];
    __shared__ float Bsm[2][16*136];
    int tid = threadIdx.x;
    int lane = tid & 31, wid = tid >> 5;
    int wm = wid & 1, wn = wid >> 1;
    int g = lane >> 2, t4 = lane & 3;
    int row0 = blockIdx.y * 128, col0 = blockIdx.x * 128;
    int arow = tid >> 1, akq = (tid & 1) * 8;
    int bkr = tid >> 4, bnc = (tid & 15) * 8;

    {
        const float* ap = A + (size_t)(row0 + arow) * LDA + akq;
        float4 a0 = *(const float4*)ap;
        float4 a1 = *(const float4*)(ap + 4);
        float* as = &Asm[0][arow*20 + akq];
        as[0]=f2tf(a0.x); as[1]=f2tf(a0.y); as[2]=f2tf(a0.z); as[3]=f2tf(a0.w);
        as[4]=f2tf(a1.x); as[5]=f2tf(a1.y); as[6]=f2tf(a1.z); as[7]=f2tf(a1.w);
        const float* bp = B + (size_t)bkr * LDB + col0 + bnc;
        float4 b0 = *(const float4*)bp;
        float4 b1 = *(const float4*)(bp + 4);
        float* bs = &Bsm[0][bkr*136 + bnc];
        bs[0]=f2tf(b0.x); bs[1]=f2tf(b0.y); bs[2]=f2tf(b0.z); bs[3]=f2tf(b0.w);
        bs[4]=f2tf(b1.x); bs[5]=f2tf(b1.y); bs[6]=f2tf(b1.z); bs[7]=f2tf(b1.w);
    }
    __syncthreads();

    float c[4][4][4];
#pragma unroll
    for (int i=0;i<4;i++)
#pragma unroll
        for (int j=0;j<4;j++)
#pragma unroll
            for (int h=0;h<4;h++) c[i][j][h]=0.f;

    const int NIT = KD / 16;
    for (int it = 0; it < NIT; it++) {
        int buf = it & 1;
        float4 pa0, pa1, pb0, pb1;
        if (it + 1 < NIT) {
            int k0 = (it + 1) * 16;
            const float* ap = A + (size_t)(row0 + arow) * LDA + k0 + akq;
            pa0 = *(const float4*)ap;
            pa1 = *(const float4*)(ap + 4);
            const float* bp = B + (size_t)(k0 + bkr) * LDB + col0 + bnc;
            pb0 = *(const float4*)bp;
            pb1 = *(const float4*)(bp + 4);
        }
#pragma unroll
        for (int ks = 0; ks < 16; ks += 8) {
            uint32_t af[4][4], bf[4][2];
#pragma unroll
            for (int i = 0; i < 4; i++) {
                int r0i = (wm*64 + i*16 + g) * 20 + ks + t4;
                int r1i = r0i + 8*20;
                af[i][0] = __float_as_uint(Asm[buf][r0i]);
                af[i][1] = __float_as_uint(Asm[buf][r1i]);
                af[i][2] = __float_as_uint(Asm[buf][r0i + 4]);
                af[i][3] = __float_as_uint(Asm[buf][r1i + 4]);
            }
#pragma unroll
            for (int j = 0; j < 4; j++) {
                int nc2 = wn*32 + j*8 + g;
                bf[j][0] = __float_as_uint(Bsm[buf][(ks + t4)*136 + nc2]);
                bf[j][1] = __float_as_uint(Bsm[buf][(ks + t4 + 4)*136 + nc2]);
            }
#pragma unroll
            for (int i = 0; i < 4; i++)
#pragma unroll
                for (int j = 0; j < 4; j++) {
                    asm volatile(
                        "mma.sync.aligned.m16n8k8.row.col.f32.tf32.tf32.f32 "
                        "{%0,%1,%2,%3}, {%4,%5,%6,%7}, {%8,%9}, {%0,%1,%2,%3};\n"
                        : "+f"(c[i][j][0]), "+f"(c[i][j][1]),
                          "+f"(c[i][j][2]), "+f"(c[i][j][3])
                        : "r"(af[i][0]), "r"(af[i][1]), "r"(af[i][2]), "r"(af[i][3]),
                          "r"(bf[j][0]), "r"(bf[j][1]));
                }
        }
        if (it + 1 < NIT) {
            int nb = buf ^ 1;
            float* as = &Asm[nb][arow*20 + akq];
            as[0]=f2tf(pa0.x); as[1]=f2tf(pa0.y); as[2]=f2tf(pa0.z); as[3]=f2tf(pa0.w);
            as[4]=f2tf(pa1.x); as[5]=f2tf(pa1.y); as[6]=f2tf(pa1.z); as[7]=f2tf(pa1.w);
            float* bs = &Bsm[nb][bkr*136 + bnc];
            bs[0]=f2tf(pb0.x); bs[1]=f2tf(pb0.y); bs[2]=f2tf(pb0.z); bs[3]=f2tf(pb0.w);
            bs[4]=f2tf(pb1.x); bs[5]=f2tf(pb1.y); bs[6]=f2tf(pb1.z); bs[7]=f2tf(pb1.w);
        }
        __syncthreads();
    }

#pragma unroll
    for (int i = 0; i < 4; i++) {
#pragma unroll
        for (int j = 0; j < 4; j++) {
#pragma unroll
            for (int h = 0; h < 2; h++) {
                int r = row0 + wm*64 + i*16 + g + h*8;
                int cc = col0 + wn*32 + j*8 + 2*t4;
                float v0 = c[i][j][h*2+0], v1 = c[i][j][h*2+1];
                if (EPI == 0) {
                    int b4 = r >> 12, nn = r & 4095;
                    int which = cc >> 9, cs = cc & 511;
                    int hh = cs >> 6, dh = cs & 63;
                    size_t di = ((size_t)(b4*8+hh)*4096 + nn)*64 + dh;
                    if (which == 0) {
                        *(float2*)&C0[di] = make_float2(v0*0.125f, v1*0.125f);
                    } else if (which == 1) {
                        *(float2*)&C1[di] = make_float2(v0, v1);
                    } else {
                        *(float2*)&C2[di] = make_float2(v0, v1);
                    }
                } else {
                    size_t di = (size_t)r*512 + cc;
                    float2 bias = *(const float2*)&e0[cc];
                    float2 xr = *(const float2*)&e1[di];
                    *(float2*)&C0[di] = make_float2(v0+bias.x+xr.x, v1+bias.y+xr.y);
                }
            }
        }
    }
}

// ---------------------------------------------------------------------------
// TF32 GEMM, pinv variant (proven 128x128): batched over z (stride 65536):
// C0 = cA*A + cAB*(A@B)
// ---------------------------------------------------------------------------
__global__ __launch_bounds__(256, 2) void mma_gemm_pinv(
        const float* __restrict__ A, const float* __restrict__ B,
        float* __restrict__ C0, float cA, float cAB) {
    __shared__ float Asm[2][128*20];
    __shared__ float Bsm[2][16*136];
    int tid = threadIdx.x;
    int lane = tid & 31, wid = tid >> 5;
    int wm = wid & 1, wn = wid >> 1;
    int g = lane >> 2, t4 = lane & 3;
    int row0 = blockIdx.y * 128, col0 = blockIdx.x * 128;
    const float* Ag = A + (size_t)blockIdx.z * 65536;
    const float* Bg = B + (size_t)blockIdx.z * 65536;
    int arow = tid >> 1, akq = (tid & 1) * 8;
    int bkr = tid >> 4, bnc = (tid & 15) * 8;

    {
        const float* ap = Ag + (size_t)(row0 + arow) * 256 + akq;
        float4 a0 = *(const float4*)ap;
        float4 a1 = *(const float4*)(ap + 4);
        float* as = &Asm[0][arow*20 + akq];
        as[0]=f2tf(a0.x); as[1]=f2tf(a0.y); as[2]=f2tf(a0.z); as[3]=f2tf(a0.w);
        as[4]=f2tf(a1.x); as[5]=f2tf(a1.y); as[6]=f2tf(a1.z); as[7]=f2tf(a1.w);
        const float* bp = Bg + (size_t)bkr * 256 + col0 + bnc;
        float4 b0 = *(const float4*)bp;
        float4 b1 = *(const float4*)(bp + 4);
        float* bs = &Bsm[0][bkr*136 + bnc];
        bs[0]=f2tf(b0.x); bs[1]=f2tf(b0.y); bs[2]=f2tf(b0.z); bs[3]=f2tf(b0.w);
        bs[4]=f2tf(b1.x); bs[5]=f2tf(b1.y); bs[6]=f2tf(b1.z); bs[7]=f2tf(b1.w);
    }
    __syncthreads();

    float c[4][4][4];
#pragma unroll
    for (int i=0;i<4;i++)
#pragma unroll
        for (int j=0;j<4;j++)
#pragma unroll
            for (int h=0;h<4;h++) c[i][j][h]=0.f;

    const int NIT = 16;
    for (int it = 0; it < NIT; it++) {
        int buf = it & 1;
        float4 pa0, pa1, pb0, pb1;
        if (it + 1 < NIT) {
            int k0 = (it + 1) * 16;
            const float* ap = Ag + (size_t)(row0 + arow) * 256 + k0 + akq;
            pa0 = *(const float4*)ap;
            pa1 = *(const float4*)(ap + 4);
            const float* bp = Bg + (size_t)(k0 + bkr) * 256 + col0 + bnc;
            pb0 = *(const float4*)bp;
            pb1 = *(const float4*)(bp + 4);
        }
#pragma unroll
        for (int ks = 0; ks < 16; ks += 8) {
            uint32_t af[4][4], bf[4][2];
#pragma unroll
            for (int i = 0; i < 4; i++) {
                int r0i = (wm*64 + i*16 + g) * 20 + ks + t4;
                int r1i = r0i + 8*20;
                af[i][0] = __float_as_uint(Asm[buf][r0i]);
                af[i][1] = __float_as_uint(Asm[buf][r1i]);
                af[i][2] = __float_as_uint(Asm[buf][r0i + 4]);
                af[i][3] = __float_as_uint(Asm[buf][r1i + 4]);
            }
#pragma unroll
            for (int j = 0; j < 4; j++) {
                int nc2 = wn*32 + j*8 + g;
                bf[j][0] = __float_as_uint(Bsm[buf][(ks + t4)*136 + nc2]);
                bf[j][1] = __float_as_uint(Bsm[buf][(ks + t4 + 4)*136 + nc2]);
            }
#pragma unroll
            for (int i = 0; i < 4; i++)
#pragma unroll
                for (int j = 0; j < 4; j++) {
                    asm volatile(
                        "mma.sync.aligned.m16n8k8.row.col.f32.tf32.tf32.f32 "
                        "{%0,%1,%2,%3}, {%4,%5,%6,%7}, {%8,%9}, {%0,%1,%2,%3};\n"
                        : "+f"(c[i][j][0]), "+f"(c[i][j][1]),
                          "+f"(c[i][j][2]), "+f"(c[i][j][3])
                        : "r"(af[i][0]), "r"(af[i][1]), "r"(af[i][2]), "r"(af[i][3]),
                          "r"(bf[j][0]), "r"(bf[j][1]));
                }
        }
        if (it + 1 < NIT) {
            int nb = buf ^ 1;
            float* as = &Asm[nb][arow*20 + akq];
            as[0]=f2tf(pa0.x); as[1]=f2tf(pa0.y); as[2]=f2tf(pa0.z); as[3]=f2tf(pa0.w);
            as[4]=f2tf(pa1.x); as[5]=f2tf(pa1.y); as[6]=f2tf(pa1.z); as[7]=f2tf(pa1.w);
            float* bs = &Bsm[nb][bkr*136 + bnc];
            bs[0]=f2tf(pb0.x); bs[1]=f2tf(pb0.y); bs[2]=f2tf(pb0.z); bs[3]=f2tf(pb0.w);
            bs[4]=f2tf(pb1.x); bs[5]=f2tf(pb1.y); bs[6]=f2tf(pb1.z); bs[7]=f2tf(pb1.w);
        }
        __syncthreads();
    }

#pragma unroll
    for (int i = 0; i < 4; i++) {
#pragma unroll
        for (int j = 0; j < 4; j++) {
#pragma unroll
            for (int h = 0; h < 2; h++) {
                int r = row0 + wm*64 + i*16 + g + h*8;
                int cc = col0 + wn*32 + j*8 + 2*t4;
                float v0 = c[i][j][h*2+0], v1 = c[i][j][h*2+1];
                float2 ae = *(const float2*)&Ag[(size_t)r*256 + cc];
                size_t di = (size_t)blockIdx.z*65536 + (size_t)r*256 + cc;
                *(float2*)&C0[di] = make_float2(cA*ae.x + cAB*v0,
                                                cA*ae.y + cAB*v1);
            }
        }
    }
}

// ---------------------------------------------------------------------------
// TF32 MMA narrow GEMM: C = cB*B + cAB*(A@B), A [32][256][256], B,C [32][256][64].
// ---------------------------------------------------------------------------
__global__ __launch_bounds__(256, 2) void mma_nar_kernel(
        const float* __restrict__ A, const float* __restrict__ B,
        float* __restrict__ C, float cB, float cAB) {
    __shared__ float Asm[2][128*20];
    __shared__ float Bsm[2][16*72];
    int tid = threadIdx.x;
    int lane = tid & 31, wid = tid >> 5;
    int wm = wid & 3, wn = wid >> 2;
    int g = lane >> 2, t4 = lane & 3;
    int row0 = blockIdx.y * 128;
    const float* Ag = A + (size_t)blockIdx.z * 65536;
    const float* Bg = B + (size_t)blockIdx.z * 16384;
    float* Cg = C + (size_t)blockIdx.z * 16384;
    int arow = tid >> 1, akq = (tid & 1) * 8;
    int bkr = tid >> 4, bnc = (tid & 15) * 4;

    {
        const float* ap = Ag + (size_t)(row0 + arow) * 256 + akq;
        float4 a0 = *(const float4*)ap;
        float4 a1 = *(const float4*)(ap + 4);
        float* as = &Asm[0][arow*20 + akq];
        as[0]=f2tf(a0.x); as[1]=f2tf(a0.y); as[2]=f2tf(a0.z); as[3]=f2tf(a0.w);
        as[4]=f2tf(a1.x); as[5]=f2tf(a1.y); as[6]=f2tf(a1.z); as[7]=f2tf(a1.w);
        float4 bv = *(const float4*)(Bg + (size_t)bkr * 64 + bnc);
        float* bs = &Bsm[0][bkr*72 + bnc];
        bs[0]=f2tf(bv.x); bs[1]=f2tf(bv.y); bs[2]=f2tf(bv.z); bs[3]=f2tf(bv.w);
    }
    __syncthreads();

    float c[2][4][4];
#pragma unroll
    for (int i=0;i<2;i++)
#pragma unroll
        for (int j=0;j<4;j++)
#pragma unroll
            for (int h=0;h<4;h++) c[i][j][h]=0.f;

    const int NIT = 16;
    for (int it = 0; it < NIT; it++) {
        int buf = it & 1;
        float4 pa0, pa1, pb;
        if (it + 1 < NIT) {
            int k0 = (it + 1) * 16;
            const float* ap = Ag + (size_t)(row0 + arow) * 256 + k0 + akq;
            pa0 = *(const float4*)ap;
            pa1 = *(const float4*)(ap + 4);
            pb = *(const float4*)(Bg + (size_t)(k0 + bkr) * 64 + bnc);
        }
#pragma unroll
        for (int ks = 0; ks < 16; ks += 8) {
            uint32_t af[2][4], bf[4][2];
#pragma unroll
            for (int i = 0; i < 2; i++) {
                int r0i = (wm*32 + i*16 + g) * 20 + ks + t4;
                int r1i = r0i + 8*20;
                af[i][0] = __float_as_uint(Asm[buf][r0i]);
                af[i][1] = __float_as_uint(Asm[buf][r1i]);
                af[i][2] = __float_as_uint(Asm[buf][r0i + 4]);
                af[i][3] = __float_as_uint(Asm[buf][r1i + 4]);
            }
#pragma unroll
            for (int j = 0; j < 4; j++) {
                int nc2 = wn*32 + j*8 + g;
                bf[j][0] = __float_as_uint(Bsm[buf][(ks + t4)*72 + nc2]);
                bf[j][1] = __float_as_uint(Bsm[buf][(ks + t4 + 4)*72 + nc2]);
            }
#pragma unroll
            for (int i = 0; i < 2; i++)
#pragma unroll
                for (int j = 0; j < 4; j++) {
                    asm volatile(
                        "mma.sync.aligned.m16n8k8.row.col.f32.tf32.tf32.f32 "
                        "{%0,%1,%2,%3}, {%4,%5,%6,%7}, {%8,%9}, {%0,%1,%2,%3};\n"
                        : "+f"(c[i][j][0]), "+f"(c[i][j][1]),
                          "+f"(c[i][j][2]), "+f"(c[i][j][3])
                        : "r"(af[i][0]), "r"(af[i][1]), "r"(af[i][2]), "r"(af[i][3]),
                          "r"(bf[j][0]), "r"(bf[j][1]));
                }
        }
        if (it + 1 < NIT) {
            int nb = buf ^ 1;
            float* as = &Asm[nb][arow*20 + akq];
            as[0]=f2tf(pa0.x); as[1]=f2tf(pa0.y); as[2]=f2tf(pa0.z); as[3]=f2tf(pa0.w);
            as[4]=f2tf(pa1.x); as[5]=f2tf(pa1.y); as[6]=f2tf(pa1.z); as[7]=f2tf(pa1.w);
            float* bs = &Bsm[nb][bkr*72 + bnc];
            bs[0]=f2tf(pb.x); bs[1]=f2tf(pb.y); bs[2]=f2tf(pb.z); bs[3]=f2tf(pb.w);
        }
        __syncthreads();
    }

#pragma unroll
    for (int i = 0; i < 2; i++)
#pragma unroll
        for (int j = 0; j < 4; j++)
#pragma unroll
            for (int h = 0; h < 2; h++) {
                int r = row0 + wm*32 + i*16 + g + h*8;
                int cc = wn*32 + j*8 + 2*t4;
                float v0 = cAB * c[i][j][h*2+0];
                float v1 = cAB * c[i][j][h*2+1];
                if (cB != 0.f) {
                    float2 be = *(const float2*)&Bg[(size_t)r*64 + cc];
                    v0 += cB * be.x; v1 += cB * be.y;
                }
                *(float2*)&Cg[(size_t)r*64 + cc] = make_float2(v0, v1);
            }
}

// ---------------------------------------------------------------------------
// u5 = 13*w - 15*r1 + 7*r2 - r3  (elementwise, MD elems)
// ---------------------------------------------------------------------------
__global__ void comb4_kernel(const float* __restrict__ w, const float* __restrict__ r1,
                             const float* __restrict__ r2, const float* __restrict__ r3,
                             float* __restrict__ u5) {
    int i = blockIdx.x * 256 + threadIdx.x;
    u5[i] = 13.f*w[i] - 15.f*r1[i] + 7.f*r2[i] - r3[i];
}

// ---------------------------------------------------------------------------
// TF32 MMA a2 = softmax(q_l @ k_l^T), 64-row tiles -> grid (4,32) = 128 CTAs
// 8 warps: each owns all 64 rows x a 32-col slice (wn = wid).
// ---------------------------------------------------------------------------
#define A2_KS   4352
#define A2_RM   21760
#define A2_RS   22272
#define SMEM_A2 (22784*4)
__global__ __launch_bounds__(256, 1) void a2_tc_kernel(
        const float* __restrict__ ql, const float* __restrict__ kl,
        float* __restrict__ a2) {
    extern __shared__ float sm2[];
    float* Qs = sm2;                       // [64][68]
    float* Ks = sm2 + A2_KS;               // [256][68]
    float (*redm)[8] = (float(*)[8])(sm2 + A2_RM);
    float (*reds)[8] = (float(*)[8])(sm2 + A2_RS);

    int tid = threadIdx.x;
    int lane = tid & 31, wn = tid >> 5;
    int g = lane >> 2, t4 = lane & 3;
    int bh = blockIdx.y;
    int row0 = blockIdx.x * 64;
    const float* qb = ql + ((size_t)bh*256 + row0) * 64;
    const float* kb = kl + (size_t)bh*256*64;

    for (int i = tid*4; i < 4096; i += 1024) {
        float4 qv = *(const float4*)&qb[i];
        int r = i >> 6, cc = i & 63;
        float* qs = &Qs[r*68 + cc];
        qs[0]=f2tf(qv.x); qs[1]=f2tf(qv.y); qs[2]=f2tf(qv.z); qs[3]=f2tf(qv.w);
    }
    for (int i = tid*4; i < 16384; i += 1024) {
        float4 kv = *(const float4*)&kb[i];
        int r = i >> 6, cc = i & 63;
        float* ks = &Ks[r*68 + cc];
        ks[0]=f2tf(kv.x); ks[1]=f2tf(kv.y); ks[2]=f2tf(kv.z); ks[3]=f2tf(kv.w);
    }
    __syncthreads();

    float c[4][4][4];
#pragma unroll
    for (int i=0;i<4;i++)
#pragma unroll
        for (int j=0;j<4;j++)
#pragma unroll
            for (int h=0;h<4;h++) c[i][j][h]=0.f;

#pragma unroll
    for (int ks = 0; ks < 64; ks += 8) {
        uint32_t af[4][4], bf[4][2];
#pragma unroll
        for (int i = 0; i < 4; i++) {
            int r0i = (i*16 + g)*68 + ks + t4;
            int r1i = r0i + 8*68;
            af[i][0] = __float_as_uint(Qs[r0i]);
            af[i][1] = __float_as_uint(Qs[r1i]);
            af[i][2] = __float_as_uint(Qs[r0i + 4]);
            af[i][3] = __float_as_uint(Qs[r1i + 4]);
        }
#pragma unroll
        for (int j = 0; j < 4; j++) {
            int cr = (wn*32 + j*8 + g)*68 + ks + t4;
            bf[j][0] = __float_as_uint(Ks[cr]);
            bf[j][1] = __float_as_uint(Ks[cr + 4]);
        }
#pragma unroll
        for (int i = 0; i < 4; i++)
#pragma unroll
            for (int j = 0; j < 4; j++) {
                asm volatile(
                    "mma.sync.aligned.m16n8k8.row.col.f32.tf32.tf32.f32 "
                    "{%0,%1,%2,%3}, {%4,%5,%6,%7}, {%8,%9}, {%0,%1,%2,%3};\n"
                    : "+f"(c[i][j][0]), "+f"(c[i][j][1]),
                      "+f"(c[i][j][2]), "+f"(c[i][j][3])
                    : "r"(af[i][0]), "r"(af[i][1]), "r"(af[i][2]), "r"(af[i][3]),
                      "r"(bf[j][0]), "r"(bf[j][1]));
            }
    }

    float pm[4][2];
#pragma unroll
    for (int i=0;i<4;i++)
#pragma unroll
        for (int h=0;h<2;h++) {
            float m = c[i][0][2*h];
#pragma unroll
            for (int j=0;j<4;j++) {
                m = fmaxf(m, c[i][j][2*h]);
                m = fmaxf(m, c[i][j][2*h+1]);
            }
#pragma unroll
            for (int off = 1; off <= 2; off <<= 1)
                m = fmaxf(m, __shfl_xor_sync(0xffffffffu, m, off));
            pm[i][h] = m;
        }
    if (t4 == 0) {
#pragma unroll
        for (int i=0;i<4;i++)
#pragma unroll
            for (int h=0;h<2;h++)
                redm[i*16 + g + h*8][wn] = pm[i][h];
    }
    __syncthreads();

    float psum[4][2];
#pragma unroll
    for (int i=0;i<4;i++)
#pragma unroll
        for (int h=0;h<2;h++) {
            int r = i*16 + g + h*8;
            float m = redm[r][0];
#pragma unroll
            for (int u=1;u<8;u++) m = fmaxf(m, redm[r][u]);
            float s = 0.f;
#pragma unroll
            for (int j=0;j<4;j++) {
                float p0 = __expf(c[i][j][2*h]   - m);
                float p1 = __expf(c[i][j][2*h+1] - m);
                c[i][j][2*h] = p0; c[i][j][2*h+1] = p1;
                s += p0 + p1;
            }
#pragma unroll
            for (int off = 1; off <= 2; off <<= 1)
                s += __shfl_xor_sync(0xffffffffu, s, off);
            psum[i][h] = s;
        }
    if (t4 == 0) {
#pragma unroll
        for (int i=0;i<4;i++)
#pragma unroll
            for (int h=0;h<2;h++)
                reds[i*16 + g + h*8][wn] = psum[i][h];
    }
    __syncthreads();

#pragma unroll
    for (int i=0;i<4;i++)
#pragma unroll
        for (int h=0;h<2;h++) {
            int r = i*16 + g + h*8;
            float ss = reds[r][0];
#pragma unroll
            for (int u=1;u<8;u++) ss += reds[r][u];
            float inv = 1.f / ss;
            float* orow = a2 + ((size_t)bh*256 + row0 + r) * 256;
#pragma unroll
            for (int j=0;j<4;j++) {
                int cc = wn*32 + j*8 + 2*t4;
                *(float2*)&orow[cc] = make_float2(c[i][j][2*h]*inv, c[i][j][2*h+1]*inv);
            }
        }
}

// ---------------------------------------------------------------------------
// Landmarks (merged q+k)
// ---------------------------------------------------------------------------
__global__ void landmark2_kernel(const float* __restrict__ q, const float* __restrict__ k,
                                 float* __restrict__ ql, float* __restrict__ kl) {
    int gidx = blockIdx.x * 256 + threadIdx.x;
    const float* src = (gidx < 524288) ? q : k;
    float* dst = (gidx < 524288) ? ql : kl;
    int idx = gidx & 524287;
    int dh = idx & 63;
    int mi = (idx >> 6) & 255;
    int bh = idx >> 14;
    const float* p = src + ((size_t)bh*4096 + mi*16)*64 + dh;
    float s = 0.f;
#pragma unroll
    for (int j = 0; j < 16; j++) s += p[j*64];
    dst[idx] = s * 0.0625f;
}

// ---------------------------------------------------------------------------
// pinv scalars. colsum split over 4 column-chunks -> grid (4,32) = 128 CTAs.
// ---------------------------------------------------------------------------
__global__ void red_init_kernel(float* g) { if (threadIdx.x < 2) g[threadIdx.x] = 0.f; }

__global__ void colsum_kernel(const float* __restrict__ a2, float* __restrict__ gred) {
    int bh = blockIdx.y;
    int j = blockIdx.x * 64 + threadIdx.x;   // 64 threads per CTA
    const float* base = a2 + (size_t)bh*65536;
    float s = 0.f;
    for (int i = 0; i < 256; i++) s += fabsf(base[(size_t)i*256 + j]);
#pragma unroll
    for (int o = 16; o; o >>= 1) s = fmaxf(s, __shfl_xor_sync(0xffffffffu, s, o));
    __shared__ float red[2];
    if ((threadIdx.x & 31) == 0) red[threadIdx.x >> 5] = s;
    __syncthreads();
    if (threadIdx.x == 0)
        atomicMax((int*)&gred[1], __float_as_int(fmaxf(red[0], red[1])));
}

// zinit via 32x32 smem-tile transpose: z[bh][i][j] = a2[bh][j][i] * inv.
// Coalesced reads AND writes (old version had stride-256 scalar reads:
// 8x sector amplification). grid (8, 8, 32), block (32, 8).
__global__ void zinit_kernel(const float* __restrict__ a2, const float* __restrict__ gred,
                             float* __restrict__ z) {
    __shared__ float tile[32][33];
    int bh = blockIdx.z;
    int i0 = blockIdx.x * 32, j0 = blockIdx.y * 32;
    const float* base = a2 + (size_t)bh * 65536;
    float* zb = z + (size_t)bh * 65536;
    int c = threadIdx.x, r0 = threadIdx.y;
#pragma unroll
    for (int rr = 0; rr < 4; rr++) {
        int r = r0*4 + rr;
        tile[r][c] = base[(size_t)(j0 + r)*256 + i0 + c];
    }
    __syncthreads();
    float inv = 1.f / gred[1];
#pragma unroll
    for (int rr = 0; rr < 4; rr++) {
        int r = r0*4 + rr;
        zb[(size_t)(i0 + r)*256 + j0 + c] = tile[c][r] * inv;
    }
}

// ---------------------------------------------------------------------------
// TF32 flash attention with optional split-K (used for flash-1, nk=4096)
// ---------------------------------------------------------------------------
#define QP 68
#define VP 72
#define OFF_KS   4352
#define OFF_PS   8704
#define OFF_VS   13056
#define OFF_ROWM 17664
#define OFF_ROWL 17728
#define OFF_REDM 17792
#define OFF_REDS 18048
#define SMEM_FLASH_TC ((18304)*4)

__global__ __launch_bounds__(256) void flash_tc_kernel(
        const float* __restrict__ Q, const float* __restrict__ K,
        const float* __restrict__ V, float* __restrict__ O, int nq, int nk,
        int chunk, float* __restrict__ mpart, float* __restrict__ lpart) {
    extern __shared__ float sm[];
    float (*Qs)[QP] = (float(*)[QP])sm;
    float (*Ks)[QP] = (float(*)[QP])(sm + OFF_KS);
    float (*Ps)[QP] = (float(*)[QP])(sm + OFF_PS);
    float (*Vs)[VP] = (float(*)[VP])(sm + OFF_VS);
    float* rowm = sm + OFF_ROWM;
    float* rowl = sm + OFF_ROWL;
    float (*redm)[4] = (float(*)[4])(sm + OFF_REDM);
    float (*reds)[4] = (float(*)[4])(sm + OFF_REDS);

    int tid = threadIdx.x;
    int lane = tid & 31, wid = tid >> 5;
    int wm = wid & 1, wn = wid >> 1;
    int g = lane >> 2, t4 = lane & 3;
    int bh = blockIdx.y;
    int q0 = blockIdx.x * 64;
    size_t koff = (size_t)blockIdx.z * chunk * 64;
    const float* Qb = Q + ((size_t)bh*nq + q0) * 64;
    const float* Kb = K + (size_t)bh*nk*64 + koff;
    const float* Vb = V + (size_t)bh*nk*64 + koff;

    {
        int r = tid >> 2, kc = (tid & 3) * 16;
#pragma unroll
        for (int ii = 0; ii < 4; ii++) {
            float4 qv = *(const float4*)&Qb[(size_t)r*64 + kc + ii*4];
            Qs[r][kc+ii*4+0]=f2tf(qv.x); Qs[r][kc+ii*4+1]=f2tf(qv.y);
            Qs[r][kc+ii*4+2]=f2tf(qv.z); Qs[r][kc+ii*4+3]=f2tf(qv.w);
        }
    }
    if (tid < 64) { rowm[tid] = -1e30f; rowl[tid] = 0.f; }
    float o[2][2][4];
#pragma unroll
    for (int i=0;i<2;i++)
#pragma unroll
        for (int j=0;j<2;j++)
#pragma unroll
            for (int h=0;h<4;h++) o[i][j][h]=0.f;
    __syncthreads();

    for (int c0 = 0; c0 < chunk; c0 += 64) {
        {
            int r = tid >> 2, kc = (tid & 3) * 16;
#pragma unroll
            for (int ii = 0; ii < 4; ii++) {
                float4 kv = *(const float4*)&Kb[(size_t)(c0+r)*64 + kc + ii*4];
                Ks[r][kc+ii*4+0]=f2tf(kv.x); Ks[r][kc+ii*4+1]=f2tf(kv.y);
                Ks[r][kc+ii*4+2]=f2tf(kv.z); Ks[r][kc+ii*4+3]=f2tf(kv.w);
                float4 vv = *(const float4*)&Vb[(size_t)(c0+r)*64 + kc + ii*4];
                Vs[r][kc+ii*4+0]=f2tf(vv.x); Vs[r][kc+ii*4+1]=f2tf(vv.y);
                Vs[r][kc+ii*4+2]=f2tf(vv.z); Vs[r][kc+ii*4+3]=f2tf(vv.w);
            }
        }
        __syncthreads();

        float s[2][2][4];
#pragma unroll
        for (int i=0;i<2;i++)
#pragma unroll
            for (int j=0;j<2;j++)
#pragma unroll
                for (int h=0;h<4;h++) s[i][j][h]=0.f;
#pragma unroll
        for (int ks = 0; ks < 64; ks += 8) {
            uint32_t af[2][4], bf[2][2];
#pragma unroll
            for (int i = 0; i < 2; i++) {
                int r = wm*32 + i*16 + g;
                af[i][0] = __float_as_uint(Qs[r][ks+t4]);
                af[i][1] = __float_as_uint(Qs[r+8][ks+t4]);
                af[i][2] = __float_as_uint(Qs[r][ks+t4+4]);
                af[i][3] = __float_as_uint(Qs[r+8][ks+t4+4]);
            }
#pragma unroll
            for (int j = 0; j < 2; j++) {
                int cc = wn*16 + j*8 + g;
                bf[j][0] = __float_as_uint(Ks[cc][ks+t4]);
                bf[j][1] = __float_as_uint(Ks[cc][ks+t4+4]);
            }
#pragma unroll
            for (int i = 0; i < 2; i++)
#pragma unroll
                for (int j = 0; j < 2; j++) {
                    asm volatile(
                        "mma.sync.aligned.m16n8k8.row.col.f32.tf32.tf32.f32 "
                        "{%0,%1,%2,%3}, {%4,%5,%6,%7}, {%8,%9}, {%0,%1,%2,%3};\n"
                        : "+f"(s[i][j][0]), "+f"(s[i][j][1]),
                          "+f"(s[i][j][2]), "+f"(s[i][j][3])
                        : "r"(af[i][0]), "r"(af[i][1]), "r"(af[i][2]), "r"(af[i][3]),
                          "r"(bf[j][0]), "r"(bf[j][1]));
                }
        }

        float pm[2][2];
#pragma unroll
        for (int i=0;i<2;i++)
#pragma unroll
            for (int h=0;h<2;h++)
                pm[i][h] = fmaxf(fmaxf(s[i][0][2*h], s[i][0][2*h+1]),
                                 fmaxf(s[i][1][2*h], s[i][1][2*h+1]));
#pragma unroll
        for (int off = 1; off <= 2; off <<= 1) {
#pragma unroll
            for (int i=0;i<2;i++)
#pragma unroll
                for (int h=0;h<2;h++)
                    pm[i][h] = fmaxf(pm[i][h], __shfl_xor_sync(0xffffffffu, pm[i][h], off));
        }
        if (t4 == 0) {
#pragma unroll
            for (int i=0;i<2;i++)
#pragma unroll
                for (int h=0;h<2;h++)
                    redm[wm*32 + i*16 + g + h*8][wn] = pm[i][h];
        }
        __syncthreads();

        float mnew[2][2], scale[2][2];
#pragma unroll
        for (int i=0;i<2;i++)
#pragma unroll
            for (int h=0;h<2;h++) {
                int r = wm*32 + i*16 + g + h*8;
                float m = fmaxf(fmaxf(redm[r][0], redm[r][1]),
                                fmaxf(redm[r][2], redm[r][3]));
                float mo = rowm[r];
                mnew[i][h] = fmaxf(mo, m);
                scale[i][h] = __expf(mo - mnew[i][h]);
            }

        float psum[2][2] = {{0.f,0.f},{0.f,0.f}};
#pragma unroll
        for (int i=0;i<2;i++)
#pragma unroll
            for (int j=0;j<2;j++)
#pragma unroll
                for (int h=0;h<2;h++) {
                    int r = wm*32 + i*16 + g + h*8;
                    float p0 = __expf(s[i][j][2*h]   - mnew[i][h]);
                    float p1 = __expf(s[i][j][2*h+1] - mnew[i][h]);
                    *(float2*)&Ps[r][wn*16 + j*8 + 2*t4] = make_float2(f2tf(p0), f2tf(p1));
                    psum[i][h] += p0 + p1;
                    o[i][j][2*h]   *= scale[i][h];
                    o[i][j][2*h+1] *= scale[i][h];
                }
#pragma unroll
        for (int off = 1; off <= 2; off <<= 1) {
#pragma unroll
            for (int i=0;i<2;i++)
#pragma unroll
                for (int h=0;h<2;h++)
                    psum[i][h] += __shfl_xor_sync(0xffffffffu, psum[i][h], off);
        }
        if (t4 == 0) {
#pragma unroll
            for (int i=0;i<2;i++)
#pragma unroll
                for (int h=0;h<2;h++)
                    reds[wm*32 + i*16 + g + h*8][wn] = psum[i][h];
        }
        __syncthreads();

        if (wn == 0 && t4 == 0) {
#pragma unroll
            for (int i=0;i<2;i++)
#pragma unroll
                for (int h=0;h<2;h++) {
                    int r = wm*32 + i*16 + g + h*8;
                    float ps = reds[r][0] + reds[r][1] + reds[r][2] + reds[r][3];
                    rowl[r] = rowl[r]*scale[i][h] + ps;
                    rowm[r] = mnew[i][h];
                }
        }

#pragma unroll
        for (int ks = 0; ks < 64; ks += 8) {
            uint32_t af[2][4], bf[2][2];
#pragma unroll
            for (int i = 0; i < 2; i++) {
                int r = wm*32 + i*16 + g;
                af[i][0] = __float_as_uint(Ps[r][ks+t4]);
                af[i][1] = __float_as_uint(Ps[r+8][ks+t4]);
                af[i][2] = __float_as_uint(Ps[r][ks+t4+4]);
                af[i][3] = __float_as_uint(Ps[r+8][ks+t4+4]);
            }
#pragma unroll
            for (int j = 0; j < 2; j++) {
                int cc = wn*16 + j*8 + g;
                bf[j][0] = __float_as_uint(Vs[ks+t4][cc]);
                bf[j][1] = __float_as_uint(Vs[ks+t4+4][cc]);
            }
#pragma unroll
            for (int i = 0; i < 2; i++)
#pragma unroll
                for (int j = 0; j < 2; j++) {
                    asm volatile(
                        "mma.sync.aligned.m16n8k8.row.col.f32.tf32.tf32.f32 "
                        "{%0,%1,%2,%3}, {%4,%5,%6,%7}, {%8,%9}, {%0,%1,%2,%3};\n"
                        : "+f"(o[i][j][0]), "+f"(o[i][j][1]),
                          "+f"(o[i][j][2]), "+f"(o[i][j][3])
                        : "r"(af[i][0]), "r"(af[i][1]), "r"(af[i][2]), "r"(af[i][3]),
                          "r"(bf[j][0]), "r"(bf[j][1]));
                }
        }
        __syncthreads();
    }

    if (lpart != nullptr) {
        float* Ob = O + ((size_t)(blockIdx.z*32 + bh)*nq + q0) * 64;
#pragma unroll
        for (int i=0;i<2;i++)
#pragma unroll
            for (int j=0;j<2;j++)
#pragma unroll
                for (int h=0;h<2;h++) {
                    int r = wm*32 + i*16 + g + h*8;
                    int cc = wn*16 + j*8 + 2*t4;
                    *(float2*)&Ob[(size_t)r*64 + cc] =
                        make_float2(o[i][j][2*h], o[i][j][2*h+1]);
                }
        if (tid < 64) {
            size_t ri = (size_t)(blockIdx.z*32 + bh)*nq + q0 + tid;
            mpart[ri] = rowm[tid];
            lpart[ri] = rowl[tid];
        }
    } else {
        float* Ob = O + ((size_t)bh*nq + q0) * 64;
#pragma unroll
        for (int i=0;i<2;i++)
#pragma unroll
            for (int j=0;j<2;j++)
#pragma unroll
                for (int h=0;h<2;h++) {
                    int r = wm*32 + i*16 + g + h*8;
                    int cc = wn*16 + j*8 + 2*t4;
                    float inv = 1.f / rowl[r];
                    *(float2*)&Ob[(size_t)r*64 + cc] =
                        make_float2(o[i][j][2*h]*inv, o[i][j][2*h+1]*inv);
                }
    }
}

// ---------------------------------------------------------------------------
// Single-pass flash for flash-2 (nk == 256)
// ---------------------------------------------------------------------------
__global__ __launch_bounds__(256) void flash2_sp_kernel(
        const float* __restrict__ Q, const float* __restrict__ K,
        const float* __restrict__ V, float* __restrict__ O) {
    extern __shared__ float sm[];
    float (*Qs)[QP] = (float(*)[QP])sm;
    float (*Ks)[QP] = (float(*)[QP])(sm + OFF_KS);
    float (*Ps)[QP] = (float(*)[QP])(sm + OFF_PS);
    float (*Vs)[VP] = (float(*)[VP])(sm + OFF_VS);
    float (*redm)[4] = (float(*)[4])(sm + OFF_REDM);
    float (*reds)[4] = (float(*)[4])(sm + OFF_REDS);

    int tid = threadIdx.x;
    int lane = tid & 31, wid = tid >> 5;
    int wm = wid & 1, wn = wid >> 1;
    int g = lane >> 2, t4 = lane & 3;
    int bh = blockIdx.y;
    int q0 = blockIdx.x * 64;
    const float* Qb = Q + ((size_t)bh*4096 + q0) * 64;
    const float* Kb = K + (size_t)bh*256*64;
    const float* Vb = V + (size_t)bh*256*64;
    float* Ob = O + ((size_t)bh*4096 + q0) * 64;

    int lr = tid >> 2, lk = (tid & 3) * 16;
    {
#pragma unroll
        for (int ii = 0; ii < 4; ii++) {
            float4 qv = *(const float4*)&Qb[(size_t)lr*64 + lk + ii*4];
            Qs[lr][lk+ii*4+0]=f2tf(qv.x); Qs[lr][lk+ii*4+1]=f2tf(qv.y);
            Qs[lr][lk+ii*4+2]=f2tf(qv.z); Qs[lr][lk+ii*4+3]=f2tf(qv.w);
        }
    }

    float s[4][2][2][4];
    float o[2][2][4];
#pragma unroll
    for (int i=0;i<2;i++)
#pragma unroll
        for (int j=0;j<2;j++)
#pragma unroll
            for (int h=0;h<4;h++) o[i][j][h]=0.f;

#pragma unroll
    for (int t = 0; t < 4; t++) {
        {
#pragma unroll
            for (int ii = 0; ii < 4; ii++) {
                float4 kv = *(const float4*)&Kb[(size_t)(t*64+lr)*64 + lk + ii*4];
                Ks[lr][lk+ii*4+0]=f2tf(kv.x); Ks[lr][lk+ii*4+1]=f2tf(kv.y);
                Ks[lr][lk+ii*4+2]=f2tf(kv.z); Ks[lr][lk+ii*4+3]=f2tf(kv.w);
            }
        }
        __syncthreads();
#pragma unroll
        for (int i=0;i<2;i++)
#pragma unroll
            for (int j=0;j<2;j++)
#pragma unroll
                for (int h=0;h<4;h++) s[t][i][j][h]=0.f;
#pragma unroll
        for (int ks = 0; ks < 64; ks += 8) {
            uint32_t af[2][4], bf[2][2];
#pragma unroll
            for (int i = 0; i < 2; i++) {
                int r = wm*32 + i*16 + g;
                af[i][0] = __float_as_uint(Qs[r][ks+t4]);
                af[i][1] = __float_as_uint(Qs[r+8][ks+t4]);
                af[i][2] = __float_as_uint(Qs[r][ks+t4+4]);
                af[i][3] = __float_as_uint(Qs[r+8][ks+t4+4]);
            }
#pragma unroll
            for (int j = 0; j < 2; j++) {
                int cc = wn*16 + j*8 + g;
                bf[j][0] = __float_as_uint(Ks[cc][ks+t4]);
                bf[j][1] = __float_as_uint(Ks[cc][ks+t4+4]);
            }
#pragma unroll
            for (int i = 0; i < 2; i++)
#pragma unroll
                for (int j = 0; j < 2; j++) {
                    asm volatile(
                        "mma.sync.aligned.m16n8k8.row.col.f32.tf32.tf32.f32 "
                        "{%0,%1,%2,%3}, {%4,%5,%6,%7}, {%8,%9}, {%0,%1,%2,%3};\n"
                        : "+f"(s[t][i][j][0]), "+f"(s[t][i][j][1]),
                          "+f"(s[t][i][j][2]), "+f"(s[t][i][j][3])
                        : "r"(af[i][0]), "r"(af[i][1]), "r"(af[i][2]), "r"(af[i][3]),
                          "r"(bf[j][0]), "r"(bf[j][1]));
                }
        }
        __syncthreads();
    }

    float pm[2][2];
#pragma unroll
    for (int i=0;i<2;i++)
#pragma unroll
        for (int h=0;h<2;h++) {
            float m = s[0][i][0][2*h];
#pragma unroll
            for (int t=0;t<4;t++)
#pragma unroll
                for (int j=0;j<2;j++) {
                    m = fmaxf(m, s[t][i][j][2*h]);
                    m = fmaxf(m, s[t][i][j][2*h+1]);
                }
#pragma unroll
            for (int off = 1; off <= 2; off <<= 1)
                m = fmaxf(m, __shfl_xor_sync(0xffffffffu, m, off));
            pm[i][h] = m;
        }
    if (t4 == 0) {
#pragma unroll
        for (int i=0;i<2;i++)
#pragma unroll
            for (int h=0;h<2;h++)
                redm[wm*32 + i*16 + g + h*8][wn] = pm[i][h];
    }
    __syncthreads();

    float linv[2][2];
    {
        float psum[2][2];
#pragma unroll
        for (int i=0;i<2;i++)
#pragma unroll
            for (int h=0;h<2;h++) {
                int r = wm*32 + i*16 + g + h*8;
                float m = fmaxf(fmaxf(redm[r][0], redm[r][1]),
                                fmaxf(redm[r][2], redm[r][3]));
                float ps = 0.f;
#pragma unroll
                for (int t=0;t<4;t++)
#pragma unroll
                    for (int j=0;j<2;j++) {
                        float p0 = __expf(s[t][i][j][2*h]   - m);
                        float p1 = __expf(s[t][i][j][2*h+1] - m);
                        s[t][i][j][2*h] = p0; s[t][i][j][2*h+1] = p1;
                        ps += p0 + p1;
                    }
#pragma unroll
                for (int off = 1; off <= 2; off <<= 1)
                    ps += __shfl_xor_sync(0xffffffffu, ps, off);
                psum[i][h] = ps;
            }
        if (t4 == 0) {
#pragma unroll
            for (int i=0;i<2;i++)
#pragma unroll
                for (int h=0;h<2;h++)
                    reds[wm*32 + i*16 + g + h*8][wn] = psum[i][h];
        }
        __syncthreads();
#pragma unroll
        for (int i=0;i<2;i++)
#pragma unroll
            for (int h=0;h<2;h++) {
                int r = wm*32 + i*16 + g + h*8;
                linv[i][h] = 1.f / (reds[r][0]+reds[r][1]+reds[r][2]+reds[r][3]);
            }
    }

#pragma unroll
    for (int t = 0; t < 4; t++) {
#pragma unroll
        for (int i=0;i<2;i++)
#pragma unroll
            for (int j=0;j<2;j++)
#pragma unroll
                for (int h=0;h<2;h++) {
                    int r = wm*32 + i*16 + g + h*8;
                    *(float2*)&Ps[r][wn*16 + j*8 + 2*t4] =
                        make_float2(f2tf(s[t][i][j][2*h]), f2tf(s[t][i][j][2*h+1]));
                }
        {
#pragma unroll
            for (int ii = 0; ii < 4; ii++) {
                float4 vv = *(const float4*)&Vb[(size_t)(t*64+lr)*64 + lk + ii*4];
                Vs[lr][lk+ii*4+0]=f2tf(vv.x); Vs[lr][lk+ii*4+1]=f2tf(vv.y);
                Vs[lr][lk+ii*4+2]=f2tf(vv.z); Vs[lr][lk+ii*4+3]=f2tf(vv.w);
            }
        }
        __syncthreads();
#pragma unroll
        for (int ks = 0; ks < 64; ks += 8) {
            uint32_t af[2][4], bf[2][2];
#pragma unroll
            for (int i = 0; i < 2; i++) {
                int r = wm*32 + i*16 + g;
                af[i][0] = __float_as_uint(Ps[r][ks+t4]);
                af[i][1] = __float_as_uint(Ps[r+8][ks+t4]);
                af[i][2] = __float_as_uint(Ps[r][ks+t4+4]);
                af[i][3] = __float_as_uint(Ps[r+8][ks+t4+4]);
            }
#pragma unroll
            for (int j = 0; j < 2; j++) {
                int cc = wn*16 + j*8 + g;
                bf[j][0] = __float_as_uint(Vs[ks+t4][cc]);
                bf[j][1] = __float_as_uint(Vs[ks+t4+4][cc]);
            }
#pragma unroll
            for (int i = 0; i < 2; i++)
#pragma unroll
                for (int j = 0; j < 2; j++) {
                    asm volatile(
                        "mma.sync.aligned.m16n8k8.row.col.f32.tf32.tf32.f32 "
                        "{%0,%1,%2,%3}, {%4,%5,%6,%7}, {%8,%9}, {%0,%1,%2,%3};\n"
                        : "+f"(o[i][j][0]), "+f"(o[i][j][1]),
                          "+f"(o[i][j][2]), "+f"(o[i][j][3])
                        : "r"(af[i][0]), "r"(af[i][1]), "r"(af[i][2]), "r"(af[i][3]),
                          "r"(bf[j][0]), "r"(bf[j][1]));
                }
        }
        __syncthreads();
    }

#pragma unroll
    for (int i=0;i<2;i++)
#pragma unroll
        for (int j=0;j<2;j++)
#pragma unroll
            for (int h=0;h<2;h++) {
                int r = wm*32 + i*16 + g + h*8;
                int cc = wn*16 + j*8 + 2*t4;
                *(float2*)&Ob[(size_t)r*64 + cc] =
                    make_float2(o[i][j][2*h]*linv[i][h], o[i][j][2*h+1]*linv[i][h]);
            }
}

// ---------------------------------------------------------------------------
// Split-K combine
// ---------------------------------------------------------------------------
__global__ void combine_kernel(const float* __restrict__ Op,
                               const float* __restrict__ mp,
                               const float* __restrict__ lp,
                               float* __restrict__ w) {
    int row = blockIdx.x;
    int c = threadIdx.x;
    int bh = row >> 8, qr = row & 255;
    float m0 = mp[(0*32+bh)*256+qr], m1 = mp[(1*32+bh)*256+qr];
    float m2 = mp[(2*32+bh)*256+qr], m3 = mp[(3*32+bh)*256+qr];
    float ms = fmaxf(fmaxf(m0,m1), fmaxf(m2,m3));
    float w0 = __expf(m0-ms), w1 = __expf(m1-ms), w2 = __expf(m2-ms), w3 = __expf(m3-ms);
    float l = w0*lp[(0*32+bh)*256+qr] + w1*lp[(1*32+bh)*256+qr]
            + w2*lp[(2*32+bh)*256+qr] + w3*lp[(3*32+bh)*256+qr];
    float acc = w0*Op[((size_t)(0*32+bh)*256+qr)*64 + c]
              + w1*Op[((size_t)(1*32+bh)*256+qr)*64 + c]
              + w2*Op[((size_t)(2*32+bh)*256+qr)*64 + c]
              + w3*Op[((size_t)(3*32+bh)*256+qr)*64 + c];
    w[((size_t)bh*256+qr)*64 + c] = acc / l;
}

// ---------------------------------------------------------------------------
// Depthwise seq-conv residual + layout transform
// ---------------------------------------------------------------------------
__global__ __launch_bounds__(256) void conv_kernel(
        const float* __restrict__ attn, const float* __restrict__ v,
        const float* __restrict__ cw, float* __restrict__ attn2) {
    __shared__ float vt[96][64];
    __shared__ float wk[33];
    int bh = blockIdx.y; int h = bh & 7; int b4 = bh >> 3;
    int row0 = blockIdx.x * 64;
    int t = threadIdx.x;
    if (t < 33) wk[t] = cw[h*33 + t];
    const float* vb = v + (size_t)bh*4096*64;
#pragma unroll
    for (int i=0;i<6;i++){
        int f = t + i*256;
        int r = f >> 4;
        int c4 = (f & 15) * 4;
        int gr = row0 - 16 + r;
        float4 val = make_float4(0.f,0.f,0.f,0.f);
        if (gr >= 0 && gr < 4096) val = *(const float4*)&vb[(size_t)gr*64 + c4];
        *(float4*)&vt[r][c4] = val;
    }
    __syncthreads();
    int dh = t & 63;
    int rr = t >> 6;
#pragma unroll
    for (int q=0;q<16;q++){
        int lr = rr + q*4;
        float acc = attn[((size_t)bh*4096 + row0 + lr)*64 + dh];
#pragma unroll
        for (int s=0;s<33;s++) acc += wk[s]*vt[lr+s][dh];
        attn2[((size_t)b4*4096 + row0 + lr)*512 + h*64 + dh] = acc;
    }
}

// ---------------------------------------------------------------------------
// Host orchestration
// ---------------------------------------------------------------------------
extern "C" void kernel_launch(void* const* d_in, const int* in_sizes, int n_in,
                              void* d_out, int out_size) {
    const float* x      = (const float*)d_in[0];
    const float* norm_w = (const float*)d_in[1];
    const float* norm_b = (const float*)d_in[2];
    const float* Wqkv   = (const float*)d_in[3];
    const float* Wout   = (const float*)d_in[4];
    const float* bout   = (const float*)d_in[5];
    const float* conv_w = (const float*)d_in[6];
    float* out = (float*)d_out;

    float *xn,*q,*k,*v,*ql,*kl,*a2,*z0,*t1,*t2,*t3,*w,*w2,*uu,*r3,*u5,*attn,*attn2,*red;
    float *w4s[5];
    cudaGetSymbolAddress((void**)&xn,   g_xn);
    cudaGetSymbolAddress((void**)&q,    g_q);
    cudaGetSymbolAddress((void**)&k,    g_k);
    cudaGetSymbolAddress((void**)&v,    g_v);
    cudaGetSymbolAddress((void**)&ql,   g_ql);
    cudaGetSymbolAddress((void**)&kl,   g_kl);
    cudaGetSymbolAddress((void**)&a2,   g_a2);
    cudaGetSymbolAddress((void**)&z0,   g_z0);
    cudaGetSymbolAddress((void**)&t1,   g_t1);
    cudaGetSymbolAddress((void**)&t2,   g_t2);
    cudaGetSymbolAddress((void**)&t3,   g_t3);
    cudaGetSymbolAddress((void**)&w4s[0], g_w40);
    cudaGetSymbolAddress((void**)&w4s[1], g_w41);
    cudaGetSymbolAddress((void**)&w4s[2], g_w42);
    cudaGetSymbolAddress((void**)&w4s[3], g_w43);
    cudaGetSymbolAddress((void**)&w4s[4], g_w44);
    cudaGetSymbolAddress((void**)&w,    g_w);
    cudaGetSymbolAddress((void**)&w2,   g_w2);
    cudaGetSymbolAddress((void**)&uu,   g_u);
    cudaGetSymbolAddress((void**)&r3,   g_r3);
    cudaGetSymbolAddress((void**)&u5,   g_u5);
    cudaGetSymbolAddress((void**)&attn, g_attn);
    cudaGetSymbolAddress((void**)&attn2,g_attn2);
    cudaGetSymbolAddress((void**)&red,  g_red);

    cudaFuncSetAttribute(flash_tc_kernel, cudaFuncAttributeMaxDynamicSharedMemorySize, SMEM_FLASH_TC);
    cudaFuncSetAttribute(flash2_sp_kernel, cudaFuncAttributeMaxDynamicSharedMemorySize, SMEM_FLASH_TC);
    cudaFuncSetAttribute(a2_tc_kernel, cudaFuncAttributeMaxDynamicSharedMemorySize, SMEM_A2);

    // 1. LayerNorm
    ln_kernel<<<16384, 128>>>(x, norm_w, norm_b, xn);
    // 2. QKV projection (tf32 MMA, fused scatter + q scale)
    mma_gemm<0,512,1536,512><<<dim3(12,128), 256>>>(
        xn, Wqkv, q, k, v, nullptr, nullptr);
    // 3. landmarks (merged)
    landmark2_kernel<<<4096, 256>>>(q, k, ql, kl);
    // 4. a2 = softmax(q_l k_l^T) (tf32 MMA, 64-row tiles -> 128 CTAs)
    a2_tc_kernel<<<dim3(4,32), 256, SMEM_A2>>>(ql, kl, a2);
    // 5. pinv init scalar (split colsum, 128 CTAs) + z0 = s*a2^T (smem transpose)
    red_init_kernel<<<1, 32>>>(red);
    colsum_kernel<<<dim3(4,32), 64>>>(a2, red);
    zinit_kernel<<<dim3(8,8,32), dim3(32,8)>>>(a2, red, z0);
    // 6. w = softmax(q_l k^T) @ v — split-K x4 flash + combine
    flash_tc_kernel<<<dim3(4,32,4), 256, SMEM_FLASH_TC>>>(
        ql, k, v, t1, 256, 4096, 1024, t2, t2 + 32768);
    combine_kernel<<<8192, 64>>>(t1, t2, t2 + 32768, w);
    // 7. Newton-Schulz pinv, Y-only recurrence, 128x128 tiles (proven):
    //    W2 = Y(7I-Y); W4_i = Y(15I-W2); Y' = 0.25*Y(13I-W4_i)   [it=0..4]
    mma_gemm_pinv<<<dim3(2,2,32), 256>>>(a2, z0, t1, 0.f, 1.f);   // Y0 = a2 @ z0
    float* Y = t1; float* Yn = t3;
    for (int it = 0; it < 5; it++) {
        mma_gemm_pinv<<<dim3(2,2,32), 256>>>(Y, Y, t2, 7.f, -1.f);        // W2
        mma_gemm_pinv<<<dim3(2,2,32), 256>>>(Y, t2, w4s[it], 15.f, -1.f); // W4_i
        mma_gemm_pinv<<<dim3(2,2,32), 256>>>(Y, w4s[it], Yn, 3.25f, -0.25f);
        float* tmp = Y; Y = Yn; Yn = tmp;
    }
    // Y == Y5. Narrow last iteration: u5 = 13w - 15 Y5w + 7 Y5^2w - Y5^3w
    mma_nar_kernel<<<dim3(1,2,32), 256>>>(Y, w,  uu, 0.f, 1.f);   // r1
    mma_nar_kernel<<<dim3(1,2,32), 256>>>(Y, uu, w2, 0.f, 1.f);   // r2
    mma_nar_kernel<<<dim3(1,2,32), 256>>>(Y, w2, r3, 0.f, 1.f);   // r3
    comb4_kernel<<<2048, 256>>>(w, uu, w2, r3, u5);
    // 8. narrow chain down: u_i = 13*u_{i+1} - W4_i @ u_{i+1}
    mma_nar_kernel<<<dim3(1,2,32), 256>>>(w4s[4], u5, uu, 13.f, -1.f);
    mma_nar_kernel<<<dim3(1,2,32), 256>>>(w4s[3], uu, w2, 13.f, -1.f);
    mma_nar_kernel<<<dim3(1,2,32), 256>>>(w4s[2], w2, uu, 13.f, -1.f);
    mma_nar_kernel<<<dim3(1,2,32), 256>>>(w4s[1], uu, w2, 13.f, -1.f);
    mma_nar_kernel<<<dim3(1,2,32), 256>>>(w4s[0], w2, uu, 13.f, -1.f);
    mma_nar_kernel<<<dim3(1,2,32), 256>>>(z0, uu, w2, 0.f, 1.f/4096.f);
    // 9. attn = softmax(q k_l^T) @ w2 — single-pass flash (nk=256)
    flash2_sp_kernel<<<dim3(64,32), 256, SMEM_FLASH_TC>>>(q, kl, w2, attn);
    // 10. conv residual + layout
    conv_kernel<<<dim3(64,32), 256>>>(attn, v, conv_w, attn2);
    // 11. output projection + bias + input residual (tf32 MMA)
    mma_gemm<1,512,512,512><<<dim3(4,128), 256>>>(
        attn2, Wout, out, nullptr, nullptr, bout, x);
}

// round 16
// speedup vs baseline: 1.0654x; 1.0061x over previous
#include <cuda_runtime.h>
#include <cuda_bf16.h>
#include <cstdint>

// ---------------------------------------------------------------------------
// Problem constants: b=4, n=4096, D=512, H=8, dh=64, M=256, l=16, 6 iters,
// conv k=33, eps=1e-5
// ---------------------------------------------------------------------------
#define NB   (4*4096*512)
#define MM   (32*256*256)
#define MD   (32*256*64)

__device__ float g_xn[NB];
__device__ float g_q[NB];
__device__ float g_k[NB];
__device__ float g_v[NB];
__device__ float g_ql[MD];
__device__ float g_kl[MD];
__device__ float g_a2[MM];
__device__ float g_z0[MM];
__device__ float g_t1[MM];   // Y ping / flash1 split-K O partials
__device__ float g_t2[MM];   // W2 scratch / flash1 split-K m/l partials
__device__ float g_t3[MM];   // Y pong
__device__ float g_w40[MM];
__device__ float g_w41[MM];
__device__ float g_w42[MM];
__device__ float g_w43[MM];
__device__ float g_w44[MM];
__device__ float g_w[MD];
__device__ float g_w2[MD];
__device__ float g_u[MD];
__device__ float g_r3[MD];
__device__ float g_u5[MD];
__device__ float g_attn2[NB];
__device__ float g_red[2];

__device__ __forceinline__ float f2tf(float x) {
    uint32_t u;
    asm("cvt.rna.tf32.f32 %0, %1;" : "=r"(u) : "f"(x));
    return __uint_as_float(u);
}

// ---------------------------------------------------------------------------
// LayerNorm
// ---------------------------------------------------------------------------
__global__ void ln_kernel(const float* __restrict__ x, const float* __restrict__ w,
                          const float* __restrict__ bb, float* __restrict__ out) {
    int row = blockIdx.x;
    const float* xr = x + (size_t)row * 512;
    float* orow = out + (size_t)row * 512;
    int t = threadIdx.x;
    float v[4];
    float s = 0.f;
#pragma unroll
    for (int i = 0; i < 4; i++) { v[i] = xr[t + 128*i]; s += v[i]; }
#pragma unroll
    for (int o = 16; o; o >>= 1) s += __shfl_xor_sync(0xffffffffu, s, o);
    __shared__ float red[4];
    if ((t & 31) == 0) red[t >> 5] = s;
    __syncthreads();
    float mean = (red[0]+red[1]+red[2]+red[3]) * (1.f/512.f);
    float vs = 0.f;
#pragma unroll
    for (int i = 0; i < 4; i++) { float d = v[i]-mean; vs += d*d; }
#pragma unroll
    for (int o = 16; o; o >>= 1) vs += __shfl_xor_sync(0xffffffffu, vs, o);
    __syncthreads();
    if ((t & 31) == 0) red[t >> 5] = vs;
    __syncthreads();
    float var = (red[0]+red[1]+red[2]+red[3]) * (1.f/512.f);
    float rstd = rsqrtf(var + 1e-5f);
#pragma unroll
    for (int i = 0; i < 4; i++) {
        int c = t + 128*i;
        orow[c] = (v[i]-mean)*rstd*w[c] + bb[c];
    }
}

// ---------------------------------------------------------------------------
// TF32 GEMM (proven): block 128x128, BK=16, 8 warps 64x32, occ 2.
// EPI 0: QKV scatter. EPI 1: bias + residual.
// ---------------------------------------------------------------------------
template<int EPI, int LDA, int LDB, int KD>
__global__ __launch_bounds__(256, 2) void mma_gemm(
        const float* __restrict__ A, const float* __restrict__ B,
        float* __restrict__ C0, float* __restrict__ C1, float* __restrict__ C2,
        const float* __restrict__ e0, const float* __restrict__ e1) {
    __shared__ float Asm[2][128*20];
    __shared__ float Bsm[2][16*136];
    int tid = threadIdx.x;
    int lane = tid & 31, wid = tid >> 5;
    int wm = wid & 1, wn = wid >> 1;
    int g = lane >> 2, t4 = lane & 3;
    int row0 = blockIdx.y * 128, col0 = blockIdx.x * 128;
    int arow = tid >> 1, akq = (tid & 1) * 8;
    int bkr = tid >> 4, bnc = (tid & 15) * 8;

    {
        const float* ap = A + (size_t)(row0 + arow) * LDA + akq;
        float4 a0 = *(const float4*)ap;
        float4 a1 = *(const float4*)(ap + 4);
        float* as = &Asm[0][arow*20 + akq];
        as[0]=f2tf(a0.x); as[1]=f2tf(a0.y); as[2]=f2tf(a0.z); as[3]=f2tf(a0.w);
        as[4]=f2tf(a1.x); as[5]=f2tf(a1.y); as[6]=f2tf(a1.z); as[7]=f2tf(a1.w);
        const float* bp = B + (size_t)bkr * LDB + col0 + bnc;
        float4 b0 = *(const float4*)bp;
        float4 b1 = *(const float4*)(bp + 4);
        float* bs = &Bsm[0][bkr*136 + bnc];
        bs[0]=f2tf(b0.x); bs[1]=f2tf(b0.y); bs[2]=f2tf(b0.z); bs[3]=f2tf(b0.w);
        bs[4]=f2tf(b1.x); bs[5]=f2tf(b1.y); bs[6]=f2tf(b1.z); bs[7]=f2tf(b1.w);
    }
    __syncthreads();

    float c[4][4][4];
#pragma unroll
    for (int i=0;i<4;i++)
#pragma unroll
        for (int j=0;j<4;j++)
#pragma unroll
            for (int h=0;h<4;h++) c[i][j][h]=0.f;

    const int NIT = KD / 16;
    for (int it = 0; it < NIT; it++) {
        int buf = it & 1;
        float4 pa0, pa1, pb0, pb1;
        if (it + 1 < NIT) {
            int k0 = (it + 1) * 16;
            const float* ap = A + (size_t)(row0 + arow) * LDA + k0 + akq;
            pa0 = *(const float4*)ap;
            pa1 = *(const float4*)(ap + 4);
            const float* bp = B + (size_t)(k0 + bkr) * LDB + col0 + bnc;
            pb0 = *(const float4*)bp;
            pb1 = *(const float4*)(bp + 4);
        }
#pragma unroll
        for (int ks = 0; ks < 16; ks += 8) {
            uint32_t af[4][4], bf[4][2];
#pragma unroll
            for (int i = 0; i < 4; i++) {
                int r0i = (wm*64 + i*16 + g) * 20 + ks + t4;
                int r1i = r0i + 8*20;
                af[i][0] = __float_as_uint(Asm[buf][r0i]);
                af[i][1] = __float_as_uint(Asm[buf][r1i]);
                af[i][2] = __float_as_uint(Asm[buf][r0i + 4]);
                af[i][3] = __float_as_uint(Asm[buf][r1i + 4]);
            }
#pragma unroll
            for (int j = 0; j < 4; j++) {
                int nc2 = wn*32 + j*8 + g;
                bf[j][0] = __float_as_uint(Bsm[buf][(ks + t4)*136 + nc2]);
                bf[j][1] = __float_as_uint(Bsm[buf][(ks + t4 + 4)*136 + nc2]);
            }
#pragma unroll
            for (int i = 0; i < 4; i++)
#pragma unroll
                for (int j = 0; j < 4; j++) {
                    asm volatile(
                        "mma.sync.aligned.m16n8k8.row.col.f32.tf32.tf32.f32 "
                        "{%0,%1,%2,%3}, {%4,%5,%6,%7}, {%8,%9}, {%0,%1,%2,%3};\n"
                        : "+f"(c[i][j][0]), "+f"(c[i][j][1]),
                          "+f"(c[i][j][2]), "+f"(c[i][j][3])
                        : "r"(af[i][0]), "r"(af[i][1]), "r"(af[i][2]), "r"(af[i][3]),
                          "r"(bf[j][0]), "r"(bf[j][1]));
                }
        }
        if (it + 1 < NIT) {
            int nb = buf ^ 1;
            float* as = &Asm[nb][arow*20 + akq];
            as[0]=f2tf(pa0.x); as[1]=f2tf(pa0.y); as[2]=f2tf(pa0.z); as[3]=f2tf(pa0.w);
            as[4]=f2tf(pa1.x); as[5]=f2tf(pa1.y); as[6]=f2tf(pa1.z); as[7]=f2tf(pa1.w);
            float* bs = &Bsm[nb][bkr*136 + bnc];
            bs[0]=f2tf(pb0.x); bs[1]=f2tf(pb0.y); bs[2]=f2tf(pb0.z); bs[3]=f2tf(pb0.w);
            bs[4]=f2tf(pb1.x); bs[5]=f2tf(pb1.y); bs[6]=f2tf(pb1.z); bs[7]=f2tf(pb1.w);
        }
        __syncthreads();
    }

#pragma unroll
    for (int i = 0; i < 4; i++) {
#pragma unroll
        for (int j = 0; j < 4; j++) {
#pragma unroll
            for (int h = 0; h < 2; h++) {
                int r = row0 + wm*64 + i*16 + g + h*8;
                int cc = col0 + wn*32 + j*8 + 2*t4;
                float v0 = c[i][j][h*2+0], v1 = c[i][j][h*2+1];
                if (EPI == 0) {
                    int b4 = r >> 12, nn = r & 4095;
                    int which = cc >> 9, cs = cc & 511;
                    int hh = cs >> 6, dh = cs & 63;
                    size_t di = ((size_t)(b4*8+hh)*4096 + nn)*64 + dh;
                    if (which == 0) {
                        *(float2*)&C0[di] = make_float2(v0*0.125f, v1*0.125f);
                    } else if (which == 1) {
                        *(float2*)&C1[di] = make_float2(v0, v1);
                    } else {
                        *(float2*)&C2[di] = make_float2(v0, v1);
                    }
                } else {
                    size_t di = (size_t)r*512 + cc;
                    float2 bias = *(const float2*)&e0[cc];
                    float2 xr = *(const float2*)&e1[di];
                    *(float2*)&C0[di] = make_float2(v0+bias.x+xr.x, v1+bias.y+xr.y);
                }
            }
        }
    }
}

// ---------------------------------------------------------------------------
// TF32 GEMM, pinv variant (proven 128x128): batched over z (stride 65536):
// C0 = cA*A + cAB*(A@B)
// ---------------------------------------------------------------------------
__global__ __launch_bounds__(256, 2) void mma_gemm_pinv(
        const float* __restrict__ A, const float* __restrict__ B,
        float* __restrict__ C0, float cA, float cAB) {
    __shared__ float Asm[2][128*20];
    __shared__ float Bsm[2][16*136];
    int tid = threadIdx.x;
    int lane = tid & 31, wid = tid >> 5;
    int wm = wid & 1, wn = wid >> 1;
    int g = lane >> 2, t4 = lane & 3;
    int row0 = blockIdx.y * 128, col0 = blockIdx.x * 128;
    const float* Ag = A + (size_t)blockIdx.z * 65536;
    const float* Bg = B + (size_t)blockIdx.z * 65536;
    int arow = tid >> 1, akq = (tid & 1) * 8;
    int bkr = tid >> 4, bnc = (tid & 15) * 8;

    {
        const float* ap = Ag + (size_t)(row0 + arow) * 256 + akq;
        float4 a0 = *(const float4*)ap;
        float4 a1 = *(const float4*)(ap + 4);
        float* as = &Asm[0][arow*20 + akq];
        as[0]=f2tf(a0.x); as[1]=f2tf(a0.y); as[2]=f2tf(a0.z); as[3]=f2tf(a0.w);
        as[4]=f2tf(a1.x); as[5]=f2tf(a1.y); as[6]=f2tf(a1.z); as[7]=f2tf(a1.w);
        const float* bp = Bg + (size_t)bkr * 256 + col0 + bnc;
        float4 b0 = *(const float4*)bp;
        float4 b1 = *(const float4*)(bp + 4);
        float* bs = &Bsm[0][bkr*136 + bnc];
        bs[0]=f2tf(b0.x); bs[1]=f2tf(b0.y); bs[2]=f2tf(b0.z); bs[3]=f2tf(b0.w);
        bs[4]=f2tf(b1.x); bs[5]=f2tf(b1.y); bs[6]=f2tf(b1.z); bs[7]=f2tf(b1.w);
    }
    __syncthreads();

    float c[4][4][4];
#pragma unroll
    for (int i=0;i<4;i++)
#pragma unroll
        for (int j=0;j<4;j++)
#pragma unroll
            for (int h=0;h<4;h++) c[i][j][h]=0.f;

    const int NIT = 16;
    for (int it = 0; it < NIT; it++) {
        int buf = it & 1;
        float4 pa0, pa1, pb0, pb1;
        if (it + 1 < NIT) {
            int k0 = (it + 1) * 16;
            const float* ap = Ag + (size_t)(row0 + arow) * 256 + k0 + akq;
            pa0 = *(const float4*)ap;
            pa1 = *(const float4*)(ap + 4);
            const float* bp = Bg + (size_t)(k0 + bkr) * 256 + col0 + bnc;
            pb0 = *(const float4*)bp;
            pb1 = *(const float4*)(bp + 4);
        }
#pragma unroll
        for (int ks = 0; ks < 16; ks += 8) {
            uint32_t af[4][4], bf[4][2];
#pragma unroll
            for (int i = 0; i < 4; i++) {
                int r0i = (wm*64 + i*16 + g) * 20 + ks + t4;
                int r1i = r0i + 8*20;
                af[i][0] = __float_as_uint(Asm[buf][r0i]);
                af[i][1] = __float_as_uint(Asm[buf][r1i]);
                af[i][2] = __float_as_uint(Asm[buf][r0i + 4]);
                af[i][3] = __float_as_uint(Asm[buf][r1i + 4]);
            }
#pragma unroll
            for (int j = 0; j < 4; j++) {
                int nc2 = wn*32 + j*8 + g;
                bf[j][0] = __float_as_uint(Bsm[buf][(ks + t4)*136 + nc2]);
                bf[j][1] = __float_as_uint(Bsm[buf][(ks + t4 + 4)*136 + nc2]);
            }
#pragma unroll
            for (int i = 0; i < 4; i++)
#pragma unroll
                for (int j = 0; j < 4; j++) {
                    asm volatile(
                        "mma.sync.aligned.m16n8k8.row.col.f32.tf32.tf32.f32 "
                        "{%0,%1,%2,%3}, {%4,%5,%6,%7}, {%8,%9}, {%0,%1,%2,%3};\n"
                        : "+f"(c[i][j][0]), "+f"(c[i][j][1]),
                          "+f"(c[i][j][2]), "+f"(c[i][j][3])
                        : "r"(af[i][0]), "r"(af[i][1]), "r"(af[i][2]), "r"(af[i][3]),
                          "r"(bf[j][0]), "r"(bf[j][1]));
                }
        }
        if (it + 1 < NIT) {
            int nb = buf ^ 1;
            float* as = &Asm[nb][arow*20 + akq];
            as[0]=f2tf(pa0.x); as[1]=f2tf(pa0.y); as[2]=f2tf(pa0.z); as[3]=f2tf(pa0.w);
            as[4]=f2tf(pa1.x); as[5]=f2tf(pa1.y); as[6]=f2tf(pa1.z); as[7]=f2tf(pa1.w);
            float* bs = &Bsm[nb][bkr*136 + bnc];
            bs[0]=f2tf(pb0.x); bs[1]=f2tf(pb0.y); bs[2]=f2tf(pb0.z); bs[3]=f2tf(pb0.w);
            bs[4]=f2tf(pb1.x); bs[5]=f2tf(pb1.y); bs[6]=f2tf(pb1.z); bs[7]=f2tf(pb1.w);
        }
        __syncthreads();
    }

#pragma unroll
    for (int i = 0; i < 4; i++) {
#pragma unroll
        for (int j = 0; j < 4; j++) {
#pragma unroll
            for (int h = 0; h < 2; h++) {
                int r = row0 + wm*64 + i*16 + g + h*8;
                int cc = col0 + wn*32 + j*8 + 2*t4;
                float v0 = c[i][j][h*2+0], v1 = c[i][j][h*2+1];
                float2 ae = *(const float2*)&Ag[(size_t)r*256 + cc];
                size_t di = (size_t)blockIdx.z*65536 + (size_t)r*256 + cc;
                *(float2*)&C0[di] = make_float2(cA*ae.x + cAB*v0,
                                                cA*ae.y + cAB*v1);
            }
        }
    }
}

// ---------------------------------------------------------------------------
// TF32 MMA narrow GEMM: C = cB*B + cAB*(A@B), A [32][256][256], B,C [32][256][64].
// ---------------------------------------------------------------------------
__global__ __launch_bounds__(256, 2) void mma_nar_kernel(
        const float* __restrict__ A, const float* __restrict__ B,
        float* __restrict__ C, float cB, float cAB) {
    __shared__ float Asm[2][128*20];
    __shared__ float Bsm[2][16*72];
    int tid = threadIdx.x;
    int lane = tid & 31, wid = tid >> 5;
    int wm = wid & 3, wn = wid >> 2;
    int g = lane >> 2, t4 = lane & 3;
    int row0 = blockIdx.y * 128;
    const float* Ag = A + (size_t)blockIdx.z * 65536;
    const float* Bg = B + (size_t)blockIdx.z * 16384;
    float* Cg = C + (size_t)blockIdx.z * 16384;
    int arow = tid >> 1, akq = (tid & 1) * 8;
    int bkr = tid >> 4, bnc = (tid & 15) * 4;

    {
        const float* ap = Ag + (size_t)(row0 + arow) * 256 + akq;
        float4 a0 = *(const float4*)ap;
        float4 a1 = *(const float4*)(ap + 4);
        float* as = &Asm[0][arow*20 + akq];
        as[0]=f2tf(a0.x); as[1]=f2tf(a0.y); as[2]=f2tf(a0.z); as[3]=f2tf(a0.w);
        as[4]=f2tf(a1.x); as[5]=f2tf(a1.y); as[6]=f2tf(a1.z); as[7]=f2tf(a1.w);
        float4 bv = *(const float4*)(Bg + (size_t)bkr * 64 + bnc);
        float* bs = &Bsm[0][bkr*72 + bnc];
        bs[0]=f2tf(bv.x); bs[1]=f2tf(bv.y); bs[2]=f2tf(bv.z); bs[3]=f2tf(bv.w);
    }
    __syncthreads();

    float c[2][4][4];
#pragma unroll
    for (int i=0;i<2;i++)
#pragma unroll
        for (int j=0;j<4;j++)
#pragma unroll
            for (int h=0;h<4;h++) c[i][j][h]=0.f;

    const int NIT = 16;
    for (int it = 0; it < NIT; it++) {
        int buf = it & 1;
        float4 pa0, pa1, pb;
        if (it + 1 < NIT) {
            int k0 = (it + 1) * 16;
            const float* ap = Ag + (size_t)(row0 + arow) * 256 + k0 + akq;
            pa0 = *(const float4*)ap;
            pa1 = *(const float4*)(ap + 4);
            pb = *(const float4*)(Bg + (size_t)(k0 + bkr) * 64 + bnc);
        }
#pragma unroll
        for (int ks = 0; ks < 16; ks += 8) {
            uint32_t af[2][4], bf[4][2];
#pragma unroll
            for (int i = 0; i < 2; i++) {
                int r0i = (wm*32 + i*16 + g) * 20 + ks + t4;
                int r1i = r0i + 8*20;
                af[i][0] = __float_as_uint(Asm[buf][r0i]);
                af[i][1] = __float_as_uint(Asm[buf][r1i]);
                af[i][2] = __float_as_uint(Asm[buf][r0i + 4]);
                af[i][3] = __float_as_uint(Asm[buf][r1i + 4]);
            }
#pragma unroll
            for (int j = 0; j < 4; j++) {
                int nc2 = wn*32 + j*8 + g;
                bf[j][0] = __float_as_uint(Bsm[buf][(ks + t4)*72 + nc2]);
                bf[j][1] = __float_as_uint(Bsm[buf][(ks + t4 + 4)*72 + nc2]);
            }
#pragma unroll
            for (int i = 0; i < 2; i++)
#pragma unroll
                for (int j = 0; j < 4; j++) {
                    asm volatile(
                        "mma.sync.aligned.m16n8k8.row.col.f32.tf32.tf32.f32 "
                        "{%0,%1,%2,%3}, {%4,%5,%6,%7}, {%8,%9}, {%0,%1,%2,%3};\n"
                        : "+f"(c[i][j][0]), "+f"(c[i][j][1]),
                          "+f"(c[i][j][2]), "+f"(c[i][j][3])
                        : "r"(af[i][0]), "r"(af[i][1]), "r"(af[i][2]), "r"(af[i][3]),
                          "r"(bf[j][0]), "r"(bf[j][1]));
                }
        }
        if (it + 1 < NIT) {
            int nb = buf ^ 1;
            float* as = &Asm[nb][arow*20 + akq];
            as[0]=f2tf(pa0.x); as[1]=f2tf(pa0.y); as[2]=f2tf(pa0.z); as[3]=f2tf(pa0.w);
            as[4]=f2tf(pa1.x); as[5]=f2tf(pa1.y); as[6]=f2tf(pa1.z); as[7]=f2tf(pa1.w);
            float* bs = &Bsm[nb][bkr*72 + bnc];
            bs[0]=f2tf(pb.x); bs[1]=f2tf(pb.y); bs[2]=f2tf(pb.z); bs[3]=f2tf(pb.w);
        }
        __syncthreads();
    }

#pragma unroll
    for (int i = 0; i < 2; i++)
#pragma unroll
        for (int j = 0; j < 4; j++)
#pragma unroll
            for (int h = 0; h < 2; h++) {
                int r = row0 + wm*32 + i*16 + g + h*8;
                int cc = wn*32 + j*8 + 2*t4;
                float v0 = cAB * c[i][j][h*2+0];
                float v1 = cAB * c[i][j][h*2+1];
                if (cB != 0.f) {
                    float2 be = *(const float2*)&Bg[(size_t)r*64 + cc];
                    v0 += cB * be.x; v1 += cB * be.y;
                }
                *(float2*)&Cg[(size_t)r*64 + cc] = make_float2(v0, v1);
            }
}

// ---------------------------------------------------------------------------
// u5 = 13*w - 15*r1 + 7*r2 - r3  (elementwise, MD elems)
// ---------------------------------------------------------------------------
__global__ void comb4_kernel(const float* __restrict__ w, const float* __restrict__ r1,
                             const float* __restrict__ r2, const float* __restrict__ r3,
                             float* __restrict__ u5) {
    int i = blockIdx.x * 256 + threadIdx.x;
    u5[i] = 13.f*w[i] - 15.f*r1[i] + 7.f*r2[i] - r3[i];
}

// ---------------------------------------------------------------------------
// TF32 MMA a2 = softmax(q_l @ k_l^T), 64-row tiles -> grid (4,32) = 128 CTAs
// ---------------------------------------------------------------------------
#define A2_KS   4352
#define A2_RM   21760
#define A2_RS   22272
#define SMEM_A2 (22784*4)
__global__ __launch_bounds__(256, 1) void a2_tc_kernel(
        const float* __restrict__ ql, const float* __restrict__ kl,
        float* __restrict__ a2) {
    extern __shared__ float sm2[];
    float* Qs = sm2;                       // [64][68]
    float* Ks = sm2 + A2_KS;               // [256][68]
    float (*redm)[8] = (float(*)[8])(sm2 + A2_RM);
    float (*reds)[8] = (float(*)[8])(sm2 + A2_RS);

    int tid = threadIdx.x;
    int lane = tid & 31, wn = tid >> 5;
    int g = lane >> 2, t4 = lane & 3;
    int bh = blockIdx.y;
    int row0 = blockIdx.x * 64;
    const float* qb = ql + ((size_t)bh*256 + row0) * 64;
    const float* kb = kl + (size_t)bh*256*64;

    for (int i = tid*4; i < 4096; i += 1024) {
        float4 qv = *(const float4*)&qb[i];
        int r = i >> 6, cc = i & 63;
        float* qs = &Qs[r*68 + cc];
        qs[0]=f2tf(qv.x); qs[1]=f2tf(qv.y); qs[2]=f2tf(qv.z); qs[3]=f2tf(qv.w);
    }
    for (int i = tid*4; i < 16384; i += 1024) {
        float4 kv = *(const float4*)&kb[i];
        int r = i >> 6, cc = i & 63;
        float* ks = &Ks[r*68 + cc];
        ks[0]=f2tf(kv.x); ks[1]=f2tf(kv.y); ks[2]=f2tf(kv.z); ks[3]=f2tf(kv.w);
    }
    __syncthreads();

    float c[4][4][4];
#pragma unroll
    for (int i=0;i<4;i++)
#pragma unroll
        for (int j=0;j<4;j++)
#pragma unroll
            for (int h=0;h<4;h++) c[i][j][h]=0.f;

#pragma unroll
    for (int ks = 0; ks < 64; ks += 8) {
        uint32_t af[4][4], bf[4][2];
#pragma unroll
        for (int i = 0; i < 4; i++) {
            int r0i = (i*16 + g)*68 + ks + t4;
            int r1i = r0i + 8*68;
            af[i][0] = __float_as_uint(Qs[r0i]);
            af[i][1] = __float_as_uint(Qs[r1i]);
            af[i][2] = __float_as_uint(Qs[r0i + 4]);
            af[i][3] = __float_as_uint(Qs[r1i + 4]);
        }
#pragma unroll
        for (int j = 0; j < 4; j++) {
            int cr = (wn*32 + j*8 + g)*68 + ks + t4;
            bf[j][0] = __float_as_uint(Ks[cr]);
            bf[j][1] = __float_as_uint(Ks[cr + 4]);
        }
#pragma unroll
        for (int i = 0; i < 4; i++)
#pragma unroll
            for (int j = 0; j < 4; j++) {
                asm volatile(
                    "mma.sync.aligned.m16n8k8.row.col.f32.tf32.tf32.f32 "
                    "{%0,%1,%2,%3}, {%4,%5,%6,%7}, {%8,%9}, {%0,%1,%2,%3};\n"
                    : "+f"(c[i][j][0]), "+f"(c[i][j][1]),
                      "+f"(c[i][j][2]), "+f"(c[i][j][3])
                    : "r"(af[i][0]), "r"(af[i][1]), "r"(af[i][2]), "r"(af[i][3]),
                      "r"(bf[j][0]), "r"(bf[j][1]));
            }
    }

    float pm[4][2];
#pragma unroll
    for (int i=0;i<4;i++)
#pragma unroll
        for (int h=0;h<2;h++) {
            float m = c[i][0][2*h];
#pragma unroll
            for (int j=0;j<4;j++) {
                m = fmaxf(m, c[i][j][2*h]);
                m = fmaxf(m, c[i][j][2*h+1]);
            }
#pragma unroll
            for (int off = 1; off <= 2; off <<= 1)
                m = fmaxf(m, __shfl_xor_sync(0xffffffffu, m, off));
            pm[i][h] = m;
        }
    if (t4 == 0) {
#pragma unroll
        for (int i=0;i<4;i++)
#pragma unroll
            for (int h=0;h<2;h++)
                redm[i*16 + g + h*8][wn] = pm[i][h];
    }
    __syncthreads();

    float psum[4][2];
#pragma unroll
    for (int i=0;i<4;i++)
#pragma unroll
        for (int h=0;h<2;h++) {
            int r = i*16 + g + h*8;
            float m = redm[r][0];
#pragma unroll
            for (int u=1;u<8;u++) m = fmaxf(m, redm[r][u]);
            float s = 0.f;
#pragma unroll
            for (int j=0;j<4;j++) {
                float p0 = __expf(c[i][j][2*h]   - m);
                float p1 = __expf(c[i][j][2*h+1] - m);
                c[i][j][2*h] = p0; c[i][j][2*h+1] = p1;
                s += p0 + p1;
            }
#pragma unroll
            for (int off = 1; off <= 2; off <<= 1)
                s += __shfl_xor_sync(0xffffffffu, s, off);
            psum[i][h] = s;
        }
    if (t4 == 0) {
#pragma unroll
        for (int i=0;i<4;i++)
#pragma unroll
            for (int h=0;h<2;h++)
                reds[i*16 + g + h*8][wn] = psum[i][h];
    }
    __syncthreads();

#pragma unroll
    for (int i=0;i<4;i++)
#pragma unroll
        for (int h=0;h<2;h++) {
            int r = i*16 + g + h*8;
            float ss = reds[r][0];
#pragma unroll
            for (int u=1;u<8;u++) ss += reds[r][u];
            float inv = 1.f / ss;
            float* orow = a2 + ((size_t)bh*256 + row0 + r) * 256;
#pragma unroll
            for (int j=0;j<4;j++) {
                int cc = wn*32 + j*8 + 2*t4;
                *(float2*)&orow[cc] = make_float2(c[i][j][2*h]*inv, c[i][j][2*h+1]*inv);
            }
        }
}

// ---------------------------------------------------------------------------
// Landmarks (merged q+k)
// ---------------------------------------------------------------------------
__global__ void landmark2_kernel(const float* __restrict__ q, const float* __restrict__ k,
                                 float* __restrict__ ql, float* __restrict__ kl) {
    int gidx = blockIdx.x * 256 + threadIdx.x;
    const float* src = (gidx < 524288) ? q : k;
    float* dst = (gidx < 524288) ? ql : kl;
    int idx = gidx & 524287;
    int dh = idx & 63;
    int mi = (idx >> 6) & 255;
    int bh = idx >> 14;
    const float* p = src + ((size_t)bh*4096 + mi*16)*64 + dh;
    float s = 0.f;
#pragma unroll
    for (int j = 0; j < 16; j++) s += p[j*64];
    dst[idx] = s * 0.0625f;
}

// ---------------------------------------------------------------------------
// pinv scalars. colsum split over 4 column-chunks -> grid (4,32) = 128 CTAs.
// ---------------------------------------------------------------------------
__global__ void red_init_kernel(float* g) { if (threadIdx.x < 2) g[threadIdx.x] = 0.f; }

__global__ void colsum_kernel(const float* __restrict__ a2, float* __restrict__ gred) {
    int bh = blockIdx.y;
    int j = blockIdx.x * 64 + threadIdx.x;
    const float* base = a2 + (size_t)bh*65536;
    float s = 0.f;
    for (int i = 0; i < 256; i++) s += fabsf(base[(size_t)i*256 + j]);
#pragma unroll
    for (int o = 16; o; o >>= 1) s = fmaxf(s, __shfl_xor_sync(0xffffffffu, s, o));
    __shared__ float red[2];
    if ((threadIdx.x & 31) == 0) red[threadIdx.x >> 5] = s;
    __syncthreads();
    if (threadIdx.x == 0)
        atomicMax((int*)&gred[1], __float_as_int(fmaxf(red[0], red[1])));
}

// zinit via 32x32 smem-tile transpose (coalesced both ways)
__global__ void zinit_kernel(const float* __restrict__ a2, const float* __restrict__ gred,
                             float* __restrict__ z) {
    __shared__ float tile[32][33];
    int bh = blockIdx.z;
    int i0 = blockIdx.x * 32, j0 = blockIdx.y * 32;
    const float* base = a2 + (size_t)bh * 65536;
    float* zb = z + (size_t)bh * 65536;
    int c = threadIdx.x, r0 = threadIdx.y;
#pragma unroll
    for (int rr = 0; rr < 4; rr++) {
        int r = r0*4 + rr;
        tile[r][c] = base[(size_t)(j0 + r)*256 + i0 + c];
    }
    __syncthreads();
    float inv = 1.f / gred[1];
#pragma unroll
    for (int rr = 0; rr < 4; rr++) {
        int r = r0*4 + rr;
        zb[(size_t)(i0 + r)*256 + j0 + c] = tile[c][r] * inv;
    }
}

// ---------------------------------------------------------------------------
// TF32 flash attention with optional split-K (used for flash-1, nk=4096)
// ---------------------------------------------------------------------------
#define QP 68
#define VP 72
#define OFF_KS   4352
#define OFF_PS   8704
#define OFF_VS   13056
#define OFF_ROWM 17664
#define OFF_ROWL 17728
#define OFF_REDM 17792
#define OFF_REDS 18048
#define SMEM_FLASH_TC ((18304)*4)

__global__ __launch_bounds__(256) void flash_tc_kernel(
        const float* __restrict__ Q, const float* __restrict__ K,
        const float* __restrict__ V, float* __restrict__ O, int nq, int nk,
        int chunk, float* __restrict__ mpart, float* __restrict__ lpart) {
    extern __shared__ float sm[];
    float (*Qs)[QP] = (float(*)[QP])sm;
    float (*Ks)[QP] = (float(*)[QP])(sm + OFF_KS);
    float (*Ps)[QP] = (float(*)[QP])(sm + OFF_PS);
    float (*Vs)[VP] = (float(*)[VP])(sm + OFF_VS);
    float* rowm = sm + OFF_ROWM;
    float* rowl = sm + OFF_ROWL;
    float (*redm)[4] = (float(*)[4])(sm + OFF_REDM);
    float (*reds)[4] = (float(*)[4])(sm + OFF_REDS);

    int tid = threadIdx.x;
    int lane = tid & 31, wid = tid >> 5;
    int wm = wid & 1, wn = wid >> 1;
    int g = lane >> 2, t4 = lane & 3;
    int bh = blockIdx.y;
    int q0 = blockIdx.x * 64;
    size_t koff = (size_t)blockIdx.z * chunk * 64;
    const float* Qb = Q + ((size_t)bh*nq + q0) * 64;
    const float* Kb = K + (size_t)bh*nk*64 + koff;
    const float* Vb = V + (size_t)bh*nk*64 + koff;

    {
        int r = tid >> 2, kc = (tid & 3) * 16;
#pragma unroll
        for (int ii = 0; ii < 4; ii++) {
            float4 qv = *(const float4*)&Qb[(size_t)r*64 + kc + ii*4];
            Qs[r][kc+ii*4+0]=f2tf(qv.x); Qs[r][kc+ii*4+1]=f2tf(qv.y);
            Qs[r][kc+ii*4+2]=f2tf(qv.z); Qs[r][kc+ii*4+3]=f2tf(qv.w);
        }
    }
    if (tid < 64) { rowm[tid] = -1e30f; rowl[tid] = 0.f; }
    float o[2][2][4];
#pragma unroll
    for (int i=0;i<2;i++)
#pragma unroll
        for (int j=0;j<2;j++)
#pragma unroll
            for (int h=0;h<4;h++) o[i][j][h]=0.f;
    __syncthreads();

    for (int c0 = 0; c0 < chunk; c0 += 64) {
        {
            int r = tid >> 2, kc = (tid & 3) * 16;
#pragma unroll
            for (int ii = 0; ii < 4; ii++) {
                float4 kv = *(const float4*)&Kb[(size_t)(c0+r)*64 + kc + ii*4];
                Ks[r][kc+ii*4+0]=f2tf(kv.x); Ks[r][kc+ii*4+1]=f2tf(kv.y);
                Ks[r][kc+ii*4+2]=f2tf(kv.z); Ks[r][kc+ii*4+3]=f2tf(kv.w);
                float4 vv = *(const float4*)&Vb[(size_t)(c0+r)*64 + kc + ii*4];
                Vs[r][kc+ii*4+0]=f2tf(vv.x); Vs[r][kc+ii*4+1]=f2tf(vv.y);
                Vs[r][kc+ii*4+2]=f2tf(vv.z); Vs[r][kc+ii*4+3]=f2tf(vv.w);
            }
        }
        __syncthreads();

        float s[2][2][4];
#pragma unroll
        for (int i=0;i<2;i++)
#pragma unroll
            for (int j=0;j<2;j++)
#pragma unroll
                for (int h=0;h<4;h++) s[i][j][h]=0.f;
#pragma unroll
        for (int ks = 0; ks < 64; ks += 8) {
            uint32_t af[2][4], bf[2][2];
#pragma unroll
            for (int i = 0; i < 2; i++) {
                int r = wm*32 + i*16 + g;
                af[i][0] = __float_as_uint(Qs[r][ks+t4]);
                af[i][1] = __float_as_uint(Qs[r+8][ks+t4]);
                af[i][2] = __float_as_uint(Qs[r][ks+t4+4]);
                af[i][3] = __float_as_uint(Qs[r+8][ks+t4+4]);
            }
#pragma unroll
            for (int j = 0; j < 2; j++) {
                int cc = wn*16 + j*8 + g;
                bf[j][0] = __float_as_uint(Ks[cc][ks+t4]);
                bf[j][1] = __float_as_uint(Ks[cc][ks+t4+4]);
            }
#pragma unroll
            for (int i = 0; i < 2; i++)
#pragma unroll
                for (int j = 0; j < 2; j++) {
                    asm volatile(
                        "mma.sync.aligned.m16n8k8.row.col.f32.tf32.tf32.f32 "
                        "{%0,%1,%2,%3}, {%4,%5,%6,%7}, {%8,%9}, {%0,%1,%2,%3};\n"
                        : "+f"(s[i][j][0]), "+f"(s[i][j][1]),
                          "+f"(s[i][j][2]), "+f"(s[i][j][3])
                        : "r"(af[i][0]), "r"(af[i][1]), "r"(af[i][2]), "r"(af[i][3]),
                          "r"(bf[j][0]), "r"(bf[j][1]));
                }
        }

        float pm[2][2];
#pragma unroll
        for (int i=0;i<2;i++)
#pragma unroll
            for (int h=0;h<2;h++)
                pm[i][h] = fmaxf(fmaxf(s[i][0][2*h], s[i][0][2*h+1]),
                                 fmaxf(s[i][1][2*h], s[i][1][2*h+1]));
#pragma unroll
        for (int off = 1; off <= 2; off <<= 1) {
#pragma unroll
            for (int i=0;i<2;i++)
#pragma unroll
                for (int h=0;h<2;h++)
                    pm[i][h] = fmaxf(pm[i][h], __shfl_xor_sync(0xffffffffu, pm[i][h], off));
        }
        if (t4 == 0) {
#pragma unroll
            for (int i=0;i<2;i++)
#pragma unroll
                for (int h=0;h<2;h++)
                    redm[wm*32 + i*16 + g + h*8][wn] = pm[i][h];
        }
        __syncthreads();

        float mnew[2][2], scale[2][2];
#pragma unroll
        for (int i=0;i<2;i++)
#pragma unroll
            for (int h=0;h<2;h++) {
                int r = wm*32 + i*16 + g + h*8;
                float m = fmaxf(fmaxf(redm[r][0], redm[r][1]),
                                fmaxf(redm[r][2], redm[r][3]));
                float mo = rowm[r];
                mnew[i][h] = fmaxf(mo, m);
                scale[i][h] = __expf(mo - mnew[i][h]);
            }

        float psum[2][2] = {{0.f,0.f},{0.f,0.f}};
#pragma unroll
        for (int i=0;i<2;i++)
#pragma unroll
            for (int j=0;j<2;j++)
#pragma unroll
                for (int h=0;h<2;h++) {
                    int r = wm*32 + i*16 + g + h*8;
                    float p0 = __expf(s[i][j][2*h]   - mnew[i][h]);
                    float p1 = __expf(s[i][j][2*h+1] - mnew[i][h]);
                    *(float2*)&Ps[r][wn*16 + j*8 + 2*t4] = make_float2(f2tf(p0), f2tf(p1));
                    psum[i][h] += p0 + p1;
                    o[i][j][2*h]   *= scale[i][h];
                    o[i][j][2*h+1] *= scale[i][h];
                }
#pragma unroll
        for (int off = 1; off <= 2; off <<= 1) {
#pragma unroll
            for (int i=0;i<2;i++)
#pragma unroll
                for (int h=0;h<2;h++)
                    psum[i][h] += __shfl_xor_sync(0xffffffffu, psum[i][h], off);
        }
        if (t4 == 0) {
#pragma unroll
            for (int i=0;i<2;i++)
#pragma unroll
                for (int h=0;h<2;h++)
                    reds[wm*32 + i*16 + g + h*8][wn] = psum[i][h];
        }
        __syncthreads();

        if (wn == 0 && t4 == 0) {
#pragma unroll
            for (int i=0;i<2;i++)
#pragma unroll
                for (int h=0;h<2;h++) {
                    int r = wm*32 + i*16 + g + h*8;
                    float ps = reds[r][0] + reds[r][1] + reds[r][2] + reds[r][3];
                    rowl[r] = rowl[r]*scale[i][h] + ps;
                    rowm[r] = mnew[i][h];
                }
        }

#pragma unroll
        for (int ks = 0; ks < 64; ks += 8) {
            uint32_t af[2][4], bf[2][2];
#pragma unroll
            for (int i = 0; i < 2; i++) {
                int r = wm*32 + i*16 + g;
                af[i][0] = __float_as_uint(Ps[r][ks+t4]);
                af[i][1] = __float_as_uint(Ps[r+8][ks+t4]);
                af[i][2] = __float_as_uint(Ps[r][ks+t4+4]);
                af[i][3] = __float_as_uint(Ps[r+8][ks+t4+4]);
            }
#pragma unroll
            for (int j = 0; j < 2; j++) {
                int cc = wn*16 + j*8 + g;
                bf[j][0] = __float_as_uint(Vs[ks+t4][cc]);
                bf[j][1] = __float_as_uint(Vs[ks+t4+4][cc]);
            }
#pragma unroll
            for (int i = 0; i < 2; i++)
#pragma unroll
                for (int j = 0; j < 2; j++) {
                    asm volatile(
                        "mma.sync.aligned.m16n8k8.row.col.f32.tf32.tf32.f32 "
                        "{%0,%1,%2,%3}, {%4,%5,%6,%7}, {%8,%9}, {%0,%1,%2,%3};\n"
                        : "+f"(o[i][j][0]), "+f"(o[i][j][1]),
                          "+f"(o[i][j][2]), "+f"(o[i][j][3])
                        : "r"(af[i][0]), "r"(af[i][1]), "r"(af[i][2]), "r"(af[i][3]),
                          "r"(bf[j][0]), "r"(bf[j][1]));
                }
        }
        __syncthreads();
    }

    if (lpart != nullptr) {
        float* Ob = O + ((size_t)(blockIdx.z*32 + bh)*nq + q0) * 64;
#pragma unroll
        for (int i=0;i<2;i++)
#pragma unroll
            for (int j=0;j<2;j++)
#pragma unroll
                for (int h=0;h<2;h++) {
                    int r = wm*32 + i*16 + g + h*8;
                    int cc = wn*16 + j*8 + 2*t4;
                    *(float2*)&Ob[(size_t)r*64 + cc] =
                        make_float2(o[i][j][2*h], o[i][j][2*h+1]);
                }
        if (tid < 64) {
            size_t ri = (size_t)(blockIdx.z*32 + bh)*nq + q0 + tid;
            mpart[ri] = rowm[tid];
            lpart[ri] = rowl[tid];
        }
    } else {
        float* Ob = O + ((size_t)bh*nq + q0) * 64;
#pragma unroll
        for (int i=0;i<2;i++)
#pragma unroll
            for (int j=0;j<2;j++)
#pragma unroll
                for (int h=0;h<2;h++) {
                    int r = wm*32 + i*16 + g + h*8;
                    int cc = wn*16 + j*8 + 2*t4;
                    float inv = 1.f / rowl[r];
                    *(float2*)&Ob[(size_t)r*64 + cc] =
                        make_float2(o[i][j][2*h]*inv, o[i][j][2*h+1]*inv);
                }
    }
}

// ---------------------------------------------------------------------------
// Single-pass flash for flash-2 (nk == 256) with FUSED depthwise conv +
// layout transform. Eliminates the attn intermediate (128 MB round-trip) and
// the standalone conv kernel. Epilogue stages O through Ps, then applies the
// 33-tap conv with the conflict-free (row, dh) thread mapping and writes
// attn2[b][n][512] directly.
// Extra smem: vt[96][64] halo tile of v + wk[33+pad] weights.
// ---------------------------------------------------------------------------
#define OFF_VT   18304
#define OFF_WK   (18304 + 96*64)
#define SMEM_FLASH2 ((OFF_WK + 36)*4)

__global__ __launch_bounds__(256) void flash2_conv_kernel(
        const float* __restrict__ Q, const float* __restrict__ K,
        const float* __restrict__ V, const float* __restrict__ vfull,
        const float* __restrict__ cw, float* __restrict__ attn2) {
    extern __shared__ float sm[];
    float (*Qs)[QP] = (float(*)[QP])sm;
    float (*Ks)[QP] = (float(*)[QP])(sm + OFF_KS);
    float (*Ps)[QP] = (float(*)[QP])(sm + OFF_PS);
    float (*Vs)[VP] = (float(*)[VP])(sm + OFF_VS);
    float (*redm)[4] = (float(*)[4])(sm + OFF_REDM);
    float (*reds)[4] = (float(*)[4])(sm + OFF_REDS);
    float (*vt)[64] = (float(*)[64])(sm + OFF_VT);
    float* wk = sm + OFF_WK;

    int tid = threadIdx.x;
    int lane = tid & 31, wid = tid >> 5;
    int wm = wid & 1, wn = wid >> 1;
    int g = lane >> 2, t4 = lane & 3;
    int bh = blockIdx.y;
    int hh = bh & 7, b4 = bh >> 3;
    int q0 = blockIdx.x * 64;
    const float* Qb = Q + ((size_t)bh*4096 + q0) * 64;
    const float* Kb = K + (size_t)bh*256*64;
    const float* Vb = V + (size_t)bh*256*64;
    const float* vfb = vfull + (size_t)bh*4096*64;

    int lr = tid >> 2, lk = (tid & 3) * 16;
    {
#pragma unroll
        for (int ii = 0; ii < 4; ii++) {
            float4 qv = *(const float4*)&Qb[(size_t)lr*64 + lk + ii*4];
            Qs[lr][lk+ii*4+0]=f2tf(qv.x); Qs[lr][lk+ii*4+1]=f2tf(qv.y);
            Qs[lr][lk+ii*4+2]=f2tf(qv.z); Qs[lr][lk+ii*4+3]=f2tf(qv.w);
        }
    }
    // stage conv v halo tile (96 rows x 64) + weights (independent of attention)
#pragma unroll
    for (int i = 0; i < 6; i++) {
        int f = tid + i*256;
        int r = f >> 4;
        int c4 = (f & 15) * 4;
        int gr = q0 - 16 + r;
        float4 val = make_float4(0.f,0.f,0.f,0.f);
        if (gr >= 0 && gr < 4096) val = *(const float4*)&vfb[(size_t)gr*64 + c4];
        *(float4*)&vt[r][c4] = val;
    }
    if (tid < 33) wk[tid] = cw[hh*33 + tid];

    float s[4][2][2][4];
    float o[2][2][4];
#pragma unroll
    for (int i=0;i<2;i++)
#pragma unroll
        for (int j=0;j<2;j++)
#pragma unroll
            for (int h=0;h<4;h++) o[i][j][h]=0.f;

#pragma unroll
    for (int t = 0; t < 4; t++) {
        {
#pragma unroll
            for (int ii = 0; ii < 4; ii++) {
                float4 kv = *(const float4*)&Kb[(size_t)(t*64+lr)*64 + lk + ii*4];
                Ks[lr][lk+ii*4+0]=f2tf(kv.x); Ks[lr][lk+ii*4+1]=f2tf(kv.y);
                Ks[lr][lk+ii*4+2]=f2tf(kv.z); Ks[lr][lk+ii*4+3]=f2tf(kv.w);
            }
        }
        __syncthreads();
#pragma unroll
        for (int i=0;i<2;i++)
#pragma unroll
            for (int j=0;j<2;j++)
#pragma unroll
                for (int h=0;h<4;h++) s[t][i][j][h]=0.f;
#pragma unroll
        for (int ks = 0; ks < 64; ks += 8) {
            uint32_t af[2][4], bf[2][2];
#pragma unroll
            for (int i = 0; i < 2; i++) {
                int r = wm*32 + i*16 + g;
                af[i][0] = __float_as_uint(Qs[r][ks+t4]);
                af[i][1] = __float_as_uint(Qs[r+8][ks+t4]);
                af[i][2] = __float_as_uint(Qs[r][ks+t4+4]);
                af[i][3] = __float_as_uint(Qs[r+8][ks+t4+4]);
            }
#pragma unroll
            for (int j = 0; j < 2; j++) {
                int cc = wn*16 + j*8 + g;
                bf[j][0] = __float_as_uint(Ks[cc][ks+t4]);
                bf[j][1] = __float_as_uint(Ks[cc][ks+t4+4]);
            }
#pragma unroll
            for (int i = 0; i < 2; i++)
#pragma unroll
                for (int j = 0; j < 2; j++) {
                    asm volatile(
                        "mma.sync.aligned.m16n8k8.row.col.f32.tf32.tf32.f32 "
                        "{%0,%1,%2,%3}, {%4,%5,%6,%7}, {%8,%9}, {%0,%1,%2,%3};\n"
                        : "+f"(s[t][i][j][0]), "+f"(s[t][i][j][1]),
                          "+f"(s[t][i][j][2]), "+f"(s[t][i][j][3])
                        : "r"(af[i][0]), "r"(af[i][1]), "r"(af[i][2]), "r"(af[i][3]),
                          "r"(bf[j][0]), "r"(bf[j][1]));
                }
        }
        __syncthreads();
    }

    float pm[2][2];
#pragma unroll
    for (int i=0;i<2;i++)
#pragma unroll
        for (int h=0;h<2;h++) {
            float m = s[0][i][0][2*h];
#pragma unroll
            for (int t=0;t<4;t++)
#pragma unroll
                for (int j=0;j<2;j++) {
                    m = fmaxf(m, s[t][i][j][2*h]);
                    m = fmaxf(m, s[t][i][j][2*h+1]);
                }
#pragma unroll
            for (int off = 1; off <= 2; off <<= 1)
                m = fmaxf(m, __shfl_xor_sync(0xffffffffu, m, off));
            pm[i][h] = m;
        }
    if (t4 == 0) {
#pragma unroll
        for (int i=0;i<2;i++)
#pragma unroll
            for (int h=0;h<2;h++)
                redm[wm*32 + i*16 + g + h*8][wn] = pm[i][h];
    }
    __syncthreads();

    float linv[2][2];
    {
        float psum[2][2];
#pragma unroll
        for (int i=0;i<2;i++)
#pragma unroll
            for (int h=0;h<2;h++) {
                int r = wm*32 + i*16 + g + h*8;
                float m = fmaxf(fmaxf(redm[r][0], redm[r][1]),
                                fmaxf(redm[r][2], redm[r][3]));
                float ps = 0.f;
#pragma unroll
                for (int t=0;t<4;t++)
#pragma unroll
                    for (int j=0;j<2;j++) {
                        float p0 = __expf(s[t][i][j][2*h]   - m);
                        float p1 = __expf(s[t][i][j][2*h+1] - m);
                        s[t][i][j][2*h] = p0; s[t][i][j][2*h+1] = p1;
                        ps += p0 + p1;
                    }
#pragma unroll
                for (int off = 1; off <= 2; off <<= 1)
                    ps += __shfl_xor_sync(0xffffffffu, ps, off);
                psum[i][h] = ps;
            }
        if (t4 == 0) {
#pragma unroll
            for (int i=0;i<2;i++)
#pragma unroll
                for (int h=0;h<2;h++)
                    reds[wm*32 + i*16 + g + h*8][wn] = psum[i][h];
        }
        __syncthreads();
#pragma unroll
        for (int i=0;i<2;i++)
#pragma unroll
            for (int h=0;h<2;h++) {
                int r = wm*32 + i*16 + g + h*8;
                linv[i][h] = 1.f / (reds[r][0]+reds[r][1]+reds[r][2]+reds[r][3]);
            }
    }

#pragma unroll
    for (int t = 0; t < 4; t++) {
#pragma unroll
        for (int i=0;i<2;i++)
#pragma unroll
            for (int j=0;j<2;j++)
#pragma unroll
                for (int h=0;h<2;h++) {
                    int r = wm*32 + i*16 + g + h*8;
                    *(float2*)&Ps[r][wn*16 + j*8 + 2*t4] =
                        make_float2(f2tf(s[t][i][j][2*h]), f2tf(s[t][i][j][2*h+1]));
                }
        {
#pragma unroll
            for (int ii = 0; ii < 4; ii++) {
                float4 vv = *(const float4*)&Vb[(size_t)(t*64+lr)*64 + lk + ii*4];
                Vs[lr][lk+ii*4+0]=f2tf(vv.x); Vs[lr][lk+ii*4+1]=f2tf(vv.y);
                Vs[lr][lk+ii*4+2]=f2tf(vv.z); Vs[lr][lk+ii*4+3]=f2tf(vv.w);
            }
        }
        __syncthreads();
#pragma unroll
        for (int ks = 0; ks < 64; ks += 8) {
            uint32_t af[2][4], bf[2][2];
#pragma unroll
            for (int i = 0; i < 2; i++) {
                int r = wm*32 + i*16 + g;
                af[i][0] = __float_as_uint(Ps[r][ks+t4]);
                af[i][1] = __float_as_uint(Ps[r+8][ks+t4]);
                af[i][2] = __float_as_uint(Ps[r][ks+t4+4]);
                af[i][3] = __float_as_uint(Ps[r+8][ks+t4+4]);
            }
#pragma unroll
            for (int j = 0; j < 2; j++) {
                int cc = wn*16 + j*8 + g;
                bf[j][0] = __float_as_uint(Vs[ks+t4][cc]);
                bf[j][1] = __float_as_uint(Vs[ks+t4+4][cc]);
            }
#pragma unroll
            for (int i = 0; i < 2; i++)
#pragma unroll
                for (int j = 0; j < 2; j++) {
                    asm volatile(
                        "mma.sync.aligned.m16n8k8.row.col.f32.tf32.tf32.f32 "
                        "{%0,%1,%2,%3}, {%4,%5,%6,%7}, {%8,%9}, {%0,%1,%2,%3};\n"
                        : "+f"(o[i][j][0]), "+f"(o[i][j][1]),
                          "+f"(o[i][j][2]), "+f"(o[i][j][3])
                        : "r"(af[i][0]), "r"(af[i][1]), "r"(af[i][2]), "r"(af[i][3]),
                          "r"(bf[j][0]), "r"(bf[j][1]));
                }
        }
        __syncthreads();
    }

    // stage O/l into Ps, then conv with conflict-free (row, dh) mapping
#pragma unroll
    for (int i=0;i<2;i++)
#pragma unroll
        for (int j=0;j<2;j++)
#pragma unroll
            for (int h=0;h<2;h++) {
                int r = wm*32 + i*16 + g + h*8;
                int cc = wn*16 + j*8 + 2*t4;
                *(float2*)&Ps[r][cc] =
                    make_float2(o[i][j][2*h]*linv[i][h], o[i][j][2*h+1]*linv[i][h]);
            }
    __syncthreads();

    {
        int dh = tid & 63;
        int rr0 = tid >> 6;
#pragma unroll
        for (int qq = 0; qq < 16; qq++) {
            int lrow = rr0 + qq*4;
            float acc = Ps[lrow][dh];
#pragma unroll
            for (int ss = 0; ss < 33; ss++) acc += wk[ss]*vt[lrow+ss][dh];
            attn2[((size_t)(b4*4096 + q0 + lrow))*512 + hh*64 + dh] = acc;
        }
    }
}

// ---------------------------------------------------------------------------
// Split-K combine
// ---------------------------------------------------------------------------
__global__ void combine_kernel(const float* __restrict__ Op,
                               const float* __restrict__ mp,
                               const float* __restrict__ lp,
                               float* __restrict__ w) {
    int row = blockIdx.x;
    int c = threadIdx.x;
    int bh = row >> 8, qr = row & 255;
    float m0 = mp[(0*32+bh)*256+qr], m1 = mp[(1*32+bh)*256+qr];
    float m2 = mp[(2*32+bh)*256+qr], m3 = mp[(3*32+bh)*256+qr];
    float ms = fmaxf(fmaxf(m0,m1), fmaxf(m2,m3));
    float w0 = __expf(m0-ms), w1 = __expf(m1-ms), w2 = __expf(m2-ms), w3 = __expf(m3-ms);
    float l = w0*lp[(0*32+bh)*256+qr] + w1*lp[(1*32+bh)*256+qr]
            + w2*lp[(2*32+bh)*256+qr] + w3*lp[(3*32+bh)*256+qr];
    float acc = w0*Op[((size_t)(0*32+bh)*256+qr)*64 + c]
              + w1*Op[((size_t)(1*32+bh)*256+qr)*64 + c]
              + w2*Op[((size_t)(2*32+bh)*256+qr)*64 + c]
              + w3*Op[((size_t)(3*32+bh)*256+qr)*64 + c];
    w[((size_t)bh*256+qr)*64 + c] = acc / l;
}

// ---------------------------------------------------------------------------
// Host orchestration
// ---------------------------------------------------------------------------
extern "C" void kernel_launch(void* const* d_in, const int* in_sizes, int n_in,
                              void* d_out, int out_size) {
    const float* x      = (const float*)d_in[0];
    const float* norm_w = (const float*)d_in[1];
    const float* norm_b = (const float*)d_in[2];
    const float* Wqkv   = (const float*)d_in[3];
    const float* Wout   = (const float*)d_in[4];
    const float* bout   = (const float*)d_in[5];
    const float* conv_w = (const float*)d_in[6];
    float* out = (float*)d_out;

    float *xn,*q,*k,*v,*ql,*kl,*a2,*z0,*t1,*t2,*t3,*w,*w2,*uu,*r3,*u5,*attn2,*red;
    float *w4s[5];
    cudaGetSymbolAddress((void**)&xn,   g_xn);
    cudaGetSymbolAddress((void**)&q,    g_q);
    cudaGetSymbolAddress((void**)&k,    g_k);
    cudaGetSymbolAddress((void**)&v,    g_v);
    cudaGetSymbolAddress((void**)&ql,   g_ql);
    cudaGetSymbolAddress((void**)&kl,   g_kl);
    cudaGetSymbolAddress((void**)&a2,   g_a2);
    cudaGetSymbolAddress((void**)&z0,   g_z0);
    cudaGetSymbolAddress((void**)&t1,   g_t1);
    cudaGetSymbolAddress((void**)&t2,   g_t2);
    cudaGetSymbolAddress((void**)&t3,   g_t3);
    cudaGetSymbolAddress((void**)&w4s[0], g_w40);
    cudaGetSymbolAddress((void**)&w4s[1], g_w41);
    cudaGetSymbolAddress((void**)&w4s[2], g_w42);
    cudaGetSymbolAddress((void**)&w4s[3], g_w43);
    cudaGetSymbolAddress((void**)&w4s[4], g_w44);
    cudaGetSymbolAddress((void**)&w,    g_w);
    cudaGetSymbolAddress((void**)&w2,   g_w2);
    cudaGetSymbolAddress((void**)&uu,   g_u);
    cudaGetSymbolAddress((void**)&r3,   g_r3);
    cudaGetSymbolAddress((void**)&u5,   g_u5);
    cudaGetSymbolAddress((void**)&attn2,g_attn2);
    cudaGetSymbolAddress((void**)&red,  g_red);

    cudaFuncSetAttribute(flash_tc_kernel, cudaFuncAttributeMaxDynamicSharedMemorySize, SMEM_FLASH_TC);
    cudaFuncSetAttribute(flash2_conv_kernel, cudaFuncAttributeMaxDynamicSharedMemorySize, SMEM_FLASH2);
    cudaFuncSetAttribute(a2_tc_kernel, cudaFuncAttributeMaxDynamicSharedMemorySize, SMEM_A2);

    // 1. LayerNorm
    ln_kernel<<<16384, 128>>>(x, norm_w, norm_b, xn);
    // 2. QKV projection (tf32 MMA, fused scatter + q scale)
    mma_gemm<0,512,1536,512><<<dim3(12,128), 256>>>(
        xn, Wqkv, q, k, v, nullptr, nullptr);
    // 3. landmarks (merged)
    landmark2_kernel<<<4096, 256>>>(q, k, ql, kl);
    // 4. a2 = softmax(q_l k_l^T) (tf32 MMA, 64-row tiles -> 128 CTAs)
    a2_tc_kernel<<<dim3(4,32), 256, SMEM_A2>>>(ql, kl, a2);
    // 5. pinv init scalar (split colsum) + z0 = s*a2^T (smem transpose)
    red_init_kernel<<<1, 32>>>(red);
    colsum_kernel<<<dim3(4,32), 64>>>(a2, red);
    zinit_kernel<<<dim3(8,8,32), dim3(32,8)>>>(a2, red, z0);
    // 6. w = softmax(q_l k^T) @ v — split-K x4 flash + combine
    flash_tc_kernel<<<dim3(4,32,4), 256, SMEM_FLASH_TC>>>(
        ql, k, v, t1, 256, 4096, 1024, t2, t2 + 32768);
    combine_kernel<<<8192, 64>>>(t1, t2, t2 + 32768, w);
    // 7. Newton-Schulz pinv, Y-only recurrence, 128x128 tiles (proven):
    //    W2 = Y(7I-Y); W4_i = Y(15I-W2); Y' = 0.25*Y(13I-W4_i)   [it=0..4]
    mma_gemm_pinv<<<dim3(2,2,32), 256>>>(a2, z0, t1, 0.f, 1.f);   // Y0 = a2 @ z0
    float* Y = t1; float* Yn = t3;
    for (int it = 0; it < 5; it++) {
        mma_gemm_pinv<<<dim3(2,2,32), 256>>>(Y, Y, t2, 7.f, -1.f);        // W2
        mma_gemm_pinv<<<dim3(2,2,32), 256>>>(Y, t2, w4s[it], 15.f, -1.f); // W4_i
        mma_gemm_pinv<<<dim3(2,2,32), 256>>>(Y, w4s[it], Yn, 3.25f, -0.25f);
        float* tmp = Y; Y = Yn; Yn = tmp;
    }
    // Y == Y5. Narrow last iteration: u5 = 13w - 15 Y5w + 7 Y5^2w - Y5^3w
    mma_nar_kernel<<<dim3(1,2,32), 256>>>(Y, w,  uu, 0.f, 1.f);   // r1
    mma_nar_kernel<<<dim3(1,2,32), 256>>>(Y, uu, w2, 0.f, 1.f);   // r2
    mma_nar_kernel<<<dim3(1,2,32), 256>>>(Y, w2, r3, 0.f, 1.f);   // r3
    comb4_kernel<<<2048, 256>>>(w, uu, w2, r3, u5);
    // 8. narrow chain down: u_i = 13*u_{i+1} - W4_i @ u_{i+1}
    mma_nar_kernel<<<dim3(1,2,32), 256>>>(w4s[4], u5, uu, 13.f, -1.f);
    mma_nar_kernel<<<dim3(1,2,32), 256>>>(w4s[3], uu, w2, 13.f, -1.f);
    mma_nar_kernel<<<dim3(1,2,32), 256>>>(w4s[2], w2, uu, 13.f, -1.f);
    mma_nar_kernel<<<dim3(1,2,32), 256>>>(w4s[1], uu, w2, 13.f, -1.f);
    mma_nar_kernel<<<dim3(1,2,32), 256>>>(w4s[0], w2, uu, 13.f, -1.f);
    mma_nar_kernel<<<dim3(1,2,32), 256>>>(z0, uu, w2, 0.f, 1.f/4096.f);
    // 9+10. attn = softmax(q k_l^T) @ w2 with FUSED conv residual + layout
    flash2_conv_kernel<<<dim3(64,32), 256, SMEM_FLASH2>>>(
        q, kl, w2, v, conv_w, attn2);
    // 11. output projection + bias + input residual (tf32 MMA)
    mma_gemm<1,512,512,512><<<dim3(4,128), 256>>>(
        attn2, Wout, out, nullptr, nullptr, bout, x);
}

// round 17
// speedup vs baseline: 1.0930x; 1.0259x over previous
#include <cuda_runtime.h>
#include <cuda_bf16.h>
#include <cstdint>

// ---------------------------------------------------------------------------
// Problem constants: b=4, n=4096, D=512, H=8, dh=64, M=256, l=16, 6 iters,
// conv k=33, eps=1e-5
// ---------------------------------------------------------------------------
#define NB   (4*4096*512)
#define MM   (32*256*256)
#define MD   (32*256*64)

__device__ float g_xn[NB];
__device__ float g_q[NB];
__device__ float g_k[NB];
__device__ float g_v[NB];
__device__ float g_ql[MD];
__device__ float g_kl[MD];
__device__ float g_a2[MM];
__device__ float g_z0[MM];
__device__ float g_t1[MM];   // Y ping / flash1 split-K O partials
__device__ float g_t2[MM];   // W2 scratch / flash1 split-K m/l partials
__device__ float g_t3[MM];   // Y pong
__device__ float g_w40[MM];
__device__ float g_w41[MM];
__device__ float g_w42[MM];
__device__ float g_w43[MM];
__device__ float g_w44[MM];
__device__ float g_w[MD];
__device__ float g_w2[MD];
__device__ float g_u[MD];
__device__ float g_u5[MD];
__device__ float g_attn2[NB];
__device__ float g_red[2];

__device__ __forceinline__ float f2tf(float x) {
    uint32_t u;
    asm("cvt.rna.tf32.f32 %0, %1;" : "=r"(u) : "f"(x));
    return __uint_as_float(u);
}

// ---------------------------------------------------------------------------
// LayerNorm
// ---------------------------------------------------------------------------
__global__ void ln_kernel(const float* __restrict__ x, const float* __restrict__ w,
                          const float* __restrict__ bb, float* __restrict__ out) {
    int row = blockIdx.x;
    const float* xr = x + (size_t)row * 512;
    float* orow = out + (size_t)row * 512;
    int t = threadIdx.x;
    float v[4];
    float s = 0.f;
#pragma unroll
    for (int i = 0; i < 4; i++) { v[i] = xr[t + 128*i]; s += v[i]; }
#pragma unroll
    for (int o = 16; o; o >>= 1) s += __shfl_xor_sync(0xffffffffu, s, o);
    __shared__ float red[4];
    if ((t & 31) == 0) red[t >> 5] = s;
    __syncthreads();
    float mean = (red[0]+red[1]+red[2]+red[3]) * (1.f/512.f);
    float vs = 0.f;
#pragma unroll
    for (int i = 0; i < 4; i++) { float d = v[i]-mean; vs += d*d; }
#pragma unroll
    for (int o = 16; o; o >>= 1) vs += __shfl_xor_sync(0xffffffffu, vs, o);
    __syncthreads();
    if ((t & 31) == 0) red[t >> 5] = vs;
    __syncthreads();
    float var = (red[0]+red[1]+red[2]+red[3]) * (1.f/512.f);
    float rstd = rsqrtf(var + 1e-5f);
#pragma unroll
    for (int i = 0; i < 4; i++) {
        int c = t + 128*i;
        orow[c] = (v[i]-mean)*rstd*w[c] + bb[c];
    }
}

// ---------------------------------------------------------------------------
// TF32 GEMM (proven): block 128x128, BK=16, 8 warps 64x32, occ 2.
// EPI 0: QKV scatter. EPI 1: bias + residual.
// ---------------------------------------------------------------------------
template<int EPI, int LDA, int LDB, int KD>
__global__ __launch_bounds__(256, 2) void mma_gemm(
        const float* __restrict__ A, const float* __restrict__ B,
        float* __restrict__ C0, float* __restrict__ C1, float* __restrict__ C2,
        const float* __restrict__ e0, const float* __restrict__ e1) {
    __shared__ float Asm[2][128*20];
    __shared__ float Bsm[2][16*136];
    int tid = threadIdx.x;
    int lane = tid & 31, wid = tid >> 5;
    int wm = wid & 1, wn = wid >> 1;
    int g = lane >> 2, t4 = lane & 3;
    int row0 = blockIdx.y * 128, col0 = blockIdx.x * 128;
    int arow = tid >> 1, akq = (tid & 1) * 8;
    int bkr = tid >> 4, bnc = (tid & 15) * 8;

    {
        const float* ap = A + (size_t)(row0 + arow) * LDA + akq;
        float4 a0 = *(const float4*)ap;
        float4 a1 = *(const float4*)(ap + 4);
        float* as = &Asm[0][arow*20 + akq];
        as[0]=f2tf(a0.x); as[1]=f2tf(a0.y); as[2]=f2tf(a0.z); as[3]=f2tf(a0.w);
        as[4]=f2tf(a1.x); as[5]=f2tf(a1.y); as[6]=f2tf(a1.z); as[7]=f2tf(a1.w);
        const float* bp = B + (size_t)bkr * LDB + col0 + bnc;
        float4 b0 = *(const float4*)bp;
        float4 b1 = *(const float4*)(bp + 4);
        float* bs = &Bsm[0][bkr*136 + bnc];
        bs[0]=f2tf(b0.x); bs[1]=f2tf(b0.y); bs[2]=f2tf(b0.z); bs[3]=f2tf(b0.w);
        bs[4]=f2tf(b1.x); bs[5]=f2tf(b1.y); bs[6]=f2tf(b1.z); bs[7]=f2tf(b1.w);
    }
    __syncthreads();

    float c[4][4][4];
#pragma unroll
    for (int i=0;i<4;i++)
#pragma unroll
        for (int j=0;j<4;j++)
#pragma unroll
            for (int h=0;h<4;h++) c[i][j][h]=0.f;

    const int NIT = KD / 16;
    for (int it = 0; it < NIT; it++) {
        int buf = it & 1;
        float4 pa0, pa1, pb0, pb1;
        if (it + 1 < NIT) {
            int k0 = (it + 1) * 16;
            const float* ap = A + (size_t)(row0 + arow) * LDA + k0 + akq;
            pa0 = *(const float4*)ap;
            pa1 = *(const float4*)(ap + 4);
            const float* bp = B + (size_t)(k0 + bkr) * LDB + col0 + bnc;
            pb0 = *(const float4*)bp;
            pb1 = *(const float4*)(bp + 4);
        }
#pragma unroll
        for (int ks = 0; ks < 16; ks += 8) {
            uint32_t af[4][4], bf[4][2];
#pragma unroll
            for (int i = 0; i < 4; i++) {
                int r0i = (wm*64 + i*16 + g) * 20 + ks + t4;
                int r1i = r0i + 8*20;
                af[i][0] = __float_as_uint(Asm[buf][r0i]);
                af[i][1] = __float_as_uint(Asm[buf][r1i]);
                af[i][2] = __float_as_uint(Asm[buf][r0i + 4]);
                af[i][3] = __float_as_uint(Asm[buf][r1i + 4]);
            }
#pragma unroll
            for (int j = 0; j < 4; j++) {
                int nc2 = wn*32 + j*8 + g;
                bf[j][0] = __float_as_uint(Bsm[buf][(ks + t4)*136 + nc2]);
                bf[j][1] = __float_as_uint(Bsm[buf][(ks + t4 + 4)*136 + nc2]);
            }
#pragma unroll
            for (int i = 0; i < 4; i++)
#pragma unroll
                for (int j = 0; j < 4; j++) {
                    asm volatile(
                        "mma.sync.aligned.m16n8k8.row.col.f32.tf32.tf32.f32 "
                        "{%0,%1,%2,%3}, {%4,%5,%6,%7}, {%8,%9}, {%0,%1,%2,%3};\n"
                        : "+f"(c[i][j][0]), "+f"(c[i][j][1]),
                          "+f"(c[i][j][2]), "+f"(c[i][j][3])
                        : "r"(af[i][0]), "r"(af[i][1]), "r"(af[i][2]), "r"(af[i][3]),
                          "r"(bf[j][0]), "r"(bf[j][1]));
                }
        }
        if (it + 1 < NIT) {
            int nb = buf ^ 1;
            float* as = &Asm[nb][arow*20 + akq];
            as[0]=f2tf(pa0.x); as[1]=f2tf(pa0.y); as[2]=f2tf(pa0.z); as[3]=f2tf(pa0.w);
            as[4]=f2tf(pa1.x); as[5]=f2tf(pa1.y); as[6]=f2tf(pa1.z); as[7]=f2tf(pa1.w);
            float* bs = &Bsm[nb][bkr*136 + bnc];
            bs[0]=f2tf(pb0.x); bs[1]=f2tf(pb0.y); bs[2]=f2tf(pb0.z); bs[3]=f2tf(pb0.w);
            bs[4]=f2tf(pb1.x); bs[5]=f2tf(pb1.y); bs[6]=f2tf(pb1.z); bs[7]=f2tf(pb1.w);
        }
        __syncthreads();
    }

#pragma unroll
    for (int i = 0; i < 4; i++) {
#pragma unroll
        for (int j = 0; j < 4; j++) {
#pragma unroll
            for (int h = 0; h < 2; h++) {
                int r = row0 + wm*64 + i*16 + g + h*8;
                int cc = col0 + wn*32 + j*8 + 2*t4;
                float v0 = c[i][j][h*2+0], v1 = c[i][j][h*2+1];
                if (EPI == 0) {
                    int b4 = r >> 12, nn = r & 4095;
                    int which = cc >> 9, cs = cc & 511;
                    int hh = cs >> 6, dh = cs & 63;
                    size_t di = ((size_t)(b4*8+hh)*4096 + nn)*64 + dh;
                    if (which == 0) {
                        *(float2*)&C0[di] = make_float2(v0*0.125f, v1*0.125f);
                    } else if (which == 1) {
                        *(float2*)&C1[di] = make_float2(v0, v1);
                    } else {
                        *(float2*)&C2[di] = make_float2(v0, v1);
                    }
                } else {
                    size_t di = (size_t)r*512 + cc;
                    float2 bias = *(const float2*)&e0[cc];
                    float2 xr = *(const float2*)&e1[di];
                    *(float2*)&C0[di] = make_float2(v0+bias.x+xr.x, v1+bias.y+xr.y);
                }
            }
        }
    }
}

// ---------------------------------------------------------------------------
// TF32 GEMM, pinv variant (proven 128x128): batched over z (stride 65536):
// C0 = cA*A + cAB*(A@B)
// ---------------------------------------------------------------------------
__global__ __launch_bounds__(256, 2) void mma_gemm_pinv(
        const float* __restrict__ A, const float* __restrict__ B,
        float* __restrict__ C0, float cA, float cAB) {
    __shared__ float Asm[2][128*20];
    __shared__ float Bsm[2][16*136];
    int tid = threadIdx.x;
    int lane = tid & 31, wid = tid >> 5;
    int wm = wid & 1, wn = wid >> 1;
    int g = lane >> 2, t4 = lane & 3;
    int row0 = blockIdx.y * 128, col0 = blockIdx.x * 128;
    const float* Ag = A + (size_t)blockIdx.z * 65536;
    const float* Bg = B + (size_t)blockIdx.z * 65536;
    int arow = tid >> 1, akq = (tid & 1) * 8;
    int bkr = tid >> 4, bnc = (tid & 15) * 8;

    {
        const float* ap = Ag + (size_t)(row0 + arow) * 256 + akq;
        float4 a0 = *(const float4*)ap;
        float4 a1 = *(const float4*)(ap + 4);
        float* as = &Asm[0][arow*20 + akq];
        as[0]=f2tf(a0.x); as[1]=f2tf(a0.y); as[2]=f2tf(a0.z); as[3]=f2tf(a0.w);
        as[4]=f2tf(a1.x); as[5]=f2tf(a1.y); as[6]=f2tf(a1.z); as[7]=f2tf(a1.w);
        const float* bp = Bg + (size_t)bkr * 256 + col0 + bnc;
        float4 b0 = *(const float4*)bp;
        float4 b1 = *(const float4*)(bp + 4);
        float* bs = &Bsm[0][bkr*136 + bnc];
        bs[0]=f2tf(b0.x); bs[1]=f2tf(b0.y); bs[2]=f2tf(b0.z); bs[3]=f2tf(b0.w);
        bs[4]=f2tf(b1.x); bs[5]=f2tf(b1.y); bs[6]=f2tf(b1.z); bs[7]=f2tf(b1.w);
    }
    __syncthreads();

    float c[4][4][4];
#pragma unroll
    for (int i=0;i<4;i++)
#pragma unroll
        for (int j=0;j<4;j++)
#pragma unroll
            for (int h=0;h<4;h++) c[i][j][h]=0.f;

    const int NIT = 16;
    for (int it = 0; it < NIT; it++) {
        int buf = it & 1;
        float4 pa0, pa1, pb0, pb1;
        if (it + 1 < NIT) {
            int k0 = (it + 1) * 16;
            const float* ap = Ag + (size_t)(row0 + arow) * 256 + k0 + akq;
            pa0 = *(const float4*)ap;
            pa1 = *(const float4*)(ap + 4);
            const float* bp = Bg + (size_t)(k0 + bkr) * 256 + col0 + bnc;
            pb0 = *(const float4*)bp;
            pb1 = *(const float4*)(bp + 4);
        }
#pragma unroll
        for (int ks = 0; ks < 16; ks += 8) {
            uint32_t af[4][4], bf[4][2];
#pragma unroll
            for (int i = 0; i < 4; i++) {
                int r0i = (wm*64 + i*16 + g) * 20 + ks + t4;
                int r1i = r0i + 8*20;
                af[i][0] = __float_as_uint(Asm[buf][r0i]);
                af[i][1] = __float_as_uint(Asm[buf][r1i]);
                af[i][2] = __float_as_uint(Asm[buf][r0i + 4]);
                af[i][3] = __float_as_uint(Asm[buf][r1i + 4]);
            }
#pragma unroll
            for (int j = 0; j < 4; j++) {
                int nc2 = wn*32 + j*8 + g;
                bf[j][0] = __float_as_uint(Bsm[buf][(ks + t4)*136 + nc2]);
                bf[j][1] = __float_as_uint(Bsm[buf][(ks + t4 + 4)*136 + nc2]);
            }
#pragma unroll
            for (int i = 0; i < 4; i++)
#pragma unroll
                for (int j = 0; j < 4; j++) {
                    asm volatile(
                        "mma.sync.aligned.m16n8k8.row.col.f32.tf32.tf32.f32 "
                        "{%0,%1,%2,%3}, {%4,%5,%6,%7}, {%8,%9}, {%0,%1,%2,%3};\n"
                        : "+f"(c[i][j][0]), "+f"(c[i][j][1]),
                          "+f"(c[i][j][2]), "+f"(c[i][j][3])
                        : "r"(af[i][0]), "r"(af[i][1]), "r"(af[i][2]), "r"(af[i][3]),
                          "r"(bf[j][0]), "r"(bf[j][1]));
                }
        }
        if (it + 1 < NIT) {
            int nb = buf ^ 1;
            float* as = &Asm[nb][arow*20 + akq];
            as[0]=f2tf(pa0.x); as[1]=f2tf(pa0.y); as[2]=f2tf(pa0.z); as[3]=f2tf(pa0.w);
            as[4]=f2tf(pa1.x); as[5]=f2tf(pa1.y); as[6]=f2tf(pa1.z); as[7]=f2tf(pa1.w);
            float* bs = &Bsm[nb][bkr*136 + bnc];
            bs[0]=f2tf(pb0.x); bs[1]=f2tf(pb0.y); bs[2]=f2tf(pb0.z); bs[3]=f2tf(pb0.w);
            bs[4]=f2tf(pb1.x); bs[5]=f2tf(pb1.y); bs[6]=f2tf(pb1.z); bs[7]=f2tf(pb1.w);
        }
        __syncthreads();
    }

#pragma unroll
    for (int i = 0; i < 4; i++) {
#pragma unroll
        for (int j = 0; j < 4; j++) {
#pragma unroll
            for (int h = 0; h < 2; h++) {
                int r = row0 + wm*64 + i*16 + g + h*8;
                int cc = col0 + wn*32 + j*8 + 2*t4;
                float v0 = c[i][j][h*2+0], v1 = c[i][j][h*2+1];
                float2 ae = *(const float2*)&Ag[(size_t)r*256 + cc];
                size_t di = (size_t)blockIdx.z*65536 + (size_t)r*256 + cc;
                *(float2*)&C0[di] = make_float2(cA*ae.x + cAB*v0,
                                                cA*ae.y + cAB*v1);
            }
        }
    }
}

// ---------------------------------------------------------------------------
// TF32 MMA narrow GEMM, 64-row tiles -> grid (1,4,32)=128 CTAs (was 64).
// A [32][256][256], B,C [32][256][64].
// 8 warps: wm=wid&1 (32 rows), wn=wid>>1 (16 cols each, 4 col quarters).
// EPI 0: C = cB*B + cAB*(A@B)
// EPI 1: C = 13*e0 - 15*e1 + 7*B - (A@B)   (fused r3 + comb4 -> u5)
// ---------------------------------------------------------------------------
template<int EPI>
__global__ __launch_bounds__(256, 2) void mma_nar_kernel(
        const float* __restrict__ A, const float* __restrict__ B,
        float* __restrict__ C, float cB, float cAB,
        const float* __restrict__ e0, const float* __restrict__ e1) {
    __shared__ float Asm[2][64*20];
    __shared__ float Bsm[2][16*72];
    int tid = threadIdx.x;
    int lane = tid & 31, wid = tid >> 5;
    int wm = wid & 1, wn = wid >> 1;
    int g = lane >> 2, t4 = lane & 3;
    int row0 = blockIdx.y * 64;
    const float* Ag = A + (size_t)blockIdx.z * 65536;
    const float* Bg = B + (size_t)blockIdx.z * 16384;
    float* Cg = C + (size_t)blockIdx.z * 16384;
    int arow = tid >> 2, akq = (tid & 3) * 4;
    int bkr = tid >> 4, bnc = (tid & 15) * 4;

    {
        float4 av = *(const float4*)(Ag + (size_t)(row0 + arow) * 256 + akq);
        float* as = &Asm[0][arow*20 + akq];
        as[0]=f2tf(av.x); as[1]=f2tf(av.y); as[2]=f2tf(av.z); as[3]=f2tf(av.w);
        float4 bv = *(const float4*)(Bg + (size_t)bkr * 64 + bnc);
        float* bs = &Bsm[0][bkr*72 + bnc];
        bs[0]=f2tf(bv.x); bs[1]=f2tf(bv.y); bs[2]=f2tf(bv.z); bs[3]=f2tf(bv.w);
    }
    __syncthreads();

    float c[2][2][4];
#pragma unroll
    for (int i=0;i<2;i++)
#pragma unroll
        for (int j=0;j<2;j++)
#pragma unroll
            for (int h=0;h<4;h++) c[i][j][h]=0.f;

    const int NIT = 16;
    for (int it = 0; it < NIT; it++) {
        int buf = it & 1;
        float4 pa, pb;
        if (it + 1 < NIT) {
            int k0 = (it + 1) * 16;
            pa = *(const float4*)(Ag + (size_t)(row0 + arow) * 256 + k0 + akq);
            pb = *(const float4*)(Bg + (size_t)(k0 + bkr) * 64 + bnc);
        }
#pragma unroll
        for (int ks = 0; ks < 16; ks += 8) {
            uint32_t af[2][4], bf[2][2];
#pragma unroll
            for (int i = 0; i < 2; i++) {
                int r0i = (wm*32 + i*16 + g) * 20 + ks + t4;
                int r1i = r0i + 8*20;
                af[i][0] = __float_as_uint(Asm[buf][r0i]);
                af[i][1] = __float_as_uint(Asm[buf][r1i]);
                af[i][2] = __float_as_uint(Asm[buf][r0i + 4]);
                af[i][3] = __float_as_uint(Asm[buf][r1i + 4]);
            }
#pragma unroll
            for (int j = 0; j < 2; j++) {
                int nc2 = wn*16 + j*8 + g;
                bf[j][0] = __float_as_uint(Bsm[buf][(ks + t4)*72 + nc2]);
                bf[j][1] = __float_as_uint(Bsm[buf][(ks + t4 + 4)*72 + nc2]);
            }
#pragma unroll
            for (int i = 0; i < 2; i++)
#pragma unroll
                for (int j = 0; j < 2; j++) {
                    asm volatile(
                        "mma.sync.aligned.m16n8k8.row.col.f32.tf32.tf32.f32 "
                        "{%0,%1,%2,%3}, {%4,%5,%6,%7}, {%8,%9}, {%0,%1,%2,%3};\n"
                        : "+f"(c[i][j][0]), "+f"(c[i][j][1]),
                          "+f"(c[i][j][2]), "+f"(c[i][j][3])
                        : "r"(af[i][0]), "r"(af[i][1]), "r"(af[i][2]), "r"(af[i][3]),
                          "r"(bf[j][0]), "r"(bf[j][1]));
                }
        }
        if (it + 1 < NIT) {
            int nb = buf ^ 1;
            float* as = &Asm[nb][arow*20 + akq];
            as[0]=f2tf(pa.x); as[1]=f2tf(pa.y); as[2]=f2tf(pa.z); as[3]=f2tf(pa.w);
            float* bs = &Bsm[nb][bkr*72 + bnc];
            bs[0]=f2tf(pb.x); bs[1]=f2tf(pb.y); bs[2]=f2tf(pb.z); bs[3]=f2tf(pb.w);
        }
        __syncthreads();
    }

#pragma unroll
    for (int i = 0; i < 2; i++)
#pragma unroll
        for (int j = 0; j < 2; j++)
#pragma unroll
            for (int h = 0; h < 2; h++) {
                int r = row0 + wm*32 + i*16 + g + h*8;
                int cc = wn*16 + j*8 + 2*t4;
                size_t di = (size_t)r*64 + cc;
                float a0 = c[i][j][h*2+0], a1 = c[i][j][h*2+1];
                float v0, v1;
                if (EPI == 0) {
                    v0 = cAB * a0; v1 = cAB * a1;
                    if (cB != 0.f) {
                        float2 be = *(const float2*)&Bg[di];
                        v0 += cB * be.x; v1 += cB * be.y;
                    }
                } else {
                    // u5 = 13*w - 15*r1 + 7*r2 - r3 ; B holds r2, acc is r3
                    const float* wg  = e0 + (size_t)blockIdx.z * 16384;
                    const float* r1g = e1 + (size_t)blockIdx.z * 16384;
                    float2 wv  = *(const float2*)&wg[di];
                    float2 r1v = *(const float2*)&r1g[di];
                    float2 r2v = *(const float2*)&Bg[di];
                    v0 = 13.f*wv.x - 15.f*r1v.x + 7.f*r2v.x - a0;
                    v1 = 13.f*wv.y - 15.f*r1v.y + 7.f*r2v.y - a1;
                }
                *(float2*)&Cg[di] = make_float2(v0, v1);
            }
}

// ---------------------------------------------------------------------------
// TF32 MMA a2 = softmax(q_l @ k_l^T), 64-row tiles -> grid (4,32) = 128 CTAs
// ---------------------------------------------------------------------------
#define A2_KS   4352
#define A2_RM   21760
#define A2_RS   22272
#define SMEM_A2 (22784*4)
__global__ __launch_bounds__(256, 1) void a2_tc_kernel(
        const float* __restrict__ ql, const float* __restrict__ kl,
        float* __restrict__ a2) {
    extern __shared__ float sm2[];
    float* Qs = sm2;                       // [64][68]
    float* Ks = sm2 + A2_KS;               // [256][68]
    float (*redm)[8] = (float(*)[8])(sm2 + A2_RM);
    float (*reds)[8] = (float(*)[8])(sm2 + A2_RS);

    int tid = threadIdx.x;
    int lane = tid & 31, wn = tid >> 5;
    int g = lane >> 2, t4 = lane & 3;
    int bh = blockIdx.y;
    int row0 = blockIdx.x * 64;
    const float* qb = ql + ((size_t)bh*256 + row0) * 64;
    const float* kb = kl + (size_t)bh*256*64;

    for (int i = tid*4; i < 4096; i += 1024) {
        float4 qv = *(const float4*)&qb[i];
        int r = i >> 6, cc = i & 63;
        float* qs = &Qs[r*68 + cc];
        qs[0]=f2tf(qv.x); qs[1]=f2tf(qv.y); qs[2]=f2tf(qv.z); qs[3]=f2tf(qv.w);
    }
    for (int i = tid*4; i < 16384; i += 1024) {
        float4 kv = *(const float4*)&kb[i];
        int r = i >> 6, cc = i & 63;
        float* ks = &Ks[r*68 + cc];
        ks[0]=f2tf(kv.x); ks[1]=f2tf(kv.y); ks[2]=f2tf(kv.z); ks[3]=f2tf(kv.w);
    }
    __syncthreads();

    float c[4][4][4];
#pragma unroll
    for (int i=0;i<4;i++)
#pragma unroll
        for (int j=0;j<4;j++)
#pragma unroll
            for (int h=0;h<4;h++) c[i][j][h]=0.f;

#pragma unroll
    for (int ks = 0; ks < 64; ks += 8) {
        uint32_t af[4][4], bf[4][2];
#pragma unroll
        for (int i = 0; i < 4; i++) {
            int r0i = (i*16 + g)*68 + ks + t4;
            int r1i = r0i + 8*68;
            af[i][0] = __float_as_uint(Qs[r0i]);
            af[i][1] = __float_as_uint(Qs[r1i]);
            af[i][2] = __float_as_uint(Qs[r0i + 4]);
            af[i][3] = __float_as_uint(Qs[r1i + 4]);
        }
#pragma unroll
        for (int j = 0; j < 4; j++) {
            int cr = (wn*32 + j*8 + g)*68 + ks + t4;
            bf[j][0] = __float_as_uint(Ks[cr]);
            bf[j][1] = __float_as_uint(Ks[cr + 4]);
        }
#pragma unroll
        for (int i = 0; i < 4; i++)
#pragma unroll
            for (int j = 0; j < 4; j++) {
                asm volatile(
                    "mma.sync.aligned.m16n8k8.row.col.f32.tf32.tf32.f32 "
                    "{%0,%1,%2,%3}, {%4,%5,%6,%7}, {%8,%9}, {%0,%1,%2,%3};\n"
                    : "+f"(c[i][j][0]), "+f"(c[i][j][1]),
                      "+f"(c[i][j][2]), "+f"(c[i][j][3])
                    : "r"(af[i][0]), "r"(af[i][1]), "r"(af[i][2]), "r"(af[i][3]),
                      "r"(bf[j][0]), "r"(bf[j][1]));
            }
    }

    float pm[4][2];
#pragma unroll
    for (int i=0;i<4;i++)
#pragma unroll
        for (int h=0;h<2;h++) {
            float m = c[i][0][2*h];
#pragma unroll
            for (int j=0;j<4;j++) {
                m = fmaxf(m, c[i][j][2*h]);
                m = fmaxf(m, c[i][j][2*h+1]);
            }
#pragma unroll
            for (int off = 1; off <= 2; off <<= 1)
                m = fmaxf(m, __shfl_xor_sync(0xffffffffu, m, off));
            pm[i][h] = m;
        }
    if (t4 == 0) {
#pragma unroll
        for (int i=0;i<4;i++)
#pragma unroll
            for (int h=0;h<2;h++)
                redm[i*16 + g + h*8][wn] = pm[i][h];
    }
    __syncthreads();

    float psum[4][2];
#pragma unroll
    for (int i=0;i<4;i++)
#pragma unroll
        for (int h=0;h<2;h++) {
            int r = i*16 + g + h*8;
            float m = redm[r][0];
#pragma unroll
            for (int u=1;u<8;u++) m = fmaxf(m, redm[r][u]);
            float s = 0.f;
#pragma unroll
            for (int j=0;j<4;j++) {
                float p0 = __expf(c[i][j][2*h]   - m);
                float p1 = __expf(c[i][j][2*h+1] - m);
                c[i][j][2*h] = p0; c[i][j][2*h+1] = p1;
                s += p0 + p1;
            }
#pragma unroll
            for (int off = 1; off <= 2; off <<= 1)
                s += __shfl_xor_sync(0xffffffffu, s, off);
            psum[i][h] = s;
        }
    if (t4 == 0) {
#pragma unroll
        for (int i=0;i<4;i++)
#pragma unroll
            for (int h=0;h<2;h++)
                reds[i*16 + g + h*8][wn] = psum[i][h];
    }
    __syncthreads();

#pragma unroll
    for (int i=0;i<4;i++)
#pragma unroll
        for (int h=0;h<2;h++) {
            int r = i*16 + g + h*8;
            float ss = reds[r][0];
#pragma unroll
            for (int u=1;u<8;u++) ss += reds[r][u];
            float inv = 1.f / ss;
            float* orow = a2 + ((size_t)bh*256 + row0 + r) * 256;
#pragma unroll
            for (int j=0;j<4;j++) {
                int cc = wn*32 + j*8 + 2*t4;
                *(float2*)&orow[cc] = make_float2(c[i][j][2*h]*inv, c[i][j][2*h+1]*inv);
            }
        }
}

// ---------------------------------------------------------------------------
// Landmarks (merged q+k)
// ---------------------------------------------------------------------------
__global__ void landmark2_kernel(const float* __restrict__ q, const float* __restrict__ k,
                                 float* __restrict__ ql, float* __restrict__ kl) {
    int gidx = blockIdx.x * 256 + threadIdx.x;
    const float* src = (gidx < 524288) ? q : k;
    float* dst = (gidx < 524288) ? ql : kl;
    int idx = gidx & 524287;
    int dh = idx & 63;
    int mi = (idx >> 6) & 255;
    int bh = idx >> 14;
    const float* p = src + ((size_t)bh*4096 + mi*16)*64 + dh;
    float s = 0.f;
#pragma unroll
    for (int j = 0; j < 16; j++) s += p[j*64];
    dst[idx] = s * 0.0625f;
}

// ---------------------------------------------------------------------------
// pinv scalars. colsum split over 4 column-chunks -> grid (4,32) = 128 CTAs.
// ---------------------------------------------------------------------------
__global__ void red_init_kernel(float* g) { if (threadIdx.x < 2) g[threadIdx.x] = 0.f; }

__global__ void colsum_kernel(const float* __restrict__ a2, float* __restrict__ gred) {
    int bh = blockIdx.y;
    int j = blockIdx.x * 64 + threadIdx.x;
    const float* base = a2 + (size_t)bh*65536;
    float s = 0.f;
    for (int i = 0; i < 256; i++) s += fabsf(base[(size_t)i*256 + j]);
#pragma unroll
    for (int o = 16; o; o >>= 1) s = fmaxf(s, __shfl_xor_sync(0xffffffffu, s, o));
    __shared__ float red[2];
    if ((threadIdx.x & 31) == 0) red[threadIdx.x >> 5] = s;
    __syncthreads();
    if (threadIdx.x == 0)
        atomicMax((int*)&gred[1], __float_as_int(fmaxf(red[0], red[1])));
}

// zinit via 32x32 smem-tile transpose (coalesced both ways)
__global__ void zinit_kernel(const float* __restrict__ a2, const float* __restrict__ gred,
                             float* __restrict__ z) {
    __shared__ float tile[32][33];
    int bh = blockIdx.z;
    int i0 = blockIdx.x * 32, j0 = blockIdx.y * 32;
    const float* base = a2 + (size_t)bh * 65536;
    float* zb = z + (size_t)bh * 65536;
    int c = threadIdx.x, r0 = threadIdx.y;
#pragma unroll
    for (int rr = 0; rr < 4; rr++) {
        int r = r0*4 + rr;
        tile[r][c] = base[(size_t)(j0 + r)*256 + i0 + c];
    }
    __syncthreads();
    float inv = 1.f / gred[1];
#pragma unroll
    for (int rr = 0; rr < 4; rr++) {
        int r = r0*4 + rr;
        zb[(size_t)(i0 + r)*256 + j0 + c] = tile[c][r] * inv;
    }
}

// ---------------------------------------------------------------------------
// TF32 flash attention with optional split-K (used for flash-1, nk=4096)
// ---------------------------------------------------------------------------
#define QP 68
#define VP 72
#define OFF_KS   4352
#define OFF_PS   8704
#define OFF_VS   13056
#define OFF_ROWM 17664
#define OFF_ROWL 17728
#define OFF_REDM 17792
#define OFF_REDS 18048
#define SMEM_FLASH_TC ((18304)*4)

__global__ __launch_bounds__(256) void flash_tc_kernel(
        const float* __restrict__ Q, const float* __restrict__ K,
        const float* __restrict__ V, float* __restrict__ O, int nq, int nk,
        int chunk, float* __restrict__ mpart, float* __restrict__ lpart) {
    extern __shared__ float sm[];
    float (*Qs)[QP] = (float(*)[QP])sm;
    float (*Ks)[QP] = (float(*)[QP])(sm + OFF_KS);
    float (*Ps)[QP] = (float(*)[QP])(sm + OFF_PS);
    float (*Vs)[VP] = (float(*)[VP])(sm + OFF_VS);
    float* rowm = sm + OFF_ROWM;
    float* rowl = sm + OFF_ROWL;
    float (*redm)[4] = (float(*)[4])(sm + OFF_REDM);
    float (*reds)[4] = (float(*)[4])(sm + OFF_REDS);

    int tid = threadIdx.x;
    int lane = tid & 31, wid = tid >> 5;
    int wm = wid & 1, wn = wid >> 1;
    int g = lane >> 2, t4 = lane & 3;
    int bh = blockIdx.y;
    int q0 = blockIdx.x * 64;
    size_t koff = (size_t)blockIdx.z * chunk * 64;
    const float* Qb = Q + ((size_t)bh*nq + q0) * 64;
    const float* Kb = K + (size_t)bh*nk*64 + koff;
    const float* Vb = V + (size_t)bh*nk*64 + koff;

    {
        int r = tid >> 2, kc = (tid & 3) * 16;
#pragma unroll
        for (int ii = 0; ii < 4; ii++) {
            float4 qv = *(const float4*)&Qb[(size_t)r*64 + kc + ii*4];
            Qs[r][kc+ii*4+0]=f2tf(qv.x); Qs[r][kc+ii*4+1]=f2tf(qv.y);
            Qs[r][kc+ii*4+2]=f2tf(qv.z); Qs[r][kc+ii*4+3]=f2tf(qv.w);
        }
    }
    if (tid < 64) { rowm[tid] = -1e30f; rowl[tid] = 0.f; }
    float o[2][2][4];
#pragma unroll
    for (int i=0;i<2;i++)
#pragma unroll
        for (int j=0;j<2;j++)
#pragma unroll
            for (int h=0;h<4;h++) o[i][j][h]=0.f;
    __syncthreads();

    for (int c0 = 0; c0 < chunk; c0 += 64) {
        {
            int r = tid >> 2, kc = (tid & 3) * 16;
#pragma unroll
            for (int ii = 0; ii < 4; ii++) {
                float4 kv = *(const float4*)&Kb[(size_t)(c0+r)*64 + kc + ii*4];
                Ks[r][kc+ii*4+0]=f2tf(kv.x); Ks[r][kc+ii*4+1]=f2tf(kv.y);
                Ks[r][kc+ii*4+2]=f2tf(kv.z); Ks[r][kc+ii*4+3]=f2tf(kv.w);
                float4 vv = *(const float4*)&Vb[(size_t)(c0+r)*64 + kc + ii*4];
                Vs[r][kc+ii*4+0]=f2tf(vv.x); Vs[r][kc+ii*4+1]=f2tf(vv.y);
                Vs[r][kc+ii*4+2]=f2tf(vv.z); Vs[r][kc+ii*4+3]=f2tf(vv.w);
            }
        }
        __syncthreads();

        float s[2][2][4];
#pragma unroll
        for (int i=0;i<2;i++)
#pragma unroll
            for (int j=0;j<2;j++)
#pragma unroll
                for (int h=0;h<4;h++) s[i][j][h]=0.f;
#pragma unroll
        for (int ks = 0; ks < 64; ks += 8) {
            uint32_t af[2][4], bf[2][2];
#pragma unroll
            for (int i = 0; i < 2; i++) {
                int r = wm*32 + i*16 + g;
                af[i][0] = __float_as_uint(Qs[r][ks+t4]);
                af[i][1] = __float_as_uint(Qs[r+8][ks+t4]);
                af[i][2] = __float_as_uint(Qs[r][ks+t4+4]);
                af[i][3] = __float_as_uint(Qs[r+8][ks+t4+4]);
            }
#pragma unroll
            for (int j = 0; j < 2; j++) {
                int cc = wn*16 + j*8 + g;
                bf[j][0] = __float_as_uint(Ks[cc][ks+t4]);
                bf[j][1] = __float_as_uint(Ks[cc][ks+t4+4]);
            }
#pragma unroll
            for (int i = 0; i < 2; i++)
#pragma unroll
                for (int j = 0; j < 2; j++) {
                    asm volatile(
                        "mma.sync.aligned.m16n8k8.row.col.f32.tf32.tf32.f32 "
                        "{%0,%1,%2,%3}, {%4,%5,%6,%7}, {%8,%9}, {%0,%1,%2,%3};\n"
                        : "+f"(s[i][j][0]), "+f"(s[i][j][1]),
                          "+f"(s[i][j][2]), "+f"(s[i][j][3])
                        : "r"(af[i][0]), "r"(af[i][1]), "r"(af[i][2]), "r"(af[i][3]),
                          "r"(bf[j][0]), "r"(bf[j][1]));
                }
        }

        float pm[2][2];
#pragma unroll
        for (int i=0;i<2;i++)
#pragma unroll
            for (int h=0;h<2;h++)
                pm[i][h] = fmaxf(fmaxf(s[i][0][2*h], s[i][0][2*h+1]),
                                 fmaxf(s[i][1][2*h], s[i][1][2*h+1]));
#pragma unroll
        for (int off = 1; off <= 2; off <<= 1) {
#pragma unroll
            for (int i=0;i<2;i++)
#pragma unroll
                for (int h=0;h<2;h++)
                    pm[i][h] = fmaxf(pm[i][h], __shfl_xor_sync(0xffffffffu, pm[i][h], off));
        }
        if (t4 == 0) {
#pragma unroll
            for (int i=0;i<2;i++)
#pragma unroll
                for (int h=0;h<2;h++)
                    redm[wm*32 + i*16 + g + h*8][wn] = pm[i][h];
        }
        __syncthreads();

        float mnew[2][2], scale[2][2];
#pragma unroll
        for (int i=0;i<2;i++)
#pragma unroll
            for (int h=0;h<2;h++) {
                int r = wm*32 + i*16 + g + h*8;
                float m = fmaxf(fmaxf(redm[r][0], redm[r][1]),
                                fmaxf(redm[r][2], redm[r][3]));
                float mo = rowm[r];
                mnew[i][h] = fmaxf(mo, m);
                scale[i][h] = __expf(mo - mnew[i][h]);
            }

        float psum[2][2] = {{0.f,0.f},{0.f,0.f}};
#pragma unroll
        for (int i=0;i<2;i++)
#pragma unroll
            for (int j=0;j<2;j++)
#pragma unroll
                for (int h=0;h<2;h++) {
                    int r = wm*32 + i*16 + g + h*8;
                    float p0 = __expf(s[i][j][2*h]   - mnew[i][h]);
                    float p1 = __expf(s[i][j][2*h+1] - mnew[i][h]);
                    *(float2*)&Ps[r][wn*16 + j*8 + 2*t4] = make_float2(f2tf(p0), f2tf(p1));
                    psum[i][h] += p0 + p1;
                    o[i][j][2*h]   *= scale[i][h];
                    o[i][j][2*h+1] *= scale[i][h];
                }
#pragma unroll
        for (int off = 1; off <= 2; off <<= 1) {
#pragma unroll
            for (int i=0;i<2;i++)
#pragma unroll
                for (int h=0;h<2;h++)
                    psum[i][h] += __shfl_xor_sync(0xffffffffu, psum[i][h], off);
        }
        if (t4 == 0) {
#pragma unroll
            for (int i=0;i<2;i++)
#pragma unroll
                for (int h=0;h<2;h++)
                    reds[wm*32 + i*16 + g + h*8][wn] = psum[i][h];
        }
        __syncthreads();

        if (wn == 0 && t4 == 0) {
#pragma unroll
            for (int i=0;i<2;i++)
#pragma unroll
                for (int h=0;h<2;h++) {
                    int r = wm*32 + i*16 + g + h*8;
                    float ps = reds[r][0] + reds[r][1] + reds[r][2] + reds[r][3];
                    rowl[r] = rowl[r]*scale[i][h] + ps;
                    rowm[r] = mnew[i][h];
                }
        }

#pragma unroll
        for (int ks = 0; ks < 64; ks += 8) {
            uint32_t af[2][4], bf[2][2];
#pragma unroll
            for (int i = 0; i < 2; i++) {
                int r = wm*32 + i*16 + g;
                af[i][0] = __float_as_uint(Ps[r][ks+t4]);
                af[i][1] = __float_as_uint(Ps[r+8][ks+t4]);
                af[i][2] = __float_as_uint(Ps[r][ks+t4+4]);
                af[i][3] = __float_as_uint(Ps[r+8][ks+t4+4]);
            }
#pragma unroll
            for (int j = 0; j < 2; j++) {
                int cc = wn*16 + j*8 + g;
                bf[j][0] = __float_as_uint(Vs[ks+t4][cc]);
                bf[j][1] = __float_as_uint(Vs[ks+t4+4][cc]);
            }
#pragma unroll
            for (int i = 0; i < 2; i++)
#pragma unroll
                for (int j = 0; j < 2; j++) {
                    asm volatile(
                        "mma.sync.aligned.m16n8k8.row.col.f32.tf32.tf32.f32 "
                        "{%0,%1,%2,%3}, {%4,%5,%6,%7}, {%8,%9}, {%0,%1,%2,%3};\n"
                        : "+f"(o[i][j][0]), "+f"(o[i][j][1]),
                          "+f"(o[i][j][2]), "+f"(o[i][j][3])
                        : "r"(af[i][0]), "r"(af[i][1]), "r"(af[i][2]), "r"(af[i][3]),
                          "r"(bf[j][0]), "r"(bf[j][1]));
                }
        }
        __syncthreads();
    }

    if (lpart != nullptr) {
        float* Ob = O + ((size_t)(blockIdx.z*32 + bh)*nq + q0) * 64;
#pragma unroll
        for (int i=0;i<2;i++)
#pragma unroll
            for (int j=0;j<2;j++)
#pragma unroll
                for (int h=0;h<2;h++) {
                    int r = wm*32 + i*16 + g + h*8;
                    int cc = wn*16 + j*8 + 2*t4;
                    *(float2*)&Ob[(size_t)r*64 + cc] =
                        make_float2(o[i][j][2*h], o[i][j][2*h+1]);
                }
        if (tid < 64) {
            size_t ri = (size_t)(blockIdx.z*32 + bh)*nq + q0 + tid;
            mpart[ri] = rowm[tid];
            lpart[ri] = rowl[tid];
        }
    } else {
        float* Ob = O + ((size_t)bh*nq + q0) * 64;
#pragma unroll
        for (int i=0;i<2;i++)
#pragma unroll
            for (int j=0;j<2;j++)
#pragma unroll
                for (int h=0;h<2;h++) {
                    int r = wm*32 + i*16 + g + h*8;
                    int cc = wn*16 + j*8 + 2*t4;
                    float inv = 1.f / rowl[r];
                    *(float2*)&Ob[(size_t)r*64 + cc] =
                        make_float2(o[i][j][2*h]*inv, o[i][j][2*h+1]*inv);
                }
    }
}

// ---------------------------------------------------------------------------
// Single-pass flash for flash-2 (nk == 256) with FUSED depthwise conv +
// layout transform (proven R16).
// ---------------------------------------------------------------------------
#define OFF_VT   18304
#define OFF_WK   (18304 + 96*64)
#define SMEM_FLASH2 ((OFF_WK + 36)*4)

__global__ __launch_bounds__(256) void flash2_conv_kernel(
        const float* __restrict__ Q, const float* __restrict__ K,
        const float* __restrict__ V, const float* __restrict__ vfull,
        const float* __restrict__ cw, float* __restrict__ attn2) {
    extern __shared__ float sm[];
    float (*Qs)[QP] = (float(*)[QP])sm;
    float (*Ks)[QP] = (float(*)[QP])(sm + OFF_KS);
    float (*Ps)[QP] = (float(*)[QP])(sm + OFF_PS);
    float (*Vs)[VP] = (float(*)[VP])(sm + OFF_VS);
    float (*redm)[4] = (float(*)[4])(sm + OFF_REDM);
    float (*reds)[4] = (float(*)[4])(sm + OFF_REDS);
    float (*vt)[64] = (float(*)[64])(sm + OFF_VT);
    float* wk = sm + OFF_WK;

    int tid = threadIdx.x;
    int lane = tid & 31, wid = tid >> 5;
    int wm = wid & 1, wn = wid >> 1;
    int g = lane >> 2, t4 = lane & 3;
    int bh = blockIdx.y;
    int hh = bh & 7, b4 = bh >> 3;
    int q0 = blockIdx.x * 64;
    const float* Qb = Q + ((size_t)bh*4096 + q0) * 64;
    const float* Kb = K + (size_t)bh*256*64;
    const float* Vb = V + (size_t)bh*256*64;
    const float* vfb = vfull + (size_t)bh*4096*64;

    int lr = tid >> 2, lk = (tid & 3) * 16;
    {
#pragma unroll
        for (int ii = 0; ii < 4; ii++) {
            float4 qv = *(const float4*)&Qb[(size_t)lr*64 + lk + ii*4];
            Qs[lr][lk+ii*4+0]=f2tf(qv.x); Qs[lr][lk+ii*4+1]=f2tf(qv.y);
            Qs[lr][lk+ii*4+2]=f2tf(qv.z); Qs[lr][lk+ii*4+3]=f2tf(qv.w);
        }
    }
#pragma unroll
    for (int i = 0; i < 6; i++) {
        int f = tid + i*256;
        int r = f >> 4;
        int c4 = (f & 15) * 4;
        int gr = q0 - 16 + r;
        float4 val = make_float4(0.f,0.f,0.f,0.f);
        if (gr >= 0 && gr < 4096) val = *(const float4*)&vfb[(size_t)gr*64 + c4];
        *(float4*)&vt[r][c4] = val;
    }
    if (tid < 33) wk[tid] = cw[hh*33 + tid];

    float s[4][2][2][4];
    float o[2][2][4];
#pragma unroll
    for (int i=0;i<2;i++)
#pragma unroll
        for (int j=0;j<2;j++)
#pragma unroll
            for (int h=0;h<4;h++) o[i][j][h]=0.f;

#pragma unroll
    for (int t = 0; t < 4; t++) {
        {
#pragma unroll
            for (int ii = 0; ii < 4; ii++) {
                float4 kv = *(const float4*)&Kb[(size_t)(t*64+lr)*64 + lk + ii*4];
                Ks[lr][lk+ii*4+0]=f2tf(kv.x); Ks[lr][lk+ii*4+1]=f2tf(kv.y);
                Ks[lr][lk+ii*4+2]=f2tf(kv.z); Ks[lr][lk+ii*4+3]=f2tf(kv.w);
            }
        }
        __syncthreads();
#pragma unroll
        for (int i=0;i<2;i++)
#pragma unroll
            for (int j=0;j<2;j++)
#pragma unroll
                for (int h=0;h<4;h++) s[t][i][j][h]=0.f;
#pragma unroll
        for (int ks = 0; ks < 64; ks += 8) {
            uint32_t af[2][4], bf[2][2];
#pragma unroll
            for (int i = 0; i < 2; i++) {
                int r = wm*32 + i*16 + g;
                af[i][0] = __float_as_uint(Qs[r][ks+t4]);
                af[i][1] = __float_as_uint(Qs[r+8][ks+t4]);
                af[i][2] = __float_as_uint(Qs[r][ks+t4+4]);
                af[i][3] = __float_as_uint(Qs[r+8][ks+t4+4]);
            }
#pragma unroll
            for (int j = 0; j < 2; j++) {
                int cc = wn*16 + j*8 + g;
                bf[j][0] = __float_as_uint(Ks[cc][ks+t4]);
                bf[j][1] = __float_as_uint(Ks[cc][ks+t4+4]);
            }
#pragma unroll
            for (int i = 0; i < 2; i++)
#pragma unroll
                for (int j = 0; j < 2; j++) {
                    asm volatile(
                        "mma.sync.aligned.m16n8k8.row.col.f32.tf32.tf32.f32 "
                        "{%0,%1,%2,%3}, {%4,%5,%6,%7}, {%8,%9}, {%0,%1,%2,%3};\n"
                        : "+f"(s[t][i][j][0]), "+f"(s[t][i][j][1]),
                          "+f"(s[t][i][j][2]), "+f"(s[t][i][j][3])
                        : "r"(af[i][0]), "r"(af[i][1]), "r"(af[i][2]), "r"(af[i][3]),
                          "r"(bf[j][0]), "r"(bf[j][1]));
                }
        }
        __syncthreads();
    }

    float pm[2][2];
#pragma unroll
    for (int i=0;i<2;i++)
#pragma unroll
        for (int h=0;h<2;h++) {
            float m = s[0][i][0][2*h];
#pragma unroll
            for (int t=0;t<4;t++)
#pragma unroll
                for (int j=0;j<2;j++) {
                    m = fmaxf(m, s[t][i][j][2*h]);
                    m = fmaxf(m, s[t][i][j][2*h+1]);
                }
#pragma unroll
            for (int off = 1; off <= 2; off <<= 1)
                m = fmaxf(m, __shfl_xor_sync(0xffffffffu, m, off));
            pm[i][h] = m;
        }
    if (t4 == 0) {
#pragma unroll
        for (int i=0;i<2;i++)
#pragma unroll
            for (int h=0;h<2;h++)
                redm[wm*32 + i*16 + g + h*8][wn] = pm[i][h];
    }
    __syncthreads();

    float linv[2][2];
    {
        float psum[2][2];
#pragma unroll
        for (int i=0;i<2;i++)
#pragma unroll
            for (int h=0;h<2;h++) {
                int r = wm*32 + i*16 + g + h*8;
                float m = fmaxf(fmaxf(redm[r][0], redm[r][1]),
                                fmaxf(redm[r][2], redm[r][3]));
                float ps = 0.f;
#pragma unroll
                for (int t=0;t<4;t++)
#pragma unroll
                    for (int j=0;j<2;j++) {
                        float p0 = __expf(s[t][i][j][2*h]   - m);
                        float p1 = __expf(s[t][i][j][2*h+1] - m);
                        s[t][i][j][2*h] = p0; s[t][i][j][2*h+1] = p1;
                        ps += p0 + p1;
                    }
#pragma unroll
                for (int off = 1; off <= 2; off <<= 1)
                    ps += __shfl_xor_sync(0xffffffffu, ps, off);
                psum[i][h] = ps;
            }
        if (t4 == 0) {
#pragma unroll
            for (int i=0;i<2;i++)
#pragma unroll
                for (int h=0;h<2;h++)
                    reds[wm*32 + i*16 + g + h*8][wn] = psum[i][h];
        }
        __syncthreads();
#pragma unroll
        for (int i=0;i<2;i++)
#pragma unroll
            for (int h=0;h<2;h++) {
                int r = wm*32 + i*16 + g + h*8;
                linv[i][h] = 1.f / (reds[r][0]+reds[r][1]+reds[r][2]+reds[r][3]);
            }
    }

#pragma unroll
    for (int t = 0; t < 4; t++) {
#pragma unroll
        for (int i=0;i<2;i++)
#pragma unroll
            for (int j=0;j<2;j++)
#pragma unroll
                for (int h=0;h<2;h++) {
                    int r = wm*32 + i*16 + g + h*8;
                    *(float2*)&Ps[r][wn*16 + j*8 + 2*t4] =
                        make_float2(f2tf(s[t][i][j][2*h]), f2tf(s[t][i][j][2*h+1]));
                }
        {
#pragma unroll
            for (int ii = 0; ii < 4; ii++) {
                float4 vv = *(const float4*)&Vb[(size_t)(t*64+lr)*64 + lk + ii*4];
                Vs[lr][lk+ii*4+0]=f2tf(vv.x); Vs[lr][lk+ii*4+1]=f2tf(vv.y);
                Vs[lr][lk+ii*4+2]=f2tf(vv.z); Vs[lr][lk+ii*4+3]=f2tf(vv.w);
            }
        }
        __syncthreads();
#pragma unroll
        for (int ks = 0; ks < 64; ks += 8) {
            uint32_t af[2][4], bf[2][2];
#pragma unroll
            for (int i = 0; i < 2; i++) {
                int r = wm*32 + i*16 + g;
                af[i][0] = __float_as_uint(Ps[r][ks+t4]);
                af[i][1] = __float_as_uint(Ps[r+8][ks+t4]);
                af[i][2] = __float_as_uint(Ps[r][ks+t4+4]);
                af[i][3] = __float_as_uint(Ps[r+8][ks+t4+4]);
            }
#pragma unroll
            for (int j = 0; j < 2; j++) {
                int cc = wn*16 + j*8 + g;
                bf[j][0] = __float_as_uint(Vs[ks+t4][cc]);
                bf[j][1] = __float_as_uint(Vs[ks+t4+4][cc]);
            }
#pragma unroll
            for (int i = 0; i < 2; i++)
#pragma unroll
                for (int j = 0; j < 2; j++) {
                    asm volatile(
                        "mma.sync.aligned.m16n8k8.row.col.f32.tf32.tf32.f32 "
                        "{%0,%1,%2,%3}, {%4,%5,%6,%7}, {%8,%9}, {%0,%1,%2,%3};\n"
                        : "+f"(o[i][j][0]), "+f"(o[i][j][1]),
                          "+f"(o[i][j][2]), "+f"(o[i][j][3])
                        : "r"(af[i][0]), "r"(af[i][1]), "r"(af[i][2]), "r"(af[i][3]),
                          "r"(bf[j][0]), "r"(bf[j][1]));
                }
        }
        __syncthreads();
    }

    // stage O into Ps, then conv with conflict-free (row, dh) mapping
#pragma unroll
    for (int i=0;i<2;i++)
#pragma unroll
        for (int j=0;j<2;j++)
#pragma unroll
            for (int h=0;h<2;h++) {
                int r = wm*32 + i*16 + g + h*8;
                int cc = wn*16 + j*8 + 2*t4;
                *(float2*)&Ps[r][cc] =
                    make_float2(o[i][j][2*h]*linv[i][h], o[i][j][2*h+1]*linv[i][h]);
            }
    __syncthreads();

    {
        int dh = tid & 63;
        int rr0 = tid >> 6;
#pragma unroll
        for (int qq = 0; qq < 16; qq++) {
            int lrow = rr0 + qq*4;
            float acc = Ps[lrow][dh];
#pragma unroll
            for (int ss = 0; ss < 33; ss++) acc += wk[ss]*vt[lrow+ss][dh];
            attn2[((size_t)(b4*4096 + q0 + lrow))*512 + hh*64 + dh] = acc;
        }
    }
}

// ---------------------------------------------------------------------------
// Split-K combine
// ---------------------------------------------------------------------------
__global__ void combine_kernel(const float* __restrict__ Op,
                               const float* __restrict__ mp,
                               const float* __restrict__ lp,
                               float* __restrict__ w) {
    int row = blockIdx.x;
    int c = threadIdx.x;
    int bh = row >> 8, qr = row & 255;
    float m0 = mp[(0*32+bh)*256+qr], m1 = mp[(1*32+bh)*256+qr];
    float m2 = mp[(2*32+bh)*256+qr], m3 = mp[(3*32+bh)*256+qr];
    float ms = fmaxf(fmaxf(m0,m1), fmaxf(m2,m3));
    float w0 = __expf(m0-ms), w1 = __expf(m1-ms), w2 = __expf(m2-ms), w3 = __expf(m3-ms);
    float l = w0*lp[(0*32+bh)*256+qr] + w1*lp[(1*32+bh)*256+qr]
            + w2*lp[(2*32+bh)*256+qr] + w3*lp[(3*32+bh)*256+qr];
    float acc = w0*Op[((size_t)(0*32+bh)*256+qr)*64 + c]
              + w1*Op[((size_t)(1*32+bh)*256+qr)*64 + c]
              + w2*Op[((size_t)(2*32+bh)*256+qr)*64 + c]
              + w3*Op[((size_t)(3*32+bh)*256+qr)*64 + c];
    w[((size_t)bh*256+qr)*64 + c] = acc / l;
}

// ---------------------------------------------------------------------------
// Host orchestration
// ---------------------------------------------------------------------------
extern "C" void kernel_launch(void* const* d_in, const int* in_sizes, int n_in,
                              void* d_out, int out_size) {
    const float* x      = (const float*)d_in[0];
    const float* norm_w = (const float*)d_in[1];
    const float* norm_b = (const float*)d_in[2];
    const float* Wqkv   = (const float*)d_in[3];
    const float* Wout   = (const float*)d_in[4];
    const float* bout   = (const float*)d_in[5];
    const float* conv_w = (const float*)d_in[6];
    float* out = (float*)d_out;

    float *xn,*q,*k,*v,*ql,*kl,*a2,*z0,*t1,*t2,*t3,*w,*w2,*uu,*u5,*attn2,*red;
    float *w4s[5];
    cudaGetSymbolAddress((void**)&xn,   g_xn);
    cudaGetSymbolAddress((void**)&q,    g_q);
    cudaGetSymbolAddress((void**)&k,    g_k);
    cudaGetSymbolAddress((void**)&v,    g_v);
    cudaGetSymbolAddress((void**)&ql,   g_ql);
    cudaGetSymbolAddress((void**)&kl,   g_kl);
    cudaGetSymbolAddress((void**)&a2,   g_a2);
    cudaGetSymbolAddress((void**)&z0,   g_z0);
    cudaGetSymbolAddress((void**)&t1,   g_t1);
    cudaGetSymbolAddress((void**)&t2,   g_t2);
    cudaGetSymbolAddress((void**)&t3,   g_t3);
    cudaGetSymbolAddress((void**)&w4s[0], g_w40);
    cudaGetSymbolAddress((void**)&w4s[1], g_w41);
    cudaGetSymbolAddress((void**)&w4s[2], g_w42);
    cudaGetSymbolAddress((void**)&w4s[3], g_w43);
    cudaGetSymbolAddress((void**)&w4s[4], g_w44);
    cudaGetSymbolAddress((void**)&w,    g_w);
    cudaGetSymbolAddress((void**)&w2,   g_w2);
    cudaGetSymbolAddress((void**)&uu,   g_u);
    cudaGetSymbolAddress((void**)&u5,   g_u5);
    cudaGetSymbolAddress((void**)&attn2,g_attn2);
    cudaGetSymbolAddress((void**)&red,  g_red);

    cudaFuncSetAttribute(flash_tc_kernel, cudaFuncAttributeMaxDynamicSharedMemorySize, SMEM_FLASH_TC);
    cudaFuncSetAttribute(flash2_conv_kernel, cudaFuncAttributeMaxDynamicSharedMemorySize, SMEM_FLASH2);
    cudaFuncSetAttribute(a2_tc_kernel, cudaFuncAttributeMaxDynamicSharedMemorySize, SMEM_A2);

    // 1. LayerNorm
    ln_kernel<<<16384, 128>>>(x, norm_w, norm_b, xn);
    // 2. QKV projection (tf32 MMA, fused scatter + q scale)
    mma_gemm<0,512,1536,512><<<dim3(12,128), 256>>>(
        xn, Wqkv, q, k, v, nullptr, nullptr);
    // 3. landmarks (merged)
    landmark2_kernel<<<4096, 256>>>(q, k, ql, kl);
    // 4. a2 = softmax(q_l k_l^T) (tf32 MMA, 64-row tiles -> 128 CTAs)
    a2_tc_kernel<<<dim3(4,32), 256, SMEM_A2>>>(ql, kl, a2);
    // 5. pinv init scalar (split colsum) + z0 = s*a2^T (smem transpose)
    red_init_kernel<<<1, 32>>>(red);
    colsum_kernel<<<dim3(4,32), 64>>>(a2, red);
    zinit_kernel<<<dim3(8,8,32), dim3(32,8)>>>(a2, red, z0);
    // 6. w = softmax(q_l k^T) @ v — split-K x4 flash + combine
    flash_tc_kernel<<<dim3(4,32,4), 256, SMEM_FLASH_TC>>>(
        ql, k, v, t1, 256, 4096, 1024, t2, t2 + 32768);
    combine_kernel<<<8192, 64>>>(t1, t2, t2 + 32768, w);
    // 7. Newton-Schulz pinv, Y-only recurrence, 128x128 tiles (proven):
    //    W2 = Y(7I-Y); W4_i = Y(15I-W2); Y' = 0.25*Y(13I-W4_i)   [it=0..4]
    mma_gemm_pinv<<<dim3(2,2,32), 256>>>(a2, z0, t1, 0.f, 1.f);   // Y0 = a2 @ z0
    float* Y = t1; float* Yn = t3;
    for (int it = 0; it < 5; it++) {
        mma_gemm_pinv<<<dim3(2,2,32), 256>>>(Y, Y, t2, 7.f, -1.f);        // W2
        mma_gemm_pinv<<<dim3(2,2,32), 256>>>(Y, t2, w4s[it], 15.f, -1.f); // W4_i
        mma_gemm_pinv<<<dim3(2,2,32), 256>>>(Y, w4s[it], Yn, 3.25f, -0.25f);
        float* tmp = Y; Y = Yn; Yn = tmp;
    }
    // Y == Y5. Narrow last iteration (64-row tiles, 128 CTAs):
    // r1 = Y5 w; r2 = Y5 r1; u5 = 13w - 15 r1 + 7 r2 - Y5 r2 (fused EPI=1)
    mma_nar_kernel<0><<<dim3(1,4,32), 256>>>(Y, w,  uu, 0.f, 1.f, nullptr, nullptr); // r1
    mma_nar_kernel<0><<<dim3(1,4,32), 256>>>(Y, uu, w2, 0.f, 1.f, nullptr, nullptr); // r2
    mma_nar_kernel<1><<<dim3(1,4,32), 256>>>(Y, w2, u5, 0.f, 1.f, w, uu);            // u5
    // 8. narrow chain down: u_i = 13*u_{i+1} - W4_i @ u_{i+1}
    mma_nar_kernel<0><<<dim3(1,4,32), 256>>>(w4s[4], u5, uu, 13.f, -1.f, nullptr, nullptr);
    mma_nar_kernel<0><<<dim3(1,4,32), 256>>>(w4s[3], uu, w2, 13.f, -1.f, nullptr, nullptr);
    mma_nar_kernel<0><<<dim3(1,4,32), 256>>>(w4s[2], w2, uu, 13.f, -1.f, nullptr, nullptr);
    mma_nar_kernel<0><<<dim3(1,4,32), 256>>>(w4s[1], uu, w2, 13.f, -1.f, nullptr, nullptr);
    mma_nar_kernel<0><<<dim3(1,4,32), 256>>>(w4s[0], w2, uu, 13.f, -1.f, nullptr, nullptr);
    mma_nar_kernel<0><<<dim3(1,4,32), 256>>>(z0, uu, w2, 0.f, 1.f/4096.f, nullptr, nullptr);
    // 9+10. attn = softmax(q k_l^T) @ w2 with FUSED conv residual + layout
    flash2_conv_kernel<<<dim3(64,32), 256, SMEM_FLASH2>>>(
        q, kl, w2, v, conv_w, attn2);
    // 11. output projection + bias + input residual (tf32 MMA)
    mma_gemm<1,512,512,512><<<dim3(4,128), 256>>>(
        attn2, Wout, out, nullptr, nullptr, bout, x);
}